// round 3
// baseline (speedup 1.0000x reference)
#include <cuda_runtime.h>
#include <math.h>
#include <stdint.h>

#define SQ 4096
#define CHN 1280
#define CC 768
#define NHEAD 8
#define HD 160
#define NCTX 77
#define NCTXP 96
#define NST 9
#define NSTR 8
#define LLOC 257
#define LLOCP 288
#define BK 32
#define STG 3
#define SMEMG (STG * 2 * 4096 * 4)

// ---------------- scratch ----------------
__device__ __align__(256) float g_hsP[2 * SQ * CHN];
__device__ __align__(256) float g_ctxP[NST * NCTX * CC];
__device__ __align__(256) float g_lfP[NSTR * LLOC * CC];
__device__ __align__(256) float g_q2[2 * SQ * CHN];
__device__ __align__(256) float g_k[NST * NCTX * CHN];
__device__ __align__(256) float g_v[NST * NCTX * CHN];
__device__ __align__(256) float g_kg[NSTR * NCTX * CHN];
__device__ __align__(256) float g_vg[NSTR * NCTX * CHN];
__device__ __align__(256) float g_kl[NSTR * LLOC * CHN];
__device__ __align__(256) float g_vl[NSTR * LLOC * CHN];
__device__ __align__(256) float g_WqT[CHN * CHN];
__device__ __align__(256) float g_WkT[CHN * CC];
__device__ __align__(256) float g_WvT[CHN * CC];
__device__ __align__(256) float g_WkgT[CHN * CC];
__device__ __align__(256) float g_WvgT[CHN * CC];
__device__ __align__(256) float g_WklT[CHN * CC];
__device__ __align__(256) float g_WvlT[CHN * CC];
__device__ __align__(256) float g_WoutT[CHN * CHN];
__device__ __align__(256) float g_vT[NST * CHN * NCTXP];
__device__ __align__(256) float g_vlT[NSTR * CHN * LLOCP];
__device__ __align__(256) float g_scg[72 * SQ * NCTXP];
__device__ __align__(256) float g_scl[64L * SQ * LLOCP];
__device__ __align__(256) float g_pre[NST * SQ * CHN];
__device__ __align__(256) float g_mix[SQ * CHN];
__device__ __align__(256) float g_out2[2 * SQ * CHN];
__device__ float g_mraw[NSTR * NHEAD * SQ];
__device__ float g_mmax[NSTR];
__device__ float g_sumw[SQ];

__device__ const float* d_Ap[320];
__device__ const float* d_Bp[320];
__device__ float*       d_Cp[320];

// ---------------- helpers ----------------
// pair-permutation within each 8-group of the K dim: logical c -> physical pp8(c)
__device__ __forceinline__ int pp8(int c) {
    int b = c & 7;
    return (c & ~7) + ((b < 4) ? (b << 1) : (((b - 4) << 1) + 1));
}
// inverse: physical p -> logical
__device__ __forceinline__ int up8(int p) {
    int b = p & 7;
    return (p & ~7) + ((b & 1) ? ((b >> 1) + 4) : (b >> 1));
}
__device__ __forceinline__ float tfr(float x) {
    uint32_t r;
    asm("cvt.rna.tf32.f32 %0, %1;" : "=r"(r) : "f"(x));
    return __uint_as_float(r);
}
__device__ __forceinline__ void cp16(float* sdst, const float* gsrc, bool p) {
    uint32_t sa = (uint32_t)__cvta_generic_to_shared(sdst);
    int sz = p ? 16 : 0;
    asm volatile("cp.async.cg.shared.global [%0], [%1], 16, %2;" :: "r"(sa), "l"(gsrc), "r"(sz));
}
#define CP_COMMIT asm volatile("cp.async.commit_group;")
__device__ __forceinline__ void mma8(float* c, const uint32_t* a, const uint32_t* b) {
    asm volatile(
        "mma.sync.aligned.m16n8k8.row.col.f32.tf32.tf32.f32 "
        "{%0,%1,%2,%3}, {%4,%5,%6,%7}, {%8,%9}, {%0,%1,%2,%3};"
        : "+f"(c[0]), "+f"(c[1]), "+f"(c[2]), "+f"(c[3])
        : "r"(a[0]), "r"(a[1]), "r"(a[2]), "r"(a[3]), "r"(b[0]), "r"(b[1]));
}

// ---------------- setup: batch pointer tables ----------------
__global__ void setup_k() {
    int z = threadIdx.x;
    if (z == 0) {
        d_Ap[0] = g_hsP;               d_Bp[0] = g_WqT;   d_Cp[0] = g_q2;
        d_Ap[1] = g_ctxP;              d_Bp[1] = g_WkT;   d_Cp[1] = g_k;
        d_Ap[2] = g_ctxP;              d_Bp[2] = g_WvT;   d_Cp[2] = g_v;
        d_Ap[3] = g_ctxP + NCTX * CC;  d_Bp[3] = g_WkgT;  d_Cp[3] = g_kg;
        d_Ap[4] = g_ctxP + NCTX * CC;  d_Bp[4] = g_WvgT;  d_Cp[4] = g_vg;
        d_Ap[5] = g_lfP;               d_Bp[5] = g_WklT;  d_Cp[5] = g_kl;
        d_Ap[6] = g_lfP;               d_Bp[6] = g_WvlT;  d_Cp[6] = g_vl;
        d_Ap[7] = g_pre;               d_Bp[7] = g_WoutT; d_Cp[7] = g_out2;
        d_Ap[8] = g_mix;               d_Bp[8] = g_WoutT; d_Cp[8] = g_out2 + (size_t)SQ * CHN;
    }
    if (z < 72) {
        d_Ap[16 + z] = g_q2 + (z >= 8 ? (size_t)SQ * CHN : 0) + (z & 7) * HD;
        d_Bp[16 + z] = g_k + (size_t)(z >> 3) * NCTX * CHN + (z & 7) * HD;
        d_Cp[16 + z] = g_scg + (size_t)z * SQ * NCTXP;
        d_Ap[96 + z] = g_scg + (size_t)z * SQ * NCTXP;
        d_Bp[96 + z] = g_vT + (size_t)(z >> 3) * CHN * NCTXP + (z & 7) * HD * NCTXP;
        d_Cp[96 + z] = g_pre + (size_t)(z >> 3) * SQ * CHN + (z & 7) * HD;
    }
    if (z < 64) {
        d_Ap[176 + z] = g_q2 + (size_t)SQ * CHN + (z & 7) * HD;
        d_Bp[176 + z] = g_kl + (size_t)(z >> 3) * LLOC * CHN + (z & 7) * HD;
        d_Cp[176 + z] = g_scl + (size_t)z * SQ * LLOCP;
        d_Ap[240 + z] = g_scl + (size_t)z * SQ * LLOCP;
        d_Bp[240 + z] = g_vlT + (size_t)(z >> 3) * CHN * LLOCP + (z & 7) * HD * LLOCP;
        d_Cp[240 + z] = g_pre + (size_t)((z >> 3) + 1) * SQ * CHN + (z & 7) * HD;
    }
}

// ---------------- round + pair-permute pass (inputs) ----------------
__global__ void roundperm_k(const float* __restrict__ src, float* __restrict__ dst,
                            long long n, int cols) {
    long long i = (long long)blockIdx.x * blockDim.x + threadIdx.x;
    if (i >= n) return;
    int c = (int)(i % cols);
    long long r = i / cols;
    dst[r * cols + pp8(c)] = tfr(src[i]);
}

// --------- transpose: dst[drow][pp8(rr)] = src[rr][cc], zero-fill pads --------
__global__ void transpose_k(const float* __restrict__ src, float* __restrict__ dst,
                            int R, int C, int ldS, int ldD, long long sBS, long long dBS,
                            int permRow, int rnd) {
    __shared__ float t[32][33];
    src += blockIdx.z * sBS;
    dst += blockIdx.z * dBS;
    int c0 = blockIdx.x << 5, r0 = blockIdx.y << 5;
    int tx = threadIdx.x, ty = threadIdx.y;
#pragma unroll
    for (int j = 0; j < 4; j++) {
        int rr = r0 + ty + j * 8, cc = c0 + tx;
        t[ty + j * 8][tx] = (rr < R && cc < C) ? src[(size_t)rr * ldS + cc] : 0.f;
    }
    __syncthreads();
#pragma unroll
    for (int j = 0; j < 4; j++) {
        int cc = c0 + ty + j * 8, rr = r0 + tx;
        if (cc < C && rr < ldD) {
            int drow = permRow ? pp8(cc) : cc;
            float v = t[tx][ty + j * 8];
            dst[(size_t)drow * ldD + pp8(rr)] = rnd ? tfr(v) : v;
        }
    }
}

// ---------------- batched NT tf32 GEMM, BK=32, 3-stage pipeline ----------------
// mode: 1=round output (tf32), 2=blend (0.5*C + acc), 4=permute store columns
__global__ void __launch_bounds__(256) gemm_tf32(int slot, int M, int N, int K,
                                                 int lda, int ldb, int ldc, int mode) {
    extern __shared__ float sm[];
    float* As = sm;
    float* Bs = sm + STG * 4096;
    const float* Ab = d_Ap[slot + blockIdx.z];
    const float* Bb = d_Bp[slot + blockIdx.z];
    float* Cm = d_Cp[slot + blockIdx.z];
    int tid = threadIdx.x, lane = tid & 31, warp = tid >> 5;
    int mBase = blockIdx.y << 7, nBase = blockIdx.x << 7;
    int mW = (warp >> 2) << 6, nW = (warp & 3) << 5;
    float acc[4][4][4];
#pragma unroll
    for (int a = 0; a < 4; a++)
#pragma unroll
        for (int b = 0; b < 4; b++)
#pragma unroll
            for (int cI = 0; cI < 4; cI++) acc[a][b][cI] = 0.f;

    // staging: 2 rows per thread-pair, 4 x 16B units each
    int sRow = tid >> 1;
    int aRowG = mBase + sRow; bool pa = aRowG < M; if (!pa) aRowG = M - 1;
    int bRowG = nBase + sRow; bool pb = bRowG < N; if (!pb) bRowG = N - 1;
    const float* aSrc = Ab + (size_t)aRowG * lda + ((tid & 1) << 4);
    const float* bSrc = Bb + (size_t)bRowG * ldb + ((tid & 1) << 4);
    int upo[4];
#pragma unroll
    for (int j = 0; j < 4; j++) {
        int u = ((tid & 1) << 2) + j;
        upo[j] = (((((u >> 1) ^ (sRow & 3)) << 1) + (u & 1)) << 2);  // float offset
    }
    float* aDst = As + sRow * 32;
    float* bDst = Bs + sRow * 32;
    int KT = K / BK;

    auto issue = [&](int stage, int kt) {
        int k0 = kt * BK;
        float* ad = aDst + stage * 4096;
        float* bd = bDst + stage * 4096;
#pragma unroll
        for (int j = 0; j < 4; j++) {
            cp16(ad + upo[j], aSrc + k0 + j * 4, pa);
            cp16(bd + upo[j], bSrc + k0 + j * 4, pb);
        }
        CP_COMMIT;
    };
    for (int s = 0; s < STG - 1 && s < KT; s++) issue(s, s);

    int q = lane >> 2, c2 = (lane & 3) << 1;
    int goff[4];
#pragma unroll
    for (int kk = 0; kk < 4; kk++) goff[kk] = ((kk ^ (q & 3)) << 3) + c2;

    for (int kt = 0; kt < KT; kt++) {
        if (kt == KT - 1) { asm volatile("cp.async.wait_group 0;"); }
        else              { asm volatile("cp.async.wait_group 1;"); }
        __syncthreads();
        int pf = kt + STG - 1;
        if (pf < KT) issue(pf % STG, pf);
        const float* pA = As + (kt % STG) * 4096;
        const float* pB = Bs + (kt % STG) * 4096;
#pragma unroll
        for (int kk = 0; kk < 4; kk++) {
            uint32_t af[4][4], bf[4][2];
#pragma unroll
            for (int mi = 0; mi < 4; mi++) {
                const float* base = pA + (mW + (mi << 4) + q) * 32 + goff[kk];
                float2 lo = *(const float2*)base;
                float2 hi = *(const float2*)(base + 256);  // +8 rows
                af[mi][0] = __float_as_uint(lo.x); af[mi][1] = __float_as_uint(hi.x);
                af[mi][2] = __float_as_uint(lo.y); af[mi][3] = __float_as_uint(hi.y);
            }
#pragma unroll
            for (int ni = 0; ni < 4; ni++) {
                const float* base = pB + (nW + (ni << 3) + q) * 32 + goff[kk];
                float2 b = *(const float2*)base;
                bf[ni][0] = __float_as_uint(b.x); bf[ni][1] = __float_as_uint(b.y);
            }
#pragma unroll
            for (int mi = 0; mi < 4; mi++)
#pragma unroll
                for (int ni = 0; ni < 4; ni++) mma8(acc[mi][ni], af[mi], bf[ni]);
        }
    }

    int rnd = mode & 1, blend = mode & 2, permN = mode & 4;
#pragma unroll
    for (int mi = 0; mi < 4; mi++) {
#pragma unroll
        for (int half = 0; half < 2; half++) {
            int gm = mBase + mW + (mi << 4) + q + half * 8;
            if (gm >= M) continue;
            float* crow = Cm + (size_t)gm * ldc;
#pragma unroll
            for (int ni = 0; ni < 4; ni++) {
                int gn = nBase + nW + (ni << 3) + c2;
                float v0 = acc[mi][ni][half * 2], v1 = acc[mi][ni][half * 2 + 1];
                int p0 = permN ? pp8(gn) : gn;
                int stp = permN ? 2 : 1;
                if (gn < N) {
                    float o = v0;
                    if (blend) o = 0.5f * crow[p0] + o;
                    if (rnd) o = tfr(o);
                    crow[p0] = o;
                }
                if (gn + 1 < N) {
                    float o = v1;
                    if (blend) o = 0.5f * crow[p0 + stp] + o;
                    if (rnd) o = tfr(o);
                    crow[p0 + stp] = o;
                }
            }
        }
    }
}

// ---------------- ELITE K/V select ----------------
__global__ void kv_select_k(const int* __restrict__ lidx) {
    int idx = blockIdx.x * 256 + threadIdx.x;
    const int tot = NSTR * NCTX * CHN;
    if (idx >= tot) return;
    int st = idx / (NCTX * CHN);
    if (lidx[st] >= 0) {
        g_k[NCTX * CHN + idx] = g_kg[idx];
        g_v[NCTX * CHN + idx] = g_vg[idx];
    }
}

// ---------------- global softmax (positional, 96 slots) + gate gather ----------
__global__ void __launch_bounds__(256) softmax_g_k(const int* __restrict__ lidx) {
    __shared__ int spos[8];
    if (threadIdx.x < 8) spos[threadIdx.x] = pp8(lidx[threadIdx.x]);
    __syncthreads();
    int bh = blockIdx.y;
    int w = threadIdx.x >> 5, lane = threadIdx.x & 31;
    int s = blockIdx.x * 8 + w;
    float* row = g_scg + ((size_t)bh * SQ + s) * NCTXP;
    const float scale = 0.07905694150420949f;
    int p2 = 64 + lane;
    bool v2 = up8(p2) < NCTX;
    float x0 = row[lane], x1 = row[32 + lane];
    float x2 = v2 ? row[p2] : -1e30f;
    float m = fmaxf(fmaxf(x0, x1), x2);
#pragma unroll
    for (int o = 16; o; o >>= 1) m = fmaxf(m, __shfl_xor_sync(0xffffffffu, m, o));
    float e0 = __expf((x0 - m) * scale);
    float e1 = __expf((x1 - m) * scale);
    float e2 = v2 ? __expf((x2 - m) * scale) : 0.f;
    float ss = e0 + e1 + e2;
#pragma unroll
    for (int o = 16; o; o >>= 1) ss += __shfl_xor_sync(0xffffffffu, ss, o);
    float inv = 1.f / ss;
    e0 *= inv; e1 *= inv; e2 *= inv;
    row[lane] = tfr(e0);
    row[32 + lane] = tfr(e1);
    row[p2] = v2 ? tfr(e2) : 0.f;
    if (bh < 8) {
#pragma unroll
        for (int i = 0; i < 8; i++) {
            int pos = spos[i];
            int seg = pos >> 5, src = pos & 31;
            float cand = (seg == 0) ? e0 : ((seg == 1) ? e1 : e2);
            float v = __shfl_sync(0xffffffffu, cand, src);
            if (lane == 0) g_mraw[((size_t)i * NHEAD + bh) * SQ + s] = v;
        }
    }
}

// ---------------- per-instance gate max ----------------
__global__ void mmax_k() {
    __shared__ float red[256];
    int i = blockIdx.x;
    float mx = 0.f;
    const float* p = g_mraw + (size_t)i * NHEAD * SQ;
    for (int idx = threadIdx.x; idx < NHEAD * SQ; idx += 256) mx = fmaxf(mx, p[idx]);
    red[threadIdx.x] = mx;
    __syncthreads();
    for (int s = 128; s > 0; s >>= 1) {
        if (threadIdx.x < s) red[threadIdx.x] = fmaxf(red[threadIdx.x], red[threadIdx.x + s]);
        __syncthreads();
    }
    if (threadIdx.x == 0) g_mmax[i] = red[0];
}

// ---------------- local softmax (positional, 288 slots), gate folded ----------
__global__ void __launch_bounds__(256) softmax_l_k() {
    int z = blockIdx.y;
    int w = threadIdx.x >> 5, lane = threadIdx.x & 31;
    int s = blockIdx.x * 8 + w;
    float* row = g_scl + ((size_t)z * SQ + s) * LLOCP;
    const float scale = 0.07905694150420949f;
    float x[9];
    bool val[9];
#pragma unroll
    for (int j = 0; j < 9; j++) {
        int p = j * 32 + lane;
        val[j] = up8(p) < LLOC;
        x[j] = val[j] ? row[p] : -1e30f;
    }
    float m = -1e30f;
#pragma unroll
    for (int j = 0; j < 9; j++) m = fmaxf(m, x[j]);
#pragma unroll
    for (int o = 16; o; o >>= 1) m = fmaxf(m, __shfl_xor_sync(0xffffffffu, m, o));
    float ss = 0.f;
#pragma unroll
    for (int j = 0; j < 9; j++) {
        x[j] = val[j] ? __expf((x[j] - m) * scale) : 0.f;
        ss += x[j];
    }
#pragma unroll
    for (int o = 16; o; o >>= 1) ss += __shfl_xor_sync(0xffffffffu, ss, o);
    float gate = 0.5f * g_mraw[(size_t)z * SQ + s] / g_mmax[z >> 3];
    float f = gate / ss;
#pragma unroll
    for (int j = 0; j < 9; j++) row[j * 32 + lane] = tfr(x[j] * f);
}

// ---------------- fuser premix ----------------
__global__ void premix_k(const float* __restrict__ bbox) {
    int s = blockIdx.x;
    int y = s >> 6, x = s & 63;
    float wgt[8];
    wgt[0] = 1.f;
    float sw = 1.f;
    const int off[4] = {3, 4, 11, 12};
#pragma unroll
    for (int i = 0; i < 7; i++) {
        float wmin = floorf(1024.f * bbox[i * 4 + 0]);
        float hmin = floorf(1024.f * bbox[i * 4 + 1]);
        float wmax = floorf(1024.f * bbox[i * 4 + 2]);
        float hmax = floorf(1024.f * bbox[i * 4 + 3]);
        float R = 0.f, Cv = 0.f;
#pragma unroll
        for (int j = 0; j < 4; j++) {
            float yy = (float)(16 * y + off[j]);
            float xx = (float)(16 * x + off[j]);
            if (yy >= hmin && yy < hmax) R += 0.25f;
            if (xx >= wmin && xx < wmax) Cv += 0.25f;
        }
        float g = 10.f * R * Cv;
        wgt[i + 1] = g;
        sw += g;
    }
    if (threadIdx.x == 0) g_sumw[s] = sw;
    for (int c = threadIdx.x; c < CHN; c += 256) {
        float acc = 0.f;
#pragma unroll
        for (int j = 0; j < 8; j++) acc += wgt[j] * g_pre[((size_t)(1 + j) * SQ + s) * CHN + c];
        g_mix[(size_t)s * CHN + c] = tfr(acc);
    }
}

// ---------------- final ----------------
__global__ void final_k(const float* __restrict__ bout, float* __restrict__ out) {
    int s = blockIdx.x;
    float sw = g_sumw[s];
    float den = 1.f / (sw + 1e-6f);
    for (int c = threadIdx.x; c < CHN; c += 256) {
        float b = bout[c];
        out[(size_t)s * CHN + c] = g_out2[(size_t)s * CHN + c] + b;
        out[(size_t)(SQ + s) * CHN + c] = (g_out2[(size_t)(SQ + s) * CHN + c] + b * sw) * den;
    }
}

// ---------------- launch ----------------
extern "C" void kernel_launch(void* const* d_in, const int* in_sizes, int n_in,
                              void* d_out, int out_size) {
    const float* hs   = (const float*)d_in[0];
    const float* ctx  = (const float*)d_in[1];
    const float* lf   = (const float*)d_in[2];
    const float* bbox = (const float*)d_in[3];
    const float* Wq   = (const float*)d_in[4];
    const float* Wk   = (const float*)d_in[5];
    const float* Wv   = (const float*)d_in[6];
    const float* Wkg  = (const float*)d_in[7];
    const float* Wvg  = (const float*)d_in[8];
    const float* Wkl  = (const float*)d_in[9];
    const float* Wvl  = (const float*)d_in[10];
    const float* Wout = (const float*)d_in[11];
    const float* bout = (const float*)d_in[12];
    const int*   lidx = (const int*)d_in[13];
    float* out = (float*)d_out;

    float *hsP, *ctxP, *lfP, *WqT, *WkT, *WvT, *WkgT, *WvgT, *WklT, *WvlT, *WoutT;
    float *vp, *vTp, *vlp, *vlTp;
    cudaGetSymbolAddress((void**)&hsP, g_hsP);
    cudaGetSymbolAddress((void**)&ctxP, g_ctxP);
    cudaGetSymbolAddress((void**)&lfP, g_lfP);
    cudaGetSymbolAddress((void**)&WqT, g_WqT);
    cudaGetSymbolAddress((void**)&WkT, g_WkT);
    cudaGetSymbolAddress((void**)&WvT, g_WvT);
    cudaGetSymbolAddress((void**)&WkgT, g_WkgT);
    cudaGetSymbolAddress((void**)&WvgT, g_WvgT);
    cudaGetSymbolAddress((void**)&WklT, g_WklT);
    cudaGetSymbolAddress((void**)&WvlT, g_WvlT);
    cudaGetSymbolAddress((void**)&WoutT, g_WoutT);
    cudaGetSymbolAddress((void**)&vp, g_v);
    cudaGetSymbolAddress((void**)&vTp, g_vT);
    cudaGetSymbolAddress((void**)&vlp, g_vl);
    cudaGetSymbolAddress((void**)&vlTp, g_vlT);

    cudaFuncSetAttribute(gemm_tf32, cudaFuncAttributeMaxDynamicSharedMemorySize, SMEMG);

    dim3 tb(32, 8);
    setup_k<<<1, 256>>>();

    // pre-round + pair-permute raw inputs
    long long nHs = 2LL * SQ * CHN, nCtx = (long long)NST * NCTX * CC, nLf = (long long)NSTR * LLOC * CC;
    roundperm_k<<<(int)((nHs + 255) / 256), 256>>>(hs, hsP, nHs, CHN);
    roundperm_k<<<(int)((nCtx + 255) / 256), 256>>>(ctx, ctxP, nCtx, CC);
    roundperm_k<<<(int)((nLf + 255) / 256), 256>>>(lf, lfP, nLf, CC);

    // weight transposes: permuted K-dim, permuted out rows (except Wout), rounded
    transpose_k<<<dim3(40, 40, 1), tb>>>(Wq, WqT, CHN, CHN, CHN, CHN, 0, 0, 1, 1);
    transpose_k<<<dim3(40, 24, 1), tb>>>(Wk, WkT, CC, CHN, CHN, CC, 0, 0, 1, 1);
    transpose_k<<<dim3(40, 24, 1), tb>>>(Wv, WvT, CC, CHN, CHN, CC, 0, 0, 1, 1);
    transpose_k<<<dim3(40, 24, 1), tb>>>(Wkg, WkgT, CC, CHN, CHN, CC, 0, 0, 1, 1);
    transpose_k<<<dim3(40, 24, 1), tb>>>(Wvg, WvgT, CC, CHN, CHN, CC, 0, 0, 1, 1);
    transpose_k<<<dim3(40, 24, 1), tb>>>(Wkl, WklT, CC, CHN, CHN, CC, 0, 0, 1, 1);
    transpose_k<<<dim3(40, 24, 1), tb>>>(Wvl, WvlT, CC, CHN, CHN, CC, 0, 0, 1, 1);
    transpose_k<<<dim3(40, 40, 1), tb>>>(Wout, WoutT, CHN, CHN, CHN, CHN, 0, 0, 0, 1);

    // projections (round outputs)
    gemm_tf32<<<dim3(10, 64, 1), 256, SMEMG>>>(0, 2 * SQ, CHN, CHN, CHN, CHN, CHN, 1);
    gemm_tf32<<<dim3(10, 6, 1), 256, SMEMG>>>(1, NST * NCTX, CHN, CC, CC, CC, CHN, 1);
    gemm_tf32<<<dim3(10, 6, 1), 256, SMEMG>>>(2, NST * NCTX, CHN, CC, CC, CC, CHN, 1);
    gemm_tf32<<<dim3(10, 5, 1), 256, SMEMG>>>(3, NSTR * NCTX, CHN, CC, CC, CC, CHN, 1);
    gemm_tf32<<<dim3(10, 5, 1), 256, SMEMG>>>(4, NSTR * NCTX, CHN, CC, CC, CC, CHN, 1);
    gemm_tf32<<<dim3(10, 17, 1), 256, SMEMG>>>(5, NSTR * LLOC, CHN, CC, CC, CC, CHN, 1);
    gemm_tf32<<<dim3(10, 17, 1), 256, SMEMG>>>(6, NSTR * LLOC, CHN, CC, CC, CC, CHN, 1);
    kv_select_k<<<(NSTR * NCTX * CHN + 255) / 256, 256>>>(lidx);

    // V transposes for PV (keys permuted; channels already in permuted space)
    transpose_k<<<dim3(40, 3, NST), tb>>>(vp, vTp, NCTX, CHN, CHN, NCTXP,
                                          (long long)NCTX * CHN, (long long)CHN * NCTXP, 0, 0);
    transpose_k<<<dim3(40, 9, NSTR), tb>>>(vlp, vlTp, LLOC, CHN, CHN, LLOCP,
                                           (long long)LLOC * CHN, (long long)CHN * LLOCP, 0, 0);

    // global attention
    gemm_tf32<<<dim3(1, 32, 72), 256, SMEMG>>>(16, SQ, NCTX, HD, CHN, CHN, NCTXP, 4);
    softmax_g_k<<<dim3(512, 72), 256>>>(lidx);
    mmax_k<<<8, 256>>>();
    gemm_tf32<<<dim3(2, 32, 72), 256, SMEMG>>>(96, SQ, HD, NCTXP, NCTXP, NCTXP, CHN, 1);

    // local attention
    gemm_tf32<<<dim3(3, 32, 64), 256, SMEMG>>>(176, SQ, LLOC, HD, CHN, CHN, LLOCP, 4);
    softmax_l_k<<<dim3(512, 64), 256>>>();
    gemm_tf32<<<dim3(2, 32, 64), 256, SMEMG>>>(240, SQ, HD, LLOCP, LLOCP, LLOCP, CHN, 3);

    // fuser premix + output projection
    premix_k<<<SQ, 256>>>(bbox);
    gemm_tf32<<<dim3(10, 32, 1), 256, SMEMG>>>(7, SQ, CHN, CHN, CHN, CHN, CHN, 0);
    gemm_tf32<<<dim3(10, 32, 1), 256, SMEMG>>>(8, SQ, CHN, CHN, CHN, CHN, CHN, 0);
    final_k<<<SQ, 256>>>(bout, out);
}

// round 4
// speedup vs baseline: 1.2112x; 1.2112x over previous
#include <cuda_runtime.h>
#include <math.h>
#include <stdint.h>

#define SQ 4096
#define CHN 1280
#define CC 768
#define NHEAD 8
#define HD 160
#define NCTX 77
#define NCTXP 80
#define NST 9
#define NSTR 8
#define LLOC 257
#define LLOCP 272

// ---------------- scratch ----------------
__device__ __align__(256) float g_hsR[2 * SQ * CHN];
__device__ __align__(256) float g_ctxR[NST * NCTX * CC];
__device__ __align__(256) float g_lfR[NSTR * LLOC * CC];
__device__ __align__(256) float g_q2[2 * SQ * CHN];
__device__ __align__(256) float g_k[NST * NCTX * CHN];
__device__ __align__(256) float g_v[NST * NCTX * CHN];
__device__ __align__(256) float g_kg[NSTR * NCTX * CHN];
__device__ __align__(256) float g_vg[NSTR * NCTX * CHN];
__device__ __align__(256) float g_kl[NSTR * LLOC * CHN];
__device__ __align__(256) float g_vl[NSTR * LLOC * CHN];
__device__ __align__(256) float g_WqT[CHN * CHN];
__device__ __align__(256) float g_WkT[CHN * CC];
__device__ __align__(256) float g_WvT[CHN * CC];
__device__ __align__(256) float g_WkgT[CHN * CC];
__device__ __align__(256) float g_WvgT[CHN * CC];
__device__ __align__(256) float g_WklT[CHN * CC];
__device__ __align__(256) float g_WvlT[CHN * CC];
__device__ __align__(256) float g_WoutT[CHN * CHN];
__device__ __align__(256) float g_vT[NST * CHN * NCTXP];
__device__ __align__(256) float g_vlT[NSTR * CHN * LLOCP];
__device__ __align__(256) float g_scg[72 * SQ * NCTXP];
__device__ __align__(256) float g_scl[64L * SQ * LLOCP];
__device__ __align__(256) float g_pre[NST * SQ * CHN];
__device__ __align__(256) float g_mix[SQ * CHN];
__device__ __align__(256) float g_out2[2 * SQ * CHN];
__device__ float g_mraw[NSTR * NHEAD * SQ];
__device__ float g_mmax[NSTR];
__device__ float g_sumw[SQ];

__device__ const float* d_Ap[320];
__device__ const float* d_Bp[320];
__device__ float*       d_Cp[320];
__device__ int          d_Mt[320];

// ---------------- helpers ----------------
__device__ __forceinline__ float tfr(float x) {
    uint32_t r;
    asm("cvt.rna.tf32.f32 %0, %1;" : "=r"(r) : "f"(x));
    return __uint_as_float(r);
}
__device__ __forceinline__ void cp16(float* sdst, const float* gsrc, bool p) {
    uint32_t sa = (uint32_t)__cvta_generic_to_shared(sdst);
    int sz = p ? 16 : 0;
    asm volatile("cp.async.cg.shared.global [%0], [%1], 16, %2;" :: "r"(sa), "l"(gsrc), "r"(sz));
}
#define CP_COMMIT asm volatile("cp.async.commit_group;")
__device__ __forceinline__ void mma8(float* c, const uint32_t* a, const uint32_t* b) {
    asm volatile(
        "mma.sync.aligned.m16n8k8.row.col.f32.tf32.tf32.f32 "
        "{%0,%1,%2,%3}, {%4,%5,%6,%7}, {%8,%9}, {%0,%1,%2,%3};"
        : "+f"(c[0]), "+f"(c[1]), "+f"(c[2]), "+f"(c[3])
        : "r"(a[0]), "r"(a[1]), "r"(a[2]), "r"(a[3]), "r"(b[0]), "r"(b[1]));
}
// swizzled smem offset for [128][16] tile, conflict-free fragment reads
#define SWOFF(r, c) (((r) << 4) + ((((((c) >> 2) ^ (((r) >> 1) & 3))) << 2) | ((c) & 3)))

// ---------------- setup: batch pointer + M tables ----------------
__global__ void setup_k() {
    int z = threadIdx.x;
    if (z == 0) {
        d_Ap[0] = g_hsR;               d_Bp[0] = g_WqT;   d_Cp[0] = g_q2;    d_Mt[0] = 2 * SQ;
        d_Ap[1] = g_ctxR;              d_Bp[1] = g_WkT;   d_Cp[1] = g_k;     d_Mt[1] = NST * NCTX;
        d_Ap[2] = g_ctxR;              d_Bp[2] = g_WvT;   d_Cp[2] = g_v;     d_Mt[2] = NST * NCTX;
        d_Ap[3] = g_ctxR + NCTX * CC;  d_Bp[3] = g_WkgT;  d_Cp[3] = g_kg;    d_Mt[3] = NSTR * NCTX;
        d_Ap[4] = g_ctxR + NCTX * CC;  d_Bp[4] = g_WvgT;  d_Cp[4] = g_vg;    d_Mt[4] = NSTR * NCTX;
        d_Ap[5] = g_lfR;               d_Bp[5] = g_WklT;  d_Cp[5] = g_kl;    d_Mt[5] = NSTR * LLOC;
        d_Ap[6] = g_lfR;               d_Bp[6] = g_WvlT;  d_Cp[6] = g_vl;    d_Mt[6] = NSTR * LLOC;
        d_Ap[7] = g_pre;               d_Bp[7] = g_WoutT; d_Cp[7] = g_out2;  d_Mt[7] = SQ;
        d_Ap[8] = g_mix;               d_Bp[8] = g_WoutT; d_Cp[8] = g_out2 + (size_t)SQ * CHN;
        d_Mt[8] = SQ;
    }
    if (z < 72) {
        d_Ap[16 + z] = g_q2 + (z >= 8 ? (size_t)SQ * CHN : 0) + (z & 7) * HD;
        d_Bp[16 + z] = g_k + (size_t)(z >> 3) * NCTX * CHN + (z & 7) * HD;
        d_Cp[16 + z] = g_scg + (size_t)z * SQ * NCTXP;
        d_Mt[16 + z] = SQ;
        d_Ap[96 + z] = g_scg + (size_t)z * SQ * NCTXP;
        d_Bp[96 + z] = g_vT + (size_t)(z >> 3) * CHN * NCTXP + (z & 7) * HD * NCTXP;
        d_Cp[96 + z] = g_pre + (size_t)(z >> 3) * SQ * CHN + (z & 7) * HD;
        d_Mt[96 + z] = SQ;
    }
    if (z < 64) {
        d_Ap[176 + z] = g_q2 + (size_t)SQ * CHN + (z & 7) * HD;
        d_Bp[176 + z] = g_kl + (size_t)(z >> 3) * LLOC * CHN + (z & 7) * HD;
        d_Cp[176 + z] = g_scl + (size_t)z * SQ * LLOCP;
        d_Mt[176 + z] = SQ;
        d_Ap[240 + z] = g_scl + (size_t)z * SQ * LLOCP;
        d_Bp[240 + z] = g_vlT + (size_t)(z >> 3) * CHN * LLOCP + (z & 7) * HD * LLOCP;
        d_Cp[240 + z] = g_pre + (size_t)((z >> 3) + 1) * SQ * CHN + (z & 7) * HD;
        d_Mt[240 + z] = SQ;
    }
}

// ---------------- round pass (inputs -> tf32 values) ----------------
__global__ void round_k(const float* __restrict__ src, float* __restrict__ dst, long long n) {
    long long i = ((long long)blockIdx.x * blockDim.x + threadIdx.x) * 4;
    if (i + 3 < n) {
        float4 v = *(const float4*)(src + i);
        v.x = tfr(v.x); v.y = tfr(v.y); v.z = tfr(v.z); v.w = tfr(v.w);
        *(float4*)(dst + i) = v;
    } else {
        for (long long j = i; j < n; j++) dst[j] = tfr(src[j]);
    }
}

// ---------------- transpose: dst[c][r] = src[r][c], zero-fill r in [R, ldD) ---
__global__ void transpose_k(const float* __restrict__ src, float* __restrict__ dst,
                            int R, int C, int ldS, int ldD, long long sBS, long long dBS,
                            int rnd) {
    __shared__ float t[32][33];
    src += blockIdx.z * sBS;
    dst += blockIdx.z * dBS;
    int c0 = blockIdx.x << 5, r0 = blockIdx.y << 5;
    int tx = threadIdx.x, ty = threadIdx.y;
#pragma unroll
    for (int j = 0; j < 4; j++) {
        int rr = r0 + ty + j * 8, cc = c0 + tx;
        t[ty + j * 8][tx] = (rr < R && cc < C) ? src[(size_t)rr * ldS + cc] : 0.f;
    }
    __syncthreads();
#pragma unroll
    for (int j = 0; j < 4; j++) {
        int cc = c0 + ty + j * 8, rr = r0 + tx;
        if (cc < C && rr < ldD) {
            float v = t[tx][ty + j * 8];
            dst[(size_t)cc * ldD + rr] = rnd ? tfr(v) : v;
        }
    }
}

// ---------------- batched NT tf32 GEMM (operands pre-rounded) -----------------
// mode bits: 1 = round output to tf32, 2 = blend (0.5*C + acc)
__global__ void __launch_bounds__(256) gemm_tf32(int slot, int N, int K,
                                                 int lda, int ldb, int ldc, int mode) {
    const float* Ab = d_Ap[slot + blockIdx.z];
    const float* Bb = d_Bp[slot + blockIdx.z];
    float* Cm       = d_Cp[slot + blockIdx.z];
    const int M     = d_Mt[slot + blockIdx.z];
    __shared__ __align__(16) float As[2][128 * 16];
    __shared__ __align__(16) float Bs[2][128 * 16];
    int tid = threadIdx.x, lane = tid & 31, warp = tid >> 5;
    int mBase = blockIdx.y << 7, nBase = blockIdx.x << 7;
    int mW = (warp >> 2) << 6, nW = (warp & 3) << 5;
    float acc[4][4][4];
#pragma unroll
    for (int a = 0; a < 4; a++)
#pragma unroll
        for (int b = 0; b < 4; b++)
#pragma unroll
            for (int cidx = 0; cidx < 4; cidx++) acc[a][b][cidx] = 0.f;

    const int lr = tid >> 2, lc4 = tid & 3;
    int KT = K >> 4;
    // prologue: stage 0
#pragma unroll
    for (int i = 0; i < 2; i++) {
        int r = lr + (i << 6);
        int gr = mBase + r; bool pa = gr < M; if (!pa) gr = M - 1;
        cp16(&As[0][SWOFF(r, lc4 << 2)], Ab + (size_t)gr * lda + (lc4 << 2), pa);
        int gn = nBase + r; bool pb = gn < N; if (!pb) gn = N - 1;
        cp16(&Bs[0][SWOFF(r, lc4 << 2)], Bb + (size_t)gn * ldb + (lc4 << 2), pb);
    }
    CP_COMMIT;

    for (int kt = 0; kt < KT; kt++) {
        int cur = kt & 1;
        if (kt + 1 < KT) {
            int k0 = (kt + 1) << 4, nxt = cur ^ 1;
#pragma unroll
            for (int i = 0; i < 2; i++) {
                int r = lr + (i << 6);
                int gr = mBase + r; bool pa = gr < M; if (!pa) gr = M - 1;
                cp16(&As[nxt][SWOFF(r, lc4 << 2)], Ab + (size_t)gr * lda + k0 + (lc4 << 2), pa);
                int gn = nBase + r; bool pb = gn < N; if (!pb) gn = N - 1;
                cp16(&Bs[nxt][SWOFF(r, lc4 << 2)], Bb + (size_t)gn * ldb + k0 + (lc4 << 2), pb);
            }
            CP_COMMIT;
            asm volatile("cp.async.wait_group 1;");
        } else {
            asm volatile("cp.async.wait_group 0;");
        }
        __syncthreads();
        const float* pA = As[cur];
        const float* pB = Bs[cur];
#pragma unroll
        for (int kk = 0; kk < 2; kk++) {
            int ck = (kk << 3) + (lane & 3);
            uint32_t af[4][4], bf[4][2];
#pragma unroll
            for (int mi = 0; mi < 4; mi++) {
                int r0 = mW + (mi << 4) + (lane >> 2);
                af[mi][0] = __float_as_uint(pA[SWOFF(r0, ck)]);
                af[mi][1] = __float_as_uint(pA[SWOFF(r0 + 8, ck)]);
                af[mi][2] = __float_as_uint(pA[SWOFF(r0, ck + 4)]);
                af[mi][3] = __float_as_uint(pA[SWOFF(r0 + 8, ck + 4)]);
            }
#pragma unroll
            for (int ni = 0; ni < 4; ni++) {
                int r0 = nW + (ni << 3) + (lane >> 2);
                bf[ni][0] = __float_as_uint(pB[SWOFF(r0, ck)]);
                bf[ni][1] = __float_as_uint(pB[SWOFF(r0, ck + 4)]);
            }
#pragma unroll
            for (int mi = 0; mi < 4; mi++)
#pragma unroll
                for (int ni = 0; ni < 4; ni++) mma8(acc[mi][ni], af[mi], bf[ni]);
        }
        __syncthreads();
    }
    // epilogue
    int rnd = mode & 1, blend = mode & 2;
#pragma unroll
    for (int mi = 0; mi < 4; mi++) {
#pragma unroll
        for (int half = 0; half < 2; half++) {
            int gm = mBase + mW + (mi << 4) + (lane >> 2) + half * 8;
            if (gm >= M) continue;
            float* crow = Cm + (size_t)gm * ldc;
#pragma unroll
            for (int ni = 0; ni < 4; ni++) {
                int gn = nBase + nW + (ni << 3) + ((lane & 3) << 1);
                float v0 = acc[mi][ni][half * 2], v1 = acc[mi][ni][half * 2 + 1];
                if (gn < N) {
                    float o = v0;
                    if (blend) o = 0.5f * crow[gn] + o;
                    if (rnd) o = tfr(o);
                    crow[gn] = o;
                }
                if (gn + 1 < N) {
                    float o = v1;
                    if (blend) o = 0.5f * crow[gn + 1] + o;
                    if (rnd) o = tfr(o);
                    crow[gn + 1] = o;
                }
            }
        }
    }
}

// ---------------- ELITE K/V select ----------------
__global__ void kv_select_k(const int* __restrict__ lidx) {
    int idx = blockIdx.x * 256 + threadIdx.x;
    const int tot = NSTR * NCTX * CHN;
    if (idx >= tot) return;
    int st = idx / (NCTX * CHN);
    if (lidx[st] >= 0) {
        g_k[NCTX * CHN + idx] = g_kg[idx];
        g_v[NCTX * CHN + idx] = g_vg[idx];
    }
}

// ---------------- global softmax (77 keys) + gate gather ----------------
__global__ void __launch_bounds__(256) softmax_g_k(const int* __restrict__ lidx) {
    __shared__ int sidx[8];
    if (threadIdx.x < 8) sidx[threadIdx.x] = lidx[threadIdx.x];
    __syncthreads();
    int bh = blockIdx.y;
    int w = threadIdx.x >> 5, lane = threadIdx.x & 31;
    int s = blockIdx.x * 8 + w;
    float* row = g_scg + ((size_t)bh * SQ + s) * NCTXP;
    const float scale = 0.07905694150420949f;
    float x0 = row[lane];
    float x1 = row[32 + lane];
    float x2 = (lane < 13) ? row[64 + lane] : -1e30f;
    float m = fmaxf(fmaxf(x0, x1), x2);
#pragma unroll
    for (int o = 16; o; o >>= 1) m = fmaxf(m, __shfl_xor_sync(0xffffffffu, m, o));
    float e0 = __expf((x0 - m) * scale);
    float e1 = __expf((x1 - m) * scale);
    float e2 = (lane < 13) ? __expf((x2 - m) * scale) : 0.f;
    float ss = e0 + e1 + e2;
#pragma unroll
    for (int o = 16; o; o >>= 1) ss += __shfl_xor_sync(0xffffffffu, ss, o);
    float inv = 1.f / ss;
    e0 *= inv; e1 *= inv; e2 *= inv;
    row[lane] = tfr(e0);
    row[32 + lane] = tfr(e1);
    if (lane < 16) row[64 + lane] = (lane < 13) ? tfr(e2) : 0.f;
    if (bh < 8) {
#pragma unroll
        for (int i = 0; i < 8; i++) {
            int li = sidx[i];
            int seg = li >> 5, src = li & 31;
            float cand = (seg == 0) ? e0 : ((seg == 1) ? e1 : e2);
            float v = __shfl_sync(0xffffffffu, cand, src);
            if (lane == 0) g_mraw[((size_t)i * NHEAD + bh) * SQ + s] = v;
        }
    }
}

// ---------------- per-instance gate max ----------------
__global__ void mmax_k() {
    __shared__ float red[256];
    int i = blockIdx.x;
    float mx = 0.f;
    const float* p = g_mraw + (size_t)i * NHEAD * SQ;
    for (int idx = threadIdx.x; idx < NHEAD * SQ; idx += 256) mx = fmaxf(mx, p[idx]);
    red[threadIdx.x] = mx;
    __syncthreads();
    for (int s = 128; s > 0; s >>= 1) {
        if (threadIdx.x < s) red[threadIdx.x] = fmaxf(red[threadIdx.x], red[threadIdx.x + s]);
        __syncthreads();
    }
    if (threadIdx.x == 0) g_mmax[i] = red[0];
}

// ---------------- local softmax (257 keys), gate folded ----------------
__global__ void __launch_bounds__(256) softmax_l_k() {
    int z = blockIdx.y;  // inst*8 + h
    int w = threadIdx.x >> 5, lane = threadIdx.x & 31;
    int s = blockIdx.x * 8 + w;
    float* row = g_scl + ((size_t)z * SQ + s) * LLOCP;
    const float scale = 0.07905694150420949f;
    float x[9];
#pragma unroll
    for (int j = 0; j < 9; j++) {
        int c = j * 32 + lane;
        x[j] = (c < LLOC) ? row[c] : -1e30f;
    }
    float m = -1e30f;
#pragma unroll
    for (int j = 0; j < 9; j++) m = fmaxf(m, x[j]);
#pragma unroll
    for (int o = 16; o; o >>= 1) m = fmaxf(m, __shfl_xor_sync(0xffffffffu, m, o));
    float ss = 0.f;
#pragma unroll
    for (int j = 0; j < 9; j++) {
        int c = j * 32 + lane;
        x[j] = (c < LLOC) ? __expf((x[j] - m) * scale) : 0.f;
        ss += x[j];
    }
#pragma unroll
    for (int o = 16; o; o >>= 1) ss += __shfl_xor_sync(0xffffffffu, ss, o);
    float gate = 0.5f * g_mraw[(size_t)z * SQ + s] / g_mmax[z >> 3];
    float f = gate / ss;
#pragma unroll
    for (int j = 0; j < 9; j++) {
        int c = j * 32 + lane;
        if (c < LLOCP) row[c] = tfr(x[j] * f);
    }
}

// ---------------- fuser premix ----------------
__global__ void premix_k(const float* __restrict__ bbox) {
    int s = blockIdx.x;
    int y = s >> 6, x = s & 63;
    float wgt[8];
    wgt[0] = 1.f;
    float sw = 1.f;
    const int off[4] = {3, 4, 11, 12};
#pragma unroll
    for (int i = 0; i < 7; i++) {
        float wmin = floorf(1024.f * bbox[i * 4 + 0]);
        float hmin = floorf(1024.f * bbox[i * 4 + 1]);
        float wmax = floorf(1024.f * bbox[i * 4 + 2]);
        float hmax = floorf(1024.f * bbox[i * 4 + 3]);
        float R = 0.f, Cv = 0.f;
#pragma unroll
        for (int j = 0; j < 4; j++) {
            float yy = (float)(16 * y + off[j]);
            float xx = (float)(16 * x + off[j]);
            if (yy >= hmin && yy < hmax) R += 0.25f;
            if (xx >= wmin && xx < wmax) Cv += 0.25f;
        }
        float g = 10.f * R * Cv;
        wgt[i + 1] = g;
        sw += g;
    }
    if (threadIdx.x == 0) g_sumw[s] = sw;
    for (int c = threadIdx.x; c < CHN; c += 256) {
        float acc = 0.f;
#pragma unroll
        for (int j = 0; j < 8; j++) acc += wgt[j] * g_pre[((size_t)(1 + j) * SQ + s) * CHN + c];
        g_mix[(size_t)s * CHN + c] = tfr(acc);
    }
}

// ---------------- final ----------------
__global__ void final_k(const float* __restrict__ bout, float* __restrict__ out) {
    int s = blockIdx.x;
    float sw = g_sumw[s];
    float den = 1.f / (sw + 1e-6f);
    for (int c = threadIdx.x; c < CHN; c += 256) {
        float b = bout[c];
        out[(size_t)s * CHN + c] = g_out2[(size_t)s * CHN + c] + b;
        out[(size_t)(SQ + s) * CHN + c] = (g_out2[(size_t)(SQ + s) * CHN + c] + b * sw) * den;
    }
}

// ---------------- launch ----------------
extern "C" void kernel_launch(void* const* d_in, const int* in_sizes, int n_in,
                              void* d_out, int out_size) {
    const float* hs   = (const float*)d_in[0];
    const float* ctx  = (const float*)d_in[1];
    const float* lf   = (const float*)d_in[2];
    const float* bbox = (const float*)d_in[3];
    const float* Wq   = (const float*)d_in[4];
    const float* Wk   = (const float*)d_in[5];
    const float* Wv   = (const float*)d_in[6];
    const float* Wkg  = (const float*)d_in[7];
    const float* Wvg  = (const float*)d_in[8];
    const float* Wkl  = (const float*)d_in[9];
    const float* Wvl  = (const float*)d_in[10];
    const float* Wout = (const float*)d_in[11];
    const float* bout = (const float*)d_in[12];
    const int*   lidx = (const int*)d_in[13];
    float* out = (float*)d_out;

    float *hsR, *ctxR, *lfR, *WqT, *WkT, *WvT, *WkgT, *WvgT, *WklT, *WvlT, *WoutT;
    float *vp, *vTp, *vlp, *vlTp;
    cudaGetSymbolAddress((void**)&hsR, g_hsR);
    cudaGetSymbolAddress((void**)&ctxR, g_ctxR);
    cudaGetSymbolAddress((void**)&lfR, g_lfR);
    cudaGetSymbolAddress((void**)&WqT, g_WqT);
    cudaGetSymbolAddress((void**)&WkT, g_WkT);
    cudaGetSymbolAddress((void**)&WvT, g_WvT);
    cudaGetSymbolAddress((void**)&WkgT, g_WkgT);
    cudaGetSymbolAddress((void**)&WvgT, g_WvgT);
    cudaGetSymbolAddress((void**)&WklT, g_WklT);
    cudaGetSymbolAddress((void**)&WvlT, g_WvlT);
    cudaGetSymbolAddress((void**)&WoutT, g_WoutT);
    cudaGetSymbolAddress((void**)&vp, g_v);
    cudaGetSymbolAddress((void**)&vTp, g_vT);
    cudaGetSymbolAddress((void**)&vlp, g_vl);
    cudaGetSymbolAddress((void**)&vlTp, g_vlT);

    dim3 tb(32, 8);
    setup_k<<<1, 256>>>();

    // pre-round raw inputs to tf32 values (cvt hoisted out of GEMM inner loop)
    long long nHs = 2LL * SQ * CHN, nCtx = (long long)NST * NCTX * CC, nLf = (long long)NSTR * LLOC * CC;
    round_k<<<(int)((nHs / 4 + 255) / 256), 256>>>(hs, hsR, nHs);
    round_k<<<(int)((nCtx / 4 + 255) / 256), 256>>>(ctx, ctxR, nCtx);
    round_k<<<(int)((nLf / 4 + 255) / 256), 256>>>(lf, lfR, nLf);

    // weight transposes (rounded)
    transpose_k<<<dim3(40, 40, 1), tb>>>(Wq, WqT, CHN, CHN, CHN, CHN, 0, 0, 1);
    transpose_k<<<dim3(40, 24, 1), tb>>>(Wk, WkT, CC, CHN, CHN, CC, 0, 0, 1);
    transpose_k<<<dim3(40, 24, 1), tb>>>(Wv, WvT, CC, CHN, CHN, CC, 0, 0, 1);
    transpose_k<<<dim3(40, 24, 1), tb>>>(Wkg, WkgT, CC, CHN, CHN, CC, 0, 0, 1);
    transpose_k<<<dim3(40, 24, 1), tb>>>(Wvg, WvgT, CC, CHN, CHN, CC, 0, 0, 1);
    transpose_k<<<dim3(40, 24, 1), tb>>>(Wkl, WklT, CC, CHN, CHN, CC, 0, 0, 1);
    transpose_k<<<dim3(40, 24, 1), tb>>>(Wvl, WvlT, CC, CHN, CHN, CC, 0, 0, 1);
    transpose_k<<<dim3(40, 40, 1), tb>>>(Wout, WoutT, CHN, CHN, CHN, CHN, 0, 0, 1);

    // projections (outputs rounded to tf32)
    gemm_tf32<<<dim3(10, 64, 1), 256>>>(0, CHN, CHN, CHN, CHN, CHN, 1);     // Q
    gemm_tf32<<<dim3(10, 6, 4), 256>>>(1, CHN, CC, CC, CC, CHN, 1);         // K,V,Kg,Vg batched
    gemm_tf32<<<dim3(10, 17, 2), 256>>>(5, CHN, CC, CC, CC, CHN, 1);        // Kl,Vl batched
    kv_select_k<<<(NSTR * NCTX * CHN + 255) / 256, 256>>>(lidx);

    // V transposes for PV GEMMs (already rounded values)
    transpose_k<<<dim3(40, 3, NST), tb>>>(vp, vTp, NCTX, CHN, CHN, NCTXP,
                                          (long long)NCTX * CHN, (long long)CHN * NCTXP, 0);
    transpose_k<<<dim3(40, 9, NSTR), tb>>>(vlp, vlTp, LLOC, CHN, CHN, LLOCP,
                                           (long long)LLOC * CHN, (long long)CHN * LLOCP, 0);

    // global attention
    gemm_tf32<<<dim3(1, 32, 72), 256>>>(16, NCTX, HD, CHN, CHN, NCTXP, 0);     // scores
    softmax_g_k<<<dim3(512, 72), 256>>>(lidx);
    mmax_k<<<8, 256>>>();
    gemm_tf32<<<dim3(2, 32, 72), 256>>>(96, HD, NCTXP, NCTXP, NCTXP, CHN, 1);  // PV (round pre)

    // local attention
    gemm_tf32<<<dim3(3, 32, 64), 256>>>(176, LLOC, HD, CHN, CHN, LLOCP, 0);    // scores
    softmax_l_k<<<dim3(512, 64), 256>>>();
    gemm_tf32<<<dim3(2, 32, 64), 256>>>(240, HD, LLOCP, LLOCP, LLOCP, CHN, 3); // PV + blend + round

    // fuser premix + output projection (batched)
    premix_k<<<SQ, 256>>>(bbox);
    gemm_tf32<<<dim3(10, 32, 2), 256>>>(7, CHN, CHN, CHN, CHN, CHN, 0);
    final_k<<<SQ, 256>>>(bout, out);
}

// round 5
// speedup vs baseline: 1.3298x; 1.0980x over previous
#include <cuda_runtime.h>
#include <math.h>
#include <stdint.h>

#define SQ 4096
#define CHN 1280
#define CC 768
#define NHEAD 8
#define HD 160
#define NCTX 77
#define NCTXP 80
#define NST 9
#define NSTR 8
#define LLOC 257
#define LLOCP 272
#define PST 84
#define SST 276

// ---------------- scratch ----------------
__device__ __align__(256) float g_hsR[2 * SQ * CHN];
__device__ __align__(256) float g_ctxR[NST * NCTX * CC];
__device__ __align__(256) float g_lfR[NSTR * LLOC * CC];
__device__ __align__(256) float g_q2[2 * SQ * CHN];
__device__ __align__(256) float g_k[NST * NCTX * CHN];
__device__ __align__(256) float g_v[NST * NCTX * CHN];
__device__ __align__(256) float g_kg[NSTR * NCTX * CHN];
__device__ __align__(256) float g_vg[NSTR * NCTX * CHN];
__device__ __align__(256) float g_kl[NSTR * LLOC * CHN];
__device__ __align__(256) float g_vl[NSTR * LLOC * CHN];
__device__ __align__(256) float g_WqT[CHN * CHN];
__device__ __align__(256) float g_WkT[CHN * CC];
__device__ __align__(256) float g_WvT[CHN * CC];
__device__ __align__(256) float g_WkgT[CHN * CC];
__device__ __align__(256) float g_WvgT[CHN * CC];
__device__ __align__(256) float g_WklT[CHN * CC];
__device__ __align__(256) float g_WvlT[CHN * CC];
__device__ __align__(256) float g_WoutT[CHN * CHN];
__device__ __align__(256) float g_vT[NST * CHN * NCTXP];
__device__ __align__(256) float g_vlT[NSTR * CHN * LLOCP];
__device__ __align__(256) float g_scl[64L * SQ * LLOCP];
__device__ __align__(256) float g_pre[NST * SQ * CHN];
__device__ __align__(256) float g_mix[SQ * CHN];
__device__ __align__(256) float g_out2[2 * SQ * CHN];
__device__ float g_mraw[NSTR * NHEAD * SQ];
__device__ float g_mmax[NSTR];
__device__ float g_sumw[SQ];

__device__ const float* d_Ap[320];
__device__ const float* d_Bp[320];
__device__ float*       d_Cp[320];
__device__ int          d_Mt[320];

// ---------------- helpers ----------------
__device__ __forceinline__ float tfr(float x) {
    uint32_t r;
    asm("cvt.rna.tf32.f32 %0, %1;" : "=r"(r) : "f"(x));
    return __uint_as_float(r);
}
__device__ __forceinline__ void cp16(float* sdst, const float* gsrc, bool p) {
    uint32_t sa = (uint32_t)__cvta_generic_to_shared(sdst);
    int sz = p ? 16 : 0;
    asm volatile("cp.async.cg.shared.global [%0], [%1], 16, %2;" :: "r"(sa), "l"(gsrc), "r"(sz));
}
#define CP_COMMIT asm volatile("cp.async.commit_group;")
#define CP_WAIT0 asm volatile("cp.async.wait_group 0;")
#define CP_WAIT1 asm volatile("cp.async.wait_group 1;")
#define CP_WAIT2 asm volatile("cp.async.wait_group 2;")
__device__ __forceinline__ void mma8(float* c, const uint32_t* a, const uint32_t* b) {
    asm volatile(
        "mma.sync.aligned.m16n8k8.row.col.f32.tf32.tf32.f32 "
        "{%0,%1,%2,%3}, {%4,%5,%6,%7}, {%8,%9}, {%0,%1,%2,%3};"
        : "+f"(c[0]), "+f"(c[1]), "+f"(c[2]), "+f"(c[3])
        : "r"(a[0]), "r"(a[1]), "r"(a[2]), "r"(a[3]), "r"(b[0]), "r"(b[1]));
}
#define SWOFF(r, c) (((r) << 4) + ((((((c) >> 2) ^ (((r) >> 1) & 3))) << 2) | ((c) & 3)))

// ---------------- setup: batch pointer + M tables ----------------
__global__ void setup_k() {
    int z = threadIdx.x;
    if (z == 0) {
        d_Ap[0] = g_hsR;               d_Bp[0] = g_WqT;   d_Cp[0] = g_q2;    d_Mt[0] = 2 * SQ;
        d_Ap[1] = g_ctxR;              d_Bp[1] = g_WkT;   d_Cp[1] = g_k;     d_Mt[1] = NST * NCTX;
        d_Ap[2] = g_ctxR;              d_Bp[2] = g_WvT;   d_Cp[2] = g_v;     d_Mt[2] = NST * NCTX;
        d_Ap[3] = g_ctxR + NCTX * CC;  d_Bp[3] = g_WkgT;  d_Cp[3] = g_kg;    d_Mt[3] = NSTR * NCTX;
        d_Ap[4] = g_ctxR + NCTX * CC;  d_Bp[4] = g_WvgT;  d_Cp[4] = g_vg;    d_Mt[4] = NSTR * NCTX;
        d_Ap[5] = g_lfR;               d_Bp[5] = g_WklT;  d_Cp[5] = g_kl;    d_Mt[5] = NSTR * LLOC;
        d_Ap[6] = g_lfR;               d_Bp[6] = g_WvlT;  d_Cp[6] = g_vl;    d_Mt[6] = NSTR * LLOC;
        d_Ap[7] = g_pre;               d_Bp[7] = g_WoutT; d_Cp[7] = g_out2;  d_Mt[7] = SQ;
        d_Ap[8] = g_mix;               d_Bp[8] = g_WoutT; d_Cp[8] = g_out2 + (size_t)SQ * CHN;
        d_Mt[8] = SQ;
    }
    if (z < 64) {
        d_Ap[176 + z] = g_q2 + (size_t)SQ * CHN + (z & 7) * HD;
        d_Bp[176 + z] = g_kl + (size_t)(z >> 3) * LLOC * CHN + (z & 7) * HD;
        d_Cp[176 + z] = g_scl + (size_t)z * SQ * LLOCP;
        d_Mt[176 + z] = SQ;
    }
}

// ---------------- round pass ----------------
__global__ void round_k(const float* __restrict__ src, float* __restrict__ dst, long long n) {
    long long i = ((long long)blockIdx.x * blockDim.x + threadIdx.x) * 4;
    if (i + 3 < n) {
        float4 v = *(const float4*)(src + i);
        v.x = tfr(v.x); v.y = tfr(v.y); v.z = tfr(v.z); v.w = tfr(v.w);
        *(float4*)(dst + i) = v;
    } else {
        for (long long j = i; j < n; j++) dst[j] = tfr(src[j]);
    }
}

// ---------------- transpose ----------------
__global__ void transpose_k(const float* __restrict__ src, float* __restrict__ dst,
                            int R, int C, int ldS, int ldD, long long sBS, long long dBS,
                            int rnd) {
    __shared__ float t[32][33];
    src += blockIdx.z * sBS;
    dst += blockIdx.z * dBS;
    int c0 = blockIdx.x << 5, r0 = blockIdx.y << 5;
    int tx = threadIdx.x, ty = threadIdx.y;
#pragma unroll
    for (int j = 0; j < 4; j++) {
        int rr = r0 + ty + j * 8, cc = c0 + tx;
        t[ty + j * 8][tx] = (rr < R && cc < C) ? src[(size_t)rr * ldS + cc] : 0.f;
    }
    __syncthreads();
#pragma unroll
    for (int j = 0; j < 4; j++) {
        int cc = c0 + ty + j * 8, rr = r0 + tx;
        if (cc < C && rr < ldD) {
            float v = t[tx][ty + j * 8];
            dst[(size_t)cc * ldD + rr] = rnd ? tfr(v) : v;
        }
    }
}

// ---------------- batched NT tf32 GEMM (R4, proven) ----------------
__global__ void __launch_bounds__(256) gemm_tf32(int slot, int N, int K,
                                                 int lda, int ldb, int ldc, int mode) {
    const float* Ab = d_Ap[slot + blockIdx.z];
    const float* Bb = d_Bp[slot + blockIdx.z];
    float* Cm       = d_Cp[slot + blockIdx.z];
    const int M     = d_Mt[slot + blockIdx.z];
    __shared__ __align__(16) float As[2][128 * 16];
    __shared__ __align__(16) float Bs[2][128 * 16];
    int tid = threadIdx.x, lane = tid & 31, warp = tid >> 5;
    int mBase = blockIdx.y << 7, nBase = blockIdx.x << 7;
    int mW = (warp >> 2) << 6, nW = (warp & 3) << 5;
    float acc[4][4][4];
#pragma unroll
    for (int a = 0; a < 4; a++)
#pragma unroll
        for (int b = 0; b < 4; b++)
#pragma unroll
            for (int cidx = 0; cidx < 4; cidx++) acc[a][b][cidx] = 0.f;

    const int lr = tid >> 2, lc4 = tid & 3;
    int KT = K >> 4;
#pragma unroll
    for (int i = 0; i < 2; i++) {
        int r = lr + (i << 6);
        int gr = mBase + r; bool pa = gr < M; if (!pa) gr = M - 1;
        cp16(&As[0][SWOFF(r, lc4 << 2)], Ab + (size_t)gr * lda + (lc4 << 2), pa);
        int gn = nBase + r; bool pb = gn < N; if (!pb) gn = N - 1;
        cp16(&Bs[0][SWOFF(r, lc4 << 2)], Bb + (size_t)gn * ldb + (lc4 << 2), pb);
    }
    CP_COMMIT;

    for (int kt = 0; kt < KT; kt++) {
        int cur = kt & 1;
        if (kt + 1 < KT) {
            int k0 = (kt + 1) << 4, nxt = cur ^ 1;
#pragma unroll
            for (int i = 0; i < 2; i++) {
                int r = lr + (i << 6);
                int gr = mBase + r; bool pa = gr < M; if (!pa) gr = M - 1;
                cp16(&As[nxt][SWOFF(r, lc4 << 2)], Ab + (size_t)gr * lda + k0 + (lc4 << 2), pa);
                int gn = nBase + r; bool pb = gn < N; if (!pb) gn = N - 1;
                cp16(&Bs[nxt][SWOFF(r, lc4 << 2)], Bb + (size_t)gn * ldb + k0 + (lc4 << 2), pb);
            }
            CP_COMMIT;
            CP_WAIT1;
        } else {
            CP_WAIT0;
        }
        __syncthreads();
        const float* pA = As[cur];
        const float* pB = Bs[cur];
#pragma unroll
        for (int kk = 0; kk < 2; kk++) {
            int ck = (kk << 3) + (lane & 3);
            uint32_t af[4][4], bf[4][2];
#pragma unroll
            for (int mi = 0; mi < 4; mi++) {
                int r0 = mW + (mi << 4) + (lane >> 2);
                af[mi][0] = __float_as_uint(pA[SWOFF(r0, ck)]);
                af[mi][1] = __float_as_uint(pA[SWOFF(r0 + 8, ck)]);
                af[mi][2] = __float_as_uint(pA[SWOFF(r0, ck + 4)]);
                af[mi][3] = __float_as_uint(pA[SWOFF(r0 + 8, ck + 4)]);
            }
#pragma unroll
            for (int ni = 0; ni < 4; ni++) {
                int r0 = nW + (ni << 3) + (lane >> 2);
                bf[ni][0] = __float_as_uint(pB[SWOFF(r0, ck)]);
                bf[ni][1] = __float_as_uint(pB[SWOFF(r0, ck + 4)]);
            }
#pragma unroll
            for (int mi = 0; mi < 4; mi++)
#pragma unroll
                for (int ni = 0; ni < 4; ni++) mma8(acc[mi][ni], af[mi], bf[ni]);
        }
        __syncthreads();
    }
    int rnd = mode & 1, blend = mode & 2;
#pragma unroll
    for (int mi = 0; mi < 4; mi++) {
#pragma unroll
        for (int half = 0; half < 2; half++) {
            int gm = mBase + mW + (mi << 4) + (lane >> 2) + half * 8;
            if (gm >= M) continue;
            float* crow = Cm + (size_t)gm * ldc;
#pragma unroll
            for (int ni = 0; ni < 4; ni++) {
                int gn = nBase + nW + (ni << 3) + ((lane & 3) << 1);
                float v0 = acc[mi][ni][half * 2], v1 = acc[mi][ni][half * 2 + 1];
                if (gn < N) {
                    float o = v0;
                    if (blend) o = 0.5f * crow[gn] + o;
                    if (rnd) o = tfr(o);
                    crow[gn] = o;
                }
                if (gn + 1 < N) {
                    float o = v1;
                    if (blend) o = 0.5f * crow[gn + 1] + o;
                    if (rnd) o = tfr(o);
                    crow[gn + 1] = o;
                }
            }
        }
    }
}

// ---------------- ELITE K/V select ----------------
__global__ void kv_select_k(const int* __restrict__ lidx) {
    int idx = blockIdx.x * 256 + threadIdx.x;
    const int tot = NSTR * NCTX * CHN;
    if (idx >= tot) return;
    int st = idx / (NCTX * CHN);
    if (lidx[st] >= 0) {
        g_k[NCTX * CHN + idx] = g_kg[idx];
        g_v[NCTX * CHN + idx] = g_vg[idx];
    }
}

// ============ fused global attention: scores + softmax + PV + gate ============
// grid (32 qtiles, 72 bh), 256 threads
__global__ void __launch_bounds__(256) fused_g_k(const int* __restrict__ lidx) {
    extern __shared__ __align__(16) float sm[];
    float* qb  = sm;                    // 2 * 2048
    float* kb  = sm + 4096;             // 2 * 2048
    float* psm = sm + 8192;             // 128 * PST
    float* vsm = psm + 128 * PST;       // 160 * PST
    float* smx = vsm + 160 * PST;       // 2 * 128
    float* ssu = smx + 256;             // 2 * 128
    __shared__ int sidx[8];

    int bh = blockIdx.y;
    int stream = bh >> 3, h = bh & 7;
    int q0 = blockIdx.x << 7;
    int tid = threadIdx.x, lane = tid & 31, warp = tid >> 5;
    if (tid < 8) sidx[tid] = lidx[tid];

    const float* Qb = g_q2 + (stream ? (size_t)SQ * CHN : 0) + (size_t)q0 * CHN + h * HD;
    const float* Kb = g_k + (size_t)stream * NCTX * CHN + h * HD;
    const float* Vt = g_vT + (size_t)stream * CHN * NCTXP + (size_t)h * HD * NCTXP;

    // V^T preload (group 0): 160 rows x 80 cols
    for (int u = tid; u < 160 * 20; u += 256) {
        int d = u / 20, c4 = (u % 20) * 4;
        cp16(vsm + d * PST + c4, Vt + (size_t)d * NCTXP + c4, true);
    }
    CP_COMMIT;

    const int lr = tid >> 2, lc4 = tid & 3;
    auto issueQK = [&](int st, int kt) {
        int k0 = kt << 4;
#pragma unroll
        for (int i = 0; i < 2; i++) {
            int r = lr + (i << 6);
            cp16(&qb[st * 2048 + SWOFF(r, lc4 << 2)], Qb + (size_t)r * CHN + k0 + (lc4 << 2), true);
            int kr = (r < NCTX) ? r : (NCTX - 1);
            cp16(&kb[st * 2048 + SWOFF(r, lc4 << 2)], Kb + (size_t)kr * CHN + k0 + (lc4 << 2), true);
        }
        CP_COMMIT;
    };
    issueQK(0, 0);

    int mW = (warp >> 1) << 5;       // 0,32,64,96
    int nWs = (warp & 1) * 40;       // scores n-offset
    float sc[2][5][4];
#pragma unroll
    for (int a = 0; a < 2; a++)
#pragma unroll
        for (int b = 0; b < 5; b++)
#pragma unroll
            for (int c = 0; c < 4; c++) sc[a][b][c] = 0.f;

    for (int kt = 0; kt < 10; kt++) {
        if (kt < 9) { issueQK((kt + 1) & 1, kt + 1); CP_WAIT1; }
        else        { CP_WAIT0; }
        __syncthreads();
        const float* pQ = qb + (kt & 1) * 2048;
        const float* pK = kb + (kt & 1) * 2048;
#pragma unroll
        for (int kk = 0; kk < 2; kk++) {
            int ck = (kk << 3) + (lane & 3);
            uint32_t af[2][4], bf[5][2];
#pragma unroll
            for (int mi = 0; mi < 2; mi++) {
                int r0 = mW + (mi << 4) + (lane >> 2);
                af[mi][0] = __float_as_uint(pQ[SWOFF(r0, ck)]);
                af[mi][1] = __float_as_uint(pQ[SWOFF(r0 + 8, ck)]);
                af[mi][2] = __float_as_uint(pQ[SWOFF(r0, ck + 4)]);
                af[mi][3] = __float_as_uint(pQ[SWOFF(r0 + 8, ck + 4)]);
            }
#pragma unroll
            for (int ni = 0; ni < 5; ni++) {
                int r0 = nWs + (ni << 3) + (lane >> 2);
                bf[ni][0] = __float_as_uint(pK[SWOFF(r0, ck)]);
                bf[ni][1] = __float_as_uint(pK[SWOFF(r0, ck + 4)]);
            }
#pragma unroll
            for (int mi = 0; mi < 2; mi++)
#pragma unroll
                for (int ni = 0; ni < 5; ni++) mma8(sc[mi][ni], af[mi], bf[ni]);
        }
        __syncthreads();
    }

    // ---- block softmax ----
    const float scale = 0.07905694150420949f;
    int half = warp & 1;
#pragma unroll
    for (int mi = 0; mi < 2; mi++)
#pragma unroll
        for (int hf = 0; hf < 2; hf++) {
            int row = mW + mi * 16 + (lane >> 2) + hf * 8;
            float mx = -1e30f;
#pragma unroll
            for (int ni = 0; ni < 5; ni++)
#pragma unroll
                for (int c = 0; c < 2; c++) {
                    int col = nWs + ni * 8 + ((lane & 3) << 1) + c;
                    if (col < NCTX) mx = fmaxf(mx, sc[mi][ni][hf * 2 + c]);
                }
            mx = fmaxf(mx, __shfl_xor_sync(0xffffffffu, mx, 1));
            mx = fmaxf(mx, __shfl_xor_sync(0xffffffffu, mx, 2));
            if ((lane & 3) == 0) smx[half * 128 + row] = mx;
        }
    __syncthreads();
#pragma unroll
    for (int mi = 0; mi < 2; mi++)
#pragma unroll
        for (int hf = 0; hf < 2; hf++) {
            int row = mW + mi * 16 + (lane >> 2) + hf * 8;
            float m = fmaxf(smx[row], smx[128 + row]);
            float s = 0.f;
#pragma unroll
            for (int ni = 0; ni < 5; ni++)
#pragma unroll
                for (int c = 0; c < 2; c++) {
                    int col = nWs + ni * 8 + ((lane & 3) << 1) + c;
                    float e = (col < NCTX) ? __expf((sc[mi][ni][hf * 2 + c] - m) * scale) : 0.f;
                    sc[mi][ni][hf * 2 + c] = e;
                    s += e;
                }
            s += __shfl_xor_sync(0xffffffffu, s, 1);
            s += __shfl_xor_sync(0xffffffffu, s, 2);
            if ((lane & 3) == 0) ssu[half * 128 + row] = s;
        }
    __syncthreads();
#pragma unroll
    for (int mi = 0; mi < 2; mi++)
#pragma unroll
        for (int hf = 0; hf < 2; hf++) {
            int row = mW + mi * 16 + (lane >> 2) + hf * 8;
            float inv = 1.f / (ssu[row] + ssu[128 + row]);
#pragma unroll
            for (int ni = 0; ni < 5; ni++)
#pragma unroll
                for (int c = 0; c < 2; c++) {
                    int col = nWs + ni * 8 + ((lane & 3) << 1) + c;
                    psm[row * PST + col] = (col < NCTX) ? tfr(sc[mi][ni][hf * 2 + c] * inv) : 0.f;
                }
        }
    __syncthreads();

    // gate gather (stream 0 only)
    if (stream == 0) {
        for (int u = tid; u < 128 * 8; u += 256) {
            int r = u >> 3, i = u & 7;
            g_mraw[((size_t)i * NHEAD + h) * SQ + q0 + r] = psm[r * PST + sidx[i]];
        }
    }

    // ---- PV: O[128][160] = P[128][80] @ V[80][160] ----
    int nW = (warp & 1) * 80;
    float oa[2][10][4];
#pragma unroll
    for (int a = 0; a < 2; a++)
#pragma unroll
        for (int b = 0; b < 10; b++)
#pragma unroll
            for (int c = 0; c < 4; c++) oa[a][b][c] = 0.f;
#pragma unroll
    for (int kst = 0; kst < 10; kst++) {
        int ka = kst * 8 + (lane & 3);
        uint32_t af[2][4], bf[10][2];
#pragma unroll
        for (int mi = 0; mi < 2; mi++) {
            int r0 = mW + (mi << 4) + (lane >> 2);
            af[mi][0] = __float_as_uint(psm[r0 * PST + ka]);
            af[mi][1] = __float_as_uint(psm[(r0 + 8) * PST + ka]);
            af[mi][2] = __float_as_uint(psm[r0 * PST + ka + 4]);
            af[mi][3] = __float_as_uint(psm[(r0 + 8) * PST + ka + 4]);
        }
#pragma unroll
        for (int ni = 0; ni < 10; ni++) {
            int d = nW + (ni << 3) + (lane >> 2);
            bf[ni][0] = __float_as_uint(vsm[d * PST + ka]);
            bf[ni][1] = __float_as_uint(vsm[d * PST + ka + 4]);
        }
#pragma unroll
        for (int mi = 0; mi < 2; mi++)
#pragma unroll
            for (int ni = 0; ni < 10; ni++) mma8(oa[mi][ni], af[mi], bf[ni]);
    }
    // epilogue
#pragma unroll
    for (int mi = 0; mi < 2; mi++)
#pragma unroll
        for (int hf = 0; hf < 2; hf++) {
            int g = q0 + mW + mi * 16 + (lane >> 2) + hf * 8;
            float* orow = g_pre + ((size_t)stream * SQ + g) * CHN + h * HD;
#pragma unroll
            for (int ni = 0; ni < 10; ni++) {
                int col = nW + (ni << 3) + ((lane & 3) << 1);
                float2 v = make_float2(tfr(oa[mi][ni][hf * 2]), tfr(oa[mi][ni][hf * 2 + 1]));
                *(float2*)(orow + col) = v;
            }
        }
}

// ---------------- per-instance gate max ----------------
__global__ void mmax_k() {
    __shared__ float red[256];
    int i = blockIdx.x;
    float mx = 0.f;
    const float* p = g_mraw + (size_t)i * NHEAD * SQ;
    for (int idx = threadIdx.x; idx < NHEAD * SQ; idx += 256) mx = fmaxf(mx, p[idx]);
    red[threadIdx.x] = mx;
    __syncthreads();
    for (int s = 128; s > 0; s >>= 1) {
        if (threadIdx.x < s) red[threadIdx.x] = fmaxf(red[threadIdx.x], red[threadIdx.x + s]);
        __syncthreads();
    }
    if (threadIdx.x == 0) g_mmax[i] = red[0];
}

// ============ fused local softmax + PV (scores pre-materialized) ============
// grid (32 qtiles, 64 ih), 256 threads
__global__ void __launch_bounds__(256) fused_l_k() {
    extern __shared__ __align__(16) float sm[];
    float* ssm = sm;                 // 128 * SST
    float* bv  = sm + 128 * SST;     // 2 * 160 * 20

    int z = blockIdx.y;
    int inst = z >> 3, h = z & 7;
    int q0 = blockIdx.x << 7;
    int tid = threadIdx.x, lane = tid & 31, warp = tid >> 5;

    const float* Sg = g_scl + ((size_t)z * SQ + q0) * LLOCP;
    const float* Vt = g_vlT + (size_t)inst * CHN * LLOCP + (size_t)h * HD * LLOCP;

    // S tile load (group 0): 128 rows x 272 floats
    for (int u = tid; u < 128 * 68; u += 256) {
        int r = u / 68, c4 = (u % 68) * 4;
        cp16(ssm + r * SST + c4, Sg + (size_t)r * LLOCP + c4, true);
    }
    CP_COMMIT;
    auto issueV = [&](int buf, int ch) {
        for (int u = tid; u < 640; u += 256) {
            int d = u >> 2, c4 = (u & 3) * 4;
            cp16(bv + buf * 3200 + d * 20 + c4, Vt + (size_t)d * LLOCP + ch * 16 + c4, true);
        }
        CP_COMMIT;
    };
    issueV(0, 0);
    issueV(1, 1);
    CP_WAIT2;   // S ready
    __syncthreads();

    // ---- warp-per-row softmax with gate ----
    const float scale = 0.07905694150420949f;
    float gden = 0.5f / g_mmax[inst];
    for (int t = 0; t < 16; t++) {
        int row = warp * 16 + t;
        float* rp = ssm + row * SST;
        float x[9];
#pragma unroll
        for (int j = 0; j < 9; j++) {
            int c = j * 32 + lane;
            x[j] = (c < LLOC) ? rp[c] : -1e30f;
        }
        float m = -1e30f;
#pragma unroll
        for (int j = 0; j < 9; j++) m = fmaxf(m, x[j]);
#pragma unroll
        for (int o = 16; o; o >>= 1) m = fmaxf(m, __shfl_xor_sync(0xffffffffu, m, o));
        float s = 0.f;
#pragma unroll
        for (int j = 0; j < 9; j++) {
            int c = j * 32 + lane;
            x[j] = (c < LLOC) ? __expf((x[j] - m) * scale) : 0.f;
            s += x[j];
        }
#pragma unroll
        for (int o = 16; o; o >>= 1) s += __shfl_xor_sync(0xffffffffu, s, o);
        float f = g_mraw[(size_t)z * SQ + q0 + row] * gden / s;
#pragma unroll
        for (int j = 0; j < 9; j++) {
            int c = j * 32 + lane;
            if (c < LLOCP) rp[c] = (c < LLOC) ? tfr(x[j] * f) : 0.f;
        }
    }
    __syncthreads();

    // ---- PV: O[128][160] = P[128][272] @ Vl[272][160], V^T streamed ----
    int mW = (warp >> 1) << 5;
    int nW = (warp & 1) * 80;
    float oa[2][10][4];
#pragma unroll
    for (int a = 0; a < 2; a++)
#pragma unroll
        for (int b = 0; b < 10; b++)
#pragma unroll
            for (int c = 0; c < 4; c++) oa[a][b][c] = 0.f;

    for (int ch = 0; ch < 17; ch++) {
        if (ch < 16) { CP_WAIT1; } else { CP_WAIT0; }
        __syncthreads();
        const float* pb = bv + (ch & 1) * 3200;
#pragma unroll
        for (int kk = 0; kk < 2; kk++) {
            int kst = ch * 2 + kk;
            int ka = kst * 8 + (lane & 3);
            int kb = kk * 8 + (lane & 3);
            uint32_t af[2][4], bf[10][2];
#pragma unroll
            for (int mi = 0; mi < 2; mi++) {
                int r0 = mW + (mi << 4) + (lane >> 2);
                af[mi][0] = __float_as_uint(ssm[r0 * SST + ka]);
                af[mi][1] = __float_as_uint(ssm[(r0 + 8) * SST + ka]);
                af[mi][2] = __float_as_uint(ssm[r0 * SST + ka + 4]);
                af[mi][3] = __float_as_uint(ssm[(r0 + 8) * SST + ka + 4]);
            }
#pragma unroll
            for (int ni = 0; ni < 10; ni++) {
                int d = nW + (ni << 3) + (lane >> 2);
                bf[ni][0] = __float_as_uint(pb[d * 20 + kb]);
                bf[ni][1] = __float_as_uint(pb[d * 20 + kb + 4]);
            }
#pragma unroll
            for (int mi = 0; mi < 2; mi++)
#pragma unroll
                for (int ni = 0; ni < 10; ni++) mma8(oa[mi][ni], af[mi], bf[ni]);
        }
        __syncthreads();
        if (ch + 2 < 17) issueV(ch & 1, ch + 2);
    }

    // epilogue: blend 0.5*pre + O, rounded
#pragma unroll
    for (int mi = 0; mi < 2; mi++)
#pragma unroll
        for (int hf = 0; hf < 2; hf++) {
            int g = q0 + mW + mi * 16 + (lane >> 2) + hf * 8;
            float* prow = g_pre + ((size_t)(inst + 1) * SQ + g) * CHN + h * HD;
#pragma unroll
            for (int ni = 0; ni < 10; ni++) {
                int col = nW + (ni << 3) + ((lane & 3) << 1);
                float2 old = *(float2*)(prow + col);
                float2 v = make_float2(tfr(0.5f * old.x + oa[mi][ni][hf * 2]),
                                       tfr(0.5f * old.y + oa[mi][ni][hf * 2 + 1]));
                *(float2*)(prow + col) = v;
            }
        }
}

// ---------------- fuser premix ----------------
__global__ void premix_k(const float* __restrict__ bbox) {
    int s = blockIdx.x;
    int y = s >> 6, x = s & 63;
    float wgt[8];
    wgt[0] = 1.f;
    float sw = 1.f;
    const int off[4] = {3, 4, 11, 12};
#pragma unroll
    for (int i = 0; i < 7; i++) {
        float wmin = floorf(1024.f * bbox[i * 4 + 0]);
        float hmin = floorf(1024.f * bbox[i * 4 + 1]);
        float wmax = floorf(1024.f * bbox[i * 4 + 2]);
        float hmax = floorf(1024.f * bbox[i * 4 + 3]);
        float R = 0.f, Cv = 0.f;
#pragma unroll
        for (int j = 0; j < 4; j++) {
            float yy = (float)(16 * y + off[j]);
            float xx = (float)(16 * x + off[j]);
            if (yy >= hmin && yy < hmax) R += 0.25f;
            if (xx >= wmin && xx < wmax) Cv += 0.25f;
        }
        float g = 10.f * R * Cv;
        wgt[i + 1] = g;
        sw += g;
    }
    if (threadIdx.x == 0) g_sumw[s] = sw;
    for (int c = threadIdx.x; c < CHN; c += 256) {
        float acc = 0.f;
#pragma unroll
        for (int j = 0; j < 8; j++) acc += wgt[j] * g_pre[((size_t)(1 + j) * SQ + s) * CHN + c];
        g_mix[(size_t)s * CHN + c] = tfr(acc);
    }
}

// ---------------- final ----------------
__global__ void final_k(const float* __restrict__ bout, float* __restrict__ out) {
    int s = blockIdx.x;
    float sw = g_sumw[s];
    float den = 1.f / (sw + 1e-6f);
    for (int c = threadIdx.x; c < CHN; c += 256) {
        float b = bout[c];
        out[(size_t)s * CHN + c] = g_out2[(size_t)s * CHN + c] + b;
        out[(size_t)(SQ + s) * CHN + c] = (g_out2[(size_t)(SQ + s) * CHN + c] + b * sw) * den;
    }
}

// ---------------- launch ----------------
extern "C" void kernel_launch(void* const* d_in, const int* in_sizes, int n_in,
                              void* d_out, int out_size) {
    const float* hs   = (const float*)d_in[0];
    const float* ctx  = (const float*)d_in[1];
    const float* lf   = (const float*)d_in[2];
    const float* bbox = (const float*)d_in[3];
    const float* Wq   = (const float*)d_in[4];
    const float* Wk   = (const float*)d_in[5];
    const float* Wv   = (const float*)d_in[6];
    const float* Wkg  = (const float*)d_in[7];
    const float* Wvg  = (const float*)d_in[8];
    const float* Wkl  = (const float*)d_in[9];
    const float* Wvl  = (const float*)d_in[10];
    const float* Wout = (const float*)d_in[11];
    const float* bout = (const float*)d_in[12];
    const int*   lidx = (const int*)d_in[13];
    float* out = (float*)d_out;

    float *hsR, *ctxR, *lfR, *WqT, *WkT, *WvT, *WkgT, *WvgT, *WklT, *WvlT, *WoutT;
    float *vp, *vTp, *vlp, *vlTp;
    cudaGetSymbolAddress((void**)&hsR, g_hsR);
    cudaGetSymbolAddress((void**)&ctxR, g_ctxR);
    cudaGetSymbolAddress((void**)&lfR, g_lfR);
    cudaGetSymbolAddress((void**)&WqT, g_WqT);
    cudaGetSymbolAddress((void**)&WkT, g_WkT);
    cudaGetSymbolAddress((void**)&WvT, g_WvT);
    cudaGetSymbolAddress((void**)&WkgT, g_WkgT);
    cudaGetSymbolAddress((void**)&WvgT, g_WvgT);
    cudaGetSymbolAddress((void**)&WklT, g_WklT);
    cudaGetSymbolAddress((void**)&WvlT, g_WvlT);
    cudaGetSymbolAddress((void**)&WoutT, g_WoutT);
    cudaGetSymbolAddress((void**)&vp, g_v);
    cudaGetSymbolAddress((void**)&vTp, g_vT);
    cudaGetSymbolAddress((void**)&vlp, g_vl);
    cudaGetSymbolAddress((void**)&vlTp, g_vlT);

    const int smemA = (4096 + 4096 + 128 * PST + 160 * PST + 512) * 4;   // ~131.6 KB
    const int smemB = (128 * SST + 2 * 160 * 20) * 4;                     // ~166.9 KB
    cudaFuncSetAttribute(fused_g_k, cudaFuncAttributeMaxDynamicSharedMemorySize, smemA);
    cudaFuncSetAttribute(fused_l_k, cudaFuncAttributeMaxDynamicSharedMemorySize, smemB);

    dim3 tb(32, 8);
    setup_k<<<1, 256>>>();

    long long nHs = 2LL * SQ * CHN, nCtx = (long long)NST * NCTX * CC, nLf = (long long)NSTR * LLOC * CC;
    round_k<<<(int)((nHs / 4 + 255) / 256), 256>>>(hs, hsR, nHs);
    round_k<<<(int)((nCtx / 4 + 255) / 256), 256>>>(ctx, ctxR, nCtx);
    round_k<<<(int)((nLf / 4 + 255) / 256), 256>>>(lf, lfR, nLf);

    transpose_k<<<dim3(40, 40, 1), tb>>>(Wq, WqT, CHN, CHN, CHN, CHN, 0, 0, 1);
    transpose_k<<<dim3(40, 24, 1), tb>>>(Wk, WkT, CC, CHN, CHN, CC, 0, 0, 1);
    transpose_k<<<dim3(40, 24, 1), tb>>>(Wv, WvT, CC, CHN, CHN, CC, 0, 0, 1);
    transpose_k<<<dim3(40, 24, 1), tb>>>(Wkg, WkgT, CC, CHN, CHN, CC, 0, 0, 1);
    transpose_k<<<dim3(40, 24, 1), tb>>>(Wvg, WvgT, CC, CHN, CHN, CC, 0, 0, 1);
    transpose_k<<<dim3(40, 24, 1), tb>>>(Wkl, WklT, CC, CHN, CHN, CC, 0, 0, 1);
    transpose_k<<<dim3(40, 24, 1), tb>>>(Wvl, WvlT, CC, CHN, CHN, CC, 0, 0, 1);
    transpose_k<<<dim3(40, 40, 1), tb>>>(Wout, WoutT, CHN, CHN, CHN, CHN, 0, 0, 1);

    // projections
    gemm_tf32<<<dim3(10, 64, 1), 256>>>(0, CHN, CHN, CHN, CHN, CHN, 1);     // Q
    gemm_tf32<<<dim3(10, 6, 4), 256>>>(1, CHN, CC, CC, CC, CHN, 1);         // K,V,Kg,Vg
    gemm_tf32<<<dim3(10, 17, 2), 256>>>(5, CHN, CC, CC, CC, CHN, 1);        // Kl,Vl
    kv_select_k<<<(NSTR * NCTX * CHN + 255) / 256, 256>>>(lidx);

    // V transposes
    transpose_k<<<dim3(40, 3, NST), tb>>>(vp, vTp, NCTX, CHN, CHN, NCTXP,
                                          (long long)NCTX * CHN, (long long)CHN * NCTXP, 0);
    transpose_k<<<dim3(40, 9, NSTR), tb>>>(vlp, vlTp, LLOC, CHN, CHN, LLOCP,
                                           (long long)LLOC * CHN, (long long)CHN * LLOCP, 0);

    // local raw scores (independent of global attention)
    gemm_tf32<<<dim3(3, 32, 64), 256>>>(176, LLOC, HD, CHN, CHN, LLOCP, 0);

    // fused global attention -> pre (all streams) + mraw
    fused_g_k<<<dim3(32, 72), 256, smemA>>>(lidx);
    mmax_k<<<8, 256>>>();

    // fused local softmax + PV + blend
    fused_l_k<<<dim3(32, 64), 256, smemB>>>();

    // fuser premix + output projection
    premix_k<<<SQ, 256>>>(bbox);
    gemm_tf32<<<dim3(10, 32, 2), 256>>>(7, CHN, CHN, CHN, CHN, CHN, 0);
    final_k<<<SQ, 256>>>(bout, out);
}

// round 6
// speedup vs baseline: 1.3383x; 1.0064x over previous
#include <cuda_runtime.h>
#include <math.h>
#include <stdint.h>

#define SQ 4096
#define CHN 1280
#define CC 768
#define NHEAD 8
#define HD 160
#define NCTX 77
#define NCTXP 80
#define NST 9
#define NSTR 8
#define LLOC 257
#define LLOCP 272
#define PST 84
#define SST2 292
#define SMEM3 (3 * 2048 * 2 * 4)

// ---------------- scratch ----------------
__device__ __align__(256) float g_hsR[2 * SQ * CHN];
__device__ __align__(256) float g_ctxR[NST * NCTX * CC];
__device__ __align__(256) float g_lfR[NSTR * LLOC * CC];
__device__ __align__(256) float g_q2[2 * SQ * CHN];
__device__ __align__(256) float g_k[NST * NCTX * CHN];
__device__ __align__(256) float g_v[NST * NCTX * CHN];
__device__ __align__(256) float g_kg[NSTR * NCTX * CHN];
__device__ __align__(256) float g_vg[NSTR * NCTX * CHN];
__device__ __align__(256) float g_kl[NSTR * LLOC * CHN];
__device__ __align__(256) float g_vl[NSTR * LLOC * CHN];
__device__ __align__(256) float g_WqT[CHN * CHN];
__device__ __align__(256) float g_WkT[CHN * CC];
__device__ __align__(256) float g_WvT[CHN * CC];
__device__ __align__(256) float g_WkgT[CHN * CC];
__device__ __align__(256) float g_WvgT[CHN * CC];
__device__ __align__(256) float g_WklT[CHN * CC];
__device__ __align__(256) float g_WvlT[CHN * CC];
__device__ __align__(256) float g_WoutT[CHN * CHN];
__device__ __align__(256) float g_vT[NST * CHN * NCTXP];
__device__ __align__(256) float g_vlT[NSTR * CHN * LLOCP];
__device__ __align__(256) float g_pre[NST * SQ * CHN];
__device__ __align__(256) float g_mix[SQ * CHN];
__device__ __align__(256) float g_out2[2 * SQ * CHN];
__device__ float g_mraw[NSTR * NHEAD * SQ];
__device__ float g_mmax[NSTR];
__device__ float g_sumw[SQ];

__device__ const float* d_Ap[16];
__device__ const float* d_Bp[16];
__device__ float*       d_Cp[16];
__device__ int          d_Mt[16];

// ---------------- helpers ----------------
__device__ __forceinline__ float tfr(float x) {
    uint32_t r;
    asm("cvt.rna.tf32.f32 %0, %1;" : "=r"(r) : "f"(x));
    return __uint_as_float(r);
}
__device__ __forceinline__ void cp16(float* sdst, const float* gsrc, bool p) {
    uint32_t sa = (uint32_t)__cvta_generic_to_shared(sdst);
    int sz = p ? 16 : 0;
    asm volatile("cp.async.cg.shared.global [%0], [%1], 16, %2;" :: "r"(sa), "l"(gsrc), "r"(sz));
}
#define CP_COMMIT asm volatile("cp.async.commit_group;")
#define CP_WAIT0 asm volatile("cp.async.wait_group 0;")
#define CP_WAIT1 asm volatile("cp.async.wait_group 1;")
#define CP_WAIT2 asm volatile("cp.async.wait_group 2;")
__device__ __forceinline__ void mma8(float* c, const uint32_t* a, const uint32_t* b) {
    asm volatile(
        "mma.sync.aligned.m16n8k8.row.col.f32.tf32.tf32.f32 "
        "{%0,%1,%2,%3}, {%4,%5,%6,%7}, {%8,%9}, {%0,%1,%2,%3};"
        : "+f"(c[0]), "+f"(c[1]), "+f"(c[2]), "+f"(c[3])
        : "r"(a[0]), "r"(a[1]), "r"(a[2]), "r"(a[3]), "r"(b[0]), "r"(b[1]));
}
#define SWOFF(r, c) (((r) << 4) + ((((((c) >> 2) ^ (((r) >> 1) & 3))) << 2) | ((c) & 3)))

// ---------------- setup ----------------
__global__ void setup_k() {
    if (threadIdx.x == 0) {
        d_Ap[0] = g_hsR;               d_Bp[0] = g_WqT;   d_Cp[0] = g_q2;    d_Mt[0] = 2 * SQ;
        d_Ap[1] = g_ctxR;              d_Bp[1] = g_WkT;   d_Cp[1] = g_k;     d_Mt[1] = NST * NCTX;
        d_Ap[2] = g_ctxR;              d_Bp[2] = g_WvT;   d_Cp[2] = g_v;     d_Mt[2] = NST * NCTX;
        d_Ap[3] = g_ctxR + NCTX * CC;  d_Bp[3] = g_WkgT;  d_Cp[3] = g_kg;    d_Mt[3] = NSTR * NCTX;
        d_Ap[4] = g_ctxR + NCTX * CC;  d_Bp[4] = g_WvgT;  d_Cp[4] = g_vg;    d_Mt[4] = NSTR * NCTX;
        d_Ap[5] = g_lfR;               d_Bp[5] = g_WklT;  d_Cp[5] = g_kl;    d_Mt[5] = NSTR * LLOC;
        d_Ap[6] = g_lfR;               d_Bp[6] = g_WvlT;  d_Cp[6] = g_vl;    d_Mt[6] = NSTR * LLOC;
        d_Ap[7] = g_pre;               d_Bp[7] = g_WoutT; d_Cp[7] = g_out2;  d_Mt[7] = SQ;
        d_Ap[8] = g_mix;               d_Bp[8] = g_WoutT; d_Cp[8] = g_out2 + (size_t)SQ * CHN;
        d_Mt[8] = SQ;
    }
}

// ---------------- round pass ----------------
__global__ void round_k(const float* __restrict__ src, float* __restrict__ dst, long long n) {
    long long i = ((long long)blockIdx.x * blockDim.x + threadIdx.x) * 4;
    if (i + 3 < n) {
        float4 v = *(const float4*)(src + i);
        v.x = tfr(v.x); v.y = tfr(v.y); v.z = tfr(v.z); v.w = tfr(v.w);
        *(float4*)(dst + i) = v;
    } else {
        for (long long j = i; j < n; j++) dst[j] = tfr(src[j]);
    }
}

// ---------------- transpose ----------------
__global__ void transpose_k(const float* __restrict__ src, float* __restrict__ dst,
                            int R, int C, int ldS, int ldD, long long sBS, long long dBS,
                            int rnd) {
    __shared__ float t[32][33];
    src += blockIdx.z * sBS;
    dst += blockIdx.z * dBS;
    int c0 = blockIdx.x << 5, r0 = blockIdx.y << 5;
    int tx = threadIdx.x, ty = threadIdx.y;
#pragma unroll
    for (int j = 0; j < 4; j++) {
        int rr = r0 + ty + j * 8, cc = c0 + tx;
        t[ty + j * 8][tx] = (rr < R && cc < C) ? src[(size_t)rr * ldS + cc] : 0.f;
    }
    __syncthreads();
#pragma unroll
    for (int j = 0; j < 4; j++) {
        int cc = c0 + ty + j * 8, rr = r0 + tx;
        if (cc < C && rr < ldD) {
            float v = t[tx][ty + j * 8];
            dst[(size_t)cc * ldD + rr] = rnd ? tfr(v) : v;
        }
    }
}

// ---------------- batched NT tf32 GEMM, 3-stage, single sync per kt ----------
__global__ void __launch_bounds__(256) gemm_tf32(int slot, int N, int K,
                                                 int lda, int ldb, int ldc, int mode) {
    extern __shared__ __align__(16) float smg[];
    float* As = smg;                  // 3 * 2048
    float* Bs = smg + 3 * 2048;       // 3 * 2048
    const float* Ab = d_Ap[slot + blockIdx.z];
    const float* Bb = d_Bp[slot + blockIdx.z];
    float* Cm       = d_Cp[slot + blockIdx.z];
    const int M     = d_Mt[slot + blockIdx.z];
    int tid = threadIdx.x, lane = tid & 31, warp = tid >> 5;
    int mBase = blockIdx.y << 7, nBase = blockIdx.x << 7;
    int mW = (warp >> 2) << 6, nW = (warp & 3) << 5;
    float acc[4][4][4];
#pragma unroll
    for (int a = 0; a < 4; a++)
#pragma unroll
        for (int b = 0; b < 4; b++)
#pragma unroll
            for (int cidx = 0; cidx < 4; cidx++) acc[a][b][cidx] = 0.f;

    const int lr = tid >> 2, lc4 = tid & 3;
    int KT = K >> 4;
    auto issue = [&](int st, int kt) {
        int k0 = kt << 4;
#pragma unroll
        for (int i = 0; i < 2; i++) {
            int r = lr + (i << 6);
            int gr = mBase + r; bool pa = gr < M; if (!pa) gr = M - 1;
            cp16(&As[st * 2048 + SWOFF(r, lc4 << 2)], Ab + (size_t)gr * lda + k0 + (lc4 << 2), pa);
            int gn = nBase + r; bool pb = gn < N; if (!pb) gn = N - 1;
            cp16(&Bs[st * 2048 + SWOFF(r, lc4 << 2)], Bb + (size_t)gn * ldb + k0 + (lc4 << 2), pb);
        }
        CP_COMMIT;
    };
    issue(0, 0);
    issue(1, 1);

    for (int kt = 0; kt < KT; kt++) {
        if (kt + 1 < KT) { CP_WAIT1; } else { CP_WAIT0; }
        __syncthreads();
        if (kt + 2 < KT) issue((kt + 2) % 3, kt + 2);
        int cur = kt % 3;
        const float* pA = As + cur * 2048;
        const float* pB = Bs + cur * 2048;
#pragma unroll
        for (int kk = 0; kk < 2; kk++) {
            int ck = (kk << 3) + (lane & 3);
            uint32_t af[4][4], bf[4][2];
#pragma unroll
            for (int mi = 0; mi < 4; mi++) {
                int r0 = mW + (mi << 4) + (lane >> 2);
                af[mi][0] = __float_as_uint(pA[SWOFF(r0, ck)]);
                af[mi][1] = __float_as_uint(pA[SWOFF(r0 + 8, ck)]);
                af[mi][2] = __float_as_uint(pA[SWOFF(r0, ck + 4)]);
                af[mi][3] = __float_as_uint(pA[SWOFF(r0 + 8, ck + 4)]);
            }
#pragma unroll
            for (int ni = 0; ni < 4; ni++) {
                int r0 = nW + (ni << 3) + (lane >> 2);
                bf[ni][0] = __float_as_uint(pB[SWOFF(r0, ck)]);
                bf[ni][1] = __float_as_uint(pB[SWOFF(r0, ck + 4)]);
            }
#pragma unroll
            for (int mi = 0; mi < 4; mi++)
#pragma unroll
                for (int ni = 0; ni < 4; ni++) mma8(acc[mi][ni], af[mi], bf[ni]);
        }
    }
    int rnd = mode & 1, blend = mode & 2;
#pragma unroll
    for (int mi = 0; mi < 4; mi++) {
#pragma unroll
        for (int half = 0; half < 2; half++) {
            int gm = mBase + mW + (mi << 4) + (lane >> 2) + half * 8;
            if (gm >= M) continue;
            float* crow = Cm + (size_t)gm * ldc;
#pragma unroll
            for (int ni = 0; ni < 4; ni++) {
                int gn = nBase + nW + (ni << 3) + ((lane & 3) << 1);
                float v0 = acc[mi][ni][half * 2], v1 = acc[mi][ni][half * 2 + 1];
                if (gn < N) {
                    float o = v0;
                    if (blend) o = 0.5f * crow[gn] + o;
                    if (rnd) o = tfr(o);
                    crow[gn] = o;
                }
                if (gn + 1 < N) {
                    float o = v1;
                    if (blend) o = 0.5f * crow[gn + 1] + o;
                    if (rnd) o = tfr(o);
                    crow[gn + 1] = o;
                }
            }
        }
    }
}

// ---------------- ELITE K/V select ----------------
__global__ void kv_select_k(const int* __restrict__ lidx) {
    int idx = blockIdx.x * 256 + threadIdx.x;
    const int tot = NSTR * NCTX * CHN;
    if (idx >= tot) return;
    int st = idx / (NCTX * CHN);
    if (lidx[st] >= 0) {
        g_k[NCTX * CHN + idx] = g_kg[idx];
        g_v[NCTX * CHN + idx] = g_vg[idx];
    }
}

// ============ fused global attention (R5, proven) ============
__global__ void __launch_bounds__(256) fused_g_k(const int* __restrict__ lidx) {
    extern __shared__ __align__(16) float sm[];
    float* qb  = sm;
    float* kb  = sm + 4096;
    float* psm = sm + 8192;
    float* vsm = psm + 128 * PST;
    float* smx = vsm + 160 * PST;
    float* ssu = smx + 256;
    __shared__ int sidx[8];

    int bh = blockIdx.y;
    int stream = bh >> 3, h = bh & 7;
    int q0 = blockIdx.x << 7;
    int tid = threadIdx.x, lane = tid & 31, warp = tid >> 5;
    if (tid < 8) sidx[tid] = lidx[tid];

    const float* Qb = g_q2 + (stream ? (size_t)SQ * CHN : 0) + (size_t)q0 * CHN + h * HD;
    const float* Kb = g_k + (size_t)stream * NCTX * CHN + h * HD;
    const float* Vt = g_vT + (size_t)stream * CHN * NCTXP + (size_t)h * HD * NCTXP;

    for (int u = tid; u < 160 * 20; u += 256) {
        int d = u / 20, c4 = (u % 20) * 4;
        cp16(vsm + d * PST + c4, Vt + (size_t)d * NCTXP + c4, true);
    }
    CP_COMMIT;

    const int lr = tid >> 2, lc4 = tid & 3;
    auto issueQK = [&](int st, int kt) {
        int k0 = kt << 4;
#pragma unroll
        for (int i = 0; i < 2; i++) {
            int r = lr + (i << 6);
            cp16(&qb[st * 2048 + SWOFF(r, lc4 << 2)], Qb + (size_t)r * CHN + k0 + (lc4 << 2), true);
            int kr = (r < NCTX) ? r : (NCTX - 1);
            cp16(&kb[st * 2048 + SWOFF(r, lc4 << 2)], Kb + (size_t)kr * CHN + k0 + (lc4 << 2), true);
        }
        CP_COMMIT;
    };
    issueQK(0, 0);

    int mW = (warp >> 1) << 5;
    int nWs = (warp & 1) * 40;
    float sc[2][5][4];
#pragma unroll
    for (int a = 0; a < 2; a++)
#pragma unroll
        for (int b = 0; b < 5; b++)
#pragma unroll
            for (int c = 0; c < 4; c++) sc[a][b][c] = 0.f;

    for (int kt = 0; kt < 10; kt++) {
        if (kt < 9) { issueQK((kt + 1) & 1, kt + 1); CP_WAIT1; }
        else        { CP_WAIT0; }
        __syncthreads();
        const float* pQ = qb + (kt & 1) * 2048;
        const float* pK = kb + (kt & 1) * 2048;
#pragma unroll
        for (int kk = 0; kk < 2; kk++) {
            int ck = (kk << 3) + (lane & 3);
            uint32_t af[2][4], bf[5][2];
#pragma unroll
            for (int mi = 0; mi < 2; mi++) {
                int r0 = mW + (mi << 4) + (lane >> 2);
                af[mi][0] = __float_as_uint(pQ[SWOFF(r0, ck)]);
                af[mi][1] = __float_as_uint(pQ[SWOFF(r0 + 8, ck)]);
                af[mi][2] = __float_as_uint(pQ[SWOFF(r0, ck + 4)]);
                af[mi][3] = __float_as_uint(pQ[SWOFF(r0 + 8, ck + 4)]);
            }
#pragma unroll
            for (int ni = 0; ni < 5; ni++) {
                int r0 = nWs + (ni << 3) + (lane >> 2);
                bf[ni][0] = __float_as_uint(pK[SWOFF(r0, ck)]);
                bf[ni][1] = __float_as_uint(pK[SWOFF(r0, ck + 4)]);
            }
#pragma unroll
            for (int mi = 0; mi < 2; mi++)
#pragma unroll
                for (int ni = 0; ni < 5; ni++) mma8(sc[mi][ni], af[mi], bf[ni]);
        }
        __syncthreads();
    }

    const float scale = 0.07905694150420949f;
    int half = warp & 1;
#pragma unroll
    for (int mi = 0; mi < 2; mi++)
#pragma unroll
        for (int hf = 0; hf < 2; hf++) {
            int row = mW + mi * 16 + (lane >> 2) + hf * 8;
            float mx = -1e30f;
#pragma unroll
            for (int ni = 0; ni < 5; ni++)
#pragma unroll
                for (int c = 0; c < 2; c++) {
                    int col = nWs + ni * 8 + ((lane & 3) << 1) + c;
                    if (col < NCTX) mx = fmaxf(mx, sc[mi][ni][hf * 2 + c]);
                }
            mx = fmaxf(mx, __shfl_xor_sync(0xffffffffu, mx, 1));
            mx = fmaxf(mx, __shfl_xor_sync(0xffffffffu, mx, 2));
            if ((lane & 3) == 0) smx[half * 128 + row] = mx;
        }
    __syncthreads();
#pragma unroll
    for (int mi = 0; mi < 2; mi++)
#pragma unroll
        for (int hf = 0; hf < 2; hf++) {
            int row = mW + mi * 16 + (lane >> 2) + hf * 8;
            float m = fmaxf(smx[row], smx[128 + row]);
            float s = 0.f;
#pragma unroll
            for (int ni = 0; ni < 5; ni++)
#pragma unroll
                for (int c = 0; c < 2; c++) {
                    int col = nWs + ni * 8 + ((lane & 3) << 1) + c;
                    float e = (col < NCTX) ? __expf((sc[mi][ni][hf * 2 + c] - m) * scale) : 0.f;
                    sc[mi][ni][hf * 2 + c] = e;
                    s += e;
                }
            s += __shfl_xor_sync(0xffffffffu, s, 1);
            s += __shfl_xor_sync(0xffffffffu, s, 2);
            if ((lane & 3) == 0) ssu[half * 128 + row] = s;
        }
    __syncthreads();
#pragma unroll
    for (int mi = 0; mi < 2; mi++)
#pragma unroll
        for (int hf = 0; hf < 2; hf++) {
            int row = mW + mi * 16 + (lane >> 2) + hf * 8;
            float inv = 1.f / (ssu[row] + ssu[128 + row]);
#pragma unroll
            for (int ni = 0; ni < 5; ni++)
#pragma unroll
                for (int c = 0; c < 2; c++) {
                    int col = nWs + ni * 8 + ((lane & 3) << 1) + c;
                    psm[row * PST + col] = (col < NCTX) ? tfr(sc[mi][ni][hf * 2 + c] * inv) : 0.f;
                }
        }
    __syncthreads();

    if (stream == 0) {
        for (int u = tid; u < 128 * 8; u += 256) {
            int r = u >> 3, i = u & 7;
            g_mraw[((size_t)i * NHEAD + h) * SQ + q0 + r] = psm[r * PST + sidx[i]];
        }
    }

    int nW = (warp & 1) * 80;
    float oa[2][10][4];
#pragma unroll
    for (int a = 0; a < 2; a++)
#pragma unroll
        for (int b = 0; b < 10; b++)
#pragma unroll
            for (int c = 0; c < 4; c++) oa[a][b][c] = 0.f;
#pragma unroll
    for (int kst = 0; kst < 10; kst++) {
        int ka = kst * 8 + (lane & 3);
        uint32_t af[2][4], bf[10][2];
#pragma unroll
        for (int mi = 0; mi < 2; mi++) {
            int r0 = mW + (mi << 4) + (lane >> 2);
            af[mi][0] = __float_as_uint(psm[r0 * PST + ka]);
            af[mi][1] = __float_as_uint(psm[(r0 + 8) * PST + ka]);
            af[mi][2] = __float_as_uint(psm[r0 * PST + ka + 4]);
            af[mi][3] = __float_as_uint(psm[(r0 + 8) * PST + ka + 4]);
        }
#pragma unroll
        for (int ni = 0; ni < 10; ni++) {
            int d = nW + (ni << 3) + (lane >> 2);
            bf[ni][0] = __float_as_uint(vsm[d * PST + ka]);
            bf[ni][1] = __float_as_uint(vsm[d * PST + ka + 4]);
        }
#pragma unroll
        for (int mi = 0; mi < 2; mi++)
#pragma unroll
            for (int ni = 0; ni < 10; ni++) mma8(oa[mi][ni], af[mi], bf[ni]);
    }
#pragma unroll
    for (int mi = 0; mi < 2; mi++)
#pragma unroll
        for (int hf = 0; hf < 2; hf++) {
            int g = q0 + mW + mi * 16 + (lane >> 2) + hf * 8;
            float* orow = g_pre + ((size_t)stream * SQ + g) * CHN + h * HD;
#pragma unroll
            for (int ni = 0; ni < 10; ni++) {
                int col = nW + (ni << 3) + ((lane & 3) << 1);
                float2 v = make_float2(tfr(oa[mi][ni][hf * 2]), tfr(oa[mi][ni][hf * 2 + 1]));
                *(float2*)(orow + col) = v;
            }
        }
}

// ---------------- per-instance gate max ----------------
__global__ void mmax_k() {
    __shared__ float red[256];
    int i = blockIdx.x;
    float mx = 0.f;
    const float* p = g_mraw + (size_t)i * NHEAD * SQ;
    for (int idx = threadIdx.x; idx < NHEAD * SQ; idx += 256) mx = fmaxf(mx, p[idx]);
    red[threadIdx.x] = mx;
    __syncthreads();
    for (int s = 128; s > 0; s >>= 1) {
        if (threadIdx.x < s) red[threadIdx.x] = fmaxf(red[threadIdx.x], red[threadIdx.x + s]);
        __syncthreads();
    }
    if (threadIdx.x == 0) g_mmax[i] = red[0];
}

// ============ fully fused local attention: QK + softmax + gate + PV + blend ===
// grid (64 qtiles of 64 rows, 64 ih), 256 threads
__global__ void __launch_bounds__(256) fused_l2_k() {
    extern __shared__ __align__(16) float sm[];
    float* ssm  = sm;                      // 64 * SST2
    float* strm = sm + 64 * SST2;          // 2 stages * 5632 floats

    int z = blockIdx.y;
    int inst = z >> 3, h = z & 7;
    int q0 = blockIdx.x << 6;
    int tid = threadIdx.x, lane = tid & 31, warp = tid >> 5;

    const float* Qb  = g_q2 + (size_t)SQ * CHN + (size_t)q0 * CHN + h * HD;
    const float* Klb = g_kl + (size_t)inst * LLOC * CHN + h * HD;
    const float* Vt  = g_vlT + (size_t)inst * CHN * LLOCP + (size_t)h * HD * LLOCP;

    // ---- phase 1: S = Q @ Kl^T (64 x 288, K=160) ----
    auto issueQK = [&](int st, int kt) {
        int k0 = kt << 4;
        float* base = strm + st * 5632;
        {
            int r = tid >> 2, c4 = (tid & 3) << 2;
            cp16(base + SWOFF(r, c4), Qb + (size_t)r * CHN + k0 + c4, true);
        }
        for (int u = tid; u < 1152; u += 256) {
            int r = u >> 2, c4 = (u & 3) << 2;
            int kr = (r < LLOC) ? r : (LLOC - 1);
            cp16(base + 1024 + SWOFF(r, c4), Klb + (size_t)kr * CHN + k0 + c4, true);
        }
        CP_COMMIT;
    };
    issueQK(0, 0);

    int mW2 = (warp >> 2) << 5;       // 0 or 32
    int nW4 = (warp & 3) * 72;        // 0,72,144,216
    float sc[2][9][4];
#pragma unroll
    for (int a = 0; a < 2; a++)
#pragma unroll
        for (int b = 0; b < 9; b++)
#pragma unroll
            for (int c = 0; c < 4; c++) sc[a][b][c] = 0.f;

    for (int kt = 0; kt < 10; kt++) {
        if (kt < 9) { issueQK((kt + 1) & 1, kt + 1); CP_WAIT1; }
        else        { CP_WAIT0; }
        __syncthreads();
        const float* pQ = strm + (kt & 1) * 5632;
        const float* pK = pQ + 1024;
#pragma unroll
        for (int kk = 0; kk < 2; kk++) {
            int ck = (kk << 3) + (lane & 3);
            uint32_t af[2][4], bf[9][2];
#pragma unroll
            for (int mi = 0; mi < 2; mi++) {
                int r0 = mW2 + (mi << 4) + (lane >> 2);
                af[mi][0] = __float_as_uint(pQ[SWOFF(r0, ck)]);
                af[mi][1] = __float_as_uint(pQ[SWOFF(r0 + 8, ck)]);
                af[mi][2] = __float_as_uint(pQ[SWOFF(r0, ck + 4)]);
                af[mi][3] = __float_as_uint(pQ[SWOFF(r0 + 8, ck + 4)]);
            }
#pragma unroll
            for (int ni = 0; ni < 9; ni++) {
                int r0 = nW4 + (ni << 3) + (lane >> 2);
                bf[ni][0] = __float_as_uint(pK[SWOFF(r0, ck)]);
                bf[ni][1] = __float_as_uint(pK[SWOFF(r0, ck + 4)]);
            }
#pragma unroll
            for (int mi = 0; mi < 2; mi++)
#pragma unroll
                for (int ni = 0; ni < 9; ni++) mma8(sc[mi][ni], af[mi], bf[ni]);
        }
        __syncthreads();
    }
    // store S to smem
#pragma unroll
    for (int mi = 0; mi < 2; mi++)
#pragma unroll
        for (int hf = 0; hf < 2; hf++) {
            int row = mW2 + mi * 16 + (lane >> 2) + hf * 8;
#pragma unroll
            for (int ni = 0; ni < 9; ni++) {
                int col = nW4 + ni * 8 + ((lane & 3) << 1);
                ssm[row * SST2 + col]     = sc[mi][ni][hf * 2];
                ssm[row * SST2 + col + 1] = sc[mi][ni][hf * 2 + 1];
            }
        }
    __syncthreads();

    // ---- V prefetch + softmax ----
    auto issueV = [&](int buf, int ch) {
        for (int u = tid; u < 640; u += 256) {
            int d = u >> 2, c4 = (u & 3) << 2;
            cp16(strm + buf * 5632 + d * 20 + c4, Vt + (size_t)d * LLOCP + ch * 16 + c4, true);
        }
        CP_COMMIT;
    };
    issueV(0, 0);
    issueV(1, 1);

    const float scale = 0.07905694150420949f;
    float gden = 0.5f / g_mmax[inst];
    for (int t = 0; t < 8; t++) {
        int row = warp * 8 + t;
        float* rp = ssm + row * SST2;
        float x[9];
#pragma unroll
        for (int j = 0; j < 9; j++) {
            int c = j * 32 + lane;
            x[j] = (c < LLOC) ? rp[c] : -1e30f;
        }
        float m = -1e30f;
#pragma unroll
        for (int j = 0; j < 9; j++) m = fmaxf(m, x[j]);
#pragma unroll
        for (int o = 16; o; o >>= 1) m = fmaxf(m, __shfl_xor_sync(0xffffffffu, m, o));
        float s = 0.f;
#pragma unroll
        for (int j = 0; j < 9; j++) {
            int c = j * 32 + lane;
            x[j] = (c < LLOC) ? __expf((x[j] - m) * scale) : 0.f;
            s += x[j];
        }
#pragma unroll
        for (int o = 16; o; o >>= 1) s += __shfl_xor_sync(0xffffffffu, s, o);
        float f = g_mraw[(size_t)z * SQ + q0 + row] * gden / s;
#pragma unroll
        for (int j = 0; j < 9; j++) {
            int c = j * 32 + lane;
            rp[c] = (c < LLOC) ? tfr(x[j] * f) : 0.f;
        }
    }
    __syncthreads();

    // ---- PV: O[64][160] = P[64][272] @ Vl[272][160] ----
    int nW = (warp & 3) * 40;
    float oa[2][5][4];
#pragma unroll
    for (int a = 0; a < 2; a++)
#pragma unroll
        for (int b = 0; b < 5; b++)
#pragma unroll
            for (int c = 0; c < 4; c++) oa[a][b][c] = 0.f;

    for (int ch = 0; ch < 17; ch++) {
        if (ch < 16) { CP_WAIT1; } else { CP_WAIT0; }
        __syncthreads();
        const float* pb = strm + (ch & 1) * 5632;
#pragma unroll
        for (int kk = 0; kk < 2; kk++) {
            int ka = (ch * 2 + kk) * 8 + (lane & 3);
            int kb = kk * 8 + (lane & 3);
            uint32_t af[2][4], bf[5][2];
#pragma unroll
            for (int mi = 0; mi < 2; mi++) {
                int r0 = mW2 + (mi << 4) + (lane >> 2);
                af[mi][0] = __float_as_uint(ssm[r0 * SST2 + ka]);
                af[mi][1] = __float_as_uint(ssm[(r0 + 8) * SST2 + ka]);
                af[mi][2] = __float_as_uint(ssm[r0 * SST2 + ka + 4]);
                af[mi][3] = __float_as_uint(ssm[(r0 + 8) * SST2 + ka + 4]);
            }
#pragma unroll
            for (int ni = 0; ni < 5; ni++) {
                int d = nW + (ni << 3) + (lane >> 2);
                bf[ni][0] = __float_as_uint(pb[d * 20 + kb]);
                bf[ni][1] = __float_as_uint(pb[d * 20 + kb + 4]);
            }
#pragma unroll
            for (int mi = 0; mi < 2; mi++)
#pragma unroll
                for (int ni = 0; ni < 5; ni++) mma8(oa[mi][ni], af[mi], bf[ni]);
        }
        __syncthreads();
        if (ch + 2 < 17) issueV(ch & 1, ch + 2);
    }

    // epilogue: blend 0.5*pre + O, rounded
#pragma unroll
    for (int mi = 0; mi < 2; mi++)
#pragma unroll
        for (int hf = 0; hf < 2; hf++) {
            int g = q0 + mW2 + mi * 16 + (lane >> 2) + hf * 8;
            float* prow = g_pre + ((size_t)(inst + 1) * SQ + g) * CHN + h * HD;
#pragma unroll
            for (int ni = 0; ni < 5; ni++) {
                int col = nW + (ni << 3) + ((lane & 3) << 1);
                float2 old = *(float2*)(prow + col);
                float2 v = make_float2(tfr(0.5f * old.x + oa[mi][ni][hf * 2]),
                                       tfr(0.5f * old.y + oa[mi][ni][hf * 2 + 1]));
                *(float2*)(prow + col) = v;
            }
        }
}

// ---------------- fuser premix ----------------
__global__ void premix_k(const float* __restrict__ bbox) {
    int s = blockIdx.x;
    int y = s >> 6, x = s & 63;
    float wgt[8];
    wgt[0] = 1.f;
    float sw = 1.f;
    const int off[4] = {3, 4, 11, 12};
#pragma unroll
    for (int i = 0; i < 7; i++) {
        float wmin = floorf(1024.f * bbox[i * 4 + 0]);
        float hmin = floorf(1024.f * bbox[i * 4 + 1]);
        float wmax = floorf(1024.f * bbox[i * 4 + 2]);
        float hmax = floorf(1024.f * bbox[i * 4 + 3]);
        float R = 0.f, Cv = 0.f;
#pragma unroll
        for (int j = 0; j < 4; j++) {
            float yy = (float)(16 * y + off[j]);
            float xx = (float)(16 * x + off[j]);
            if (yy >= hmin && yy < hmax) R += 0.25f;
            if (xx >= wmin && xx < wmax) Cv += 0.25f;
        }
        float g = 10.f * R * Cv;
        wgt[i + 1] = g;
        sw += g;
    }
    if (threadIdx.x == 0) g_sumw[s] = sw;
    for (int c = threadIdx.x; c < CHN; c += 256) {
        float acc = 0.f;
#pragma unroll
        for (int j = 0; j < 8; j++) acc += wgt[j] * g_pre[((size_t)(1 + j) * SQ + s) * CHN + c];
        g_mix[(size_t)s * CHN + c] = tfr(acc);
    }
}

// ---------------- final ----------------
__global__ void final_k(const float* __restrict__ bout, float* __restrict__ out) {
    int s = blockIdx.x;
    float sw = g_sumw[s];
    float den = 1.f / (sw + 1e-6f);
    for (int c = threadIdx.x; c < CHN; c += 256) {
        float b = bout[c];
        out[(size_t)s * CHN + c] = g_out2[(size_t)s * CHN + c] + b;
        out[(size_t)(SQ + s) * CHN + c] = (g_out2[(size_t)(SQ + s) * CHN + c] + b * sw) * den;
    }
}

// ---------------- launch ----------------
extern "C" void kernel_launch(void* const* d_in, const int* in_sizes, int n_in,
                              void* d_out, int out_size) {
    const float* hs   = (const float*)d_in[0];
    const float* ctx  = (const float*)d_in[1];
    const float* lf   = (const float*)d_in[2];
    const float* bbox = (const float*)d_in[3];
    const float* Wq   = (const float*)d_in[4];
    const float* Wk   = (const float*)d_in[5];
    const float* Wv   = (const float*)d_in[6];
    const float* Wkg  = (const float*)d_in[7];
    const float* Wvg  = (const float*)d_in[8];
    const float* Wkl  = (const float*)d_in[9];
    const float* Wvl  = (const float*)d_in[10];
    const float* Wout = (const float*)d_in[11];
    const float* bout = (const float*)d_in[12];
    const int*   lidx = (const int*)d_in[13];
    float* out = (float*)d_out;

    float *hsR, *ctxR, *lfR, *WqT, *WkT, *WvT, *WkgT, *WvgT, *WklT, *WvlT, *WoutT;
    float *vp, *vTp, *vlp, *vlTp;
    cudaGetSymbolAddress((void**)&hsR, g_hsR);
    cudaGetSymbolAddress((void**)&ctxR, g_ctxR);
    cudaGetSymbolAddress((void**)&lfR, g_lfR);
    cudaGetSymbolAddress((void**)&WqT, g_WqT);
    cudaGetSymbolAddress((void**)&WkT, g_WkT);
    cudaGetSymbolAddress((void**)&WvT, g_WvT);
    cudaGetSymbolAddress((void**)&WkgT, g_WkgT);
    cudaGetSymbolAddress((void**)&WvgT, g_WvgT);
    cudaGetSymbolAddress((void**)&WklT, g_WklT);
    cudaGetSymbolAddress((void**)&WvlT, g_WvlT);
    cudaGetSymbolAddress((void**)&WoutT, g_WoutT);
    cudaGetSymbolAddress((void**)&vp, g_v);
    cudaGetSymbolAddress((void**)&vTp, g_vT);
    cudaGetSymbolAddress((void**)&vlp, g_vl);
    cudaGetSymbolAddress((void**)&vlTp, g_vlT);

    const int smemA = (4096 + 4096 + 128 * PST + 160 * PST + 512) * 4;
    const int smemL = (64 * SST2 + 2 * 5632) * 4;   // ~119.8 KB
    cudaFuncSetAttribute(fused_g_k, cudaFuncAttributeMaxDynamicSharedMemorySize, smemA);
    cudaFuncSetAttribute(fused_l2_k, cudaFuncAttributeMaxDynamicSharedMemorySize, smemL);
    cudaFuncSetAttribute(gemm_tf32, cudaFuncAttributeMaxDynamicSharedMemorySize, SMEM3);

    dim3 tb(32, 8);
    setup_k<<<1, 32>>>();

    long long nHs = 2LL * SQ * CHN, nCtx = (long long)NST * NCTX * CC, nLf = (long long)NSTR * LLOC * CC;
    round_k<<<(int)((nHs / 4 + 255) / 256), 256>>>(hs, hsR, nHs);
    round_k<<<(int)((nCtx / 4 + 255) / 256), 256>>>(ctx, ctxR, nCtx);
    round_k<<<(int)((nLf / 4 + 255) / 256), 256>>>(lf, lfR, nLf);

    transpose_k<<<dim3(40, 40, 1), tb>>>(Wq, WqT, CHN, CHN, CHN, CHN, 0, 0, 1);
    transpose_k<<<dim3(40, 24, 1), tb>>>(Wk, WkT, CC, CHN, CHN, CC, 0, 0, 1);
    transpose_k<<<dim3(40, 24, 1), tb>>>(Wv, WvT, CC, CHN, CHN, CC, 0, 0, 1);
    transpose_k<<<dim3(40, 24, 1), tb>>>(Wkg, WkgT, CC, CHN, CHN, CC, 0, 0, 1);
    transpose_k<<<dim3(40, 24, 1), tb>>>(Wvg, WvgT, CC, CHN, CHN, CC, 0, 0, 1);
    transpose_k<<<dim3(40, 24, 1), tb>>>(Wkl, WklT, CC, CHN, CHN, CC, 0, 0, 1);
    transpose_k<<<dim3(40, 24, 1), tb>>>(Wvl, WvlT, CC, CHN, CHN, CC, 0, 0, 1);
    transpose_k<<<dim3(40, 40, 1), tb>>>(Wout, WoutT, CHN, CHN, CHN, CHN, 0, 0, 1);

    // projections
    gemm_tf32<<<dim3(10, 64, 1), 256, SMEM3>>>(0, CHN, CHN, CHN, CHN, CHN, 1);   // Q
    gemm_tf32<<<dim3(10, 6, 4), 256, SMEM3>>>(1, CHN, CC, CC, CC, CHN, 1);       // K,V,Kg,Vg
    gemm_tf32<<<dim3(10, 17, 2), 256, SMEM3>>>(5, CHN, CC, CC, CC, CHN, 1);      // Kl,Vl
    kv_select_k<<<(NSTR * NCTX * CHN + 255) / 256, 256>>>(lidx);

    // V transposes
    transpose_k<<<dim3(40, 3, NST), tb>>>(vp, vTp, NCTX, CHN, CHN, NCTXP,
                                          (long long)NCTX * CHN, (long long)CHN * NCTXP, 0);
    transpose_k<<<dim3(40, 9, NSTR), tb>>>(vlp, vlTp, LLOC, CHN, CHN, LLOCP,
                                           (long long)LLOC * CHN, (long long)CHN * LLOCP, 0);

    // fused global attention -> pre (all streams) + mraw
    fused_g_k<<<dim3(32, 72), 256, smemA>>>(lidx);
    mmax_k<<<8, 256>>>();

    // fully fused local attention (QK + softmax + gate + PV + blend)
    fused_l2_k<<<dim3(64, 64), 256, smemL>>>();

    // fuser premix + output projection
    premix_k<<<SQ, 256>>>(bbox);
    gemm_tf32<<<dim3(10, 32, 2), 256, SMEM3>>>(7, CHN, CHN, CHN, CHN, CHN, 0);
    final_k<<<SQ, 256>>>(bout, out);
}

// round 7
// speedup vs baseline: 2.1599x; 1.6139x over previous
#include <cuda_runtime.h>
#include <cuda_fp16.h>
#include <math.h>
#include <stdint.h>

#define SQ 4096
#define CHN 1280
#define CC 768
#define NHEAD 8
#define HD 160
#define NCTX 77
#define NCTXP 80
#define NST 9
#define NSTR 8
#define LLOC 257
#define LLOCP 272
#define PSTU 44
#define PLU 140
#define SST2 292
#define SMEM3 (3 * 2048 * 2 * 4)

// ---------------- scratch ----------------
__device__ __align__(256) __half g_hsH[2 * SQ * CHN];
__device__ __align__(256) __half g_ctxH[NST * NCTX * CC];
__device__ __align__(256) __half g_lfH[NSTR * LLOC * CC];
__device__ __align__(256) __half g_q2[2 * SQ * CHN];
__device__ __align__(256) __half g_k[NST * NCTX * CHN];
__device__ __align__(256) __half g_v[NST * NCTX * CHN];
__device__ __align__(256) __half g_kg[NSTR * NCTX * CHN];
__device__ __align__(256) __half g_vg[NSTR * NCTX * CHN];
__device__ __align__(256) __half g_kl[NSTR * LLOC * CHN];
__device__ __align__(256) __half g_vl[NSTR * LLOC * CHN];
__device__ __align__(256) __half g_WqT[CHN * CHN];
__device__ __align__(256) __half g_WkT[CHN * CC];
__device__ __align__(256) __half g_WvT[CHN * CC];
__device__ __align__(256) __half g_WkgT[CHN * CC];
__device__ __align__(256) __half g_WvgT[CHN * CC];
__device__ __align__(256) __half g_WklT[CHN * CC];
__device__ __align__(256) __half g_WvlT[CHN * CC];
__device__ __align__(256) __half g_WoutT[CHN * CHN];
__device__ __align__(256) __half g_vT[NST * CHN * NCTXP];
__device__ __align__(256) __half g_vlT[NSTR * CHN * LLOCP];
__device__ __align__(256) __half g_pre[NST * SQ * CHN];
__device__ __align__(256) __half g_mix[SQ * CHN];
__device__ __align__(256) float g_out2[2 * SQ * CHN];
__device__ float g_mraw[NSTR * NHEAD * SQ];
__device__ float g_mmax[NSTR];
__device__ float g_sumw[SQ];

__device__ const __half* d_Ap[16];
__device__ const __half* d_Bp[16];
__device__ void*         d_Cp[16];
__device__ int           d_Mt[16];

// ---------------- helpers ----------------
__device__ __forceinline__ uint32_t pk2(float a, float b) {
    __half2 h = __halves2half2(__float2half_rn(a), __float2half_rn(b));
    return *(uint32_t*)&h;
}
__device__ __forceinline__ void cp16(void* sdst, const void* gsrc, bool p) {
    uint32_t sa = (uint32_t)__cvta_generic_to_shared(sdst);
    int sz = p ? 16 : 0;
    asm volatile("cp.async.cg.shared.global [%0], [%1], 16, %2;" :: "r"(sa), "l"(gsrc), "r"(sz));
}
#define CP_COMMIT asm volatile("cp.async.commit_group;")
#define CP_WAIT0 asm volatile("cp.async.wait_group 0;")
#define CP_WAIT1 asm volatile("cp.async.wait_group 1;")
#define CP_WAIT2 asm volatile("cp.async.wait_group 2;")
__device__ __forceinline__ void mma16(float* c, const uint32_t* a, const uint32_t* b) {
    asm volatile(
        "mma.sync.aligned.m16n8k16.row.col.f32.f16.f16.f32 "
        "{%0,%1,%2,%3}, {%4,%5,%6,%7}, {%8,%9}, {%0,%1,%2,%3};"
        : "+f"(c[0]), "+f"(c[1]), "+f"(c[2]), "+f"(c[3])
        : "r"(a[0]), "r"(a[1]), "r"(a[2]), "r"(a[3]), "r"(b[0]), "r"(b[1]));
}
// swizzled offset in u32 units for [128][16-u32] tile (same proven pattern)
#define SWOFF(r, c) (((r) << 4) + ((((((c) >> 2) ^ (((r) >> 1) & 3))) << 2) | ((c) & 3)))

// ---------------- setup ----------------
__global__ void setup_k() {
    if (threadIdx.x == 0) {
        d_Ap[0] = g_hsH;               d_Bp[0] = g_WqT;   d_Cp[0] = g_q2;    d_Mt[0] = 2 * SQ;
        d_Ap[1] = g_ctxH;              d_Bp[1] = g_WkT;   d_Cp[1] = g_k;     d_Mt[1] = NST * NCTX;
        d_Ap[2] = g_ctxH;              d_Bp[2] = g_WvT;   d_Cp[2] = g_v;     d_Mt[2] = NST * NCTX;
        d_Ap[3] = g_ctxH + NCTX * CC;  d_Bp[3] = g_WkgT;  d_Cp[3] = g_kg;    d_Mt[3] = NSTR * NCTX;
        d_Ap[4] = g_ctxH + NCTX * CC;  d_Bp[4] = g_WvgT;  d_Cp[4] = g_vg;    d_Mt[4] = NSTR * NCTX;
        d_Ap[5] = g_lfH;               d_Bp[5] = g_WklT;  d_Cp[5] = g_kl;    d_Mt[5] = NSTR * LLOC;
        d_Ap[6] = g_lfH;               d_Bp[6] = g_WvlT;  d_Cp[6] = g_vl;    d_Mt[6] = NSTR * LLOC;
        d_Ap[7] = g_pre;               d_Bp[7] = g_WoutT; d_Cp[7] = g_out2;  d_Mt[7] = SQ;
        d_Ap[8] = g_mix;               d_Bp[8] = g_WoutT; d_Cp[8] = g_out2 + (size_t)SQ * CHN;
        d_Mt[8] = SQ;
    }
}

// ---------------- round inputs to fp16 ----------------
__global__ void round_h(const float* __restrict__ src, __half* __restrict__ dst, long long n) {
    long long i = ((long long)blockIdx.x * blockDim.x + threadIdx.x) * 8;
    if (i + 7 < n) {
        float4 a = *(const float4*)(src + i);
        float4 b = *(const float4*)(src + i + 4);
        uint4 u;
        u.x = pk2(a.x, a.y); u.y = pk2(a.z, a.w);
        u.z = pk2(b.x, b.y); u.w = pk2(b.z, b.w);
        *(uint4*)(dst + i) = u;
    } else {
        for (long long j = i; j < n; j++) dst[j] = __float2half_rn(src[j]);
    }
}

// ---------------- transpose (templated src type) -> half ----------------
template <typename TS>
__global__ void transpose_k(const TS* __restrict__ src, __half* __restrict__ dst,
                            int R, int C, int ldS, int ldD, long long sBS, long long dBS) {
    __shared__ float t[32][33];
    src += blockIdx.z * sBS;
    dst += blockIdx.z * dBS;
    int c0 = blockIdx.x << 5, r0 = blockIdx.y << 5;
    int tx = threadIdx.x, ty = threadIdx.y;
#pragma unroll
    for (int j = 0; j < 4; j++) {
        int rr = r0 + ty + j * 8, cc = c0 + tx;
        t[ty + j * 8][tx] = (rr < R && cc < C) ? (float)src[(size_t)rr * ldS + cc] : 0.f;
    }
    __syncthreads();
#pragma unroll
    for (int j = 0; j < 4; j++) {
        int cc = c0 + ty + j * 8, rr = r0 + tx;
        if (cc < C && rr < ldD)
            dst[(size_t)cc * ldD + rr] = __float2half_rn(t[tx][ty + j * 8]);
    }
}

// ---------------- batched NT fp16 GEMM, BK=32 halfs, 3-stage ----------------
// mode: 1 = half output, 0 = float output
__global__ void __launch_bounds__(256) gemm_h(int slot, int N, int K,
                                              int lda, int ldb, int ldc, int mode) {
    extern __shared__ __align__(16) uint32_t smg[];
    uint32_t* As = smg;                  // 3 * 2048 u32
    uint32_t* Bs = smg + 3 * 2048;
    const __half* Ab = d_Ap[slot + blockIdx.z];
    const __half* Bb = d_Bp[slot + blockIdx.z];
    void* Cm         = d_Cp[slot + blockIdx.z];
    const int M      = d_Mt[slot + blockIdx.z];
    int tid = threadIdx.x, lane = tid & 31, warp = tid >> 5;
    int mBase = blockIdx.y << 7, nBase = blockIdx.x << 7;
    int mW = (warp >> 2) << 6, nW = (warp & 3) << 5;
    float acc[4][4][4];
#pragma unroll
    for (int a = 0; a < 4; a++)
#pragma unroll
        for (int b = 0; b < 4; b++)
#pragma unroll
            for (int cI = 0; cI < 4; cI++) acc[a][b][cI] = 0.f;

    const int lr = tid >> 2, lc = tid & 3;     // lc: 16B-chunk index (4 u32)
    int KT = K >> 5;
    auto issue = [&](int st, int kt) {
        int k0 = kt << 5;   // halfs
#pragma unroll
        for (int i = 0; i < 2; i++) {
            int idx = tid + (i << 8);
            int r = idx >> 2, cu = (idx & 3) << 2;
            int gr = mBase + r; bool pa = gr < M; if (!pa) gr = M - 1;
            cp16(&As[st * 2048 + SWOFF(r, cu)], Ab + (size_t)gr * lda + k0 + (cu << 1), pa);
            int gn = nBase + r; bool pb = gn < N; if (!pb) gn = N - 1;
            cp16(&Bs[st * 2048 + SWOFF(r, cu)], Bb + (size_t)gn * ldb + k0 + (cu << 1), pb);
        }
        CP_COMMIT;
    };
    issue(0, 0);
    issue(1, 1);

    for (int kt = 0; kt < KT; kt++) {
        if (kt + 1 < KT) { CP_WAIT1; } else { CP_WAIT0; }
        __syncthreads();
        if (kt + 2 < KT) issue((kt + 2) % 3, kt + 2);
        const uint32_t* pA = As + (kt % 3) * 2048;
        const uint32_t* pB = Bs + (kt % 3) * 2048;
#pragma unroll
        for (int kk = 0; kk < 2; kk++) {
            int ck = (kk << 3) + (lane & 3);
            uint32_t af[4][4], bf[4][2];
#pragma unroll
            for (int mi = 0; mi < 4; mi++) {
                int r0 = mW + (mi << 4) + (lane >> 2);
                af[mi][0] = pA[SWOFF(r0, ck)];
                af[mi][1] = pA[SWOFF(r0 + 8, ck)];
                af[mi][2] = pA[SWOFF(r0, ck + 4)];
                af[mi][3] = pA[SWOFF(r0 + 8, ck + 4)];
            }
#pragma unroll
            for (int ni = 0; ni < 4; ni++) {
                int r0 = nW + (ni << 3) + (lane >> 2);
                bf[ni][0] = pB[SWOFF(r0, ck)];
                bf[ni][1] = pB[SWOFF(r0, ck + 4)];
            }
#pragma unroll
            for (int mi = 0; mi < 4; mi++)
#pragma unroll
                for (int ni = 0; ni < 4; ni++) mma16(acc[mi][ni], af[mi], bf[ni]);
        }
    }
#pragma unroll
    for (int mi = 0; mi < 4; mi++) {
#pragma unroll
        for (int half = 0; half < 2; half++) {
            int gm = mBase + mW + (mi << 4) + (lane >> 2) + half * 8;
            if (gm >= M) continue;
#pragma unroll
            for (int ni = 0; ni < 4; ni++) {
                int gn = nBase + nW + (ni << 3) + ((lane & 3) << 1);
                if (gn + 1 >= N) continue;
                float v0 = acc[mi][ni][half * 2], v1 = acc[mi][ni][half * 2 + 1];
                if (mode & 1) {
                    __half* crow = (__half*)Cm + (size_t)gm * ldc;
                    *(uint32_t*)(crow + gn) = pk2(v0, v1);
                } else {
                    float* crow = (float*)Cm + (size_t)gm * ldc;
                    crow[gn] = v0;
                    crow[gn + 1] = v1;
                }
            }
        }
    }
}

// ---------------- ELITE K/V select (u32 = half2 copies) ----------------
__global__ void kv_select_k(const int* __restrict__ lidx) {
    int idx = blockIdx.x * 256 + threadIdx.x;
    const int tot = NSTR * NCTX * CHN / 2;
    if (idx >= tot) return;
    int st = idx / (NCTX * CHN / 2);
    if (lidx[st] >= 0) {
        ((uint32_t*)g_k)[NCTX * CHN / 2 + idx] = ((const uint32_t*)g_kg)[idx];
        ((uint32_t*)g_v)[NCTX * CHN / 2 + idx] = ((const uint32_t*)g_vg)[idx];
    }
}

// ============ fused global attention (fp16 operands) ============
// grid (32 qtiles, 72 bh), 256 threads
__global__ void __launch_bounds__(256) fused_g_k(const int* __restrict__ lidx) {
    extern __shared__ __align__(16) uint32_t smu[];
    uint32_t* qb  = smu;                       // 2 * 2048
    uint32_t* kb  = smu + 4096;                // 2 * 2048
    uint32_t* psm = smu + 8192;                // 128 * PSTU
    uint32_t* vsm = psm + 128 * PSTU;          // 160 * PSTU
    float* smx = (float*)(vsm + 160 * PSTU);   // 2 * 128
    float* ssu = smx + 256;                    // 2 * 128
    __shared__ int sidx[8];

    int bh = blockIdx.y;
    int stream = bh >> 3, h = bh & 7;
    int q0 = blockIdx.x << 7;
    int tid = threadIdx.x, lane = tid & 31, warp = tid >> 5;
    if (tid < 8) sidx[tid] = lidx[tid];

    const __half* Qb = g_q2 + (stream ? (size_t)SQ * CHN : 0) + (size_t)q0 * CHN + h * HD;
    const __half* Kb = g_k + (size_t)stream * NCTX * CHN + h * HD;
    const __half* Vt = g_vT + (size_t)stream * CHN * NCTXP + (size_t)h * HD * NCTXP;

    // V^T preload: 160 rows x 80 halfs (10 chunks of 16B per row)
    for (int u = tid; u < 160 * 10; u += 256) {
        int d = u / 10, c = u % 10;
        cp16(vsm + d * PSTU + c * 4, Vt + (size_t)d * NCTXP + c * 8, true);
    }
    CP_COMMIT;

    auto issueQK = [&](int st, int kt) {
        int k0 = kt << 5;
#pragma unroll
        for (int i = 0; i < 2; i++) {
            int idx = tid + (i << 8);
            int r = idx >> 2, cu = (idx & 3) << 2;
            cp16(&qb[st * 2048 + SWOFF(r, cu)], Qb + (size_t)r * CHN + k0 + (cu << 1), true);
            int kr = (r < NCTX) ? r : (NCTX - 1);
            cp16(&kb[st * 2048 + SWOFF(r, cu)], Kb + (size_t)kr * CHN + k0 + (cu << 1), true);
        }
        CP_COMMIT;
    };
    issueQK(0, 0);

    int mW = (warp >> 1) << 5;
    int nWs = (warp & 1) * 40;
    float sc[2][5][4];
#pragma unroll
    for (int a = 0; a < 2; a++)
#pragma unroll
        for (int b = 0; b < 5; b++)
#pragma unroll
            for (int c = 0; c < 4; c++) sc[a][b][c] = 0.f;

    for (int kt = 0; kt < 5; kt++) {
        if (kt < 4) { issueQK((kt + 1) & 1, kt + 1); CP_WAIT1; }
        else        { CP_WAIT0; }
        __syncthreads();
        const uint32_t* pQ = qb + (kt & 1) * 2048;
        const uint32_t* pK = kb + (kt & 1) * 2048;
#pragma unroll
        for (int kk = 0; kk < 2; kk++) {
            int ck = (kk << 3) + (lane & 3);
            uint32_t af[2][4], bf[5][2];
#pragma unroll
            for (int mi = 0; mi < 2; mi++) {
                int r0 = mW + (mi << 4) + (lane >> 2);
                af[mi][0] = pQ[SWOFF(r0, ck)];
                af[mi][1] = pQ[SWOFF(r0 + 8, ck)];
                af[mi][2] = pQ[SWOFF(r0, ck + 4)];
                af[mi][3] = pQ[SWOFF(r0 + 8, ck + 4)];
            }
#pragma unroll
            for (int ni = 0; ni < 5; ni++) {
                int r0 = nWs + (ni << 3) + (lane >> 2);
                bf[ni][0] = pK[SWOFF(r0, ck)];
                bf[ni][1] = pK[SWOFF(r0, ck + 4)];
            }
#pragma unroll
            for (int mi = 0; mi < 2; mi++)
#pragma unroll
                for (int ni = 0; ni < 5; ni++) mma16(sc[mi][ni], af[mi], bf[ni]);
        }
        __syncthreads();
    }

    const float scale = 0.07905694150420949f;
    int half = warp & 1;
#pragma unroll
    for (int mi = 0; mi < 2; mi++)
#pragma unroll
        for (int hf = 0; hf < 2; hf++) {
            int row = mW + mi * 16 + (lane >> 2) + hf * 8;
            float mx = -1e30f;
#pragma unroll
            for (int ni = 0; ni < 5; ni++)
#pragma unroll
                for (int c = 0; c < 2; c++) {
                    int col = nWs + ni * 8 + ((lane & 3) << 1) + c;
                    if (col < NCTX) mx = fmaxf(mx, sc[mi][ni][hf * 2 + c]);
                }
            mx = fmaxf(mx, __shfl_xor_sync(0xffffffffu, mx, 1));
            mx = fmaxf(mx, __shfl_xor_sync(0xffffffffu, mx, 2));
            if ((lane & 3) == 0) smx[half * 128 + row] = mx;
        }
    __syncthreads();
#pragma unroll
    for (int mi = 0; mi < 2; mi++)
#pragma unroll
        for (int hf = 0; hf < 2; hf++) {
            int row = mW + mi * 16 + (lane >> 2) + hf * 8;
            float m = fmaxf(smx[row], smx[128 + row]);
            float s = 0.f;
#pragma unroll
            for (int ni = 0; ni < 5; ni++)
#pragma unroll
                for (int c = 0; c < 2; c++) {
                    int col = nWs + ni * 8 + ((lane & 3) << 1) + c;
                    float e = (col < NCTX) ? __expf((sc[mi][ni][hf * 2 + c] - m) * scale) : 0.f;
                    sc[mi][ni][hf * 2 + c] = e;
                    s += e;
                }
            s += __shfl_xor_sync(0xffffffffu, s, 1);
            s += __shfl_xor_sync(0xffffffffu, s, 2);
            if ((lane & 3) == 0) ssu[half * 128 + row] = s;
        }
    __syncthreads();
#pragma unroll
    for (int mi = 0; mi < 2; mi++)
#pragma unroll
        for (int hf = 0; hf < 2; hf++) {
            int row = mW + mi * 16 + (lane >> 2) + hf * 8;
            float inv = 1.f / (ssu[row] + ssu[128 + row]);
#pragma unroll
            for (int ni = 0; ni < 5; ni++) {
                int col = nWs + ni * 8 + ((lane & 3) << 1);
                float v0 = (col < NCTX) ? sc[mi][ni][hf * 2] * inv : 0.f;
                float v1 = (col + 1 < NCTX) ? sc[mi][ni][hf * 2 + 1] * inv : 0.f;
                psm[row * PSTU + (nWs >> 1) + ni * 4 + (lane & 3)] = pk2(v0, v1);
            }
        }
    __syncthreads();

    if (stream == 0) {
        const __half* ph = (const __half*)psm;
        for (int u = tid; u < 128 * 8; u += 256) {
            int r = u >> 3, i = u & 7;
            g_mraw[((size_t)i * NHEAD + h) * SQ + q0 + r] =
                __half2float(ph[r * (2 * PSTU) + sidx[i]]);
        }
    }

    // PV: O[128][160] = P[128][80] @ V[80][160]
    int nW = (warp & 1) * 80;
    float oa[2][10][4];
#pragma unroll
    for (int a = 0; a < 2; a++)
#pragma unroll
        for (int b = 0; b < 10; b++)
#pragma unroll
            for (int c = 0; c < 4; c++) oa[a][b][c] = 0.f;
#pragma unroll
    for (int kst = 0; kst < 5; kst++) {
        int ka = kst * 8 + (lane & 3);
        uint32_t af[2][4], bf[10][2];
#pragma unroll
        for (int mi = 0; mi < 2; mi++) {
            int r0 = mW + (mi << 4) + (lane >> 2);
            af[mi][0] = psm[r0 * PSTU + ka];
            af[mi][1] = psm[(r0 + 8) * PSTU + ka];
            af[mi][2] = psm[r0 * PSTU + ka + 4];
            af[mi][3] = psm[(r0 + 8) * PSTU + ka + 4];
        }
#pragma unroll
        for (int ni = 0; ni < 10; ni++) {
            int d = nW + (ni << 3) + (lane >> 2);
            bf[ni][0] = vsm[d * PSTU + ka];
            bf[ni][1] = vsm[d * PSTU + ka + 4];
        }
#pragma unroll
        for (int mi = 0; mi < 2; mi++)
#pragma unroll
            for (int ni = 0; ni < 10; ni++) mma16(oa[mi][ni], af[mi], bf[ni]);
    }
#pragma unroll
    for (int mi = 0; mi < 2; mi++)
#pragma unroll
        for (int hf = 0; hf < 2; hf++) {
            int g = q0 + mW + mi * 16 + (lane >> 2) + hf * 8;
            __half* orow = g_pre + ((size_t)stream * SQ + g) * CHN + h * HD;
#pragma unroll
            for (int ni = 0; ni < 10; ni++) {
                int col = nW + (ni << 3) + ((lane & 3) << 1);
                *(uint32_t*)(orow + col) = pk2(oa[mi][ni][hf * 2], oa[mi][ni][hf * 2 + 1]);
            }
        }
}

// ---------------- per-instance gate max ----------------
__global__ void mmax_k() {
    __shared__ float red[256];
    int i = blockIdx.x;
    float mx = 0.f;
    const float* p = g_mraw + (size_t)i * NHEAD * SQ;
    for (int idx = threadIdx.x; idx < NHEAD * SQ; idx += 256) mx = fmaxf(mx, p[idx]);
    red[threadIdx.x] = mx;
    __syncthreads();
    for (int s = 128; s > 0; s >>= 1) {
        if (threadIdx.x < s) red[threadIdx.x] = fmaxf(red[threadIdx.x], red[threadIdx.x + s]);
        __syncthreads();
    }
    if (threadIdx.x == 0) g_mmax[i] = red[0];
}

// ============ fully fused local attention (fp16 operands) ============
// grid (64 qtiles of 64 rows, 64 ih), 256 threads
__global__ void __launch_bounds__(256) fused_l2_k() {
    extern __shared__ __align__(16) uint32_t smu[];
    float*    ssm  = (float*)smu;              // 64 * SST2 f32 (scores/probs)
    uint32_t* plm  = smu + 64 * SST2;          // 64 * PLU u32 (P halfs)
    uint32_t* strm = smu + 64 * SST2 + 64 * PLU; // 2 stages * 5632 u32

    int z = blockIdx.y;
    int inst = z >> 3, h = z & 7;
    int q0 = blockIdx.x << 6;
    int tid = threadIdx.x, lane = tid & 31, warp = tid >> 5;

    const __half* Qb  = g_q2 + (size_t)SQ * CHN + (size_t)q0 * CHN + h * HD;
    const __half* Klb = g_kl + (size_t)inst * LLOC * CHN + h * HD;
    const __half* Vt  = g_vlT + (size_t)inst * CHN * LLOCP + (size_t)h * HD * LLOCP;

    // phase 1: S = Q @ Kl^T (64 x 288, K=160 halfs)
    auto issueQK = [&](int st, int kt) {
        int k0 = kt << 5;
        uint32_t* base = strm + st * 5632;
        {
            int r = tid >> 2, cu = (tid & 3) << 2;
            cp16(base + SWOFF(r, cu), Qb + (size_t)r * CHN + k0 + (cu << 1), true);
        }
        for (int u = tid; u < 1152; u += 256) {
            int r = u >> 2, cu = (u & 3) << 2;
            int kr = (r < LLOC) ? r : (LLOC - 1);
            cp16(base + 1024 + SWOFF(r, cu), Klb + (size_t)kr * CHN + k0 + (cu << 1), true);
        }
        CP_COMMIT;
    };
    issueQK(0, 0);

    int mW2 = (warp >> 2) << 5;
    int nW4 = (warp & 3) * 72;
    float sc[2][9][4];
#pragma unroll
    for (int a = 0; a < 2; a++)
#pragma unroll
        for (int b = 0; b < 9; b++)
#pragma unroll
            for (int c = 0; c < 4; c++) sc[a][b][c] = 0.f;

    for (int kt = 0; kt < 5; kt++) {
        if (kt < 4) { issueQK((kt + 1) & 1, kt + 1); CP_WAIT1; }
        else        { CP_WAIT0; }
        __syncthreads();
        const uint32_t* pQ = strm + (kt & 1) * 5632;
        const uint32_t* pK = pQ + 1024;
#pragma unroll
        for (int kk = 0; kk < 2; kk++) {
            int ck = (kk << 3) + (lane & 3);
            uint32_t af[2][4], bf[9][2];
#pragma unroll
            for (int mi = 0; mi < 2; mi++) {
                int r0 = mW2 + (mi << 4) + (lane >> 2);
                af[mi][0] = pQ[SWOFF(r0, ck)];
                af[mi][1] = pQ[SWOFF(r0 + 8, ck)];
                af[mi][2] = pQ[SWOFF(r0, ck + 4)];
                af[mi][3] = pQ[SWOFF(r0 + 8, ck + 4)];
            }
#pragma unroll
            for (int ni = 0; ni < 9; ni++) {
                int r0 = nW4 + (ni << 3) + (lane >> 2);
                bf[ni][0] = pK[SWOFF(r0, ck)];
                bf[ni][1] = pK[SWOFF(r0, ck + 4)];
            }
#pragma unroll
            for (int mi = 0; mi < 2; mi++)
#pragma unroll
                for (int ni = 0; ni < 9; ni++) mma16(sc[mi][ni], af[mi], bf[ni]);
        }
        __syncthreads();
    }
#pragma unroll
    for (int mi = 0; mi < 2; mi++)
#pragma unroll
        for (int hf = 0; hf < 2; hf++) {
            int row = mW2 + mi * 16 + (lane >> 2) + hf * 8;
#pragma unroll
            for (int ni = 0; ni < 9; ni++) {
                int col = nW4 + ni * 8 + ((lane & 3) << 1);
                ssm[row * SST2 + col]     = sc[mi][ni][hf * 2];
                ssm[row * SST2 + col + 1] = sc[mi][ni][hf * 2 + 1];
            }
        }
    __syncthreads();

    // V prefetch (chunks of 16 keys x 160 dims, half)
    auto issueV = [&](int buf, int ch) {
        for (int u = tid; u < 320; u += 256) {
            int d = u >> 1, c = u & 1;
            cp16(strm + buf * 5632 + d * 12 + c * 4, Vt + (size_t)d * LLOCP + ch * 16 + c * 8, true);
        }
        CP_COMMIT;
    };
    issueV(0, 0);
    issueV(1, 1);

    // softmax + gate (f32 in ssm)
    const float scale = 0.07905694150420949f;
    float gden = 0.5f / g_mmax[inst];
    for (int t = 0; t < 8; t++) {
        int row = warp * 8 + t;
        float* rp = ssm + row * SST2;
        float x[9];
#pragma unroll
        for (int j = 0; j < 9; j++) {
            int c = j * 32 + lane;
            x[j] = (c < LLOC) ? rp[c] : -1e30f;
        }
        float m = -1e30f;
#pragma unroll
        for (int j = 0; j < 9; j++) m = fmaxf(m, x[j]);
#pragma unroll
        for (int o = 16; o; o >>= 1) m = fmaxf(m, __shfl_xor_sync(0xffffffffu, m, o));
        float s = 0.f;
#pragma unroll
        for (int j = 0; j < 9; j++) {
            int c = j * 32 + lane;
            x[j] = (c < LLOC) ? __expf((x[j] - m) * scale) : 0.f;
            s += x[j];
        }
#pragma unroll
        for (int o = 16; o; o >>= 1) s += __shfl_xor_sync(0xffffffffu, s, o);
        float f = g_mraw[(size_t)z * SQ + q0 + row] * gden / s;
#pragma unroll
        for (int j = 0; j < 9; j++) rp[j * 32 + lane] = x[j] * f;
    }
    __syncthreads();

    // pack P to half pairs
    for (int u = tid; u < 64 * 136; u += 256) {
        int row = u / 136, uc = u - row * 136;
        plm[row * PLU + uc] = pk2(ssm[row * SST2 + 2 * uc], ssm[row * SST2 + 2 * uc + 1]);
    }
    __syncthreads();

    // PV: O[64][160] = P[64][272] @ Vl[272][160]
    int nW = (warp & 3) * 40;
    float oa[2][5][4];
#pragma unroll
    for (int a = 0; a < 2; a++)
#pragma unroll
        for (int b = 0; b < 5; b++)
#pragma unroll
            for (int c = 0; c < 4; c++) oa[a][b][c] = 0.f;

    for (int ch = 0; ch < 17; ch++) {
        if (ch < 16) { CP_WAIT1; } else { CP_WAIT0; }
        __syncthreads();
        const uint32_t* pb = strm + (ch & 1) * 5632;
        int ka = ch * 8 + (lane & 3);
        int kb = lane & 3;
        uint32_t af[2][4], bf[5][2];
#pragma unroll
        for (int mi = 0; mi < 2; mi++) {
            int r0 = mW2 + (mi << 4) + (lane >> 2);
            af[mi][0] = plm[r0 * PLU + ka];
            af[mi][1] = plm[(r0 + 8) * PLU + ka];
            af[mi][2] = plm[r0 * PLU + ka + 4];
            af[mi][3] = plm[(r0 + 8) * PLU + ka + 4];
        }
#pragma unroll
        for (int ni = 0; ni < 5; ni++) {
            int d = nW + (ni << 3) + (lane >> 2);
            bf[ni][0] = pb[d * 12 + kb];
            bf[ni][1] = pb[d * 12 + kb + 4];
        }
#pragma unroll
        for (int mi = 0; mi < 2; mi++)
#pragma unroll
            for (int ni = 0; ni < 5; ni++) mma16(oa[mi][ni], af[mi], bf[ni]);
        __syncthreads();
        if (ch + 2 < 17) issueV(ch & 1, ch + 2);
    }

    // epilogue: blend 0.5*pre + O
#pragma unroll
    for (int mi = 0; mi < 2; mi++)
#pragma unroll
        for (int hf = 0; hf < 2; hf++) {
            int g = q0 + mW2 + mi * 16 + (lane >> 2) + hf * 8;
            __half* prow = g_pre + ((size_t)(inst + 1) * SQ + g) * CHN + h * HD;
#pragma unroll
            for (int ni = 0; ni < 5; ni++) {
                int col = nW + (ni << 3) + ((lane & 3) << 1);
                __half2 old = *(__half2*)(prow + col);
                float o0 = 0.5f * __half2float(old.x) + oa[mi][ni][hf * 2];
                float o1 = 0.5f * __half2float(old.y) + oa[mi][ni][hf * 2 + 1];
                *(uint32_t*)(prow + col) = pk2(o0, o1);
            }
        }
}

// ---------------- fuser premix ----------------
__global__ void premix_k(const float* __restrict__ bbox) {
    int s = blockIdx.x;
    int y = s >> 6, x = s & 63;
    float wgt[8];
    wgt[0] = 1.f;
    float sw = 1.f;
    const int off[4] = {3, 4, 11, 12};
#pragma unroll
    for (int i = 0; i < 7; i++) {
        float wmin = floorf(1024.f * bbox[i * 4 + 0]);
        float hmin = floorf(1024.f * bbox[i * 4 + 1]);
        float wmax = floorf(1024.f * bbox[i * 4 + 2]);
        float hmax = floorf(1024.f * bbox[i * 4 + 3]);
        float R = 0.f, Cv = 0.f;
#pragma unroll
        for (int j = 0; j < 4; j++) {
            float yy = (float)(16 * y + off[j]);
            float xx = (float)(16 * x + off[j]);
            if (yy >= hmin && yy < hmax) R += 0.25f;
            if (xx >= wmin && xx < wmax) Cv += 0.25f;
        }
        float g = 10.f * R * Cv;
        wgt[i + 1] = g;
        sw += g;
    }
    if (threadIdx.x == 0) g_sumw[s] = sw;
    for (int c = threadIdx.x; c < CHN; c += 256) {
        float acc = 0.f;
#pragma unroll
        for (int j = 0; j < 8; j++)
            acc += wgt[j] * __half2float(g_pre[((size_t)(1 + j) * SQ + s) * CHN + c]);
        g_mix[(size_t)s * CHN + c] = __float2half_rn(acc);
    }
}

// ---------------- final ----------------
__global__ void final_k(const float* __restrict__ bout, float* __restrict__ out) {
    int s = blockIdx.x;
    float sw = g_sumw[s];
    float den = 1.f / (sw + 1e-6f);
    for (int c = threadIdx.x; c < CHN; c += 256) {
        float b = bout[c];
        out[(size_t)s * CHN + c] = g_out2[(size_t)s * CHN + c] + b;
        out[(size_t)(SQ + s) * CHN + c] = (g_out2[(size_t)(SQ + s) * CHN + c] + b * sw) * den;
    }
}

// ---------------- launch ----------------
extern "C" void kernel_launch(void* const* d_in, const int* in_sizes, int n_in,
                              void* d_out, int out_size) {
    const float* hs   = (const float*)d_in[0];
    const float* ctx  = (const float*)d_in[1];
    const float* lf   = (const float*)d_in[2];
    const float* bbox = (const float*)d_in[3];
    const float* Wq   = (const float*)d_in[4];
    const float* Wk   = (const float*)d_in[5];
    const float* Wv   = (const float*)d_in[6];
    const float* Wkg  = (const float*)d_in[7];
    const float* Wvg  = (const float*)d_in[8];
    const float* Wkl  = (const float*)d_in[9];
    const float* Wvl  = (const float*)d_in[10];
    const float* Wout = (const float*)d_in[11];
    const float* bout = (const float*)d_in[12];
    const int*   lidx = (const int*)d_in[13];
    float* out = (float*)d_out;

    __half *hsH, *ctxH, *lfH, *WqT, *WkT, *WvT, *WkgT, *WvgT, *WklT, *WvlT, *WoutT;
    __half *vp, *vTp, *vlp, *vlTp;
    cudaGetSymbolAddress((void**)&hsH, g_hsH);
    cudaGetSymbolAddress((void**)&ctxH, g_ctxH);
    cudaGetSymbolAddress((void**)&lfH, g_lfH);
    cudaGetSymbolAddress((void**)&WqT, g_WqT);
    cudaGetSymbolAddress((void**)&WkT, g_WkT);
    cudaGetSymbolAddress((void**)&WvT, g_WvT);
    cudaGetSymbolAddress((void**)&WkgT, g_WkgT);
    cudaGetSymbolAddress((void**)&WvgT, g_WvgT);
    cudaGetSymbolAddress((void**)&WklT, g_WklT);
    cudaGetSymbolAddress((void**)&WvlT, g_WvlT);
    cudaGetSymbolAddress((void**)&WoutT, g_WoutT);
    cudaGetSymbolAddress((void**)&vp, g_v);
    cudaGetSymbolAddress((void**)&vTp, g_vT);
    cudaGetSymbolAddress((void**)&vlp, g_vl);
    cudaGetSymbolAddress((void**)&vlTp, g_vlT);

    const int smemA = (2 * 2048 * 2 + 128 * PSTU + 160 * PSTU + 512) * 4;       // 85,504
    const int smemL = (64 * SST2 + 64 * PLU + 2 * 5632) * 4;                    // 155,648
    cudaFuncSetAttribute(fused_g_k, cudaFuncAttributeMaxDynamicSharedMemorySize, smemA);
    cudaFuncSetAttribute(fused_l2_k, cudaFuncAttributeMaxDynamicSharedMemorySize, smemL);
    cudaFuncSetAttribute(gemm_h, cudaFuncAttributeMaxDynamicSharedMemorySize, SMEM3);

    dim3 tb(32, 8);
    setup_k<<<1, 32>>>();

    long long nHs = 2LL * SQ * CHN, nCtx = (long long)NST * NCTX * CC, nLf = (long long)NSTR * LLOC * CC;
    round_h<<<(int)((nHs / 8 + 255) / 256), 256>>>(hs, hsH, nHs);
    round_h<<<(int)((nCtx / 8 + 255) / 256), 256>>>(ctx, ctxH, nCtx);
    round_h<<<(int)((nLf / 8 + 255) / 256), 256>>>(lf, lfH, nLf);

    transpose_k<float><<<dim3(40, 40, 1), tb>>>(Wq, WqT, CHN, CHN, CHN, CHN, 0, 0);
    transpose_k<float><<<dim3(40, 24, 1), tb>>>(Wk, WkT, CC, CHN, CHN, CC, 0, 0);
    transpose_k<float><<<dim3(40, 24, 1), tb>>>(Wv, WvT, CC, CHN, CHN, CC, 0, 0);
    transpose_k<float><<<dim3(40, 24, 1), tb>>>(Wkg, WkgT, CC, CHN, CHN, CC, 0, 0);
    transpose_k<float><<<dim3(40, 24, 1), tb>>>(Wvg, WvgT, CC, CHN, CHN, CC, 0, 0);
    transpose_k<float><<<dim3(40, 24, 1), tb>>>(Wkl, WklT, CC, CHN, CHN, CC, 0, 0);
    transpose_k<float><<<dim3(40, 24, 1), tb>>>(Wvl, WvlT, CC, CHN, CHN, CC, 0, 0);
    transpose_k<float><<<dim3(40, 40, 1), tb>>>(Wout, WoutT, CHN, CHN, CHN, CHN, 0, 0);

    // projections (fp16 out)
    gemm_h<<<dim3(10, 64, 1), 256, SMEM3>>>(0, CHN, CHN, CHN, CHN, CHN, 1);   // Q
    gemm_h<<<dim3(10, 6, 4), 256, SMEM3>>>(1, CHN, CC, CC, CC, CHN, 1);       // K,V,Kg,Vg
    gemm_h<<<dim3(10, 17, 2), 256, SMEM3>>>(5, CHN, CC, CC, CC, CHN, 1);      // Kl,Vl
    kv_select_k<<<(NSTR * NCTX * CHN / 2 + 255) / 256, 256>>>(lidx);

    // V transposes (half -> half^T, zero-padded)
    transpose_k<__half><<<dim3(40, 3, NST), tb>>>(vp, vTp, NCTX, CHN, CHN, NCTXP,
                                                  (long long)NCTX * CHN, (long long)CHN * NCTXP);
    transpose_k<__half><<<dim3(40, 9, NSTR), tb>>>(vlp, vlTp, LLOC, CHN, CHN, LLOCP,
                                                   (long long)LLOC * CHN, (long long)CHN * LLOCP);

    // fused global attention -> pre (all streams) + mraw
    fused_g_k<<<dim3(32, 72), 256, smemA>>>(lidx);
    mmax_k<<<8, 256>>>();

    // fully fused local attention
    fused_l2_k<<<dim3(64, 64), 256, smemL>>>();

    // fuser premix + output projection (float out)
    premix_k<<<SQ, 256>>>(bbox);
    gemm_h<<<dim3(10, 32, 2), 256, SMEM3>>>(7, CHN, CHN, CHN, CHN, CHN, 0);
    final_k<<<SQ, 256>>>(bout, out);
}

// round 8
// speedup vs baseline: 2.2322x; 1.0335x over previous
#include <cuda_runtime.h>
#include <cuda_fp16.h>
#include <math.h>
#include <stdint.h>

#define SQ 4096
#define CHN 1280
#define CC 768
#define NHEAD 8
#define HD 160
#define NCTX 77
#define NCTXP 80
#define NST 9
#define NSTR 8
#define LLOC 257
#define LLOCP 272
#define PSTU 44
#define PLU 140
#define SST2 292
#define SMEM3 (3 * 2048 * 2 * 4)

// ---------------- scratch ----------------
__device__ __align__(256) __half g_hsH[2 * SQ * CHN];
__device__ __align__(256) __half g_ctxH[NST * NCTX * CC];
__device__ __align__(256) __half g_lfH[NSTR * LLOC * CC];
__device__ __align__(256) __half g_q2[2 * SQ * CHN];
__device__ __align__(256) __half g_k[NST * NCTX * CHN];
__device__ __align__(256) __half g_v[NST * NCTX * CHN];
__device__ __align__(256) __half g_kg[NSTR * NCTX * CHN];
__device__ __align__(256) __half g_vg[NSTR * NCTX * CHN];
__device__ __align__(256) __half g_kl[NSTR * LLOC * CHN];
__device__ __align__(256) __half g_vl[NSTR * LLOC * CHN];
__device__ __align__(256) __half g_WqT[CHN * CHN];
__device__ __align__(256) __half g_WkT[CHN * CC];
__device__ __align__(256) __half g_WvT[CHN * CC];
__device__ __align__(256) __half g_WkgT[CHN * CC];
__device__ __align__(256) __half g_WvgT[CHN * CC];
__device__ __align__(256) __half g_WklT[CHN * CC];
__device__ __align__(256) __half g_WvlT[CHN * CC];
__device__ __align__(256) __half g_WoutT[CHN * CHN];
__device__ __align__(256) __half g_vT[NST * CHN * NCTXP];
__device__ __align__(256) __half g_vlT[NSTR * CHN * LLOCP];
__device__ __align__(256) __half g_pre[NST * SQ * CHN];
__device__ __align__(256) __half g_mix[SQ * CHN];
__device__ __align__(256) float g_out2[2 * SQ * CHN];
__device__ float g_mraw[NSTR * NHEAD * SQ];
__device__ float g_mmax[NSTR];
__device__ float g_sumw[SQ];

__device__ const __half* d_Ap[16];
__device__ const __half* d_Bp[16];
__device__ void*         d_Cp[16];
__device__ int           d_Mt[16];

// ---------------- helpers ----------------
__device__ __forceinline__ uint32_t pk2(float a, float b) {
    __half2 h = __halves2half2(__float2half_rn(a), __float2half_rn(b));
    return *(uint32_t*)&h;
}
__device__ __forceinline__ void cp16(void* sdst, const void* gsrc, bool p) {
    uint32_t sa = (uint32_t)__cvta_generic_to_shared(sdst);
    int sz = p ? 16 : 0;
    asm volatile("cp.async.cg.shared.global [%0], [%1], 16, %2;" :: "r"(sa), "l"(gsrc), "r"(sz));
}
#define CP_COMMIT asm volatile("cp.async.commit_group;")
#define CP_WAIT0 asm volatile("cp.async.wait_group 0;")
#define CP_WAIT1 asm volatile("cp.async.wait_group 1;")
#define CP_WAIT2 asm volatile("cp.async.wait_group 2;")
__device__ __forceinline__ void mma16(float* c, const uint32_t* a, const uint32_t* b) {
    asm volatile(
        "mma.sync.aligned.m16n8k16.row.col.f32.f16.f16.f32 "
        "{%0,%1,%2,%3}, {%4,%5,%6,%7}, {%8,%9}, {%0,%1,%2,%3};"
        : "+f"(c[0]), "+f"(c[1]), "+f"(c[2]), "+f"(c[3])
        : "r"(a[0]), "r"(a[1]), "r"(a[2]), "r"(a[3]), "r"(b[0]), "r"(b[1]));
}
__device__ __forceinline__ void ldsm4(uint32_t* r, uint32_t addr) {
    asm volatile("ldmatrix.sync.aligned.m8n8.x4.shared.b16 {%0,%1,%2,%3}, [%4];"
                 : "=r"(r[0]), "=r"(r[1]), "=r"(r[2]), "=r"(r[3]) : "r"(addr));
}
// swizzled offset in u32 units for [128][16-u32] tile (same proven pattern)
#define SWOFF(r, c) (((r) << 4) + ((((((c) >> 2) ^ (((r) >> 1) & 3))) << 2) | ((c) & 3)))

// ---------------- setup ----------------
__global__ void setup_k() {
    if (threadIdx.x == 0) {
        d_Ap[0] = g_hsH;               d_Bp[0] = g_WqT;   d_Cp[0] = g_q2;    d_Mt[0] = 2 * SQ;
        d_Ap[1] = g_ctxH;              d_Bp[1] = g_WkT;   d_Cp[1] = g_k;     d_Mt[1] = NST * NCTX;
        d_Ap[2] = g_ctxH;              d_Bp[2] = g_WvT;   d_Cp[2] = g_v;     d_Mt[2] = NST * NCTX;
        d_Ap[3] = g_ctxH + NCTX * CC;  d_Bp[3] = g_WkgT;  d_Cp[3] = g_kg;    d_Mt[3] = NSTR * NCTX;
        d_Ap[4] = g_ctxH + NCTX * CC;  d_Bp[4] = g_WvgT;  d_Cp[4] = g_vg;    d_Mt[4] = NSTR * NCTX;
        d_Ap[5] = g_lfH;               d_Bp[5] = g_WklT;  d_Cp[5] = g_kl;    d_Mt[5] = NSTR * LLOC;
        d_Ap[6] = g_lfH;               d_Bp[6] = g_WvlT;  d_Cp[6] = g_vl;    d_Mt[6] = NSTR * LLOC;
        d_Ap[7] = g_pre;               d_Bp[7] = g_WoutT; d_Cp[7] = g_out2;  d_Mt[7] = SQ;
        d_Ap[8] = g_mix;               d_Bp[8] = g_WoutT; d_Cp[8] = g_out2 + (size_t)SQ * CHN;
        d_Mt[8] = SQ;
    }
}

// ---------------- round inputs to fp16 ----------------
__global__ void round_h(const float* __restrict__ src, __half* __restrict__ dst, long long n) {
    long long i = ((long long)blockIdx.x * blockDim.x + threadIdx.x) * 8;
    if (i + 7 < n) {
        float4 a = *(const float4*)(src + i);
        float4 b = *(const float4*)(src + i + 4);
        uint4 u;
        u.x = pk2(a.x, a.y); u.y = pk2(a.z, a.w);
        u.z = pk2(b.x, b.y); u.w = pk2(b.z, b.w);
        *(uint4*)(dst + i) = u;
    } else {
        for (long long j = i; j < n; j++) dst[j] = __float2half_rn(src[j]);
    }
}

// ---------------- transpose (templated src type) -> half ----------------
template <typename TS>
__global__ void transpose_k(const TS* __restrict__ src, __half* __restrict__ dst,
                            int R, int C, int ldS, int ldD, long long sBS, long long dBS) {
    __shared__ float t[32][33];
    src += blockIdx.z * sBS;
    dst += blockIdx.z * dBS;
    int c0 = blockIdx.x << 5, r0 = blockIdx.y << 5;
    int tx = threadIdx.x, ty = threadIdx.y;
#pragma unroll
    for (int j = 0; j < 4; j++) {
        int rr = r0 + ty + j * 8, cc = c0 + tx;
        t[ty + j * 8][tx] = (rr < R && cc < C) ? (float)src[(size_t)rr * ldS + cc] : 0.f;
    }
    __syncthreads();
#pragma unroll
    for (int j = 0; j < 4; j++) {
        int cc = c0 + ty + j * 8, rr = r0 + tx;
        if (cc < C && rr < ldD)
            dst[(size_t)cc * ldD + rr] = __float2half_rn(t[tx][ty + j * 8]);
    }
}

// ---------------- batched NT fp16 GEMM, BK=32 halfs, 3-stage, LDSM ----------
// mode: 1 = half output, 0 = float output
__global__ void __launch_bounds__(256, 2) gemm_h(int slot, int N, int K,
                                                 int lda, int ldb, int ldc, int mode) {
    extern __shared__ __align__(16) uint32_t smg[];
    uint32_t* As = smg;                  // 3 * 2048 u32
    uint32_t* Bs = smg + 3 * 2048;
    const __half* Ab = d_Ap[slot + blockIdx.z];
    const __half* Bb = d_Bp[slot + blockIdx.z];
    void* Cm         = d_Cp[slot + blockIdx.z];
    const int M      = d_Mt[slot + blockIdx.z];
    int tid = threadIdx.x, lane = tid & 31, warp = tid >> 5;
    int mBase = blockIdx.y << 7, nBase = blockIdx.x << 7;
    int mW = (warp >> 2) << 6, nW = (warp & 3) << 5;
    float acc[4][4][4];
#pragma unroll
    for (int a = 0; a < 4; a++)
#pragma unroll
        for (int b = 0; b < 4; b++)
#pragma unroll
            for (int cI = 0; cI < 4; cI++) acc[a][b][cI] = 0.f;

    int KT = K >> 5;
    auto issue = [&](int st, int kt) {
        int k0 = kt << 5;   // halfs
#pragma unroll
        for (int i = 0; i < 2; i++) {
            int idx = tid + (i << 8);
            int r = idx >> 2, cu = (idx & 3) << 2;
            int gr = mBase + r; bool pa = gr < M; if (!pa) gr = M - 1;
            cp16(&As[st * 2048 + SWOFF(r, cu)], Ab + (size_t)gr * lda + k0 + (cu << 1), pa);
            int gn = nBase + r; bool pb = gn < N; if (!pb) gn = N - 1;
            cp16(&Bs[st * 2048 + SWOFF(r, cu)], Bb + (size_t)gn * ldb + k0 + (cu << 1), pb);
        }
        CP_COMMIT;
    };
    issue(0, 0);
    issue(1, 1);

    // ldmatrix per-lane geometry
    int lrow = lane & 7;       // row within 8x8 tile
    int lm = lane >> 3;        // matrix index 0..3
    // A: matrices (rlo,klo),(rhi,klo),(rlo,khi),(rhi,khi)
    int arow[4], axor[4];
#pragma unroll
    for (int mi = 0; mi < 4; mi++) {
        arow[mi] = mW + (mi << 4) + ((lm & 1) << 3) + lrow;
        axor[mi] = (arow[mi] >> 1) & 3;
    }
    int achk = lm >> 1;        // 0/1 -> klo/khi chunk within kk
    // B: pairs (n0 klo),(n0 khi),(n1 klo),(n1 khi)
    int brow[2], bxor[2];
#pragma unroll
    for (int np = 0; np < 2; np++) {
        brow[np] = nW + (np << 4) + ((lm >> 1) << 3) + lrow;
        bxor[np] = (brow[np] >> 1) & 3;
    }
    int bchk = lm & 1;
    uint32_t sbA = (uint32_t)__cvta_generic_to_shared(As);
    uint32_t sbB = (uint32_t)__cvta_generic_to_shared(Bs);

    for (int kt = 0; kt < KT; kt++) {
        if (kt + 1 < KT) { CP_WAIT1; } else { CP_WAIT0; }
        __syncthreads();
        if (kt + 2 < KT) issue((kt + 2) % 3, kt + 2);
        uint32_t stA = sbA + (kt % 3) * 8192;
        uint32_t stB = sbB + (kt % 3) * 8192;
#pragma unroll
        for (int kk = 0; kk < 2; kk++) {
            uint32_t af[4][4], bf[4][2];
#pragma unroll
            for (int mi = 0; mi < 4; mi++) {
                uint32_t au = (uint32_t)(arow[mi] << 4) + ((((kk << 1) + achk) ^ axor[mi]) << 2);
                ldsm4(af[mi], stA + (au << 2));
            }
#pragma unroll
            for (int np = 0; np < 2; np++) {
                uint32_t bu = (uint32_t)(brow[np] << 4) + ((((kk << 1) + bchk) ^ bxor[np]) << 2);
                uint32_t r4[4];
                ldsm4(r4, stB + (bu << 2));
                bf[np * 2][0] = r4[0]; bf[np * 2][1] = r4[1];
                bf[np * 2 + 1][0] = r4[2]; bf[np * 2 + 1][1] = r4[3];
            }
#pragma unroll
            for (int mi = 0; mi < 4; mi++)
#pragma unroll
                for (int ni = 0; ni < 4; ni++) mma16(acc[mi][ni], af[mi], bf[ni]);
        }
    }
#pragma unroll
    for (int mi = 0; mi < 4; mi++) {
#pragma unroll
        for (int half = 0; half < 2; half++) {
            int gm = mBase + mW + (mi << 4) + (lane >> 2) + half * 8;
            if (gm >= M) continue;
#pragma unroll
            for (int ni = 0; ni < 4; ni++) {
                int gn = nBase + nW + (ni << 3) + ((lane & 3) << 1);
                if (gn + 1 >= N) continue;
                float v0 = acc[mi][ni][half * 2], v1 = acc[mi][ni][half * 2 + 1];
                if (mode & 1) {
                    __half* crow = (__half*)Cm + (size_t)gm * ldc;
                    *(uint32_t*)(crow + gn) = pk2(v0, v1);
                } else {
                    float* crow = (float*)Cm + (size_t)gm * ldc;
                    crow[gn] = v0;
                    crow[gn + 1] = v1;
                }
            }
        }
    }
}

// ---------------- ELITE K/V select (u32 = half2 copies) ----------------
__global__ void kv_select_k(const int* __restrict__ lidx) {
    int idx = blockIdx.x * 256 + threadIdx.x;
    const int tot = NSTR * NCTX * CHN / 2;
    if (idx >= tot) return;
    int st = idx / (NCTX * CHN / 2);
    if (lidx[st] >= 0) {
        ((uint32_t*)g_k)[NCTX * CHN / 2 + idx] = ((const uint32_t*)g_kg)[idx];
        ((uint32_t*)g_v)[NCTX * CHN / 2 + idx] = ((const uint32_t*)g_vg)[idx];
    }
}

// ============ fused global attention (fp16 operands) ============
// grid (32 qtiles, 72 bh), 256 threads
__global__ void __launch_bounds__(256) fused_g_k(const int* __restrict__ lidx) {
    extern __shared__ __align__(16) uint32_t smu[];
    uint32_t* qb  = smu;                       // 2 * 2048
    uint32_t* kb  = smu + 4096;                // 2 * 2048
    uint32_t* psm = smu + 8192;                // 128 * PSTU
    uint32_t* vsm = psm + 128 * PSTU;          // 160 * PSTU
    float* smx = (float*)(vsm + 160 * PSTU);   // 2 * 128
    float* ssu = smx + 256;                    // 2 * 128
    __shared__ int sidx[8];

    int bh = blockIdx.y;
    int stream = bh >> 3, h = bh & 7;
    int q0 = blockIdx.x << 7;
    int tid = threadIdx.x, lane = tid & 31, warp = tid >> 5;
    if (tid < 8) sidx[tid] = lidx[tid];

    const __half* Qb = g_q2 + (stream ? (size_t)SQ * CHN : 0) + (size_t)q0 * CHN + h * HD;
    const __half* Kb = g_k + (size_t)stream * NCTX * CHN + h * HD;
    const __half* Vt = g_vT + (size_t)stream * CHN * NCTXP + (size_t)h * HD * NCTXP;

    for (int u = tid; u < 160 * 10; u += 256) {
        int d = u / 10, c = u % 10;
        cp16(vsm + d * PSTU + c * 4, Vt + (size_t)d * NCTXP + c * 8, true);
    }
    CP_COMMIT;

    auto issueQK = [&](int st, int kt) {
        int k0 = kt << 5;
#pragma unroll
        for (int i = 0; i < 2; i++) {
            int idx = tid + (i << 8);
            int r = idx >> 2, cu = (idx & 3) << 2;
            cp16(&qb[st * 2048 + SWOFF(r, cu)], Qb + (size_t)r * CHN + k0 + (cu << 1), true);
            int kr = (r < NCTX) ? r : (NCTX - 1);
            cp16(&kb[st * 2048 + SWOFF(r, cu)], Kb + (size_t)kr * CHN + k0 + (cu << 1), true);
        }
        CP_COMMIT;
    };
    issueQK(0, 0);

    int mW = (warp >> 1) << 5;
    int nWs = (warp & 1) * 40;
    float sc[2][5][4];
#pragma unroll
    for (int a = 0; a < 2; a++)
#pragma unroll
        for (int b = 0; b < 5; b++)
#pragma unroll
            for (int c = 0; c < 4; c++) sc[a][b][c] = 0.f;

    for (int kt = 0; kt < 5; kt++) {
        if (kt < 4) { issueQK((kt + 1) & 1, kt + 1); CP_WAIT1; }
        else        { CP_WAIT0; }
        __syncthreads();
        const uint32_t* pQ = qb + (kt & 1) * 2048;
        const uint32_t* pK = kb + (kt & 1) * 2048;
#pragma unroll
        for (int kk = 0; kk < 2; kk++) {
            int ck = (kk << 3) + (lane & 3);
            uint32_t af[2][4], bf[5][2];
#pragma unroll
            for (int mi = 0; mi < 2; mi++) {
                int r0 = mW + (mi << 4) + (lane >> 2);
                af[mi][0] = pQ[SWOFF(r0, ck)];
                af[mi][1] = pQ[SWOFF(r0 + 8, ck)];
                af[mi][2] = pQ[SWOFF(r0, ck + 4)];
                af[mi][3] = pQ[SWOFF(r0 + 8, ck + 4)];
            }
#pragma unroll
            for (int ni = 0; ni < 5; ni++) {
                int r0 = nWs + (ni << 3) + (lane >> 2);
                bf[ni][0] = pK[SWOFF(r0, ck)];
                bf[ni][1] = pK[SWOFF(r0, ck + 4)];
            }
#pragma unroll
            for (int mi = 0; mi < 2; mi++)
#pragma unroll
                for (int ni = 0; ni < 5; ni++) mma16(sc[mi][ni], af[mi], bf[ni]);
        }
        __syncthreads();
    }

    const float scale = 0.07905694150420949f;
    int half = warp & 1;
#pragma unroll
    for (int mi = 0; mi < 2; mi++)
#pragma unroll
        for (int hf = 0; hf < 2; hf++) {
            int row = mW + mi * 16 + (lane >> 2) + hf * 8;
            float mx = -1e30f;
#pragma unroll
            for (int ni = 0; ni < 5; ni++)
#pragma unroll
                for (int c = 0; c < 2; c++) {
                    int col = nWs + ni * 8 + ((lane & 3) << 1) + c;
                    if (col < NCTX) mx = fmaxf(mx, sc[mi][ni][hf * 2 + c]);
                }
            mx = fmaxf(mx, __shfl_xor_sync(0xffffffffu, mx, 1));
            mx = fmaxf(mx, __shfl_xor_sync(0xffffffffu, mx, 2));
            if ((lane & 3) == 0) smx[half * 128 + row] = mx;
        }
    __syncthreads();
#pragma unroll
    for (int mi = 0; mi < 2; mi++)
#pragma unroll
        for (int hf = 0; hf < 2; hf++) {
            int row = mW + mi * 16 + (lane >> 2) + hf * 8;
            float m = fmaxf(smx[row], smx[128 + row]);
            float s = 0.f;
#pragma unroll
            for (int ni = 0; ni < 5; ni++)
#pragma unroll
                for (int c = 0; c < 2; c++) {
                    int col = nWs + ni * 8 + ((lane & 3) << 1) + c;
                    float e = (col < NCTX) ? __expf((sc[mi][ni][hf * 2 + c] - m) * scale) : 0.f;
                    sc[mi][ni][hf * 2 + c] = e;
                    s += e;
                }
            s += __shfl_xor_sync(0xffffffffu, s, 1);
            s += __shfl_xor_sync(0xffffffffu, s, 2);
            if ((lane & 3) == 0) ssu[half * 128 + row] = s;
        }
    __syncthreads();
#pragma unroll
    for (int mi = 0; mi < 2; mi++)
#pragma unroll
        for (int hf = 0; hf < 2; hf++) {
            int row = mW + mi * 16 + (lane >> 2) + hf * 8;
            float inv = 1.f / (ssu[row] + ssu[128 + row]);
#pragma unroll
            for (int ni = 0; ni < 5; ni++) {
                int col = nWs + ni * 8 + ((lane & 3) << 1);
                float v0 = (col < NCTX) ? sc[mi][ni][hf * 2] * inv : 0.f;
                float v1 = (col + 1 < NCTX) ? sc[mi][ni][hf * 2 + 1] * inv : 0.f;
                psm[row * PSTU + (nWs >> 1) + ni * 4 + (lane & 3)] = pk2(v0, v1);
            }
        }
    __syncthreads();

    if (stream == 0) {
        const __half* ph = (const __half*)psm;
        for (int u = tid; u < 128 * 8; u += 256) {
            int r = u >> 3, i = u & 7;
            g_mraw[((size_t)i * NHEAD + h) * SQ + q0 + r] =
                __half2float(ph[r * (2 * PSTU) + sidx[i]]);
        }
    }

    // PV: O[128][160] = P[128][80] @ V[80][160]
    int nW = (warp & 1) * 80;
    float oa[2][10][4];
#pragma unroll
    for (int a = 0; a < 2; a++)
#pragma unroll
        for (int b = 0; b < 10; b++)
#pragma unroll
            for (int c = 0; c < 4; c++) oa[a][b][c] = 0.f;
#pragma unroll
    for (int kst = 0; kst < 5; kst++) {
        int ka = kst * 8 + (lane & 3);
        uint32_t af[2][4], bf[10][2];
#pragma unroll
        for (int mi = 0; mi < 2; mi++) {
            int r0 = mW + (mi << 4) + (lane >> 2);
            af[mi][0] = psm[r0 * PSTU + ka];
            af[mi][1] = psm[(r0 + 8) * PSTU + ka];
            af[mi][2] = psm[r0 * PSTU + ka + 4];
            af[mi][3] = psm[(r0 + 8) * PSTU + ka + 4];
        }
#pragma unroll
        for (int ni = 0; ni < 10; ni++) {
            int d = nW + (ni << 3) + (lane >> 2);
            bf[ni][0] = vsm[d * PSTU + ka];
            bf[ni][1] = vsm[d * PSTU + ka + 4];
        }
#pragma unroll
        for (int mi = 0; mi < 2; mi++)
#pragma unroll
            for (int ni = 0; ni < 10; ni++) mma16(oa[mi][ni], af[mi], bf[ni]);
    }
#pragma unroll
    for (int mi = 0; mi < 2; mi++)
#pragma unroll
        for (int hf = 0; hf < 2; hf++) {
            int g = q0 + mW + mi * 16 + (lane >> 2) + hf * 8;
            __half* orow = g_pre + ((size_t)stream * SQ + g) * CHN + h * HD;
#pragma unroll
            for (int ni = 0; ni < 10; ni++) {
                int col = nW + (ni << 3) + ((lane & 3) << 1);
                *(uint32_t*)(orow + col) = pk2(oa[mi][ni][hf * 2], oa[mi][ni][hf * 2 + 1]);
            }
        }
}

// ---------------- per-instance gate max ----------------
__global__ void mmax_k() {
    __shared__ float red[256];
    int i = blockIdx.x;
    float mx = 0.f;
    const float* p = g_mraw + (size_t)i * NHEAD * SQ;
    for (int idx = threadIdx.x; idx < NHEAD * SQ; idx += 256) mx = fmaxf(mx, p[idx]);
    red[threadIdx.x] = mx;
    __syncthreads();
    for (int s = 128; s > 0; s >>= 1) {
        if (threadIdx.x < s) red[threadIdx.x] = fmaxf(red[threadIdx.x], red[threadIdx.x + s]);
        __syncthreads();
    }
    if (threadIdx.x == 0) g_mmax[i] = red[0];
}

// ============ fully fused local attention (fp16 operands) ============
// grid (64 qtiles of 64 rows, 64 ih), 256 threads
__global__ void __launch_bounds__(256) fused_l2_k() {
    extern __shared__ __align__(16) uint32_t smu[];
    float*    ssm  = (float*)smu;              // 64 * SST2 f32 (scores/probs)
    uint32_t* plm  = smu + 64 * SST2;          // 64 * PLU u32 (P halfs)
    uint32_t* strm = smu + 64 * SST2 + 64 * PLU; // 2 stages * 5632 u32

    int z = blockIdx.y;
    int inst = z >> 3, h = z & 7;
    int q0 = blockIdx.x << 6;
    int tid = threadIdx.x, lane = tid & 31, warp = tid >> 5;

    const __half* Qb  = g_q2 + (size_t)SQ * CHN + (size_t)q0 * CHN + h * HD;
    const __half* Klb = g_kl + (size_t)inst * LLOC * CHN + h * HD;
    const __half* Vt  = g_vlT + (size_t)inst * CHN * LLOCP + (size_t)h * HD * LLOCP;

    // phase 1: S = Q @ Kl^T (64 x 288, K=160 halfs)
    auto issueQK = [&](int st, int kt) {
        int k0 = kt << 5;
        uint32_t* base = strm + st * 5632;
        {
            int r = tid >> 2, cu = (tid & 3) << 2;
            cp16(base + SWOFF(r, cu), Qb + (size_t)r * CHN + k0 + (cu << 1), true);
        }
        for (int u = tid; u < 1152; u += 256) {
            int r = u >> 2, cu = (u & 3) << 2;
            int kr = (r < LLOC) ? r : (LLOC - 1);
            cp16(base + 1024 + SWOFF(r, cu), Klb + (size_t)kr * CHN + k0 + (cu << 1), true);
        }
        CP_COMMIT;
    };
    issueQK(0, 0);

    int mW2 = (warp >> 2) << 5;
    int nW4 = (warp & 3) * 72;
    float sc[2][9][4];
#pragma unroll
    for (int a = 0; a < 2; a++)
#pragma unroll
        for (int b = 0; b < 9; b++)
#pragma unroll
            for (int c = 0; c < 4; c++) sc[a][b][c] = 0.f;

    for (int kt = 0; kt < 5; kt++) {
        if (kt < 4) { issueQK((kt + 1) & 1, kt + 1); CP_WAIT1; }
        else        { CP_WAIT0; }
        __syncthreads();
        const uint32_t* pQ = strm + (kt & 1) * 5632;
        const uint32_t* pK = pQ + 1024;
#pragma unroll
        for (int kk = 0; kk < 2; kk++) {
            int ck = (kk << 3) + (lane & 3);
            uint32_t af[2][4], bf[9][2];
#pragma unroll
            for (int mi = 0; mi < 2; mi++) {
                int r0 = mW2 + (mi << 4) + (lane >> 2);
                af[mi][0] = pQ[SWOFF(r0, ck)];
                af[mi][1] = pQ[SWOFF(r0 + 8, ck)];
                af[mi][2] = pQ[SWOFF(r0, ck + 4)];
                af[mi][3] = pQ[SWOFF(r0 + 8, ck + 4)];
            }
#pragma unroll
            for (int ni = 0; ni < 9; ni++) {
                int r0 = nW4 + (ni << 3) + (lane >> 2);
                bf[ni][0] = pK[SWOFF(r0, ck)];
                bf[ni][1] = pK[SWOFF(r0, ck + 4)];
            }
#pragma unroll
            for (int mi = 0; mi < 2; mi++)
#pragma unroll
                for (int ni = 0; ni < 9; ni++) mma16(sc[mi][ni], af[mi], bf[ni]);
        }
        __syncthreads();
    }
#pragma unroll
    for (int mi = 0; mi < 2; mi++)
#pragma unroll
        for (int hf = 0; hf < 2; hf++) {
            int row = mW2 + mi * 16 + (lane >> 2) + hf * 8;
#pragma unroll
            for (int ni = 0; ni < 9; ni++) {
                int col = nW4 + ni * 8 + ((lane & 3) << 1);
                ssm[row * SST2 + col]     = sc[mi][ni][hf * 2];
                ssm[row * SST2 + col + 1] = sc[mi][ni][hf * 2 + 1];
            }
        }
    __syncthreads();

    // V prefetch (chunks of 16 keys x 160 dims, half)
    auto issueV = [&](int buf, int ch) {
        for (int u = tid; u < 320; u += 256) {
            int d = u >> 1, c = u & 1;
            cp16(strm + buf * 5632 + d * 12 + c * 4, Vt + (size_t)d * LLOCP + ch * 16 + c * 8, true);
        }
        CP_COMMIT;
    };
    issueV(0, 0);
    issueV(1, 1);

    // softmax + gate (f32 in ssm)
    const float scale = 0.07905694150420949f;
    float gden = 0.5f / g_mmax[inst];
    for (int t = 0; t < 8; t++) {
        int row = warp * 8 + t;
        float* rp = ssm + row * SST2;
        float x[9];
#pragma unroll
        for (int j = 0; j < 9; j++) {
            int c = j * 32 + lane;
            x[j] = (c < LLOC) ? rp[c] : -1e30f;
        }
        float m = -1e30f;
#pragma unroll
        for (int j = 0; j < 9; j++) m = fmaxf(m, x[j]);
#pragma unroll
        for (int o = 16; o; o >>= 1) m = fmaxf(m, __shfl_xor_sync(0xffffffffu, m, o));
        float s = 0.f;
#pragma unroll
        for (int j = 0; j < 9; j++) {
            int c = j * 32 + lane;
            x[j] = (c < LLOC) ? __expf((x[j] - m) * scale) : 0.f;
            s += x[j];
        }
#pragma unroll
        for (int o = 16; o; o >>= 1) s += __shfl_xor_sync(0xffffffffu, s, o);
        float f = g_mraw[(size_t)z * SQ + q0 + row] * gden / s;
#pragma unroll
        for (int j = 0; j < 9; j++) rp[j * 32 + lane] = x[j] * f;
    }
    __syncthreads();

    // pack P to half pairs
    for (int u = tid; u < 64 * 136; u += 256) {
        int row = u / 136, uc = u - row * 136;
        plm[row * PLU + uc] = pk2(ssm[row * SST2 + 2 * uc], ssm[row * SST2 + 2 * uc + 1]);
    }
    __syncthreads();

    // PV: O[64][160] = P[64][272] @ Vl[272][160]
    int nW = (warp & 3) * 40;
    float oa[2][5][4];
#pragma unroll
    for (int a = 0; a < 2; a++)
#pragma unroll
        for (int b = 0; b < 5; b++)
#pragma unroll
            for (int c = 0; c < 4; c++) oa[a][b][c] = 0.f;

    for (int ch = 0; ch < 17; ch++) {
        if (ch < 16) { CP_WAIT1; } else { CP_WAIT0; }
        __syncthreads();
        const uint32_t* pb = strm + (ch & 1) * 5632;
        int ka = ch * 8 + (lane & 3);
        int kb = lane & 3;
        uint32_t af[2][4], bf[5][2];
#pragma unroll
        for (int mi = 0; mi < 2; mi++) {
            int r0 = mW2 + (mi << 4) + (lane >> 2);
            af[mi][0] = plm[r0 * PLU + ka];
            af[mi][1] = plm[(r0 + 8) * PLU + ka];
            af[mi][2] = plm[r0 * PLU + ka + 4];
            af[mi][3] = plm[(r0 + 8) * PLU + ka + 4];
        }
#pragma unroll
        for (int ni = 0; ni < 5; ni++) {
            int d = nW + (ni << 3) + (lane >> 2);
            bf[ni][0] = pb[d * 12 + kb];
            bf[ni][1] = pb[d * 12 + kb + 4];
        }
#pragma unroll
        for (int mi = 0; mi < 2; mi++)
#pragma unroll
            for (int ni = 0; ni < 5; ni++) mma16(oa[mi][ni], af[mi], bf[ni]);
        __syncthreads();
        if (ch + 2 < 17) issueV(ch & 1, ch + 2);
    }

    // epilogue: blend 0.5*pre + O
#pragma unroll
    for (int mi = 0; mi < 2; mi++)
#pragma unroll
        for (int hf = 0; hf < 2; hf++) {
            int g = q0 + mW2 + mi * 16 + (lane >> 2) + hf * 8;
            __half* prow = g_pre + ((size_t)(inst + 1) * SQ + g) * CHN + h * HD;
#pragma unroll
            for (int ni = 0; ni < 5; ni++) {
                int col = nW + (ni << 3) + ((lane & 3) << 1);
                __half2 old = *(__half2*)(prow + col);
                float o0 = 0.5f * __half2float(old.x) + oa[mi][ni][hf * 2];
                float o1 = 0.5f * __half2float(old.y) + oa[mi][ni][hf * 2 + 1];
                *(uint32_t*)(prow + col) = pk2(o0, o1);
            }
        }
}

// ---------------- fuser premix ----------------
__global__ void premix_k(const float* __restrict__ bbox) {
    int s = blockIdx.x;
    int y = s >> 6, x = s & 63;
    float wgt[8];
    wgt[0] = 1.f;
    float sw = 1.f;
    const int off[4] = {3, 4, 11, 12};
#pragma unroll
    for (int i = 0; i < 7; i++) {
        float wmin = floorf(1024.f * bbox[i * 4 + 0]);
        float hmin = floorf(1024.f * bbox[i * 4 + 1]);
        float wmax = floorf(1024.f * bbox[i * 4 + 2]);
        float hmax = floorf(1024.f * bbox[i * 4 + 3]);
        float R = 0.f, Cv = 0.f;
#pragma unroll
        for (int j = 0; j < 4; j++) {
            float yy = (float)(16 * y + off[j]);
            float xx = (float)(16 * x + off[j]);
            if (yy >= hmin && yy < hmax) R += 0.25f;
            if (xx >= wmin && xx < wmax) Cv += 0.25f;
        }
        float g = 10.f * R * Cv;
        wgt[i + 1] = g;
        sw += g;
    }
    if (threadIdx.x == 0) g_sumw[s] = sw;
    for (int c = threadIdx.x; c < CHN; c += 256) {
        float acc = 0.f;
#pragma unroll
        for (int j = 0; j < 8; j++)
            acc += wgt[j] * __half2float(g_pre[((size_t)(1 + j) * SQ + s) * CHN + c]);
        g_mix[(size_t)s * CHN + c] = __float2half_rn(acc);
    }
}

// ---------------- final ----------------
__global__ void final_k(const float* __restrict__ bout, float* __restrict__ out) {
    int s = blockIdx.x;
    float sw = g_sumw[s];
    float den = 1.f / (sw + 1e-6f);
    for (int c = threadIdx.x; c < CHN; c += 256) {
        float b = bout[c];
        out[(size_t)s * CHN + c] = g_out2[(size_t)s * CHN + c] + b;
        out[(size_t)(SQ + s) * CHN + c] = (g_out2[(size_t)(SQ + s) * CHN + c] + b * sw) * den;
    }
}

// ---------------- launch ----------------
extern "C" void kernel_launch(void* const* d_in, const int* in_sizes, int n_in,
                              void* d_out, int out_size) {
    const float* hs   = (const float*)d_in[0];
    const float* ctx  = (const float*)d_in[1];
    const float* lf   = (const float*)d_in[2];
    const float* bbox = (const float*)d_in[3];
    const float* Wq   = (const float*)d_in[4];
    const float* Wk   = (const float*)d_in[5];
    const float* Wv   = (const float*)d_in[6];
    const float* Wkg  = (const float*)d_in[7];
    const float* Wvg  = (const float*)d_in[8];
    const float* Wkl  = (const float*)d_in[9];
    const float* Wvl  = (const float*)d_in[10];
    const float* Wout = (const float*)d_in[11];
    const float* bout = (const float*)d_in[12];
    const int*   lidx = (const int*)d_in[13];
    float* out = (float*)d_out;

    __half *hsH, *ctxH, *lfH, *WqT, *WkT, *WvT, *WkgT, *WvgT, *WklT, *WvlT, *WoutT;
    __half *vp, *vTp, *vlp, *vlTp;
    cudaGetSymbolAddress((void**)&hsH, g_hsH);
    cudaGetSymbolAddress((void**)&ctxH, g_ctxH);
    cudaGetSymbolAddress((void**)&lfH, g_lfH);
    cudaGetSymbolAddress((void**)&WqT, g_WqT);
    cudaGetSymbolAddress((void**)&WkT, g_WkT);
    cudaGetSymbolAddress((void**)&WvT, g_WvT);
    cudaGetSymbolAddress((void**)&WkgT, g_WkgT);
    cudaGetSymbolAddress((void**)&WvgT, g_WvgT);
    cudaGetSymbolAddress((void**)&WklT, g_WklT);
    cudaGetSymbolAddress((void**)&WvlT, g_WvlT);
    cudaGetSymbolAddress((void**)&WoutT, g_WoutT);
    cudaGetSymbolAddress((void**)&vp, g_v);
    cudaGetSymbolAddress((void**)&vTp, g_vT);
    cudaGetSymbolAddress((void**)&vlp, g_vl);
    cudaGetSymbolAddress((void**)&vlTp, g_vlT);

    const int smemA = (2 * 2048 * 2 + 128 * PSTU + 160 * PSTU + 512) * 4;       // 85,504
    const int smemL = (64 * SST2 + 64 * PLU + 2 * 5632) * 4;                    // 155,648
    cudaFuncSetAttribute(fused_g_k, cudaFuncAttributeMaxDynamicSharedMemorySize, smemA);
    cudaFuncSetAttribute(fused_l2_k, cudaFuncAttributeMaxDynamicSharedMemorySize, smemL);
    cudaFuncSetAttribute(gemm_h, cudaFuncAttributeMaxDynamicSharedMemorySize, SMEM3);

    dim3 tb(32, 8);
    setup_k<<<1, 32>>>();

    long long nHs = 2LL * SQ * CHN, nCtx = (long long)NST * NCTX * CC, nLf = (long long)NSTR * LLOC * CC;
    round_h<<<(int)((nHs / 8 + 255) / 256), 256>>>(hs, hsH, nHs);
    round_h<<<(int)((nCtx / 8 + 255) / 256), 256>>>(ctx, ctxH, nCtx);
    round_h<<<(int)((nLf / 8 + 255) / 256), 256>>>(lf, lfH, nLf);

    transpose_k<float><<<dim3(40, 40, 1), tb>>>(Wq, WqT, CHN, CHN, CHN, CHN, 0, 0);
    transpose_k<float><<<dim3(40, 24, 1), tb>>>(Wk, WkT, CC, CHN, CHN, CC, 0, 0);
    transpose_k<float><<<dim3(40, 24, 1), tb>>>(Wv, WvT, CC, CHN, CHN, CC, 0, 0);
    transpose_k<float><<<dim3(40, 24, 1), tb>>>(Wkg, WkgT, CC, CHN, CHN, CC, 0, 0);
    transpose_k<float><<<dim3(40, 24, 1), tb>>>(Wvg, WvgT, CC, CHN, CHN, CC, 0, 0);
    transpose_k<float><<<dim3(40, 24, 1), tb>>>(Wkl, WklT, CC, CHN, CHN, CC, 0, 0);
    transpose_k<float><<<dim3(40, 24, 1), tb>>>(Wvl, WvlT, CC, CHN, CHN, CC, 0, 0);
    transpose_k<float><<<dim3(40, 40, 1), tb>>>(Wout, WoutT, CHN, CHN, CHN, CHN, 0, 0);

    // projections (fp16 out)
    gemm_h<<<dim3(10, 64, 1), 256, SMEM3>>>(0, CHN, CHN, CHN, CHN, CHN, 1);   // Q
    gemm_h<<<dim3(10, 6, 4), 256, SMEM3>>>(1, CHN, CC, CC, CC, CHN, 1);       // K,V,Kg,Vg
    gemm_h<<<dim3(10, 17, 2), 256, SMEM3>>>(5, CHN, CC, CC, CC, CHN, 1);      // Kl,Vl
    kv_select_k<<<(NSTR * NCTX * CHN / 2 + 255) / 256, 256>>>(lidx);

    // V transposes (half -> half^T, zero-padded)
    transpose_k<__half><<<dim3(40, 3, NST), tb>>>(vp, vTp, NCTX, CHN, CHN, NCTXP,
                                                  (long long)NCTX * CHN, (long long)CHN * NCTXP);
    transpose_k<__half><<<dim3(40, 9, NSTR), tb>>>(vlp, vlTp, LLOC, CHN, CHN, LLOCP,
                                                   (long long)LLOC * CHN, (long long)CHN * LLOCP);

    // fused global attention -> pre (all streams) + mraw
    fused_g_k<<<dim3(32, 72), 256, smemA>>>(lidx);
    mmax_k<<<8, 256>>>();

    // fully fused local attention
    fused_l2_k<<<dim3(64, 64), 256, smemL>>>();

    // fuser premix + output projection (float out)
    premix_k<<<SQ, 256>>>(bbox);
    gemm_h<<<dim3(10, 32, 2), 256, SMEM3>>>(7, CHN, CHN, CHN, CHN, CHN, 0);
    final_k<<<SQ, 256>>>(bout, out);
}

// round 9
// speedup vs baseline: 2.5322x; 1.1344x over previous
#include <cuda_runtime.h>
#include <cuda_fp16.h>
#include <math.h>
#include <stdint.h>

#define SQ 4096
#define CHN 1280
#define CC 768
#define NHEAD 8
#define HD 160
#define NCTX 77
#define NCTXP 80
#define NST 9
#define NSTR 8
#define LLOC 257
#define LLOCP 272
#define PSTU 44
#define PLU 140
#define VLU 140
#define SMEM3 (3 * 2048 * 2 * 4)

// ---------------- scratch ----------------
__device__ __align__(256) __half g_hsH[2 * SQ * CHN];
__device__ __align__(256) __half g_ctxH[NST * NCTX * CC];
__device__ __align__(256) __half g_lfH[NSTR * LLOC * CC];
__device__ __align__(256) __half g_q2[2 * SQ * CHN];
__device__ __align__(256) __half g_k[NST * NCTX * CHN];
__device__ __align__(256) __half g_v[NST * NCTX * CHN];
__device__ __align__(256) __half g_kg[NSTR * NCTX * CHN];
__device__ __align__(256) __half g_vg[NSTR * NCTX * CHN];
__device__ __align__(256) __half g_kl[NSTR * LLOC * CHN];
__device__ __align__(256) __half g_vl[NSTR * LLOC * CHN];
__device__ __align__(256) __half g_WqT[CHN * CHN];
__device__ __align__(256) __half g_WkT[CHN * CC];
__device__ __align__(256) __half g_WvT[CHN * CC];
__device__ __align__(256) __half g_WkgT[CHN * CC];
__device__ __align__(256) __half g_WvgT[CHN * CC];
__device__ __align__(256) __half g_WklT[CHN * CC];
__device__ __align__(256) __half g_WvlT[CHN * CC];
__device__ __align__(256) __half g_WoutT[CHN * CHN];
__device__ __align__(256) __half g_vT[NST * CHN * NCTXP];
__device__ __align__(256) __half g_vlT[NSTR * CHN * LLOCP];
__device__ __align__(256) __half g_pre[NST * SQ * CHN];
__device__ __align__(256) __half g_mix[SQ * CHN];
__device__ __align__(256) float g_out2[2 * SQ * CHN];
__device__ float g_mraw[NSTR * NHEAD * SQ];
__device__ float g_mmax[NSTR];
__device__ float g_sumw[SQ];

__device__ const __half* d_Ap[16];
__device__ const __half* d_Bp[16];
__device__ void*         d_Cp[16];
__device__ int           d_Mt[16];

// ---------------- helpers ----------------
__device__ __forceinline__ uint32_t pk2(float a, float b) {
    __half2 h = __halves2half2(__float2half_rn(a), __float2half_rn(b));
    return *(uint32_t*)&h;
}
__device__ __forceinline__ void cp16(void* sdst, const void* gsrc, bool p) {
    uint32_t sa = (uint32_t)__cvta_generic_to_shared(sdst);
    int sz = p ? 16 : 0;
    asm volatile("cp.async.cg.shared.global [%0], [%1], 16, %2;" :: "r"(sa), "l"(gsrc), "r"(sz));
}
#define CP_COMMIT asm volatile("cp.async.commit_group;")
#define CP_WAIT0 asm volatile("cp.async.wait_group 0;")
#define CP_WAIT1 asm volatile("cp.async.wait_group 1;")
__device__ __forceinline__ void mma16(float* c, const uint32_t* a, const uint32_t* b) {
    asm volatile(
        "mma.sync.aligned.m16n8k16.row.col.f32.f16.f16.f32 "
        "{%0,%1,%2,%3}, {%4,%5,%6,%7}, {%8,%9}, {%0,%1,%2,%3};"
        : "+f"(c[0]), "+f"(c[1]), "+f"(c[2]), "+f"(c[3])
        : "r"(a[0]), "r"(a[1]), "r"(a[2]), "r"(a[3]), "r"(b[0]), "r"(b[1]));
}
__device__ __forceinline__ void ldsm4(uint32_t* r, uint32_t addr) {
    asm volatile("ldmatrix.sync.aligned.m8n8.x4.shared.b16 {%0,%1,%2,%3}, [%4];"
                 : "=r"(r[0]), "=r"(r[1]), "=r"(r[2]), "=r"(r[3]) : "r"(addr));
}
#define SWOFF(r, c) (((r) << 4) + ((((((c) >> 2) ^ (((r) >> 1) & 3))) << 2) | ((c) & 3)))

// ---------------- setup ----------------
__global__ void setup_k() {
    if (threadIdx.x == 0) {
        d_Ap[0] = g_hsH;               d_Bp[0] = g_WqT;   d_Cp[0] = g_q2;    d_Mt[0] = 2 * SQ;
        d_Ap[1] = g_ctxH;              d_Bp[1] = g_WkT;   d_Cp[1] = g_k;     d_Mt[1] = NST * NCTX;
        d_Ap[2] = g_ctxH;              d_Bp[2] = g_WvT;   d_Cp[2] = g_v;     d_Mt[2] = NST * NCTX;
        d_Ap[3] = g_ctxH + NCTX * CC;  d_Bp[3] = g_WkgT;  d_Cp[3] = g_kg;    d_Mt[3] = NSTR * NCTX;
        d_Ap[4] = g_ctxH + NCTX * CC;  d_Bp[4] = g_WvgT;  d_Cp[4] = g_vg;    d_Mt[4] = NSTR * NCTX;
        d_Ap[5] = g_lfH;               d_Bp[5] = g_WklT;  d_Cp[5] = g_kl;    d_Mt[5] = NSTR * LLOC;
        d_Ap[6] = g_lfH;               d_Bp[6] = g_WvlT;  d_Cp[6] = g_vl;    d_Mt[6] = NSTR * LLOC;
        d_Ap[7] = g_pre;               d_Bp[7] = g_WoutT; d_Cp[7] = g_out2;  d_Mt[7] = SQ;
        d_Ap[8] = g_mix;               d_Bp[8] = g_WoutT; d_Cp[8] = g_out2 + (size_t)SQ * CHN;
        d_Mt[8] = SQ;
    }
}

// ---------------- round inputs to fp16 ----------------
__global__ void round_h(const float* __restrict__ src, __half* __restrict__ dst, long long n) {
    long long i = ((long long)blockIdx.x * blockDim.x + threadIdx.x) * 8;
    if (i + 7 < n) {
        float4 a = *(const float4*)(src + i);
        float4 b = *(const float4*)(src + i + 4);
        uint4 u;
        u.x = pk2(a.x, a.y); u.y = pk2(a.z, a.w);
        u.z = pk2(b.x, b.y); u.w = pk2(b.z, b.w);
        *(uint4*)(dst + i) = u;
    } else {
        for (long long j = i; j < n; j++) dst[j] = __float2half_rn(src[j]);
    }
}

// ---------------- transpose (templated src type) -> half ----------------
template <typename TS>
__global__ void transpose_k(const TS* __restrict__ src, __half* __restrict__ dst,
                            int R, int C, int ldS, int ldD, long long sBS, long long dBS) {
    __shared__ float t[32][33];
    src += blockIdx.z * sBS;
    dst += blockIdx.z * dBS;
    int c0 = blockIdx.x << 5, r0 = blockIdx.y << 5;
    int tx = threadIdx.x, ty = threadIdx.y;
#pragma unroll
    for (int j = 0; j < 4; j++) {
        int rr = r0 + ty + j * 8, cc = c0 + tx;
        t[ty + j * 8][tx] = (rr < R && cc < C) ? (float)src[(size_t)rr * ldS + cc] : 0.f;
    }
    __syncthreads();
#pragma unroll
    for (int j = 0; j < 4; j++) {
        int cc = c0 + ty + j * 8, rr = r0 + tx;
        if (cc < C && rr < ldD)
            dst[(size_t)cc * ldD + rr] = __float2half_rn(t[tx][ty + j * 8]);
    }
}

// ---------------- batched NT fp16 GEMM (R8, proven) ----------------
__global__ void __launch_bounds__(256, 2) gemm_h(int slot, int N, int K,
                                                 int lda, int ldb, int ldc, int mode) {
    extern __shared__ __align__(16) uint32_t smg[];
    uint32_t* As = smg;
    uint32_t* Bs = smg + 3 * 2048;
    const __half* Ab = d_Ap[slot + blockIdx.z];
    const __half* Bb = d_Bp[slot + blockIdx.z];
    void* Cm         = d_Cp[slot + blockIdx.z];
    const int M      = d_Mt[slot + blockIdx.z];
    int tid = threadIdx.x, lane = tid & 31, warp = tid >> 5;
    int mBase = blockIdx.y << 7, nBase = blockIdx.x << 7;
    int mW = (warp >> 2) << 6, nW = (warp & 3) << 5;
    float acc[4][4][4];
#pragma unroll
    for (int a = 0; a < 4; a++)
#pragma unroll
        for (int b = 0; b < 4; b++)
#pragma unroll
            for (int cI = 0; cI < 4; cI++) acc[a][b][cI] = 0.f;

    int KT = K >> 5;
    auto issue = [&](int st, int kt) {
        int k0 = kt << 5;
#pragma unroll
        for (int i = 0; i < 2; i++) {
            int idx = tid + (i << 8);
            int r = idx >> 2, cu = (idx & 3) << 2;
            int gr = mBase + r; bool pa = gr < M; if (!pa) gr = M - 1;
            cp16(&As[st * 2048 + SWOFF(r, cu)], Ab + (size_t)gr * lda + k0 + (cu << 1), pa);
            int gn = nBase + r; bool pb = gn < N; if (!pb) gn = N - 1;
            cp16(&Bs[st * 2048 + SWOFF(r, cu)], Bb + (size_t)gn * ldb + k0 + (cu << 1), pb);
        }
        CP_COMMIT;
    };
    issue(0, 0);
    issue(1, 1);

    int lrow = lane & 7;
    int lm = lane >> 3;
    int arow[4], axor[4];
#pragma unroll
    for (int mi = 0; mi < 4; mi++) {
        arow[mi] = mW + (mi << 4) + ((lm & 1) << 3) + lrow;
        axor[mi] = (arow[mi] >> 1) & 3;
    }
    int achk = lm >> 1;
    int brow[2], bxor[2];
#pragma unroll
    for (int np = 0; np < 2; np++) {
        brow[np] = nW + (np << 4) + ((lm >> 1) << 3) + lrow;
        bxor[np] = (brow[np] >> 1) & 3;
    }
    int bchk = lm & 1;
    uint32_t sbA = (uint32_t)__cvta_generic_to_shared(As);
    uint32_t sbB = (uint32_t)__cvta_generic_to_shared(Bs);

    for (int kt = 0; kt < KT; kt++) {
        if (kt + 1 < KT) { CP_WAIT1; } else { CP_WAIT0; }
        __syncthreads();
        if (kt + 2 < KT) issue((kt + 2) % 3, kt + 2);
        uint32_t stA = sbA + (kt % 3) * 8192;
        uint32_t stB = sbB + (kt % 3) * 8192;
#pragma unroll
        for (int kk = 0; kk < 2; kk++) {
            uint32_t af[4][4], bf[4][2];
#pragma unroll
            for (int mi = 0; mi < 4; mi++) {
                uint32_t au = (uint32_t)(arow[mi] << 4) + ((((kk << 1) + achk) ^ axor[mi]) << 2);
                ldsm4(af[mi], stA + (au << 2));
            }
#pragma unroll
            for (int np = 0; np < 2; np++) {
                uint32_t bu = (uint32_t)(brow[np] << 4) + ((((kk << 1) + bchk) ^ bxor[np]) << 2);
                uint32_t r4[4];
                ldsm4(r4, stB + (bu << 2));
                bf[np * 2][0] = r4[0]; bf[np * 2][1] = r4[1];
                bf[np * 2 + 1][0] = r4[2]; bf[np * 2 + 1][1] = r4[3];
            }
#pragma unroll
            for (int mi = 0; mi < 4; mi++)
#pragma unroll
                for (int ni = 0; ni < 4; ni++) mma16(acc[mi][ni], af[mi], bf[ni]);
        }
    }
#pragma unroll
    for (int mi = 0; mi < 4; mi++) {
#pragma unroll
        for (int half = 0; half < 2; half++) {
            int gm = mBase + mW + (mi << 4) + (lane >> 2) + half * 8;
            if (gm >= M) continue;
#pragma unroll
            for (int ni = 0; ni < 4; ni++) {
                int gn = nBase + nW + (ni << 3) + ((lane & 3) << 1);
                if (gn + 1 >= N) continue;
                float v0 = acc[mi][ni][half * 2], v1 = acc[mi][ni][half * 2 + 1];
                if (mode & 1) {
                    __half* crow = (__half*)Cm + (size_t)gm * ldc;
                    *(uint32_t*)(crow + gn) = pk2(v0, v1);
                } else {
                    float* crow = (float*)Cm + (size_t)gm * ldc;
                    crow[gn] = v0;
                    crow[gn + 1] = v1;
                }
            }
        }
    }
}

// ---------------- ELITE K/V select ----------------
__global__ void kv_select_k(const int* __restrict__ lidx) {
    int idx = blockIdx.x * 256 + threadIdx.x;
    const int tot = NSTR * NCTX * CHN / 2;
    if (idx >= tot) return;
    int st = idx / (NCTX * CHN / 2);
    if (lidx[st] >= 0) {
        ((uint32_t*)g_k)[NCTX * CHN / 2 + idx] = ((const uint32_t*)g_kg)[idx];
        ((uint32_t*)g_v)[NCTX * CHN / 2 + idx] = ((const uint32_t*)g_vg)[idx];
    }
}

// ============ fused global attention (fp16, 2 CTAs/SM) ============
__global__ void __launch_bounds__(256, 2) fused_g_k(const int* __restrict__ lidx) {
    extern __shared__ __align__(16) uint32_t smu[];
    uint32_t* qb  = smu;
    uint32_t* kb  = smu + 4096;
    uint32_t* psm = smu + 8192;
    uint32_t* vsm = psm + 128 * PSTU;
    float* smx = (float*)(vsm + 160 * PSTU);
    float* ssu = smx + 256;
    __shared__ int sidx[8];

    int bh = blockIdx.y;
    int stream = bh >> 3, h = bh & 7;
    int q0 = blockIdx.x << 7;
    int tid = threadIdx.x, lane = tid & 31, warp = tid >> 5;
    if (tid < 8) sidx[tid] = lidx[tid];

    const __half* Qb = g_q2 + (stream ? (size_t)SQ * CHN : 0) + (size_t)q0 * CHN + h * HD;
    const __half* Kb = g_k + (size_t)stream * NCTX * CHN + h * HD;
    const __half* Vt = g_vT + (size_t)stream * CHN * NCTXP + (size_t)h * HD * NCTXP;

    for (int u = tid; u < 160 * 10; u += 256) {
        int d = u / 10, c = u % 10;
        cp16(vsm + d * PSTU + c * 4, Vt + (size_t)d * NCTXP + c * 8, true);
    }
    CP_COMMIT;

    auto issueQK = [&](int st, int kt) {
        int k0 = kt << 5;
#pragma unroll
        for (int i = 0; i < 2; i++) {
            int idx = tid + (i << 8);
            int r = idx >> 2, cu = (idx & 3) << 2;
            cp16(&qb[st * 2048 + SWOFF(r, cu)], Qb + (size_t)r * CHN + k0 + (cu << 1), true);
            int kr = (r < NCTX) ? r : (NCTX - 1);
            cp16(&kb[st * 2048 + SWOFF(r, cu)], Kb + (size_t)kr * CHN + k0 + (cu << 1), true);
        }
        CP_COMMIT;
    };
    issueQK(0, 0);

    int mW = (warp >> 1) << 5;
    int nWs = (warp & 1) * 40;
    float sc[2][5][4];
#pragma unroll
    for (int a = 0; a < 2; a++)
#pragma unroll
        for (int b = 0; b < 5; b++)
#pragma unroll
            for (int c = 0; c < 4; c++) sc[a][b][c] = 0.f;

    for (int kt = 0; kt < 5; kt++) {
        if (kt < 4) { issueQK((kt + 1) & 1, kt + 1); CP_WAIT1; }
        else        { CP_WAIT0; }
        __syncthreads();
        const uint32_t* pQ = qb + (kt & 1) * 2048;
        const uint32_t* pK = kb + (kt & 1) * 2048;
#pragma unroll
        for (int kk = 0; kk < 2; kk++) {
            int ck = (kk << 3) + (lane & 3);
            uint32_t af[2][4], bf[5][2];
#pragma unroll
            for (int mi = 0; mi < 2; mi++) {
                int r0 = mW + (mi << 4) + (lane >> 2);
                af[mi][0] = pQ[SWOFF(r0, ck)];
                af[mi][1] = pQ[SWOFF(r0 + 8, ck)];
                af[mi][2] = pQ[SWOFF(r0, ck + 4)];
                af[mi][3] = pQ[SWOFF(r0 + 8, ck + 4)];
            }
#pragma unroll
            for (int ni = 0; ni < 5; ni++) {
                int r0 = nWs + (ni << 3) + (lane >> 2);
                bf[ni][0] = pK[SWOFF(r0, ck)];
                bf[ni][1] = pK[SWOFF(r0, ck + 4)];
            }
#pragma unroll
            for (int mi = 0; mi < 2; mi++)
#pragma unroll
                for (int ni = 0; ni < 5; ni++) mma16(sc[mi][ni], af[mi], bf[ni]);
        }
        __syncthreads();
    }

    const float scale = 0.07905694150420949f;
    int half = warp & 1;
#pragma unroll
    for (int mi = 0; mi < 2; mi++)
#pragma unroll
        for (int hf = 0; hf < 2; hf++) {
            int row = mW + mi * 16 + (lane >> 2) + hf * 8;
            float mx = -1e30f;
#pragma unroll
            for (int ni = 0; ni < 5; ni++)
#pragma unroll
                for (int c = 0; c < 2; c++) {
                    int col = nWs + ni * 8 + ((lane & 3) << 1) + c;
                    if (col < NCTX) mx = fmaxf(mx, sc[mi][ni][hf * 2 + c]);
                }
            mx = fmaxf(mx, __shfl_xor_sync(0xffffffffu, mx, 1));
            mx = fmaxf(mx, __shfl_xor_sync(0xffffffffu, mx, 2));
            if ((lane & 3) == 0) smx[half * 128 + row] = mx;
        }
    __syncthreads();
#pragma unroll
    for (int mi = 0; mi < 2; mi++)
#pragma unroll
        for (int hf = 0; hf < 2; hf++) {
            int row = mW + mi * 16 + (lane >> 2) + hf * 8;
            float m = fmaxf(smx[row], smx[128 + row]);
            float s = 0.f;
#pragma unroll
            for (int ni = 0; ni < 5; ni++)
#pragma unroll
                for (int c = 0; c < 2; c++) {
                    int col = nWs + ni * 8 + ((lane & 3) << 1) + c;
                    float e = (col < NCTX) ? __expf((sc[mi][ni][hf * 2 + c] - m) * scale) : 0.f;
                    sc[mi][ni][hf * 2 + c] = e;
                    s += e;
                }
            s += __shfl_xor_sync(0xffffffffu, s, 1);
            s += __shfl_xor_sync(0xffffffffu, s, 2);
            if ((lane & 3) == 0) ssu[half * 128 + row] = s;
        }
    __syncthreads();
#pragma unroll
    for (int mi = 0; mi < 2; mi++)
#pragma unroll
        for (int hf = 0; hf < 2; hf++) {
            int row = mW + mi * 16 + (lane >> 2) + hf * 8;
            float inv = 1.f / (ssu[row] + ssu[128 + row]);
#pragma unroll
            for (int ni = 0; ni < 5; ni++) {
                int col = nWs + ni * 8 + ((lane & 3) << 1);
                float v0 = (col < NCTX) ? sc[mi][ni][hf * 2] * inv : 0.f;
                float v1 = (col + 1 < NCTX) ? sc[mi][ni][hf * 2 + 1] * inv : 0.f;
                psm[row * PSTU + (nWs >> 1) + ni * 4 + (lane & 3)] = pk2(v0, v1);
            }
        }
    __syncthreads();

    if (stream == 0) {
        const __half* ph = (const __half*)psm;
        for (int u = tid; u < 128 * 8; u += 256) {
            int r = u >> 3, i = u & 7;
            g_mraw[((size_t)i * NHEAD + h) * SQ + q0 + r] =
                __half2float(ph[r * (2 * PSTU) + sidx[i]]);
        }
    }

    int nW = (warp & 1) * 80;
    float oa[2][10][4];
#pragma unroll
    for (int a = 0; a < 2; a++)
#pragma unroll
        for (int b = 0; b < 10; b++)
#pragma unroll
            for (int c = 0; c < 4; c++) oa[a][b][c] = 0.f;
#pragma unroll
    for (int kst = 0; kst < 5; kst++) {
        int ka = kst * 8 + (lane & 3);
        uint32_t af[2][4], bf[10][2];
#pragma unroll
        for (int mi = 0; mi < 2; mi++) {
            int r0 = mW + (mi << 4) + (lane >> 2);
            af[mi][0] = psm[r0 * PSTU + ka];
            af[mi][1] = psm[(r0 + 8) * PSTU + ka];
            af[mi][2] = psm[r0 * PSTU + ka + 4];
            af[mi][3] = psm[(r0 + 8) * PSTU + ka + 4];
        }
#pragma unroll
        for (int ni = 0; ni < 10; ni++) {
            int d = nW + (ni << 3) + (lane >> 2);
            bf[ni][0] = vsm[d * PSTU + ka];
            bf[ni][1] = vsm[d * PSTU + ka + 4];
        }
#pragma unroll
        for (int mi = 0; mi < 2; mi++)
#pragma unroll
            for (int ni = 0; ni < 10; ni++) mma16(oa[mi][ni], af[mi], bf[ni]);
    }
#pragma unroll
    for (int mi = 0; mi < 2; mi++)
#pragma unroll
        for (int hf = 0; hf < 2; hf++) {
            int g = q0 + mW + mi * 16 + (lane >> 2) + hf * 8;
            __half* orow = g_pre + ((size_t)stream * SQ + g) * CHN + h * HD;
#pragma unroll
            for (int ni = 0; ni < 10; ni++) {
                int col = nW + (ni << 3) + ((lane & 3) << 1);
                *(uint32_t*)(orow + col) = pk2(oa[mi][ni][hf * 2], oa[mi][ni][hf * 2 + 1]);
            }
        }
}

// ---------------- per-instance gate max ----------------
__global__ void mmax_k() {
    __shared__ float red[256];
    int i = blockIdx.x;
    float mx = 0.f;
    const float* p = g_mraw + (size_t)i * NHEAD * SQ;
    for (int idx = threadIdx.x; idx < NHEAD * SQ; idx += 256) mx = fmaxf(mx, p[idx]);
    red[threadIdx.x] = mx;
    __syncthreads();
    for (int s = 128; s > 0; s >>= 1) {
        if (threadIdx.x < s) red[threadIdx.x] = fmaxf(red[threadIdx.x], red[threadIdx.x + s]);
        __syncthreads();
    }
    if (threadIdx.x == 0) g_mmax[i] = red[0];
}

// ============ fully fused local attention: register softmax, V resident ======
// grid (64 qtiles of 64 rows, 64 ih), 256 threads
__global__ void __launch_bounds__(256) fused_l2_k() {
    extern __shared__ __align__(16) uint32_t smu[];
    uint32_t* plm = smu;                          // 64 * PLU (P as half2)
    uint32_t* vsm = smu + 64 * PLU;               // 160 * VLU (V^T resident; aliases QK staging)
    float* smx = (float*)(smu + 64 * PLU + 160 * VLU);  // 64 * 4
    float* ssu = smx + 256;                       // 64 * 4

    int z = blockIdx.y;
    int inst = z >> 3, h = z & 7;
    int q0 = blockIdx.x << 6;
    int tid = threadIdx.x, lane = tid & 31, warp = tid >> 5;

    const __half* Qb  = g_q2 + (size_t)SQ * CHN + (size_t)q0 * CHN + h * HD;
    const __half* Klb = g_kl + (size_t)inst * LLOC * CHN + h * HD;
    const __half* Vt  = g_vlT + (size_t)inst * CHN * LLOCP + (size_t)h * HD * LLOCP;

    // ---- phase 1: S = Q @ Kl^T (64 x 288, K=160), staging aliased over vsm ----
    uint32_t* strm = vsm;
    auto issueQK = [&](int st, int kt) {
        int k0 = kt << 5;
        uint32_t* base = strm + st * 5632;
        {
            int r = tid >> 2, cu = (tid & 3) << 2;
            cp16(base + SWOFF(r, cu), Qb + (size_t)r * CHN + k0 + (cu << 1), true);
        }
        for (int u = tid; u < 1152; u += 256) {
            int r = u >> 2, cu = (u & 3) << 2;
            int kr = (r < LLOC) ? r : (LLOC - 1);
            cp16(base + 1024 + SWOFF(r, cu), Klb + (size_t)kr * CHN + k0 + (cu << 1), true);
        }
        CP_COMMIT;
    };
    issueQK(0, 0);

    int mW2 = (warp >> 2) << 5;       // 0 or 32
    int nW4 = (warp & 3) * 72;        // 0,72,144,216
    float sc[2][9][4];
#pragma unroll
    for (int a = 0; a < 2; a++)
#pragma unroll
        for (int b = 0; b < 9; b++)
#pragma unroll
            for (int c = 0; c < 4; c++) sc[a][b][c] = 0.f;

    for (int kt = 0; kt < 5; kt++) {
        if (kt < 4) { issueQK((kt + 1) & 1, kt + 1); CP_WAIT1; }
        else        { CP_WAIT0; }
        __syncthreads();
        const uint32_t* pQ = strm + (kt & 1) * 5632;
        const uint32_t* pK = pQ + 1024;
#pragma unroll
        for (int kk = 0; kk < 2; kk++) {
            int ck = (kk << 3) + (lane & 3);
            uint32_t af[2][4], bf[9][2];
#pragma unroll
            for (int mi = 0; mi < 2; mi++) {
                int r0 = mW2 + (mi << 4) + (lane >> 2);
                af[mi][0] = pQ[SWOFF(r0, ck)];
                af[mi][1] = pQ[SWOFF(r0 + 8, ck)];
                af[mi][2] = pQ[SWOFF(r0, ck + 4)];
                af[mi][3] = pQ[SWOFF(r0 + 8, ck + 4)];
            }
#pragma unroll
            for (int ni = 0; ni < 9; ni++) {
                int r0 = nW4 + (ni << 3) + (lane >> 2);
                bf[ni][0] = pK[SWOFF(r0, ck)];
                bf[ni][1] = pK[SWOFF(r0, ck + 4)];
            }
#pragma unroll
            for (int mi = 0; mi < 2; mi++)
#pragma unroll
                for (int ni = 0; ni < 9; ni++) mma16(sc[mi][ni], af[mi], bf[ni]);
        }
        __syncthreads();
    }

    // ---- issue full V^T load into vsm (overwrites staging; all reads done) ----
    for (int u = tid; u < 160 * 34; u += 256) {
        int d = u / 34, c = u % 34;
        cp16(vsm + d * VLU + c * 4, Vt + (size_t)d * LLOCP + c * 8, true);
    }
    CP_COMMIT;

    // ---- register softmax with cross-warp partials ----
    const float scale = 0.07905694150420949f;
    float gden = 0.5f / g_mmax[inst];
#pragma unroll
    for (int mi = 0; mi < 2; mi++)
#pragma unroll
        for (int hf = 0; hf < 2; hf++) {
            int row = mW2 + mi * 16 + (lane >> 2) + hf * 8;
            float mx = -1e30f;
#pragma unroll
            for (int ni = 0; ni < 9; ni++)
#pragma unroll
                for (int c = 0; c < 2; c++) {
                    int col = nW4 + ni * 8 + ((lane & 3) << 1) + c;
                    if (col < LLOC) mx = fmaxf(mx, sc[mi][ni][hf * 2 + c]);
                }
            mx = fmaxf(mx, __shfl_xor_sync(0xffffffffu, mx, 1));
            mx = fmaxf(mx, __shfl_xor_sync(0xffffffffu, mx, 2));
            if ((lane & 3) == 0) smx[row * 4 + (warp & 3)] = mx;
        }
    __syncthreads();
#pragma unroll
    for (int mi = 0; mi < 2; mi++)
#pragma unroll
        for (int hf = 0; hf < 2; hf++) {
            int row = mW2 + mi * 16 + (lane >> 2) + hf * 8;
            float m = fmaxf(fmaxf(smx[row * 4], smx[row * 4 + 1]),
                            fmaxf(smx[row * 4 + 2], smx[row * 4 + 3]));
            float s = 0.f;
#pragma unroll
            for (int ni = 0; ni < 9; ni++)
#pragma unroll
                for (int c = 0; c < 2; c++) {
                    int col = nW4 + ni * 8 + ((lane & 3) << 1) + c;
                    float e = (col < LLOC) ? __expf((sc[mi][ni][hf * 2 + c] - m) * scale) : 0.f;
                    sc[mi][ni][hf * 2 + c] = e;
                    s += e;
                }
            s += __shfl_xor_sync(0xffffffffu, s, 1);
            s += __shfl_xor_sync(0xffffffffu, s, 2);
            if ((lane & 3) == 0) ssu[row * 4 + (warp & 3)] = s;
        }
    __syncthreads();
#pragma unroll
    for (int mi = 0; mi < 2; mi++)
#pragma unroll
        for (int hf = 0; hf < 2; hf++) {
            int row = mW2 + mi * 16 + (lane >> 2) + hf * 8;
            float s = ssu[row * 4] + ssu[row * 4 + 1] + ssu[row * 4 + 2] + ssu[row * 4 + 3];
            float f = g_mraw[(size_t)z * SQ + q0 + row] * gden / s;
#pragma unroll
            for (int ni = 0; ni < 9; ni++) {
                int ucol = (nW4 >> 1) + ni * 4 + (lane & 3);
                if (ucol < 136)
                    plm[row * PLU + ucol] = pk2(sc[mi][ni][hf * 2] * f, sc[mi][ni][hf * 2 + 1] * f);
            }
        }
    CP_WAIT0;
    __syncthreads();   // plm writes + V arrival visible to all

    // ---- PV: O[64][160] = P[64][272] @ Vl[272][160], fully resident, no syncs --
    int nW = (warp & 3) * 40;
    float oa[2][5][4];
#pragma unroll
    for (int a = 0; a < 2; a++)
#pragma unroll
        for (int b = 0; b < 5; b++)
#pragma unroll
            for (int c = 0; c < 4; c++) oa[a][b][c] = 0.f;

#pragma unroll 1
    for (int ch = 0; ch < 17; ch++) {
        int ka = ch * 8 + (lane & 3);
        uint32_t af[2][4], bf[5][2];
#pragma unroll
        for (int mi = 0; mi < 2; mi++) {
            int r0 = mW2 + (mi << 4) + (lane >> 2);
            af[mi][0] = plm[r0 * PLU + ka];
            af[mi][1] = plm[(r0 + 8) * PLU + ka];
            af[mi][2] = plm[r0 * PLU + ka + 4];
            af[mi][3] = plm[(r0 + 8) * PLU + ka + 4];
        }
#pragma unroll
        for (int ni = 0; ni < 5; ni++) {
            int d = nW + (ni << 3) + (lane >> 2);
            bf[ni][0] = vsm[d * VLU + ka];
            bf[ni][1] = vsm[d * VLU + ka + 4];
        }
#pragma unroll
        for (int mi = 0; mi < 2; mi++)
#pragma unroll
            for (int ni = 0; ni < 5; ni++) mma16(oa[mi][ni], af[mi], bf[ni]);
    }

    // epilogue: blend 0.5*pre + O
#pragma unroll
    for (int mi = 0; mi < 2; mi++)
#pragma unroll
        for (int hf = 0; hf < 2; hf++) {
            int g = q0 + mW2 + mi * 16 + (lane >> 2) + hf * 8;
            __half* prow = g_pre + ((size_t)(inst + 1) * SQ + g) * CHN + h * HD;
#pragma unroll
            for (int ni = 0; ni < 5; ni++) {
                int col = nW + (ni << 3) + ((lane & 3) << 1);
                __half2 old = *(__half2*)(prow + col);
                float o0 = 0.5f * __half2float(old.x) + oa[mi][ni][hf * 2];
                float o1 = 0.5f * __half2float(old.y) + oa[mi][ni][hf * 2 + 1];
                *(uint32_t*)(prow + col) = pk2(o0, o1);
            }
        }
}

// ---------------- fuser premix ----------------
__global__ void premix_k(const float* __restrict__ bbox) {
    int s = blockIdx.x;
    int y = s >> 6, x = s & 63;
    float wgt[8];
    wgt[0] = 1.f;
    float sw = 1.f;
    const int off[4] = {3, 4, 11, 12};
#pragma unroll
    for (int i = 0; i < 7; i++) {
        float wmin = floorf(1024.f * bbox[i * 4 + 0]);
        float hmin = floorf(1024.f * bbox[i * 4 + 1]);
        float wmax = floorf(1024.f * bbox[i * 4 + 2]);
        float hmax = floorf(1024.f * bbox[i * 4 + 3]);
        float R = 0.f, Cv = 0.f;
#pragma unroll
        for (int j = 0; j < 4; j++) {
            float yy = (float)(16 * y + off[j]);
            float xx = (float)(16 * x + off[j]);
            if (yy >= hmin && yy < hmax) R += 0.25f;
            if (xx >= wmin && xx < wmax) Cv += 0.25f;
        }
        float g = 10.f * R * Cv;
        wgt[i + 1] = g;
        sw += g;
    }
    if (threadIdx.x == 0) g_sumw[s] = sw;
    for (int c = threadIdx.x; c < CHN; c += 256) {
        float acc = 0.f;
#pragma unroll
        for (int j = 0; j < 8; j++)
            acc += wgt[j] * __half2float(g_pre[((size_t)(1 + j) * SQ + s) * CHN + c]);
        g_mix[(size_t)s * CHN + c] = __float2half_rn(acc);
    }
}

// ---------------- final ----------------
__global__ void final_k(const float* __restrict__ bout, float* __restrict__ out) {
    int s = blockIdx.x;
    float sw = g_sumw[s];
    float den = 1.f / (sw + 1e-6f);
    for (int c = threadIdx.x; c < CHN; c += 256) {
        float b = bout[c];
        out[(size_t)s * CHN + c] = g_out2[(size_t)s * CHN + c] + b;
        out[(size_t)(SQ + s) * CHN + c] = (g_out2[(size_t)(SQ + s) * CHN + c] + b * sw) * den;
    }
}

// ---------------- launch ----------------
extern "C" void kernel_launch(void* const* d_in, const int* in_sizes, int n_in,
                              void* d_out, int out_size) {
    const float* hs   = (const float*)d_in[0];
    const float* ctx  = (const float*)d_in[1];
    const float* lf   = (const float*)d_in[2];
    const float* bbox = (const float*)d_in[3];
    const float* Wq   = (const float*)d_in[4];
    const float* Wk   = (const float*)d_in[5];
    const float* Wv   = (const float*)d_in[6];
    const float* Wkg  = (const float*)d_in[7];
    const float* Wvg  = (const float*)d_in[8];
    const float* Wkl  = (const float*)d_in[9];
    const float* Wvl  = (const float*)d_in[10];
    const float* Wout = (const float*)d_in[11];
    const float* bout = (const float*)d_in[12];
    const int*   lidx = (const int*)d_in[13];
    float* out = (float*)d_out;

    __half *hsH, *ctxH, *lfH, *WqT, *WkT, *WvT, *WkgT, *WvgT, *WklT, *WvlT, *WoutT;
    __half *vp, *vTp, *vlp, *vlTp;
    cudaGetSymbolAddress((void**)&hsH, g_hsH);
    cudaGetSymbolAddress((void**)&ctxH, g_ctxH);
    cudaGetSymbolAddress((void**)&lfH, g_lfH);
    cudaGetSymbolAddress((void**)&WqT, g_WqT);
    cudaGetSymbolAddress((void**)&WkT, g_WkT);
    cudaGetSymbolAddress((void**)&WvT, g_WvT);
    cudaGetSymbolAddress((void**)&WkgT, g_WkgT);
    cudaGetSymbolAddress((void**)&WvgT, g_WvgT);
    cudaGetSymbolAddress((void**)&WklT, g_WklT);
    cudaGetSymbolAddress((void**)&WvlT, g_WvlT);
    cudaGetSymbolAddress((void**)&WoutT, g_WoutT);
    cudaGetSymbolAddress((void**)&vp, g_v);
    cudaGetSymbolAddress((void**)&vTp, g_vT);
    cudaGetSymbolAddress((void**)&vlp, g_vl);
    cudaGetSymbolAddress((void**)&vlTp, g_vlT);

    const int smemA = (2 * 2048 * 2 + 128 * PSTU + 160 * PSTU + 512) * 4;   // 85,504
    const int smemL = (64 * PLU + 160 * VLU + 512) * 4;                     // 127,488
    cudaFuncSetAttribute(fused_g_k, cudaFuncAttributeMaxDynamicSharedMemorySize, smemA);
    cudaFuncSetAttribute(fused_l2_k, cudaFuncAttributeMaxDynamicSharedMemorySize, smemL);
    cudaFuncSetAttribute(gemm_h, cudaFuncAttributeMaxDynamicSharedMemorySize, SMEM3);

    dim3 tb(32, 8);
    setup_k<<<1, 32>>>();

    long long nHs = 2LL * SQ * CHN, nCtx = (long long)NST * NCTX * CC, nLf = (long long)NSTR * LLOC * CC;
    round_h<<<(int)((nHs / 8 + 255) / 256), 256>>>(hs, hsH, nHs);
    round_h<<<(int)((nCtx / 8 + 255) / 256), 256>>>(ctx, ctxH, nCtx);
    round_h<<<(int)((nLf / 8 + 255) / 256), 256>>>(lf, lfH, nLf);

    transpose_k<float><<<dim3(40, 40, 1), tb>>>(Wq, WqT, CHN, CHN, CHN, CHN, 0, 0);
    transpose_k<float><<<dim3(40, 24, 1), tb>>>(Wk, WkT, CC, CHN, CHN, CC, 0, 0);
    transpose_k<float><<<dim3(40, 24, 1), tb>>>(Wv, WvT, CC, CHN, CHN, CC, 0, 0);
    transpose_k<float><<<dim3(40, 24, 1), tb>>>(Wkg, WkgT, CC, CHN, CHN, CC, 0, 0);
    transpose_k<float><<<dim3(40, 24, 1), tb>>>(Wvg, WvgT, CC, CHN, CHN, CC, 0, 0);
    transpose_k<float><<<dim3(40, 24, 1), tb>>>(Wkl, WklT, CC, CHN, CHN, CC, 0, 0);
    transpose_k<float><<<dim3(40, 24, 1), tb>>>(Wvl, WvlT, CC, CHN, CHN, CC, 0, 0);
    transpose_k<float><<<dim3(40, 40, 1), tb>>>(Wout, WoutT, CHN, CHN, CHN, CHN, 0, 0);

    // projections (fp16 out)
    gemm_h<<<dim3(10, 64, 1), 256, SMEM3>>>(0, CHN, CHN, CHN, CHN, CHN, 1);   // Q
    gemm_h<<<dim3(10, 6, 4), 256, SMEM3>>>(1, CHN, CC, CC, CC, CHN, 1);       // K,V,Kg,Vg
    gemm_h<<<dim3(10, 17, 2), 256, SMEM3>>>(5, CHN, CC, CC, CC, CHN, 1);      // Kl,Vl
    kv_select_k<<<(NSTR * NCTX * CHN / 2 + 255) / 256, 256>>>(lidx);

    // V transposes
    transpose_k<__half><<<dim3(40, 3, NST), tb>>>(vp, vTp, NCTX, CHN, CHN, NCTXP,
                                                  (long long)NCTX * CHN, (long long)CHN * NCTXP);
    transpose_k<__half><<<dim3(40, 9, NSTR), tb>>>(vlp, vlTp, LLOC, CHN, CHN, LLOCP,
                                                   (long long)LLOC * CHN, (long long)CHN * LLOCP);

    // fused global attention -> pre (all streams) + mraw
    fused_g_k<<<dim3(32, 72), 256, smemA>>>(lidx);
    mmax_k<<<8, 256>>>();

    // fully fused local attention
    fused_l2_k<<<dim3(64, 64), 256, smemL>>>();

    // fuser premix + output projection
    premix_k<<<SQ, 256>>>(bbox);
    gemm_h<<<dim3(10, 32, 2), 256, SMEM3>>>(7, CHN, CHN, CHN, CHN, CHN, 0);
    final_k<<<SQ, 256>>>(bout, out);
}

// round 10
// speedup vs baseline: 2.6420x; 1.0434x over previous
#include <cuda_runtime.h>
#include <cuda_fp16.h>
#include <math.h>
#include <stdint.h>

#define SQ 4096
#define CHN 1280
#define CC 768
#define NHEAD 8
#define HD 160
#define NCTX 77
#define NCTXP 80
#define NST 9
#define NSTR 8
#define LLOC 257
#define LLOCP 272
#define PSTU 44
#define PLU 140
#define VLU 140
#define SMEM3 (3 * 2048 * 2 * 4)

// ---------------- scratch ----------------
__device__ __align__(256) __half g_hsH[2 * SQ * CHN];
__device__ __align__(256) __half g_ctxH[NST * NCTX * CC];
__device__ __align__(256) __half g_lfH[NSTR * LLOC * CC];
__device__ __align__(256) __half g_q2[2 * SQ * CHN];
__device__ __align__(256) __half g_k[NST * NCTX * CHN];
__device__ __align__(256) __half g_v[NST * NCTX * CHN];
__device__ __align__(256) __half g_kg[NSTR * NCTX * CHN];
__device__ __align__(256) __half g_vg[NSTR * NCTX * CHN];
__device__ __align__(256) __half g_kl[NSTR * LLOC * CHN];
__device__ __align__(256) __half g_vl[NSTR * LLOC * CHN];
__device__ __align__(256) __half g_WqT[CHN * CHN];
__device__ __align__(256) __half g_WkT[CHN * CC];
__device__ __align__(256) __half g_WvT[CHN * CC];
__device__ __align__(256) __half g_WkgT[CHN * CC];
__device__ __align__(256) __half g_WvgT[CHN * CC];
__device__ __align__(256) __half g_WklT[CHN * CC];
__device__ __align__(256) __half g_WvlT[CHN * CC];
__device__ __align__(256) __half g_WoutT[CHN * CHN];
__device__ __align__(256) __half g_vT[NST * CHN * NCTXP];
__device__ __align__(256) __half g_vlT[NSTR * CHN * LLOCP];
__device__ __align__(256) __half g_pre[NST * SQ * CHN];
__device__ __align__(256) __half g_mix[SQ * CHN];
__device__ __align__(256) float g_out2[2 * SQ * CHN];
__device__ float g_mraw[NSTR * NHEAD * SQ];
__device__ float g_mmax[NSTR];
__device__ float g_sumw[SQ];

__device__ const __half* d_Ap[16];
__device__ const __half* d_Bp[16];
__device__ void*         d_Cp[16];
__device__ int           d_Mt[16];

// ---------------- streams/events (created before harness mem checkpoints) ----
struct StreamInit {
    cudaStream_t sA, sB, sC;
    cudaEvent_t evRoot, ev1, ev2, ev3, evG, evO7;
    StreamInit() {
        cudaStreamCreateWithFlags(&sA, cudaStreamNonBlocking);
        cudaStreamCreateWithFlags(&sB, cudaStreamNonBlocking);
        cudaStreamCreateWithFlags(&sC, cudaStreamNonBlocking);
        cudaEventCreateWithFlags(&evRoot, cudaEventDisableTiming);
        cudaEventCreateWithFlags(&ev1, cudaEventDisableTiming);
        cudaEventCreateWithFlags(&ev2, cudaEventDisableTiming);
        cudaEventCreateWithFlags(&ev3, cudaEventDisableTiming);
        cudaEventCreateWithFlags(&evG, cudaEventDisableTiming);
        cudaEventCreateWithFlags(&evO7, cudaEventDisableTiming);
    }
};
static StreamInit g_si;

// ---------------- helpers ----------------
__device__ __forceinline__ uint32_t pk2(float a, float b) {
    __half2 h = __halves2half2(__float2half_rn(a), __float2half_rn(b));
    return *(uint32_t*)&h;
}
__device__ __forceinline__ void cp16(void* sdst, const void* gsrc, bool p) {
    uint32_t sa = (uint32_t)__cvta_generic_to_shared(sdst);
    int sz = p ? 16 : 0;
    asm volatile("cp.async.cg.shared.global [%0], [%1], 16, %2;" :: "r"(sa), "l"(gsrc), "r"(sz));
}
#define CP_COMMIT asm volatile("cp.async.commit_group;")
#define CP_WAIT0 asm volatile("cp.async.wait_group 0;")
#define CP_WAIT1 asm volatile("cp.async.wait_group 1;")
__device__ __forceinline__ void mma16(float* c, const uint32_t* a, const uint32_t* b) {
    asm volatile(
        "mma.sync.aligned.m16n8k16.row.col.f32.f16.f16.f32 "
        "{%0,%1,%2,%3}, {%4,%5,%6,%7}, {%8,%9}, {%0,%1,%2,%3};"
        : "+f"(c[0]), "+f"(c[1]), "+f"(c[2]), "+f"(c[3])
        : "r"(a[0]), "r"(a[1]), "r"(a[2]), "r"(a[3]), "r"(b[0]), "r"(b[1]));
}
__device__ __forceinline__ void ldsm4(uint32_t* r, uint32_t addr) {
    asm volatile("ldmatrix.sync.aligned.m8n8.x4.shared.b16 {%0,%1,%2,%3}, [%4];"
                 : "=r"(r[0]), "=r"(r[1]), "=r"(r[2]), "=r"(r[3]) : "r"(addr));
}
#define SWOFF(r, c) (((r) << 4) + ((((((c) >> 2) ^ (((r) >> 1) & 3))) << 2) | ((c) & 3)))

// ---------------- setup ----------------
__global__ void setup_k() {
    if (threadIdx.x == 0) {
        d_Ap[0] = g_hsH;               d_Bp[0] = g_WqT;   d_Cp[0] = g_q2;    d_Mt[0] = 2 * SQ;
        d_Ap[1] = g_ctxH;              d_Bp[1] = g_WkT;   d_Cp[1] = g_k;     d_Mt[1] = NST * NCTX;
        d_Ap[2] = g_ctxH;              d_Bp[2] = g_WvT;   d_Cp[2] = g_v;     d_Mt[2] = NST * NCTX;
        d_Ap[3] = g_ctxH + NCTX * CC;  d_Bp[3] = g_WkgT;  d_Cp[3] = g_kg;    d_Mt[3] = NSTR * NCTX;
        d_Ap[4] = g_ctxH + NCTX * CC;  d_Bp[4] = g_WvgT;  d_Cp[4] = g_vg;    d_Mt[4] = NSTR * NCTX;
        d_Ap[5] = g_lfH;               d_Bp[5] = g_WklT;  d_Cp[5] = g_kl;    d_Mt[5] = NSTR * LLOC;
        d_Ap[6] = g_lfH;               d_Bp[6] = g_WvlT;  d_Cp[6] = g_vl;    d_Mt[6] = NSTR * LLOC;
        d_Ap[7] = g_pre;               d_Bp[7] = g_WoutT; d_Cp[7] = g_out2;  d_Mt[7] = SQ;
        d_Ap[8] = g_mix;               d_Bp[8] = g_WoutT; d_Cp[8] = g_out2 + (size_t)SQ * CHN;
        d_Mt[8] = SQ;
    }
}

// ---------------- round inputs to fp16 ----------------
__global__ void round_h(const float* __restrict__ src, __half* __restrict__ dst, long long n) {
    long long i = ((long long)blockIdx.x * blockDim.x + threadIdx.x) * 8;
    if (i + 7 < n) {
        float4 a = *(const float4*)(src + i);
        float4 b = *(const float4*)(src + i + 4);
        uint4 u;
        u.x = pk2(a.x, a.y); u.y = pk2(a.z, a.w);
        u.z = pk2(b.x, b.y); u.w = pk2(b.z, b.w);
        *(uint4*)(dst + i) = u;
    } else {
        for (long long j = i; j < n; j++) dst[j] = __float2half_rn(src[j]);
    }
}

// ---------------- transpose (templated src type) -> half ----------------
template <typename TS>
__global__ void transpose_k(const TS* __restrict__ src, __half* __restrict__ dst,
                            int R, int C, int ldS, int ldD, long long sBS, long long dBS) {
    __shared__ float t[32][33];
    src += blockIdx.z * sBS;
    dst += blockIdx.z * dBS;
    int c0 = blockIdx.x << 5, r0 = blockIdx.y << 5;
    int tx = threadIdx.x, ty = threadIdx.y;
#pragma unroll
    for (int j = 0; j < 4; j++) {
        int rr = r0 + ty + j * 8, cc = c0 + tx;
        t[ty + j * 8][tx] = (rr < R && cc < C) ? (float)src[(size_t)rr * ldS + cc] : 0.f;
    }
    __syncthreads();
#pragma unroll
    for (int j = 0; j < 4; j++) {
        int cc = c0 + ty + j * 8, rr = r0 + tx;
        if (cc < C && rr < ldD)
            dst[(size_t)cc * ldD + rr] = __float2half_rn(t[tx][ty + j * 8]);
    }
}

// ---------------- batched NT fp16 GEMM (R8, proven) ----------------
__global__ void __launch_bounds__(256, 2) gemm_h(int slot, int N, int K,
                                                 int lda, int ldb, int ldc, int mode) {
    extern __shared__ __align__(16) uint32_t smg[];
    uint32_t* As = smg;
    uint32_t* Bs = smg + 3 * 2048;
    const __half* Ab = d_Ap[slot + blockIdx.z];
    const __half* Bb = d_Bp[slot + blockIdx.z];
    void* Cm         = d_Cp[slot + blockIdx.z];
    const int M      = d_Mt[slot + blockIdx.z];
    int tid = threadIdx.x, lane = tid & 31, warp = tid >> 5;
    int mBase = blockIdx.y << 7, nBase = blockIdx.x << 7;
    int mW = (warp >> 2) << 6, nW = (warp & 3) << 5;
    float acc[4][4][4];
#pragma unroll
    for (int a = 0; a < 4; a++)
#pragma unroll
        for (int b = 0; b < 4; b++)
#pragma unroll
            for (int cI = 0; cI < 4; cI++) acc[a][b][cI] = 0.f;

    int KT = K >> 5;
    auto issue = [&](int st, int kt) {
        int k0 = kt << 5;
#pragma unroll
        for (int i = 0; i < 2; i++) {
            int idx = tid + (i << 8);
            int r = idx >> 2, cu = (idx & 3) << 2;
            int gr = mBase + r; bool pa = gr < M; if (!pa) gr = M - 1;
            cp16(&As[st * 2048 + SWOFF(r, cu)], Ab + (size_t)gr * lda + k0 + (cu << 1), pa);
            int gn = nBase + r; bool pb = gn < N; if (!pb) gn = N - 1;
            cp16(&Bs[st * 2048 + SWOFF(r, cu)], Bb + (size_t)gn * ldb + k0 + (cu << 1), pb);
        }
        CP_COMMIT;
    };
    issue(0, 0);
    issue(1, 1);

    int lrow = lane & 7;
    int lm = lane >> 3;
    int arow[4], axor[4];
#pragma unroll
    for (int mi = 0; mi < 4; mi++) {
        arow[mi] = mW + (mi << 4) + ((lm & 1) << 3) + lrow;
        axor[mi] = (arow[mi] >> 1) & 3;
    }
    int achk = lm >> 1;
    int brow[2], bxor[2];
#pragma unroll
    for (int np = 0; np < 2; np++) {
        brow[np] = nW + (np << 4) + ((lm >> 1) << 3) + lrow;
        bxor[np] = (brow[np] >> 1) & 3;
    }
    int bchk = lm & 1;
    uint32_t sbA = (uint32_t)__cvta_generic_to_shared(As);
    uint32_t sbB = (uint32_t)__cvta_generic_to_shared(Bs);

    for (int kt = 0; kt < KT; kt++) {
        if (kt + 1 < KT) { CP_WAIT1; } else { CP_WAIT0; }
        __syncthreads();
        if (kt + 2 < KT) issue((kt + 2) % 3, kt + 2);
        uint32_t stA = sbA + (kt % 3) * 8192;
        uint32_t stB = sbB + (kt % 3) * 8192;
#pragma unroll
        for (int kk = 0; kk < 2; kk++) {
            uint32_t af[4][4], bf[4][2];
#pragma unroll
            for (int mi = 0; mi < 4; mi++) {
                uint32_t au = (uint32_t)(arow[mi] << 4) + ((((kk << 1) + achk) ^ axor[mi]) << 2);
                ldsm4(af[mi], stA + (au << 2));
            }
#pragma unroll
            for (int np = 0; np < 2; np++) {
                uint32_t bu = (uint32_t)(brow[np] << 4) + ((((kk << 1) + bchk) ^ bxor[np]) << 2);
                uint32_t r4[4];
                ldsm4(r4, stB + (bu << 2));
                bf[np * 2][0] = r4[0]; bf[np * 2][1] = r4[1];
                bf[np * 2 + 1][0] = r4[2]; bf[np * 2 + 1][1] = r4[3];
            }
#pragma unroll
            for (int mi = 0; mi < 4; mi++)
#pragma unroll
                for (int ni = 0; ni < 4; ni++) mma16(acc[mi][ni], af[mi], bf[ni]);
        }
    }
#pragma unroll
    for (int mi = 0; mi < 4; mi++) {
#pragma unroll
        for (int half = 0; half < 2; half++) {
            int gm = mBase + mW + (mi << 4) + (lane >> 2) + half * 8;
            if (gm >= M) continue;
#pragma unroll
            for (int ni = 0; ni < 4; ni++) {
                int gn = nBase + nW + (ni << 3) + ((lane & 3) << 1);
                if (gn + 1 >= N) continue;
                float v0 = acc[mi][ni][half * 2], v1 = acc[mi][ni][half * 2 + 1];
                if (mode & 1) {
                    __half* crow = (__half*)Cm + (size_t)gm * ldc;
                    *(uint32_t*)(crow + gn) = pk2(v0, v1);
                } else {
                    float* crow = (float*)Cm + (size_t)gm * ldc;
                    crow[gn] = v0;
                    crow[gn + 1] = v1;
                }
            }
        }
    }
}

// ---------------- ELITE K/V select ----------------
__global__ void kv_select_k(const int* __restrict__ lidx) {
    int idx = blockIdx.x * 256 + threadIdx.x;
    const int tot = NSTR * NCTX * CHN / 2;
    if (idx >= tot) return;
    int st = idx / (NCTX * CHN / 2);
    if (lidx[st] >= 0) {
        ((uint32_t*)g_k)[NCTX * CHN / 2 + idx] = ((const uint32_t*)g_kg)[idx];
        ((uint32_t*)g_v)[NCTX * CHN / 2 + idx] = ((const uint32_t*)g_vg)[idx];
    }
}

// ============ fused global attention (fp16, 2 CTAs/SM) ============
__global__ void __launch_bounds__(256, 2) fused_g_k(const int* __restrict__ lidx) {
    extern __shared__ __align__(16) uint32_t smu[];
    uint32_t* qb  = smu;
    uint32_t* kb  = smu + 4096;
    uint32_t* psm = smu + 8192;
    uint32_t* vsm = psm + 128 * PSTU;
    float* smx = (float*)(vsm + 160 * PSTU);
    float* ssu = smx + 256;
    __shared__ int sidx[8];

    int bh = blockIdx.y;
    int stream = bh >> 3, h = bh & 7;
    int q0 = blockIdx.x << 7;
    int tid = threadIdx.x, lane = tid & 31, warp = tid >> 5;
    if (tid < 8) sidx[tid] = lidx[tid];

    const __half* Qb = g_q2 + (stream ? (size_t)SQ * CHN : 0) + (size_t)q0 * CHN + h * HD;
    const __half* Kb = g_k + (size_t)stream * NCTX * CHN + h * HD;
    const __half* Vt = g_vT + (size_t)stream * CHN * NCTXP + (size_t)h * HD * NCTXP;

    for (int u = tid; u < 160 * 10; u += 256) {
        int d = u / 10, c = u % 10;
        cp16(vsm + d * PSTU + c * 4, Vt + (size_t)d * NCTXP + c * 8, true);
    }
    CP_COMMIT;

    auto issueQK = [&](int st, int kt) {
        int k0 = kt << 5;
#pragma unroll
        for (int i = 0; i < 2; i++) {
            int idx = tid + (i << 8);
            int r = idx >> 2, cu = (idx & 3) << 2;
            cp16(&qb[st * 2048 + SWOFF(r, cu)], Qb + (size_t)r * CHN + k0 + (cu << 1), true);
            int kr = (r < NCTX) ? r : (NCTX - 1);
            cp16(&kb[st * 2048 + SWOFF(r, cu)], Kb + (size_t)kr * CHN + k0 + (cu << 1), true);
        }
        CP_COMMIT;
    };
    issueQK(0, 0);

    int mW = (warp >> 1) << 5;
    int nWs = (warp & 1) * 40;
    float sc[2][5][4];
#pragma unroll
    for (int a = 0; a < 2; a++)
#pragma unroll
        for (int b = 0; b < 5; b++)
#pragma unroll
            for (int c = 0; c < 4; c++) sc[a][b][c] = 0.f;

    for (int kt = 0; kt < 5; kt++) {
        if (kt < 4) { issueQK((kt + 1) & 1, kt + 1); CP_WAIT1; }
        else        { CP_WAIT0; }
        __syncthreads();
        const uint32_t* pQ = qb + (kt & 1) * 2048;
        const uint32_t* pK = kb + (kt & 1) * 2048;
#pragma unroll
        for (int kk = 0; kk < 2; kk++) {
            int ck = (kk << 3) + (lane & 3);
            uint32_t af[2][4], bf[5][2];
#pragma unroll
            for (int mi = 0; mi < 2; mi++) {
                int r0 = mW + (mi << 4) + (lane >> 2);
                af[mi][0] = pQ[SWOFF(r0, ck)];
                af[mi][1] = pQ[SWOFF(r0 + 8, ck)];
                af[mi][2] = pQ[SWOFF(r0, ck + 4)];
                af[mi][3] = pQ[SWOFF(r0 + 8, ck + 4)];
            }
#pragma unroll
            for (int ni = 0; ni < 5; ni++) {
                int r0 = nWs + (ni << 3) + (lane >> 2);
                bf[ni][0] = pK[SWOFF(r0, ck)];
                bf[ni][1] = pK[SWOFF(r0, ck + 4)];
            }
#pragma unroll
            for (int mi = 0; mi < 2; mi++)
#pragma unroll
                for (int ni = 0; ni < 5; ni++) mma16(sc[mi][ni], af[mi], bf[ni]);
        }
        __syncthreads();
    }

    const float scale = 0.07905694150420949f;
    int half = warp & 1;
#pragma unroll
    for (int mi = 0; mi < 2; mi++)
#pragma unroll
        for (int hf = 0; hf < 2; hf++) {
            int row = mW + mi * 16 + (lane >> 2) + hf * 8;
            float mx = -1e30f;
#pragma unroll
            for (int ni = 0; ni < 5; ni++)
#pragma unroll
                for (int c = 0; c < 2; c++) {
                    int col = nWs + ni * 8 + ((lane & 3) << 1) + c;
                    if (col < NCTX) mx = fmaxf(mx, sc[mi][ni][hf * 2 + c]);
                }
            mx = fmaxf(mx, __shfl_xor_sync(0xffffffffu, mx, 1));
            mx = fmaxf(mx, __shfl_xor_sync(0xffffffffu, mx, 2));
            if ((lane & 3) == 0) smx[half * 128 + row] = mx;
        }
    __syncthreads();
#pragma unroll
    for (int mi = 0; mi < 2; mi++)
#pragma unroll
        for (int hf = 0; hf < 2; hf++) {
            int row = mW + mi * 16 + (lane >> 2) + hf * 8;
            float m = fmaxf(smx[row], smx[128 + row]);
            float s = 0.f;
#pragma unroll
            for (int ni = 0; ni < 5; ni++)
#pragma unroll
                for (int c = 0; c < 2; c++) {
                    int col = nWs + ni * 8 + ((lane & 3) << 1) + c;
                    float e = (col < NCTX) ? __expf((sc[mi][ni][hf * 2 + c] - m) * scale) : 0.f;
                    sc[mi][ni][hf * 2 + c] = e;
                    s += e;
                }
            s += __shfl_xor_sync(0xffffffffu, s, 1);
            s += __shfl_xor_sync(0xffffffffu, s, 2);
            if ((lane & 3) == 0) ssu[half * 128 + row] = s;
        }
    __syncthreads();
#pragma unroll
    for (int mi = 0; mi < 2; mi++)
#pragma unroll
        for (int hf = 0; hf < 2; hf++) {
            int row = mW + mi * 16 + (lane >> 2) + hf * 8;
            float inv = 1.f / (ssu[row] + ssu[128 + row]);
#pragma unroll
            for (int ni = 0; ni < 5; ni++) {
                int col = nWs + ni * 8 + ((lane & 3) << 1);
                float v0 = (col < NCTX) ? sc[mi][ni][hf * 2] * inv : 0.f;
                float v1 = (col + 1 < NCTX) ? sc[mi][ni][hf * 2 + 1] * inv : 0.f;
                psm[row * PSTU + (nWs >> 1) + ni * 4 + (lane & 3)] = pk2(v0, v1);
            }
        }
    __syncthreads();

    if (stream == 0) {
        const __half* ph = (const __half*)psm;
        for (int u = tid; u < 128 * 8; u += 256) {
            int r = u >> 3, i = u & 7;
            g_mraw[((size_t)i * NHEAD + h) * SQ + q0 + r] =
                __half2float(ph[r * (2 * PSTU) + sidx[i]]);
        }
    }

    int nW = (warp & 1) * 80;
    float oa[2][10][4];
#pragma unroll
    for (int a = 0; a < 2; a++)
#pragma unroll
        for (int b = 0; b < 10; b++)
#pragma unroll
            for (int c = 0; c < 4; c++) oa[a][b][c] = 0.f;
#pragma unroll
    for (int kst = 0; kst < 5; kst++) {
        int ka = kst * 8 + (lane & 3);
        uint32_t af[2][4], bf[10][2];
#pragma unroll
        for (int mi = 0; mi < 2; mi++) {
            int r0 = mW + (mi << 4) + (lane >> 2);
            af[mi][0] = psm[r0 * PSTU + ka];
            af[mi][1] = psm[(r0 + 8) * PSTU + ka];
            af[mi][2] = psm[r0 * PSTU + ka + 4];
            af[mi][3] = psm[(r0 + 8) * PSTU + ka + 4];
        }
#pragma unroll
        for (int ni = 0; ni < 10; ni++) {
            int d = nW + (ni << 3) + (lane >> 2);
            bf[ni][0] = vsm[d * PSTU + ka];
            bf[ni][1] = vsm[d * PSTU + ka + 4];
        }
#pragma unroll
        for (int mi = 0; mi < 2; mi++)
#pragma unroll
            for (int ni = 0; ni < 10; ni++) mma16(oa[mi][ni], af[mi], bf[ni]);
    }
#pragma unroll
    for (int mi = 0; mi < 2; mi++)
#pragma unroll
        for (int hf = 0; hf < 2; hf++) {
            int g = q0 + mW + mi * 16 + (lane >> 2) + hf * 8;
            __half* orow = g_pre + ((size_t)stream * SQ + g) * CHN + h * HD;
#pragma unroll
            for (int ni = 0; ni < 10; ni++) {
                int col = nW + (ni << 3) + ((lane & 3) << 1);
                *(uint32_t*)(orow + col) = pk2(oa[mi][ni][hf * 2], oa[mi][ni][hf * 2 + 1]);
            }
        }
}

// ---------------- per-instance gate max ----------------
__global__ void mmax_k() {
    __shared__ float red[256];
    int i = blockIdx.x;
    float mx = 0.f;
    const float* p = g_mraw + (size_t)i * NHEAD * SQ;
    for (int idx = threadIdx.x; idx < NHEAD * SQ; idx += 256) mx = fmaxf(mx, p[idx]);
    red[threadIdx.x] = mx;
    __syncthreads();
    for (int s = 128; s > 0; s >>= 1) {
        if (threadIdx.x < s) red[threadIdx.x] = fmaxf(red[threadIdx.x], red[threadIdx.x + s]);
        __syncthreads();
    }
    if (threadIdx.x == 0) g_mmax[i] = red[0];
}

// ============ fully fused local attention (R9, proven) ============
__global__ void __launch_bounds__(256) fused_l2_k() {
    extern __shared__ __align__(16) uint32_t smu[];
    uint32_t* plm = smu;
    uint32_t* vsm = smu + 64 * PLU;
    float* smx = (float*)(smu + 64 * PLU + 160 * VLU);
    float* ssu = smx + 256;

    int z = blockIdx.y;
    int inst = z >> 3, h = z & 7;
    int q0 = blockIdx.x << 6;
    int tid = threadIdx.x, lane = tid & 31, warp = tid >> 5;

    const __half* Qb  = g_q2 + (size_t)SQ * CHN + (size_t)q0 * CHN + h * HD;
    const __half* Klb = g_kl + (size_t)inst * LLOC * CHN + h * HD;
    const __half* Vt  = g_vlT + (size_t)inst * CHN * LLOCP + (size_t)h * HD * LLOCP;

    uint32_t* strm = vsm;
    auto issueQK = [&](int st, int kt) {
        int k0 = kt << 5;
        uint32_t* base = strm + st * 5632;
        {
            int r = tid >> 2, cu = (tid & 3) << 2;
            cp16(base + SWOFF(r, cu), Qb + (size_t)r * CHN + k0 + (cu << 1), true);
        }
        for (int u = tid; u < 1152; u += 256) {
            int r = u >> 2, cu = (u & 3) << 2;
            int kr = (r < LLOC) ? r : (LLOC - 1);
            cp16(base + 1024 + SWOFF(r, cu), Klb + (size_t)kr * CHN + k0 + (cu << 1), true);
        }
        CP_COMMIT;
    };
    issueQK(0, 0);

    int mW2 = (warp >> 2) << 5;
    int nW4 = (warp & 3) * 72;
    float sc[2][9][4];
#pragma unroll
    for (int a = 0; a < 2; a++)
#pragma unroll
        for (int b = 0; b < 9; b++)
#pragma unroll
            for (int c = 0; c < 4; c++) sc[a][b][c] = 0.f;

    for (int kt = 0; kt < 5; kt++) {
        if (kt < 4) { issueQK((kt + 1) & 1, kt + 1); CP_WAIT1; }
        else        { CP_WAIT0; }
        __syncthreads();
        const uint32_t* pQ = strm + (kt & 1) * 5632;
        const uint32_t* pK = pQ + 1024;
#pragma unroll
        for (int kk = 0; kk < 2; kk++) {
            int ck = (kk << 3) + (lane & 3);
            uint32_t af[2][4], bf[9][2];
#pragma unroll
            for (int mi = 0; mi < 2; mi++) {
                int r0 = mW2 + (mi << 4) + (lane >> 2);
                af[mi][0] = pQ[SWOFF(r0, ck)];
                af[mi][1] = pQ[SWOFF(r0 + 8, ck)];
                af[mi][2] = pQ[SWOFF(r0, ck + 4)];
                af[mi][3] = pQ[SWOFF(r0 + 8, ck + 4)];
            }
#pragma unroll
            for (int ni = 0; ni < 9; ni++) {
                int r0 = nW4 + (ni << 3) + (lane >> 2);
                bf[ni][0] = pK[SWOFF(r0, ck)];
                bf[ni][1] = pK[SWOFF(r0, ck + 4)];
            }
#pragma unroll
            for (int mi = 0; mi < 2; mi++)
#pragma unroll
                for (int ni = 0; ni < 9; ni++) mma16(sc[mi][ni], af[mi], bf[ni]);
        }
        __syncthreads();
    }

    for (int u = tid; u < 160 * 34; u += 256) {
        int d = u / 34, c = u % 34;
        cp16(vsm + d * VLU + c * 4, Vt + (size_t)d * LLOCP + c * 8, true);
    }
    CP_COMMIT;

    const float scale = 0.07905694150420949f;
    float gden = 0.5f / g_mmax[inst];
#pragma unroll
    for (int mi = 0; mi < 2; mi++)
#pragma unroll
        for (int hf = 0; hf < 2; hf++) {
            int row = mW2 + mi * 16 + (lane >> 2) + hf * 8;
            float mx = -1e30f;
#pragma unroll
            for (int ni = 0; ni < 9; ni++)
#pragma unroll
                for (int c = 0; c < 2; c++) {
                    int col = nW4 + ni * 8 + ((lane & 3) << 1) + c;
                    if (col < LLOC) mx = fmaxf(mx, sc[mi][ni][hf * 2 + c]);
                }
            mx = fmaxf(mx, __shfl_xor_sync(0xffffffffu, mx, 1));
            mx = fmaxf(mx, __shfl_xor_sync(0xffffffffu, mx, 2));
            if ((lane & 3) == 0) smx[row * 4 + (warp & 3)] = mx;
        }
    __syncthreads();
#pragma unroll
    for (int mi = 0; mi < 2; mi++)
#pragma unroll
        for (int hf = 0; hf < 2; hf++) {
            int row = mW2 + mi * 16 + (lane >> 2) + hf * 8;
            float m = fmaxf(fmaxf(smx[row * 4], smx[row * 4 + 1]),
                            fmaxf(smx[row * 4 + 2], smx[row * 4 + 3]));
            float s = 0.f;
#pragma unroll
            for (int ni = 0; ni < 9; ni++)
#pragma unroll
                for (int c = 0; c < 2; c++) {
                    int col = nW4 + ni * 8 + ((lane & 3) << 1) + c;
                    float e = (col < LLOC) ? __expf((sc[mi][ni][hf * 2 + c] - m) * scale) : 0.f;
                    sc[mi][ni][hf * 2 + c] = e;
                    s += e;
                }
            s += __shfl_xor_sync(0xffffffffu, s, 1);
            s += __shfl_xor_sync(0xffffffffu, s, 2);
            if ((lane & 3) == 0) ssu[row * 4 + (warp & 3)] = s;
        }
    __syncthreads();
#pragma unroll
    for (int mi = 0; mi < 2; mi++)
#pragma unroll
        for (int hf = 0; hf < 2; hf++) {
            int row = mW2 + mi * 16 + (lane >> 2) + hf * 8;
            float s = ssu[row * 4] + ssu[row * 4 + 1] + ssu[row * 4 + 2] + ssu[row * 4 + 3];
            float f = g_mraw[(size_t)z * SQ + q0 + row] * gden / s;
#pragma unroll
            for (int ni = 0; ni < 9; ni++) {
                int ucol = (nW4 >> 1) + ni * 4 + (lane & 3);
                if (ucol < 136)
                    plm[row * PLU + ucol] = pk2(sc[mi][ni][hf * 2] * f, sc[mi][ni][hf * 2 + 1] * f);
            }
        }
    CP_WAIT0;
    __syncthreads();

    int nW = (warp & 3) * 40;
    float oa[2][5][4];
#pragma unroll
    for (int a = 0; a < 2; a++)
#pragma unroll
        for (int b = 0; b < 5; b++)
#pragma unroll
            for (int c = 0; c < 4; c++) oa[a][b][c] = 0.f;

#pragma unroll 1
    for (int ch = 0; ch < 17; ch++) {
        int ka = ch * 8 + (lane & 3);
        uint32_t af[2][4], bf[5][2];
#pragma unroll
        for (int mi = 0; mi < 2; mi++) {
            int r0 = mW2 + (mi << 4) + (lane >> 2);
            af[mi][0] = plm[r0 * PLU + ka];
            af[mi][1] = plm[(r0 + 8) * PLU + ka];
            af[mi][2] = plm[r0 * PLU + ka + 4];
            af[mi][3] = plm[(r0 + 8) * PLU + ka + 4];
        }
#pragma unroll
        for (int ni = 0; ni < 5; ni++) {
            int d = nW + (ni << 3) + (lane >> 2);
            bf[ni][0] = vsm[d * VLU + ka];
            bf[ni][1] = vsm[d * VLU + ka + 4];
        }
#pragma unroll
        for (int mi = 0; mi < 2; mi++)
#pragma unroll
            for (int ni = 0; ni < 5; ni++) mma16(oa[mi][ni], af[mi], bf[ni]);
    }

#pragma unroll
    for (int mi = 0; mi < 2; mi++)
#pragma unroll
        for (int hf = 0; hf < 2; hf++) {
            int g = q0 + mW2 + mi * 16 + (lane >> 2) + hf * 8;
            __half* prow = g_pre + ((size_t)(inst + 1) * SQ + g) * CHN + h * HD;
#pragma unroll
            for (int ni = 0; ni < 5; ni++) {
                int col = nW + (ni << 3) + ((lane & 3) << 1);
                __half2 old = *(__half2*)(prow + col);
                float o0 = 0.5f * __half2float(old.x) + oa[mi][ni][hf * 2];
                float o1 = 0.5f * __half2float(old.y) + oa[mi][ni][hf * 2 + 1];
                *(uint32_t*)(prow + col) = pk2(o0, o1);
            }
        }
}

// ---------------- fuser premix ----------------
__global__ void premix_k(const float* __restrict__ bbox) {
    int s = blockIdx.x;
    int y = s >> 6, x = s & 63;
    float wgt[8];
    wgt[0] = 1.f;
    float sw = 1.f;
    const int off[4] = {3, 4, 11, 12};
#pragma unroll
    for (int i = 0; i < 7; i++) {
        float wmin = floorf(1024.f * bbox[i * 4 + 0]);
        float hmin = floorf(1024.f * bbox[i * 4 + 1]);
        float wmax = floorf(1024.f * bbox[i * 4 + 2]);
        float hmax = floorf(1024.f * bbox[i * 4 + 3]);
        float R = 0.f, Cv = 0.f;
#pragma unroll
        for (int j = 0; j < 4; j++) {
            float yy = (float)(16 * y + off[j]);
            float xx = (float)(16 * x + off[j]);
            if (yy >= hmin && yy < hmax) R += 0.25f;
            if (xx >= wmin && xx < wmax) Cv += 0.25f;
        }
        float g = 10.f * R * Cv;
        wgt[i + 1] = g;
        sw += g;
    }
    if (threadIdx.x == 0) g_sumw[s] = sw;
    for (int c = threadIdx.x; c < CHN; c += 256) {
        float acc = 0.f;
#pragma unroll
        for (int j = 0; j < 8; j++)
            acc += wgt[j] * __half2float(g_pre[((size_t)(1 + j) * SQ + s) * CHN + c]);
        g_mix[(size_t)s * CHN + c] = __float2half_rn(acc);
    }
}

// ---------------- final ----------------
__global__ void final_k(const float* __restrict__ bout, float* __restrict__ out) {
    int s = blockIdx.x;
    float sw = g_sumw[s];
    float den = 1.f / (sw + 1e-6f);
    for (int c = threadIdx.x; c < CHN; c += 256) {
        float b = bout[c];
        out[(size_t)s * CHN + c] = g_out2[(size_t)s * CHN + c] + b;
        out[(size_t)(SQ + s) * CHN + c] = (g_out2[(size_t)(SQ + s) * CHN + c] + b * sw) * den;
    }
}

// ---------------- launch ----------------
extern "C" void kernel_launch(void* const* d_in, const int* in_sizes, int n_in,
                              void* d_out, int out_size) {
    const float* hs   = (const float*)d_in[0];
    const float* ctx  = (const float*)d_in[1];
    const float* lf   = (const float*)d_in[2];
    const float* bbox = (const float*)d_in[3];
    const float* Wq   = (const float*)d_in[4];
    const float* Wk   = (const float*)d_in[5];
    const float* Wv   = (const float*)d_in[6];
    const float* Wkg  = (const float*)d_in[7];
    const float* Wvg  = (const float*)d_in[8];
    const float* Wkl  = (const float*)d_in[9];
    const float* Wvl  = (const float*)d_in[10];
    const float* Wout = (const float*)d_in[11];
    const float* bout = (const float*)d_in[12];
    const int*   lidx = (const int*)d_in[13];
    float* out = (float*)d_out;

    __half *hsH, *ctxH, *lfH, *WqT, *WkT, *WvT, *WkgT, *WvgT, *WklT, *WvlT, *WoutT;
    __half *vp, *vTp, *vlp, *vlTp;
    cudaGetSymbolAddress((void**)&hsH, g_hsH);
    cudaGetSymbolAddress((void**)&ctxH, g_ctxH);
    cudaGetSymbolAddress((void**)&lfH, g_lfH);
    cudaGetSymbolAddress((void**)&WqT, g_WqT);
    cudaGetSymbolAddress((void**)&WkT, g_WkT);
    cudaGetSymbolAddress((void**)&WvT, g_WvT);
    cudaGetSymbolAddress((void**)&WkgT, g_WkgT);
    cudaGetSymbolAddress((void**)&WvgT, g_WvgT);
    cudaGetSymbolAddress((void**)&WklT, g_WklT);
    cudaGetSymbolAddress((void**)&WvlT, g_WvlT);
    cudaGetSymbolAddress((void**)&WoutT, g_WoutT);
    cudaGetSymbolAddress((void**)&vp, g_v);
    cudaGetSymbolAddress((void**)&vTp, g_vT);
    cudaGetSymbolAddress((void**)&vlp, g_vl);
    cudaGetSymbolAddress((void**)&vlTp, g_vlT);

    const int smemA = (2 * 2048 * 2 + 128 * PSTU + 160 * PSTU + 512) * 4;
    const int smemL = (64 * PLU + 160 * VLU + 512) * 4;
    cudaFuncSetAttribute(fused_g_k, cudaFuncAttributeMaxDynamicSharedMemorySize, smemA);
    cudaFuncSetAttribute(fused_l2_k, cudaFuncAttributeMaxDynamicSharedMemorySize, smemL);
    cudaFuncSetAttribute(gemm_h, cudaFuncAttributeMaxDynamicSharedMemorySize, SMEM3);

    cudaStream_t sA = g_si.sA, sB = g_si.sB, sC = g_si.sC;
    dim3 tb(32, 8);

    // root
    setup_k<<<1, 32>>>();
    cudaEventRecord(g_si.evRoot, 0);
    cudaStreamWaitEvent(sA, g_si.evRoot, 0);
    cudaStreamWaitEvent(sB, g_si.evRoot, 0);
    cudaStreamWaitEvent(sC, g_si.evRoot, 0);

    long long nHs = 2LL * SQ * CHN, nCtx = (long long)NST * NCTX * CC, nLf = (long long)NSTR * LLOC * CC;

    // main track: hs -> WqT -> Q projection
    round_h<<<(int)((nHs / 8 + 255) / 256), 256>>>(hs, hsH, nHs);
    transpose_k<float><<<dim3(40, 40, 1), tb>>>(Wq, WqT, CHN, CHN, CHN, CHN, 0, 0);
    gemm_h<<<dim3(10, 64, 1), 256, SMEM3>>>(0, CHN, CHN, CHN, CHN, CHN, 1);

    // track A: ctx -> K/V/Kg/Vg -> select -> vT
    round_h<<<(int)((nCtx / 8 + 255) / 256), 256, 0, sA>>>(ctx, ctxH, nCtx);
    transpose_k<float><<<dim3(40, 24, 1), tb, 0, sA>>>(Wk, WkT, CC, CHN, CHN, CC, 0, 0);
    transpose_k<float><<<dim3(40, 24, 1), tb, 0, sA>>>(Wv, WvT, CC, CHN, CHN, CC, 0, 0);
    transpose_k<float><<<dim3(40, 24, 1), tb, 0, sA>>>(Wkg, WkgT, CC, CHN, CHN, CC, 0, 0);
    transpose_k<float><<<dim3(40, 24, 1), tb, 0, sA>>>(Wvg, WvgT, CC, CHN, CHN, CC, 0, 0);
    gemm_h<<<dim3(10, 6, 4), 256, SMEM3, sA>>>(1, CHN, CC, CC, CC, CHN, 1);
    kv_select_k<<<(NSTR * NCTX * CHN / 2 + 255) / 256, 256, 0, sA>>>(lidx);
    transpose_k<__half><<<dim3(40, 3, NST), tb, 0, sA>>>(vp, vTp, NCTX, CHN, CHN, NCTXP,
                                                         (long long)NCTX * CHN, (long long)CHN * NCTXP);
    cudaEventRecord(g_si.ev1, sA);

    // track B: lf -> Kl/Vl -> vlT
    round_h<<<(int)((nLf / 8 + 255) / 256), 256, 0, sB>>>(lf, lfH, nLf);
    transpose_k<float><<<dim3(40, 24, 1), tb, 0, sB>>>(Wkl, WklT, CC, CHN, CHN, CC, 0, 0);
    transpose_k<float><<<dim3(40, 24, 1), tb, 0, sB>>>(Wvl, WvlT, CC, CHN, CHN, CC, 0, 0);
    gemm_h<<<dim3(10, 17, 2), 256, SMEM3, sB>>>(5, CHN, CC, CC, CC, CHN, 1);
    transpose_k<__half><<<dim3(40, 9, NSTR), tb, 0, sB>>>(vlp, vlTp, LLOC, CHN, CHN, LLOCP,
                                                          (long long)LLOC * CHN, (long long)CHN * LLOCP);
    cudaEventRecord(g_si.ev2, sB);

    // track C: Wout transpose
    transpose_k<float><<<dim3(40, 40, 1), tb, 0, sC>>>(Wout, WoutT, CHN, CHN, CHN, CHN, 0, 0);
    cudaEventRecord(g_si.ev3, sC);

    // fused global attention (needs Q [main] + K/vT [A])
    cudaStreamWaitEvent(0, g_si.ev1, 0);
    fused_g_k<<<dim3(32, 72), 256, smemA>>>(lidx);
    mmax_k<<<8, 256>>>();
    cudaEventRecord(g_si.evG, 0);

    // out-projection for uncond stream: depends only on fused_g + WoutT.
    // Runs on stream A concurrently with local attention below.
    cudaStreamWaitEvent(sA, g_si.evG, 0);
    cudaStreamWaitEvent(sA, g_si.ev3, 0);
    gemm_h<<<dim3(10, 32, 1), 256, SMEM3, sA>>>(7, CHN, CHN, CHN, CHN, CHN, 0);
    cudaEventRecord(g_si.evO7, sA);

    // local attention (needs Kl/vlT [B] + mraw/mmax [main])
    cudaStreamWaitEvent(0, g_si.ev2, 0);
    fused_l2_k<<<dim3(64, 64), 256, smemL>>>();

    // fuser premix + cond out-projection
    premix_k<<<SQ, 256>>>(bbox);
    cudaStreamWaitEvent(0, g_si.ev3, 0);
    gemm_h<<<dim3(10, 32, 1), 256, SMEM3>>>(8, CHN, CHN, CHN, CHN, CHN, 0);
    cudaStreamWaitEvent(0, g_si.evO7, 0);
    final_k<<<SQ, 256>>>(bout, out);
}

// round 11
// speedup vs baseline: 2.7031x; 1.0231x over previous
#include <cuda_runtime.h>
#include <cuda_fp16.h>
#include <math.h>
#include <stdint.h>

#define SQ 4096
#define CHN 1280
#define CC 768
#define NHEAD 8
#define HD 160
#define NCTX 77
#define NCTXP 80
#define NST 9
#define NSTR 8
#define LLOC 257
#define LLOCP 272
#define PSTU 44
#define PLU 140
#define VLU 140
#define SMEM3 (3 * 2048 * 2 * 4)

// ---------------- scratch ----------------
__device__ __align__(256) __half g_hsH[2 * SQ * CHN];
__device__ __align__(256) __half g_ctxH[NST * NCTX * CC];
__device__ __align__(256) __half g_lfH[NSTR * LLOC * CC];
__device__ __align__(256) __half g_q2[2 * SQ * CHN];
__device__ __align__(256) __half g_k[NST * NCTX * CHN];
__device__ __align__(256) __half g_v[NST * NCTX * CHN];
__device__ __align__(256) __half g_kg[NSTR * NCTX * CHN];
__device__ __align__(256) __half g_vg[NSTR * NCTX * CHN];
__device__ __align__(256) __half g_kl[NSTR * LLOC * CHN];
__device__ __align__(256) __half g_vl[NSTR * LLOC * CHN];
__device__ __align__(256) __half g_WqT[CHN * CHN];
__device__ __align__(256) __half g_WkT[CHN * CC];
__device__ __align__(256) __half g_WvT[CHN * CC];
__device__ __align__(256) __half g_WkgT[CHN * CC];
__device__ __align__(256) __half g_WvgT[CHN * CC];
__device__ __align__(256) __half g_WklT[CHN * CC];
__device__ __align__(256) __half g_WvlT[CHN * CC];
__device__ __align__(256) __half g_WoutT[CHN * CHN];
__device__ __align__(256) __half g_vT[NST * CHN * NCTXP];
__device__ __align__(256) __half g_vlT[NSTR * CHN * LLOCP];
__device__ __align__(256) __half g_pre[NST * SQ * CHN];
__device__ __align__(256) __half g_mix[SQ * CHN];
__device__ __align__(256) float g_out2[2 * SQ * CHN];
__device__ float g_mraw[NSTR * NHEAD * SQ];
__device__ float g_mmax[NSTR];
__device__ float g_sumw[SQ];

__device__ const __half* d_Ap[16];
__device__ const __half* d_Bp[16];
__device__ void*         d_Cp[16];
__device__ int           d_Mt[16];

// ---------------- streams/events ----------------
struct StreamInit {
    cudaStream_t sA, sB, sC;
    cudaEvent_t evRoot, ev1, ev2, ev3, evG, evO7;
    StreamInit() {
        cudaStreamCreateWithFlags(&sA, cudaStreamNonBlocking);
        cudaStreamCreateWithFlags(&sB, cudaStreamNonBlocking);
        cudaStreamCreateWithFlags(&sC, cudaStreamNonBlocking);
        cudaEventCreateWithFlags(&evRoot, cudaEventDisableTiming);
        cudaEventCreateWithFlags(&ev1, cudaEventDisableTiming);
        cudaEventCreateWithFlags(&ev2, cudaEventDisableTiming);
        cudaEventCreateWithFlags(&ev3, cudaEventDisableTiming);
        cudaEventCreateWithFlags(&evG, cudaEventDisableTiming);
        cudaEventCreateWithFlags(&evO7, cudaEventDisableTiming);
    }
};
static StreamInit g_si;

// ---------------- helpers ----------------
__device__ __forceinline__ uint32_t pk2(float a, float b) {
    __half2 h = __halves2half2(__float2half_rn(a), __float2half_rn(b));
    return *(uint32_t*)&h;
}
__device__ __forceinline__ void cp16(void* sdst, const void* gsrc, bool p) {
    uint32_t sa = (uint32_t)__cvta_generic_to_shared(sdst);
    int sz = p ? 16 : 0;
    asm volatile("cp.async.cg.shared.global [%0], [%1], 16, %2;" :: "r"(sa), "l"(gsrc), "r"(sz));
}
#define CP_COMMIT asm volatile("cp.async.commit_group;")
#define CP_WAIT0 asm volatile("cp.async.wait_group 0;")
#define CP_WAIT1 asm volatile("cp.async.wait_group 1;")
__device__ __forceinline__ void mma16(float* c, const uint32_t* a, const uint32_t* b) {
    asm volatile(
        "mma.sync.aligned.m16n8k16.row.col.f32.f16.f16.f32 "
        "{%0,%1,%2,%3}, {%4,%5,%6,%7}, {%8,%9}, {%0,%1,%2,%3};"
        : "+f"(c[0]), "+f"(c[1]), "+f"(c[2]), "+f"(c[3])
        : "r"(a[0]), "r"(a[1]), "r"(a[2]), "r"(a[3]), "r"(b[0]), "r"(b[1]));
}
__device__ __forceinline__ void ldsm4(uint32_t* r, uint32_t addr) {
    asm volatile("ldmatrix.sync.aligned.m8n8.x4.shared.b16 {%0,%1,%2,%3}, [%4];"
                 : "=r"(r[0]), "=r"(r[1]), "=r"(r[2]), "=r"(r[3]) : "r"(addr));
}
__device__ __forceinline__ void ldsm2(uint32_t* r, uint32_t addr) {
    asm volatile("ldmatrix.sync.aligned.m8n8.x2.shared.b16 {%0,%1}, [%2];"
                 : "=r"(r[0]), "=r"(r[1]) : "r"(addr));
}
#define SWOFF(r, c) (((r) << 4) + ((((((c) >> 2) ^ (((r) >> 1) & 3))) << 2) | ((c) & 3)))

// ---------------- setup ----------------
__global__ void setup_k() {
    if (threadIdx.x == 0) {
        d_Ap[0] = g_hsH;               d_Bp[0] = g_WqT;   d_Cp[0] = g_q2;    d_Mt[0] = 2 * SQ;
        d_Ap[1] = g_ctxH;              d_Bp[1] = g_WkT;   d_Cp[1] = g_k;     d_Mt[1] = NST * NCTX;
        d_Ap[2] = g_ctxH;              d_Bp[2] = g_WvT;   d_Cp[2] = g_v;     d_Mt[2] = NST * NCTX;
        d_Ap[3] = g_ctxH + NCTX * CC;  d_Bp[3] = g_WkgT;  d_Cp[3] = g_kg;    d_Mt[3] = NSTR * NCTX;
        d_Ap[4] = g_ctxH + NCTX * CC;  d_Bp[4] = g_WvgT;  d_Cp[4] = g_vg;    d_Mt[4] = NSTR * NCTX;
        d_Ap[5] = g_lfH;               d_Bp[5] = g_WklT;  d_Cp[5] = g_kl;    d_Mt[5] = NSTR * LLOC;
        d_Ap[6] = g_lfH;               d_Bp[6] = g_WvlT;  d_Cp[6] = g_vl;    d_Mt[6] = NSTR * LLOC;
        d_Ap[7] = g_pre;               d_Bp[7] = g_WoutT; d_Cp[7] = g_out2;  d_Mt[7] = SQ;
        d_Ap[8] = g_mix;               d_Bp[8] = g_WoutT; d_Cp[8] = g_out2 + (size_t)SQ * CHN;
        d_Mt[8] = SQ;
    }
}

// ---------------- round inputs to fp16 ----------------
__global__ void round_h(const float* __restrict__ src, __half* __restrict__ dst, long long n) {
    long long i = ((long long)blockIdx.x * blockDim.x + threadIdx.x) * 8;
    if (i + 7 < n) {
        float4 a = *(const float4*)(src + i);
        float4 b = *(const float4*)(src + i + 4);
        uint4 u;
        u.x = pk2(a.x, a.y); u.y = pk2(a.z, a.w);
        u.z = pk2(b.x, b.y); u.w = pk2(b.z, b.w);
        *(uint4*)(dst + i) = u;
    } else {
        for (long long j = i; j < n; j++) dst[j] = __float2half_rn(src[j]);
    }
}

// ---------------- transpose ----------------
template <typename TS>
__global__ void transpose_k(const TS* __restrict__ src, __half* __restrict__ dst,
                            int R, int C, int ldS, int ldD, long long sBS, long long dBS) {
    __shared__ float t[32][33];
    src += blockIdx.z * sBS;
    dst += blockIdx.z * dBS;
    int c0 = blockIdx.x << 5, r0 = blockIdx.y << 5;
    int tx = threadIdx.x, ty = threadIdx.y;
#pragma unroll
    for (int j = 0; j < 4; j++) {
        int rr = r0 + ty + j * 8, cc = c0 + tx;
        t[ty + j * 8][tx] = (rr < R && cc < C) ? (float)src[(size_t)rr * ldS + cc] : 0.f;
    }
    __syncthreads();
#pragma unroll
    for (int j = 0; j < 4; j++) {
        int cc = c0 + ty + j * 8, rr = r0 + tx;
        if (cc < C && rr < ldD)
            dst[(size_t)cc * ldD + rr] = __float2half_rn(t[tx][ty + j * 8]);
    }
}

// ---------------- batched NT fp16 GEMM (R8, proven) ----------------
__global__ void __launch_bounds__(256, 2) gemm_h(int slot, int N, int K,
                                                 int lda, int ldb, int ldc, int mode) {
    extern __shared__ __align__(16) uint32_t smg[];
    uint32_t* As = smg;
    uint32_t* Bs = smg + 3 * 2048;
    const __half* Ab = d_Ap[slot + blockIdx.z];
    const __half* Bb = d_Bp[slot + blockIdx.z];
    void* Cm         = d_Cp[slot + blockIdx.z];
    const int M      = d_Mt[slot + blockIdx.z];
    int tid = threadIdx.x, lane = tid & 31, warp = tid >> 5;
    int mBase = blockIdx.y << 7, nBase = blockIdx.x << 7;
    int mW = (warp >> 2) << 6, nW = (warp & 3) << 5;
    float acc[4][4][4];
#pragma unroll
    for (int a = 0; a < 4; a++)
#pragma unroll
        for (int b = 0; b < 4; b++)
#pragma unroll
            for (int cI = 0; cI < 4; cI++) acc[a][b][cI] = 0.f;

    int KT = K >> 5;
    auto issue = [&](int st, int kt) {
        int k0 = kt << 5;
#pragma unroll
        for (int i = 0; i < 2; i++) {
            int idx = tid + (i << 8);
            int r = idx >> 2, cu = (idx & 3) << 2;
            int gr = mBase + r; bool pa = gr < M; if (!pa) gr = M - 1;
            cp16(&As[st * 2048 + SWOFF(r, cu)], Ab + (size_t)gr * lda + k0 + (cu << 1), pa);
            int gn = nBase + r; bool pb = gn < N; if (!pb) gn = N - 1;
            cp16(&Bs[st * 2048 + SWOFF(r, cu)], Bb + (size_t)gn * ldb + k0 + (cu << 1), pb);
        }
        CP_COMMIT;
    };
    issue(0, 0);
    issue(1, 1);

    int lrow = lane & 7;
    int lm = lane >> 3;
    int arow[4], axor[4];
#pragma unroll
    for (int mi = 0; mi < 4; mi++) {
        arow[mi] = mW + (mi << 4) + ((lm & 1) << 3) + lrow;
        axor[mi] = (arow[mi] >> 1) & 3;
    }
    int achk = lm >> 1;
    int brow[2], bxor[2];
#pragma unroll
    for (int np = 0; np < 2; np++) {
        brow[np] = nW + (np << 4) + ((lm >> 1) << 3) + lrow;
        bxor[np] = (brow[np] >> 1) & 3;
    }
    int bchk = lm & 1;
    uint32_t sbA = (uint32_t)__cvta_generic_to_shared(As);
    uint32_t sbB = (uint32_t)__cvta_generic_to_shared(Bs);

    for (int kt = 0; kt < KT; kt++) {
        if (kt + 1 < KT) { CP_WAIT1; } else { CP_WAIT0; }
        __syncthreads();
        if (kt + 2 < KT) issue((kt + 2) % 3, kt + 2);
        uint32_t stA = sbA + (kt % 3) * 8192;
        uint32_t stB = sbB + (kt % 3) * 8192;
#pragma unroll
        for (int kk = 0; kk < 2; kk++) {
            uint32_t af[4][4], bf[4][2];
#pragma unroll
            for (int mi = 0; mi < 4; mi++) {
                uint32_t au = (uint32_t)(arow[mi] << 4) + ((((kk << 1) + achk) ^ axor[mi]) << 2);
                ldsm4(af[mi], stA + (au << 2));
            }
#pragma unroll
            for (int np = 0; np < 2; np++) {
                uint32_t bu = (uint32_t)(brow[np] << 4) + ((((kk << 1) + bchk) ^ bxor[np]) << 2);
                uint32_t r4[4];
                ldsm4(r4, stB + (bu << 2));
                bf[np * 2][0] = r4[0]; bf[np * 2][1] = r4[1];
                bf[np * 2 + 1][0] = r4[2]; bf[np * 2 + 1][1] = r4[3];
            }
#pragma unroll
            for (int mi = 0; mi < 4; mi++)
#pragma unroll
                for (int ni = 0; ni < 4; ni++) mma16(acc[mi][ni], af[mi], bf[ni]);
        }
    }
#pragma unroll
    for (int mi = 0; mi < 4; mi++) {
#pragma unroll
        for (int half = 0; half < 2; half++) {
            int gm = mBase + mW + (mi << 4) + (lane >> 2) + half * 8;
            if (gm >= M) continue;
#pragma unroll
            for (int ni = 0; ni < 4; ni++) {
                int gn = nBase + nW + (ni << 3) + ((lane & 3) << 1);
                if (gn + 1 >= N) continue;
                float v0 = acc[mi][ni][half * 2], v1 = acc[mi][ni][half * 2 + 1];
                if (mode & 1) {
                    __half* crow = (__half*)Cm + (size_t)gm * ldc;
                    *(uint32_t*)(crow + gn) = pk2(v0, v1);
                } else {
                    float* crow = (float*)Cm + (size_t)gm * ldc;
                    crow[gn] = v0;
                    crow[gn + 1] = v1;
                }
            }
        }
    }
}

// ---------------- ELITE K/V select ----------------
__global__ void kv_select_k(const int* __restrict__ lidx) {
    int idx = blockIdx.x * 256 + threadIdx.x;
    const int tot = NSTR * NCTX * CHN / 2;
    if (idx >= tot) return;
    int st = idx / (NCTX * CHN / 2);
    if (lidx[st] >= 0) {
        ((uint32_t*)g_k)[NCTX * CHN / 2 + idx] = ((const uint32_t*)g_kg)[idx];
        ((uint32_t*)g_v)[NCTX * CHN / 2 + idx] = ((const uint32_t*)g_vg)[idx];
    }
}

// ============ fused global attention (fp16, 2 CTAs/SM, LDSM) ============
__global__ void __launch_bounds__(256, 2) fused_g_k(const int* __restrict__ lidx) {
    extern __shared__ __align__(16) uint32_t smu[];
    uint32_t* qb  = smu;
    uint32_t* kb  = smu + 4096;
    uint32_t* psm = smu + 8192;
    uint32_t* vsm = psm + 128 * PSTU;
    float* smx = (float*)(vsm + 160 * PSTU);
    float* ssu = smx + 256;
    __shared__ int sidx[8];

    int bh = blockIdx.y;
    int stream = bh >> 3, h = bh & 7;
    int q0 = blockIdx.x << 7;
    int tid = threadIdx.x, lane = tid & 31, warp = tid >> 5;
    if (tid < 8) sidx[tid] = lidx[tid];

    const __half* Qb = g_q2 + (stream ? (size_t)SQ * CHN : 0) + (size_t)q0 * CHN + h * HD;
    const __half* Kb = g_k + (size_t)stream * NCTX * CHN + h * HD;
    const __half* Vt = g_vT + (size_t)stream * CHN * NCTXP + (size_t)h * HD * NCTXP;

    for (int u = tid; u < 160 * 10; u += 256) {
        int d = u / 10, c = u % 10;
        cp16(vsm + d * PSTU + c * 4, Vt + (size_t)d * NCTXP + c * 8, true);
    }
    CP_COMMIT;

    auto issueQK = [&](int st, int kt) {
        int k0 = kt << 5;
#pragma unroll
        for (int i = 0; i < 2; i++) {
            int idx = tid + (i << 8);
            int r = idx >> 2, cu = (idx & 3) << 2;
            cp16(&qb[st * 2048 + SWOFF(r, cu)], Qb + (size_t)r * CHN + k0 + (cu << 1), true);
            int kr = (r < NCTX) ? r : (NCTX - 1);
            cp16(&kb[st * 2048 + SWOFF(r, cu)], Kb + (size_t)kr * CHN + k0 + (cu << 1), true);
        }
        CP_COMMIT;
    };
    issueQK(0, 0);

    int mW = (warp >> 1) << 5;
    int nWs = (warp & 1) * 40;
    int lrow = lane & 7, lm = lane >> 3;
    // QK fragment geometry (SWOFF staging)
    int aqr[2], aqx[2];
#pragma unroll
    for (int mi = 0; mi < 2; mi++) {
        aqr[mi] = mW + (mi << 4) + ((lm & 1) << 3) + lrow;
        aqx[mi] = (aqr[mi] >> 1) & 3;
    }
    int achk = lm >> 1;
    int bkr[2], bkx[2];
#pragma unroll
    for (int np = 0; np < 2; np++) {
        bkr[np] = nWs + (np << 4) + ((lm >> 1) << 3) + lrow;
        bkx[np] = (bkr[np] >> 1) & 3;
    }
    int bchk = lm & 1;
    int b2r = nWs + 32 + lrow;
    int b2x = (b2r >> 1) & 3;
    int b2c = (lane >> 3) & 1;
    uint32_t sbQ = (uint32_t)__cvta_generic_to_shared(qb);
    uint32_t sbK = (uint32_t)__cvta_generic_to_shared(kb);

    float sc[2][5][4];
#pragma unroll
    for (int a = 0; a < 2; a++)
#pragma unroll
        for (int b = 0; b < 5; b++)
#pragma unroll
            for (int c = 0; c < 4; c++) sc[a][b][c] = 0.f;

    for (int kt = 0; kt < 5; kt++) {
        if (kt < 4) { issueQK((kt + 1) & 1, kt + 1); CP_WAIT1; }
        else        { CP_WAIT0; }
        __syncthreads();
        uint32_t stQ = sbQ + (kt & 1) * 8192;
        uint32_t stK = sbK + (kt & 1) * 8192;
#pragma unroll
        for (int kk = 0; kk < 2; kk++) {
            uint32_t af[2][4], bf[5][2];
#pragma unroll
            for (int mi = 0; mi < 2; mi++) {
                uint32_t au = (uint32_t)(aqr[mi] << 4) + ((((kk << 1) + achk) ^ aqx[mi]) << 2);
                ldsm4(af[mi], stQ + (au << 2));
            }
#pragma unroll
            for (int np = 0; np < 2; np++) {
                uint32_t bu = (uint32_t)(bkr[np] << 4) + ((((kk << 1) + bchk) ^ bkx[np]) << 2);
                uint32_t r4[4];
                ldsm4(r4, stK + (bu << 2));
                bf[np * 2][0] = r4[0]; bf[np * 2][1] = r4[1];
                bf[np * 2 + 1][0] = r4[2]; bf[np * 2 + 1][1] = r4[3];
            }
            {
                uint32_t bu = (uint32_t)(b2r << 4) + ((((kk << 1) + b2c) ^ b2x) << 2);
                uint32_t r2[2];
                ldsm2(r2, stK + (bu << 2));
                bf[4][0] = r2[0]; bf[4][1] = r2[1];
            }
#pragma unroll
            for (int mi = 0; mi < 2; mi++)
#pragma unroll
                for (int ni = 0; ni < 5; ni++) mma16(sc[mi][ni], af[mi], bf[ni]);
        }
        __syncthreads();
    }

    const float scale = 0.07905694150420949f;
    int half = warp & 1;
#pragma unroll
    for (int mi = 0; mi < 2; mi++)
#pragma unroll
        for (int hf = 0; hf < 2; hf++) {
            int row = mW + mi * 16 + (lane >> 2) + hf * 8;
            float mx = -1e30f;
#pragma unroll
            for (int ni = 0; ni < 5; ni++)
#pragma unroll
                for (int c = 0; c < 2; c++) {
                    int col = nWs + ni * 8 + ((lane & 3) << 1) + c;
                    if (col < NCTX) mx = fmaxf(mx, sc[mi][ni][hf * 2 + c]);
                }
            mx = fmaxf(mx, __shfl_xor_sync(0xffffffffu, mx, 1));
            mx = fmaxf(mx, __shfl_xor_sync(0xffffffffu, mx, 2));
            if ((lane & 3) == 0) smx[half * 128 + row] = mx;
        }
    __syncthreads();
#pragma unroll
    for (int mi = 0; mi < 2; mi++)
#pragma unroll
        for (int hf = 0; hf < 2; hf++) {
            int row = mW + mi * 16 + (lane >> 2) + hf * 8;
            float m = fmaxf(smx[row], smx[128 + row]);
            float s = 0.f;
#pragma unroll
            for (int ni = 0; ni < 5; ni++)
#pragma unroll
                for (int c = 0; c < 2; c++) {
                    int col = nWs + ni * 8 + ((lane & 3) << 1) + c;
                    float e = (col < NCTX) ? __expf((sc[mi][ni][hf * 2 + c] - m) * scale) : 0.f;
                    sc[mi][ni][hf * 2 + c] = e;
                    s += e;
                }
            s += __shfl_xor_sync(0xffffffffu, s, 1);
            s += __shfl_xor_sync(0xffffffffu, s, 2);
            if ((lane & 3) == 0) ssu[half * 128 + row] = s;
        }
    __syncthreads();
#pragma unroll
    for (int mi = 0; mi < 2; mi++)
#pragma unroll
        for (int hf = 0; hf < 2; hf++) {
            int row = mW + mi * 16 + (lane >> 2) + hf * 8;
            float inv = 1.f / (ssu[row] + ssu[128 + row]);
#pragma unroll
            for (int ni = 0; ni < 5; ni++) {
                int col = nWs + ni * 8 + ((lane & 3) << 1);
                float v0 = (col < NCTX) ? sc[mi][ni][hf * 2] * inv : 0.f;
                float v1 = (col + 1 < NCTX) ? sc[mi][ni][hf * 2 + 1] * inv : 0.f;
                psm[row * PSTU + (nWs >> 1) + ni * 4 + (lane & 3)] = pk2(v0, v1);
            }
        }
    __syncthreads();

    if (stream == 0) {
        const __half* ph = (const __half*)psm;
        for (int u = tid; u < 128 * 8; u += 256) {
            int r = u >> 3, i = u & 7;
            g_mraw[((size_t)i * NHEAD + h) * SQ + q0 + r] =
                __half2float(ph[r * (2 * PSTU) + sidx[i]]);
        }
    }

    // PV with LDSM on unswizzled stride-44 arrays
    int nW = (warp & 1) * 80;
    uint32_t sbP = (uint32_t)__cvta_generic_to_shared(psm);
    uint32_t sbV = (uint32_t)__cvta_generic_to_shared(vsm);
    int apr[2];
#pragma unroll
    for (int mi = 0; mi < 2; mi++) apr[mi] = mW + (mi << 4) + ((lm & 1) << 3) + lrow;
    int aco = (lm >> 1) << 2;
    int bvr[5];
#pragma unroll
    for (int np = 0; np < 5; np++) bvr[np] = nW + (np << 4) + ((lm >> 1) << 3) + lrow;
    int bco = (lm & 1) << 2;

    float oa[2][10][4];
#pragma unroll
    for (int a = 0; a < 2; a++)
#pragma unroll
        for (int b = 0; b < 10; b++)
#pragma unroll
            for (int c = 0; c < 4; c++) oa[a][b][c] = 0.f;
#pragma unroll
    for (int kst = 0; kst < 5; kst++) {
        int ka0 = kst * 8;
        uint32_t af[2][4], bf[10][2];
#pragma unroll
        for (int mi = 0; mi < 2; mi++)
            ldsm4(af[mi], sbP + ((uint32_t)(apr[mi] * PSTU + ka0 + aco) << 2));
#pragma unroll
        for (int np = 0; np < 5; np++) {
            uint32_t r4[4];
            ldsm4(r4, sbV + ((uint32_t)(bvr[np] * PSTU + ka0 + bco) << 2));
            bf[np * 2][0] = r4[0]; bf[np * 2][1] = r4[1];
            bf[np * 2 + 1][0] = r4[2]; bf[np * 2 + 1][1] = r4[3];
        }
#pragma unroll
        for (int mi = 0; mi < 2; mi++)
#pragma unroll
            for (int ni = 0; ni < 10; ni++) mma16(oa[mi][ni], af[mi], bf[ni]);
    }
#pragma unroll
    for (int mi = 0; mi < 2; mi++)
#pragma unroll
        for (int hf = 0; hf < 2; hf++) {
            int g = q0 + mW + mi * 16 + (lane >> 2) + hf * 8;
            __half* orow = g_pre + ((size_t)stream * SQ + g) * CHN + h * HD;
#pragma unroll
            for (int ni = 0; ni < 10; ni++) {
                int col = nW + (ni << 3) + ((lane & 3) << 1);
                *(uint32_t*)(orow + col) = pk2(oa[mi][ni][hf * 2], oa[mi][ni][hf * 2 + 1]);
            }
        }
}

// ---------------- per-instance gate max ----------------
__global__ void mmax_k() {
    __shared__ float red[256];
    int i = blockIdx.x;
    float mx = 0.f;
    const float* p = g_mraw + (size_t)i * NHEAD * SQ;
    for (int idx = threadIdx.x; idx < NHEAD * SQ; idx += 256) mx = fmaxf(mx, p[idx]);
    red[threadIdx.x] = mx;
    __syncthreads();
    for (int s = 128; s > 0; s >>= 1) {
        if (threadIdx.x < s) red[threadIdx.x] = fmaxf(red[threadIdx.x], red[threadIdx.x + s]);
        __syncthreads();
    }
    if (threadIdx.x == 0) g_mmax[i] = red[0];
}

// ============ fully fused local attention (LDSM) ============
__global__ void __launch_bounds__(256) fused_l2_k() {
    extern __shared__ __align__(16) uint32_t smu[];
    uint32_t* plm = smu;
    uint32_t* vsm = smu + 64 * PLU;
    float* smx = (float*)(smu + 64 * PLU + 160 * VLU);
    float* ssu = smx + 256;

    int z = blockIdx.y;
    int inst = z >> 3, h = z & 7;
    int q0 = blockIdx.x << 6;
    int tid = threadIdx.x, lane = tid & 31, warp = tid >> 5;

    const __half* Qb  = g_q2 + (size_t)SQ * CHN + (size_t)q0 * CHN + h * HD;
    const __half* Klb = g_kl + (size_t)inst * LLOC * CHN + h * HD;
    const __half* Vt  = g_vlT + (size_t)inst * CHN * LLOCP + (size_t)h * HD * LLOCP;

    uint32_t* strm = vsm;
    auto issueQK = [&](int st, int kt) {
        int k0 = kt << 5;
        uint32_t* base = strm + st * 5632;
        {
            int r = tid >> 2, cu = (tid & 3) << 2;
            cp16(base + SWOFF(r, cu), Qb + (size_t)r * CHN + k0 + (cu << 1), true);
        }
        for (int u = tid; u < 1152; u += 256) {
            int r = u >> 2, cu = (u & 3) << 2;
            int kr = (r < LLOC) ? r : (LLOC - 1);
            cp16(base + 1024 + SWOFF(r, cu), Klb + (size_t)kr * CHN + k0 + (cu << 1), true);
        }
        CP_COMMIT;
    };
    issueQK(0, 0);

    int mW2 = (warp >> 2) << 5;
    int nW4 = (warp & 3) * 72;
    int lrow = lane & 7, lm = lane >> 3;
    int aqr[2], aqx[2];
#pragma unroll
    for (int mi = 0; mi < 2; mi++) {
        aqr[mi] = mW2 + (mi << 4) + ((lm & 1) << 3) + lrow;
        aqx[mi] = (aqr[mi] >> 1) & 3;
    }
    int achk = lm >> 1;
    int bkr[4], bkx[4];
#pragma unroll
    for (int np = 0; np < 4; np++) {
        bkr[np] = nW4 + (np << 4) + ((lm >> 1) << 3) + lrow;
        bkx[np] = (bkr[np] >> 1) & 3;
    }
    int bchk = lm & 1;
    int b2r = nW4 + 64 + lrow;
    int b2x = (b2r >> 1) & 3;
    int b2c = (lane >> 3) & 1;
    uint32_t sbS = (uint32_t)__cvta_generic_to_shared(strm);

    float sc[2][9][4];
#pragma unroll
    for (int a = 0; a < 2; a++)
#pragma unroll
        for (int b = 0; b < 9; b++)
#pragma unroll
            for (int c = 0; c < 4; c++) sc[a][b][c] = 0.f;

    for (int kt = 0; kt < 5; kt++) {
        if (kt < 4) { issueQK((kt + 1) & 1, kt + 1); CP_WAIT1; }
        else        { CP_WAIT0; }
        __syncthreads();
        uint32_t stQ = sbS + (kt & 1) * 22528;            // 5632 u32
        uint32_t stK = stQ + 4096;                        // +1024 u32
#pragma unroll
        for (int kk = 0; kk < 2; kk++) {
            uint32_t af[2][4], bf[9][2];
#pragma unroll
            for (int mi = 0; mi < 2; mi++) {
                uint32_t au = (uint32_t)(aqr[mi] << 4) + ((((kk << 1) + achk) ^ aqx[mi]) << 2);
                ldsm4(af[mi], stQ + (au << 2));
            }
#pragma unroll
            for (int np = 0; np < 4; np++) {
                uint32_t bu = (uint32_t)(bkr[np] << 4) + ((((kk << 1) + bchk) ^ bkx[np]) << 2);
                uint32_t r4[4];
                ldsm4(r4, stK + (bu << 2));
                bf[np * 2][0] = r4[0]; bf[np * 2][1] = r4[1];
                bf[np * 2 + 1][0] = r4[2]; bf[np * 2 + 1][1] = r4[3];
            }
            {
                uint32_t bu = (uint32_t)(b2r << 4) + ((((kk << 1) + b2c) ^ b2x) << 2);
                uint32_t r2[2];
                ldsm2(r2, stK + (bu << 2));
                bf[8][0] = r2[0]; bf[8][1] = r2[1];
            }
#pragma unroll
            for (int mi = 0; mi < 2; mi++)
#pragma unroll
                for (int ni = 0; ni < 9; ni++) mma16(sc[mi][ni], af[mi], bf[ni]);
        }
        __syncthreads();
    }

    for (int u = tid; u < 160 * 34; u += 256) {
        int d = u / 34, c = u % 34;
        cp16(vsm + d * VLU + c * 4, Vt + (size_t)d * LLOCP + c * 8, true);
    }
    CP_COMMIT;

    const float scale = 0.07905694150420949f;
    float gden = 0.5f / g_mmax[inst];
#pragma unroll
    for (int mi = 0; mi < 2; mi++)
#pragma unroll
        for (int hf = 0; hf < 2; hf++) {
            int row = mW2 + mi * 16 + (lane >> 2) + hf * 8;
            float mx = -1e30f;
#pragma unroll
            for (int ni = 0; ni < 9; ni++)
#pragma unroll
                for (int c = 0; c < 2; c++) {
                    int col = nW4 + ni * 8 + ((lane & 3) << 1) + c;
                    if (col < LLOC) mx = fmaxf(mx, sc[mi][ni][hf * 2 + c]);
                }
            mx = fmaxf(mx, __shfl_xor_sync(0xffffffffu, mx, 1));
            mx = fmaxf(mx, __shfl_xor_sync(0xffffffffu, mx, 2));
            if ((lane & 3) == 0) smx[row * 4 + (warp & 3)] = mx;
        }
    __syncthreads();
#pragma unroll
    for (int mi = 0; mi < 2; mi++)
#pragma unroll
        for (int hf = 0; hf < 2; hf++) {
            int row = mW2 + mi * 16 + (lane >> 2) + hf * 8;
            float m = fmaxf(fmaxf(smx[row * 4], smx[row * 4 + 1]),
                            fmaxf(smx[row * 4 + 2], smx[row * 4 + 3]));
            float s = 0.f;
#pragma unroll
            for (int ni = 0; ni < 9; ni++)
#pragma unroll
                for (int c = 0; c < 2; c++) {
                    int col = nW4 + ni * 8 + ((lane & 3) << 1) + c;
                    float e = (col < LLOC) ? __expf((sc[mi][ni][hf * 2 + c] - m) * scale) : 0.f;
                    sc[mi][ni][hf * 2 + c] = e;
                    s += e;
                }
            s += __shfl_xor_sync(0xffffffffu, s, 1);
            s += __shfl_xor_sync(0xffffffffu, s, 2);
            if ((lane & 3) == 0) ssu[row * 4 + (warp & 3)] = s;
        }
    __syncthreads();
#pragma unroll
    for (int mi = 0; mi < 2; mi++)
#pragma unroll
        for (int hf = 0; hf < 2; hf++) {
            int row = mW2 + mi * 16 + (lane >> 2) + hf * 8;
            float s = ssu[row * 4] + ssu[row * 4 + 1] + ssu[row * 4 + 2] + ssu[row * 4 + 3];
            float f = g_mraw[(size_t)z * SQ + q0 + row] * gden / s;
#pragma unroll
            for (int ni = 0; ni < 9; ni++) {
                int ucol = (nW4 >> 1) + ni * 4 + (lane & 3);
                if (ucol < 136)
                    plm[row * PLU + ucol] = pk2(sc[mi][ni][hf * 2] * f, sc[mi][ni][hf * 2 + 1] * f);
            }
        }
    CP_WAIT0;
    __syncthreads();

    // PV with LDSM on unswizzled stride-140 arrays
    int nW = (warp & 3) * 40;
    uint32_t sbP = (uint32_t)__cvta_generic_to_shared(plm);
    uint32_t sbV = (uint32_t)__cvta_generic_to_shared(vsm);
    int apr[2];
#pragma unroll
    for (int mi = 0; mi < 2; mi++) apr[mi] = mW2 + (mi << 4) + ((lm & 1) << 3) + lrow;
    int aco = (lm >> 1) << 2;
    int bvr[2];
#pragma unroll
    for (int np = 0; np < 2; np++) bvr[np] = nW + (np << 4) + ((lm >> 1) << 3) + lrow;
    int bco = (lm & 1) << 2;
    int v2r = nW + 32 + lrow;
    int v2c = ((lane >> 3) & 1) << 2;

    float oa[2][5][4];
#pragma unroll
    for (int a = 0; a < 2; a++)
#pragma unroll
        for (int b = 0; b < 5; b++)
#pragma unroll
            for (int c = 0; c < 4; c++) oa[a][b][c] = 0.f;

#pragma unroll 1
    for (int ch = 0; ch < 17; ch++) {
        int ka0 = ch * 8;
        uint32_t af[2][4], bf[5][2];
#pragma unroll
        for (int mi = 0; mi < 2; mi++)
            ldsm4(af[mi], sbP + ((uint32_t)(apr[mi] * PLU + ka0 + aco) << 2));
#pragma unroll
        for (int np = 0; np < 2; np++) {
            uint32_t r4[4];
            ldsm4(r4, sbV + ((uint32_t)(bvr[np] * VLU + ka0 + bco) << 2));
            bf[np * 2][0] = r4[0]; bf[np * 2][1] = r4[1];
            bf[np * 2 + 1][0] = r4[2]; bf[np * 2 + 1][1] = r4[3];
        }
        {
            uint32_t r2[2];
            ldsm2(r2, sbV + ((uint32_t)(v2r * VLU + ka0 + v2c) << 2));
            bf[4][0] = r2[0]; bf[4][1] = r2[1];
        }
#pragma unroll
        for (int mi = 0; mi < 2; mi++)
#pragma unroll
            for (int ni = 0; ni < 5; ni++) mma16(oa[mi][ni], af[mi], bf[ni]);
    }

#pragma unroll
    for (int mi = 0; mi < 2; mi++)
#pragma unroll
        for (int hf = 0; hf < 2; hf++) {
            int g = q0 + mW2 + mi * 16 + (lane >> 2) + hf * 8;
            __half* prow = g_pre + ((size_t)(inst + 1) * SQ + g) * CHN + h * HD;
#pragma unroll
            for (int ni = 0; ni < 5; ni++) {
                int col = nW + (ni << 3) + ((lane & 3) << 1);
                __half2 old = *(__half2*)(prow + col);
                float o0 = 0.5f * __half2float(old.x) + oa[mi][ni][hf * 2];
                float o1 = 0.5f * __half2float(old.y) + oa[mi][ni][hf * 2 + 1];
                *(uint32_t*)(prow + col) = pk2(o0, o1);
            }
        }
}

// ---------------- fuser premix ----------------
__global__ void premix_k(const float* __restrict__ bbox) {
    int s = blockIdx.x;
    int y = s >> 6, x = s & 63;
    float wgt[8];
    wgt[0] = 1.f;
    float sw = 1.f;
    const int off[4] = {3, 4, 11, 12};
#pragma unroll
    for (int i = 0; i < 7; i++) {
        float wmin = floorf(1024.f * bbox[i * 4 + 0]);
        float hmin = floorf(1024.f * bbox[i * 4 + 1]);
        float wmax = floorf(1024.f * bbox[i * 4 + 2]);
        float hmax = floorf(1024.f * bbox[i * 4 + 3]);
        float R = 0.f, Cv = 0.f;
#pragma unroll
        for (int j = 0; j < 4; j++) {
            float yy = (float)(16 * y + off[j]);
            float xx = (float)(16 * x + off[j]);
            if (yy >= hmin && yy < hmax) R += 0.25f;
            if (xx >= wmin && xx < wmax) Cv += 0.25f;
        }
        float g = 10.f * R * Cv;
        wgt[i + 1] = g;
        sw += g;
    }
    if (threadIdx.x == 0) g_sumw[s] = sw;
    for (int c = threadIdx.x; c < CHN; c += 256) {
        float acc = 0.f;
#pragma unroll
        for (int j = 0; j < 8; j++)
            acc += wgt[j] * __half2float(g_pre[((size_t)(1 + j) * SQ + s) * CHN + c]);
        g_mix[(size_t)s * CHN + c] = __float2half_rn(acc);
    }
}

// ---------------- final ----------------
__global__ void final_k(const float* __restrict__ bout, float* __restrict__ out) {
    int s = blockIdx.x;
    float sw = g_sumw[s];
    float den = 1.f / (sw + 1e-6f);
    for (int c = threadIdx.x; c < CHN; c += 256) {
        float b = bout[c];
        out[(size_t)s * CHN + c] = g_out2[(size_t)s * CHN + c] + b;
        out[(size_t)(SQ + s) * CHN + c] = (g_out2[(size_t)(SQ + s) * CHN + c] + b * sw) * den;
    }
}

// ---------------- launch ----------------
extern "C" void kernel_launch(void* const* d_in, const int* in_sizes, int n_in,
                              void* d_out, int out_size) {
    const float* hs   = (const float*)d_in[0];
    const float* ctx  = (const float*)d_in[1];
    const float* lf   = (const float*)d_in[2];
    const float* bbox = (const float*)d_in[3];
    const float* Wq   = (const float*)d_in[4];
    const float* Wk   = (const float*)d_in[5];
    const float* Wv   = (const float*)d_in[6];
    const float* Wkg  = (const float*)d_in[7];
    const float* Wvg  = (const float*)d_in[8];
    const float* Wkl  = (const float*)d_in[9];
    const float* Wvl  = (const float*)d_in[10];
    const float* Wout = (const float*)d_in[11];
    const float* bout = (const float*)d_in[12];
    const int*   lidx = (const int*)d_in[13];
    float* out = (float*)d_out;

    __half *hsH, *ctxH, *lfH, *WqT, *WkT, *WvT, *WkgT, *WvgT, *WklT, *WvlT, *WoutT;
    __half *vp, *vTp, *vlp, *vlTp;
    cudaGetSymbolAddress((void**)&hsH, g_hsH);
    cudaGetSymbolAddress((void**)&ctxH, g_ctxH);
    cudaGetSymbolAddress((void**)&lfH, g_lfH);
    cudaGetSymbolAddress((void**)&WqT, g_WqT);
    cudaGetSymbolAddress((void**)&WkT, g_WkT);
    cudaGetSymbolAddress((void**)&WvT, g_WvT);
    cudaGetSymbolAddress((void**)&WkgT, g_WkgT);
    cudaGetSymbolAddress((void**)&WvgT, g_WvgT);
    cudaGetSymbolAddress((void**)&WklT, g_WklT);
    cudaGetSymbolAddress((void**)&WvlT, g_WvlT);
    cudaGetSymbolAddress((void**)&WoutT, g_WoutT);
    cudaGetSymbolAddress((void**)&vp, g_v);
    cudaGetSymbolAddress((void**)&vTp, g_vT);
    cudaGetSymbolAddress((void**)&vlp, g_vl);
    cudaGetSymbolAddress((void**)&vlTp, g_vlT);

    const int smemA = (2 * 2048 * 2 + 128 * PSTU + 160 * PSTU + 512) * 4;
    const int smemL = (64 * PLU + 160 * VLU + 512) * 4;
    cudaFuncSetAttribute(fused_g_k, cudaFuncAttributeMaxDynamicSharedMemorySize, smemA);
    cudaFuncSetAttribute(fused_l2_k, cudaFuncAttributeMaxDynamicSharedMemorySize, smemL);
    cudaFuncSetAttribute(gemm_h, cudaFuncAttributeMaxDynamicSharedMemorySize, SMEM3);

    cudaStream_t sA = g_si.sA, sB = g_si.sB, sC = g_si.sC;
    dim3 tb(32, 8);

    setup_k<<<1, 32>>>();
    cudaEventRecord(g_si.evRoot, 0);
    cudaStreamWaitEvent(sA, g_si.evRoot, 0);
    cudaStreamWaitEvent(sB, g_si.evRoot, 0);
    cudaStreamWaitEvent(sC, g_si.evRoot, 0);

    long long nHs = 2LL * SQ * CHN, nCtx = (long long)NST * NCTX * CC, nLf = (long long)NSTR * LLOC * CC;

    // main track
    round_h<<<(int)((nHs / 8 + 255) / 256), 256>>>(hs, hsH, nHs);
    transpose_k<float><<<dim3(40, 40, 1), tb>>>(Wq, WqT, CHN, CHN, CHN, CHN, 0, 0);
    gemm_h<<<dim3(10, 64, 1), 256, SMEM3>>>(0, CHN, CHN, CHN, CHN, CHN, 1);

    // track A
    round_h<<<(int)((nCtx / 8 + 255) / 256), 256, 0, sA>>>(ctx, ctxH, nCtx);
    transpose_k<float><<<dim3(40, 24, 1), tb, 0, sA>>>(Wk, WkT, CC, CHN, CHN, CC, 0, 0);
    transpose_k<float><<<dim3(40, 24, 1), tb, 0, sA>>>(Wv, WvT, CC, CHN, CHN, CC, 0, 0);
    transpose_k<float><<<dim3(40, 24, 1), tb, 0, sA>>>(Wkg, WkgT, CC, CHN, CHN, CC, 0, 0);
    transpose_k<float><<<dim3(40, 24, 1), tb, 0, sA>>>(Wvg, WvgT, CC, CHN, CHN, CC, 0, 0);
    gemm_h<<<dim3(10, 6, 4), 256, SMEM3, sA>>>(1, CHN, CC, CC, CC, CHN, 1);
    kv_select_k<<<(NSTR * NCTX * CHN / 2 + 255) / 256, 256, 0, sA>>>(lidx);
    transpose_k<__half><<<dim3(40, 3, NST), tb, 0, sA>>>(vp, vTp, NCTX, CHN, CHN, NCTXP,
                                                         (long long)NCTX * CHN, (long long)CHN * NCTXP);
    cudaEventRecord(g_si.ev1, sA);

    // track B
    round_h<<<(int)((nLf / 8 + 255) / 256), 256, 0, sB>>>(lf, lfH, nLf);
    transpose_k<float><<<dim3(40, 24, 1), tb, 0, sB>>>(Wkl, WklT, CC, CHN, CHN, CC, 0, 0);
    transpose_k<float><<<dim3(40, 24, 1), tb, 0, sB>>>(Wvl, WvlT, CC, CHN, CHN, CC, 0, 0);
    gemm_h<<<dim3(10, 17, 2), 256, SMEM3, sB>>>(5, CHN, CC, CC, CC, CHN, 1);
    transpose_k<__half><<<dim3(40, 9, NSTR), tb, 0, sB>>>(vlp, vlTp, LLOC, CHN, CHN, LLOCP,
                                                          (long long)LLOC * CHN, (long long)CHN * LLOCP);
    cudaEventRecord(g_si.ev2, sB);

    // track C
    transpose_k<float><<<dim3(40, 40, 1), tb, 0, sC>>>(Wout, WoutT, CHN, CHN, CHN, CHN, 0, 0);
    cudaEventRecord(g_si.ev3, sC);

    // global attention
    cudaStreamWaitEvent(0, g_si.ev1, 0);
    fused_g_k<<<dim3(32, 72), 256, smemA>>>(lidx);
    mmax_k<<<8, 256>>>();
    cudaEventRecord(g_si.evG, 0);

    // uncond out-projection concurrent with local attention
    cudaStreamWaitEvent(sA, g_si.evG, 0);
    cudaStreamWaitEvent(sA, g_si.ev3, 0);
    gemm_h<<<dim3(10, 32, 1), 256, SMEM3, sA>>>(7, CHN, CHN, CHN, CHN, CHN, 0);
    cudaEventRecord(g_si.evO7, sA);

    // local attention
    cudaStreamWaitEvent(0, g_si.ev2, 0);
    fused_l2_k<<<dim3(64, 64), 256, smemL>>>();

    // premix + cond out-projection
    premix_k<<<SQ, 256>>>(bbox);
    cudaStreamWaitEvent(0, g_si.ev3, 0);
    gemm_h<<<dim3(10, 32, 1), 256, SMEM3>>>(8, CHN, CHN, CHN, CHN, CHN, 0);
    cudaStreamWaitEvent(0, g_si.evO7, 0);
    final_k<<<SQ, 256>>>(bout, out);
}

// round 12
// speedup vs baseline: 2.7054x; 1.0008x over previous
#include <cuda_runtime.h>
#include <cuda_fp16.h>
#include <math.h>
#include <stdint.h>

#define SQ 4096
#define CHN 1280
#define CC 768
#define NHEAD 8
#define HD 160
#define NCTX 77
#define NCTXP 80
#define NST 9
#define NSTR 8
#define LLOC 257
#define LLOCP 272
#define PSTU 44
#define PLU 140
#define VLU 140
#define SMEM3 (3 * 2048 * 2 * 4)

// ---------------- scratch ----------------
__device__ __align__(256) __half g_hsH[2 * SQ * CHN];
__device__ __align__(256) __half g_ctxH[NST * NCTX * CC];
__device__ __align__(256) __half g_lfH[NSTR * LLOC * CC];
__device__ __align__(256) __half g_q2[2 * SQ * CHN];
__device__ __align__(256) __half g_k[NST * NCTX * CHN];
__device__ __align__(256) __half g_v[NST * NCTX * CHN];
__device__ __align__(256) __half g_kg[NSTR * NCTX * CHN];
__device__ __align__(256) __half g_vg[NSTR * NCTX * CHN];
__device__ __align__(256) __half g_kl[NSTR * LLOC * CHN];
__device__ __align__(256) __half g_vl[NSTR * LLOC * CHN];
__device__ __align__(256) __half g_WqT[CHN * CHN];
__device__ __align__(256) __half g_WkT[CHN * CC];
__device__ __align__(256) __half g_WvT[CHN * CC];
__device__ __align__(256) __half g_WkgT[CHN * CC];
__device__ __align__(256) __half g_WvgT[CHN * CC];
__device__ __align__(256) __half g_WklT[CHN * CC];
__device__ __align__(256) __half g_WvlT[CHN * CC];
__device__ __align__(256) __half g_WoutT[CHN * CHN];
__device__ __align__(256) __half g_vT[NST * CHN * NCTXP];
__device__ __align__(256) __half g_vlT[NSTR * CHN * LLOCP];
__device__ __align__(256) __half g_pre[NST * SQ * CHN];
__device__ __align__(256) __half g_mix[SQ * CHN];
__device__ __align__(256) float g_out2[2 * SQ * CHN];
__device__ float g_mraw[NSTR * NHEAD * SQ];
__device__ float g_mmax[NSTR];
__device__ float g_sumw[SQ];

__device__ const __half* d_Ap[16];
__device__ const __half* d_Bp[16];
__device__ void*         d_Cp[16];
__device__ int           d_Mt[16];

// ---------------- streams/events ----------------
struct StreamInit {
    cudaStream_t sA, sB, sC;
    cudaEvent_t evRoot, ev1, ev2, ev3, evG, evO7;
    StreamInit() {
        cudaStreamCreateWithFlags(&sA, cudaStreamNonBlocking);
        cudaStreamCreateWithFlags(&sB, cudaStreamNonBlocking);
        cudaStreamCreateWithFlags(&sC, cudaStreamNonBlocking);
        cudaEventCreateWithFlags(&evRoot, cudaEventDisableTiming);
        cudaEventCreateWithFlags(&ev1, cudaEventDisableTiming);
        cudaEventCreateWithFlags(&ev2, cudaEventDisableTiming);
        cudaEventCreateWithFlags(&ev3, cudaEventDisableTiming);
        cudaEventCreateWithFlags(&evG, cudaEventDisableTiming);
        cudaEventCreateWithFlags(&evO7, cudaEventDisableTiming);
    }
};
static StreamInit g_si;

// ---------------- helpers ----------------
__device__ __forceinline__ uint32_t pk2(float a, float b) {
    __half2 h = __halves2half2(__float2half_rn(a), __float2half_rn(b));
    return *(uint32_t*)&h;
}
__device__ __forceinline__ void cp16(void* sdst, const void* gsrc, bool p) {
    uint32_t sa = (uint32_t)__cvta_generic_to_shared(sdst);
    int sz = p ? 16 : 0;
    asm volatile("cp.async.cg.shared.global [%0], [%1], 16, %2;" :: "r"(sa), "l"(gsrc), "r"(sz));
}
#define CP_COMMIT asm volatile("cp.async.commit_group;")
#define CP_WAIT0 asm volatile("cp.async.wait_group 0;")
#define CP_WAIT1 asm volatile("cp.async.wait_group 1;")
__device__ __forceinline__ void mma16(float* c, const uint32_t* a, const uint32_t* b) {
    asm volatile(
        "mma.sync.aligned.m16n8k16.row.col.f32.f16.f16.f32 "
        "{%0,%1,%2,%3}, {%4,%5,%6,%7}, {%8,%9}, {%0,%1,%2,%3};"
        : "+f"(c[0]), "+f"(c[1]), "+f"(c[2]), "+f"(c[3])
        : "r"(a[0]), "r"(a[1]), "r"(a[2]), "r"(a[3]), "r"(b[0]), "r"(b[1]));
}
__device__ __forceinline__ void ldsm4(uint32_t* r, uint32_t addr) {
    asm volatile("ldmatrix.sync.aligned.m8n8.x4.shared.b16 {%0,%1,%2,%3}, [%4];"
                 : "=r"(r[0]), "=r"(r[1]), "=r"(r[2]), "=r"(r[3]) : "r"(addr));
}
__device__ __forceinline__ void ldsm2(uint32_t* r, uint32_t addr) {
    asm volatile("ldmatrix.sync.aligned.m8n8.x2.shared.b16 {%0,%1}, [%2];"
                 : "=r"(r[0]), "=r"(r[1]) : "r"(addr));
}
#define SWOFF(r, c) (((r) << 4) + ((((((c) >> 2) ^ (((r) >> 1) & 3))) << 2) | ((c) & 3)))

// ---------------- setup ----------------
__global__ void setup_k() {
    if (threadIdx.x == 0) {
        d_Ap[0] = g_hsH;               d_Bp[0] = g_WqT;   d_Cp[0] = g_q2;    d_Mt[0] = 2 * SQ;
        d_Ap[1] = g_ctxH;              d_Bp[1] = g_WkT;   d_Cp[1] = g_k;     d_Mt[1] = NST * NCTX;
        d_Ap[2] = g_ctxH;              d_Bp[2] = g_WvT;   d_Cp[2] = g_v;     d_Mt[2] = NST * NCTX;
        d_Ap[3] = g_ctxH + NCTX * CC;  d_Bp[3] = g_WkgT;  d_Cp[3] = g_kg;    d_Mt[3] = NSTR * NCTX;
        d_Ap[4] = g_ctxH + NCTX * CC;  d_Bp[4] = g_WvgT;  d_Cp[4] = g_vg;    d_Mt[4] = NSTR * NCTX;
        d_Ap[5] = g_lfH;               d_Bp[5] = g_WklT;  d_Cp[5] = g_kl;    d_Mt[5] = NSTR * LLOC;
        d_Ap[6] = g_lfH;               d_Bp[6] = g_WvlT;  d_Cp[6] = g_vl;    d_Mt[6] = NSTR * LLOC;
        d_Ap[7] = g_pre;               d_Bp[7] = g_WoutT; d_Cp[7] = g_out2;  d_Mt[7] = SQ;
        d_Ap[8] = g_mix;               d_Bp[8] = g_WoutT; d_Cp[8] = g_out2 + (size_t)SQ * CHN;
        d_Mt[8] = SQ;
    }
}

// ---------------- round inputs to fp16 ----------------
__global__ void round_h(const float* __restrict__ src, __half* __restrict__ dst, long long n) {
    long long i = ((long long)blockIdx.x * blockDim.x + threadIdx.x) * 8;
    if (i + 7 < n) {
        float4 a = *(const float4*)(src + i);
        float4 b = *(const float4*)(src + i + 4);
        uint4 u;
        u.x = pk2(a.x, a.y); u.y = pk2(a.z, a.w);
        u.z = pk2(b.x, b.y); u.w = pk2(b.z, b.w);
        *(uint4*)(dst + i) = u;
    } else {
        for (long long j = i; j < n; j++) dst[j] = __float2half_rn(src[j]);
    }
}

// ---------------- transpose ----------------
template <typename TS>
__global__ void transpose_k(const TS* __restrict__ src, __half* __restrict__ dst,
                            int R, int C, int ldS, int ldD, long long sBS, long long dBS) {
    __shared__ float t[32][33];
    src += blockIdx.z * sBS;
    dst += blockIdx.z * dBS;
    int c0 = blockIdx.x << 5, r0 = blockIdx.y << 5;
    int tx = threadIdx.x, ty = threadIdx.y;
#pragma unroll
    for (int j = 0; j < 4; j++) {
        int rr = r0 + ty + j * 8, cc = c0 + tx;
        t[ty + j * 8][tx] = (rr < R && cc < C) ? (float)src[(size_t)rr * ldS + cc] : 0.f;
    }
    __syncthreads();
#pragma unroll
    for (int j = 0; j < 4; j++) {
        int cc = c0 + ty + j * 8, rr = r0 + tx;
        if (cc < C && rr < ldD)
            dst[(size_t)cc * ldD + rr] = __float2half_rn(t[tx][ty + j * 8]);
    }
}

// ---------------- batched NT fp16 GEMM (R8, proven) ----------------
__global__ void __launch_bounds__(256, 2) gemm_h(int slot, int N, int K,
                                                 int lda, int ldb, int ldc, int mode) {
    extern __shared__ __align__(16) uint32_t smg[];
    uint32_t* As = smg;
    uint32_t* Bs = smg + 3 * 2048;
    const __half* Ab = d_Ap[slot + blockIdx.z];
    const __half* Bb = d_Bp[slot + blockIdx.z];
    void* Cm         = d_Cp[slot + blockIdx.z];
    const int M      = d_Mt[slot + blockIdx.z];
    int tid = threadIdx.x, lane = tid & 31, warp = tid >> 5;
    int mBase = blockIdx.y << 7, nBase = blockIdx.x << 7;
    int mW = (warp >> 2) << 6, nW = (warp & 3) << 5;
    float acc[4][4][4];
#pragma unroll
    for (int a = 0; a < 4; a++)
#pragma unroll
        for (int b = 0; b < 4; b++)
#pragma unroll
            for (int cI = 0; cI < 4; cI++) acc[a][b][cI] = 0.f;

    int KT = K >> 5;
    auto issue = [&](int st, int kt) {
        int k0 = kt << 5;
#pragma unroll
        for (int i = 0; i < 2; i++) {
            int idx = tid + (i << 8);
            int r = idx >> 2, cu = (idx & 3) << 2;
            int gr = mBase + r; bool pa = gr < M; if (!pa) gr = M - 1;
            cp16(&As[st * 2048 + SWOFF(r, cu)], Ab + (size_t)gr * lda + k0 + (cu << 1), pa);
            int gn = nBase + r; bool pb = gn < N; if (!pb) gn = N - 1;
            cp16(&Bs[st * 2048 + SWOFF(r, cu)], Bb + (size_t)gn * ldb + k0 + (cu << 1), pb);
        }
        CP_COMMIT;
    };
    issue(0, 0);
    issue(1, 1);

    int lrow = lane & 7;
    int lm = lane >> 3;
    int arow[4], axor[4];
#pragma unroll
    for (int mi = 0; mi < 4; mi++) {
        arow[mi] = mW + (mi << 4) + ((lm & 1) << 3) + lrow;
        axor[mi] = (arow[mi] >> 1) & 3;
    }
    int achk = lm >> 1;
    int brow[2], bxor[2];
#pragma unroll
    for (int np = 0; np < 2; np++) {
        brow[np] = nW + (np << 4) + ((lm >> 1) << 3) + lrow;
        bxor[np] = (brow[np] >> 1) & 3;
    }
    int bchk = lm & 1;
    uint32_t sbA = (uint32_t)__cvta_generic_to_shared(As);
    uint32_t sbB = (uint32_t)__cvta_generic_to_shared(Bs);

    for (int kt = 0; kt < KT; kt++) {
        if (kt + 1 < KT) { CP_WAIT1; } else { CP_WAIT0; }
        __syncthreads();
        if (kt + 2 < KT) issue((kt + 2) % 3, kt + 2);
        uint32_t stA = sbA + (kt % 3) * 8192;
        uint32_t stB = sbB + (kt % 3) * 8192;
#pragma unroll
        for (int kk = 0; kk < 2; kk++) {
            uint32_t af[4][4], bf[4][2];
#pragma unroll
            for (int mi = 0; mi < 4; mi++) {
                uint32_t au = (uint32_t)(arow[mi] << 4) + ((((kk << 1) + achk) ^ axor[mi]) << 2);
                ldsm4(af[mi], stA + (au << 2));
            }
#pragma unroll
            for (int np = 0; np < 2; np++) {
                uint32_t bu = (uint32_t)(brow[np] << 4) + ((((kk << 1) + bchk) ^ bxor[np]) << 2);
                uint32_t r4[4];
                ldsm4(r4, stB + (bu << 2));
                bf[np * 2][0] = r4[0]; bf[np * 2][1] = r4[1];
                bf[np * 2 + 1][0] = r4[2]; bf[np * 2 + 1][1] = r4[3];
            }
#pragma unroll
            for (int mi = 0; mi < 4; mi++)
#pragma unroll
                for (int ni = 0; ni < 4; ni++) mma16(acc[mi][ni], af[mi], bf[ni]);
        }
    }
#pragma unroll
    for (int mi = 0; mi < 4; mi++) {
#pragma unroll
        for (int half = 0; half < 2; half++) {
            int gm = mBase + mW + (mi << 4) + (lane >> 2) + half * 8;
            if (gm >= M) continue;
#pragma unroll
            for (int ni = 0; ni < 4; ni++) {
                int gn = nBase + nW + (ni << 3) + ((lane & 3) << 1);
                if (gn + 1 >= N) continue;
                float v0 = acc[mi][ni][half * 2], v1 = acc[mi][ni][half * 2 + 1];
                if (mode & 1) {
                    __half* crow = (__half*)Cm + (size_t)gm * ldc;
                    *(uint32_t*)(crow + gn) = pk2(v0, v1);
                } else {
                    float* crow = (float*)Cm + (size_t)gm * ldc;
                    crow[gn] = v0;
                    crow[gn + 1] = v1;
                }
            }
        }
    }
}

// ---------------- ELITE K/V select ----------------
__global__ void kv_select_k(const int* __restrict__ lidx) {
    int idx = blockIdx.x * 256 + threadIdx.x;
    const int tot = NSTR * NCTX * CHN / 2;
    if (idx >= tot) return;
    int st = idx / (NCTX * CHN / 2);
    if (lidx[st] >= 0) {
        ((uint32_t*)g_k)[NCTX * CHN / 2 + idx] = ((const uint32_t*)g_kg)[idx];
        ((uint32_t*)g_v)[NCTX * CHN / 2 + idx] = ((const uint32_t*)g_vg)[idx];
    }
}

// ============ fused global attention (fp16, 2 CTAs/SM, LDSM) ============
__global__ void __launch_bounds__(256, 2) fused_g_k(const int* __restrict__ lidx) {
    extern __shared__ __align__(16) uint32_t smu[];
    uint32_t* qb  = smu;
    uint32_t* kb  = smu + 4096;
    uint32_t* psm = smu + 8192;
    uint32_t* vsm = psm + 128 * PSTU;
    float* smx = (float*)(vsm + 160 * PSTU);
    float* ssu = smx + 256;
    __shared__ int sidx[8];

    int bh = blockIdx.y;
    int stream = bh >> 3, h = bh & 7;
    int q0 = blockIdx.x << 7;
    int tid = threadIdx.x, lane = tid & 31, warp = tid >> 5;
    if (tid < 8) sidx[tid] = lidx[tid];

    const __half* Qb = g_q2 + (stream ? (size_t)SQ * CHN : 0) + (size_t)q0 * CHN + h * HD;
    const __half* Kb = g_k + (size_t)stream * NCTX * CHN + h * HD;
    const __half* Vt = g_vT + (size_t)stream * CHN * NCTXP + (size_t)h * HD * NCTXP;

    for (int u = tid; u < 160 * 10; u += 256) {
        int d = u / 10, c = u % 10;
        cp16(vsm + d * PSTU + c * 4, Vt + (size_t)d * NCTXP + c * 8, true);
    }
    CP_COMMIT;

    auto issueQK = [&](int st, int kt) {
        int k0 = kt << 5;
#pragma unroll
        for (int i = 0; i < 2; i++) {
            int idx = tid + (i << 8);
            int r = idx >> 2, cu = (idx & 3) << 2;
            cp16(&qb[st * 2048 + SWOFF(r, cu)], Qb + (size_t)r * CHN + k0 + (cu << 1), true);
            int kr = (r < NCTX) ? r : (NCTX - 1);
            cp16(&kb[st * 2048 + SWOFF(r, cu)], Kb + (size_t)kr * CHN + k0 + (cu << 1), true);
        }
        CP_COMMIT;
    };
    issueQK(0, 0);

    int mW = (warp >> 1) << 5;
    int nWs = (warp & 1) * 40;
    int lrow = lane & 7, lm = lane >> 3;
    // QK fragment geometry (SWOFF staging)
    int aqr[2], aqx[2];
#pragma unroll
    for (int mi = 0; mi < 2; mi++) {
        aqr[mi] = mW + (mi << 4) + ((lm & 1) << 3) + lrow;
        aqx[mi] = (aqr[mi] >> 1) & 3;
    }
    int achk = lm >> 1;
    int bkr[2], bkx[2];
#pragma unroll
    for (int np = 0; np < 2; np++) {
        bkr[np] = nWs + (np << 4) + ((lm >> 1) << 3) + lrow;
        bkx[np] = (bkr[np] >> 1) & 3;
    }
    int bchk = lm & 1;
    int b2r = nWs + 32 + lrow;
    int b2x = (b2r >> 1) & 3;
    int b2c = (lane >> 3) & 1;
    uint32_t sbQ = (uint32_t)__cvta_generic_to_shared(qb);
    uint32_t sbK = (uint32_t)__cvta_generic_to_shared(kb);

    float sc[2][5][4];
#pragma unroll
    for (int a = 0; a < 2; a++)
#pragma unroll
        for (int b = 0; b < 5; b++)
#pragma unroll
            for (int c = 0; c < 4; c++) sc[a][b][c] = 0.f;

    for (int kt = 0; kt < 5; kt++) {
        if (kt < 4) { issueQK((kt + 1) & 1, kt + 1); CP_WAIT1; }
        else        { CP_WAIT0; }
        __syncthreads();
        uint32_t stQ = sbQ + (kt & 1) * 8192;
        uint32_t stK = sbK + (kt & 1) * 8192;
#pragma unroll
        for (int kk = 0; kk < 2; kk++) {
            uint32_t af[2][4], bf[5][2];
#pragma unroll
            for (int mi = 0; mi < 2; mi++) {
                uint32_t au = (uint32_t)(aqr[mi] << 4) + ((((kk << 1) + achk) ^ aqx[mi]) << 2);
                ldsm4(af[mi], stQ + (au << 2));
            }
#pragma unroll
            for (int np = 0; np < 2; np++) {
                uint32_t bu = (uint32_t)(bkr[np] << 4) + ((((kk << 1) + bchk) ^ bkx[np]) << 2);
                uint32_t r4[4];
                ldsm4(r4, stK + (bu << 2));
                bf[np * 2][0] = r4[0]; bf[np * 2][1] = r4[1];
                bf[np * 2 + 1][0] = r4[2]; bf[np * 2 + 1][1] = r4[3];
            }
            {
                uint32_t bu = (uint32_t)(b2r << 4) + ((((kk << 1) + b2c) ^ b2x) << 2);
                uint32_t r2[2];
                ldsm2(r2, stK + (bu << 2));
                bf[4][0] = r2[0]; bf[4][1] = r2[1];
            }
#pragma unroll
            for (int mi = 0; mi < 2; mi++)
#pragma unroll
                for (int ni = 0; ni < 5; ni++) mma16(sc[mi][ni], af[mi], bf[ni]);
        }
        __syncthreads();
    }

    const float scale = 0.07905694150420949f;
    int half = warp & 1;
#pragma unroll
    for (int mi = 0; mi < 2; mi++)
#pragma unroll
        for (int hf = 0; hf < 2; hf++) {
            int row = mW + mi * 16 + (lane >> 2) + hf * 8;
            float mx = -1e30f;
#pragma unroll
            for (int ni = 0; ni < 5; ni++)
#pragma unroll
                for (int c = 0; c < 2; c++) {
                    int col = nWs + ni * 8 + ((lane & 3) << 1) + c;
                    if (col < NCTX) mx = fmaxf(mx, sc[mi][ni][hf * 2 + c]);
                }
            mx = fmaxf(mx, __shfl_xor_sync(0xffffffffu, mx, 1));
            mx = fmaxf(mx, __shfl_xor_sync(0xffffffffu, mx, 2));
            if ((lane & 3) == 0) smx[half * 128 + row] = mx;
        }
    __syncthreads();
#pragma unroll
    for (int mi = 0; mi < 2; mi++)
#pragma unroll
        for (int hf = 0; hf < 2; hf++) {
            int row = mW + mi * 16 + (lane >> 2) + hf * 8;
            float m = fmaxf(smx[row], smx[128 + row]);
            float s = 0.f;
#pragma unroll
            for (int ni = 0; ni < 5; ni++)
#pragma unroll
                for (int c = 0; c < 2; c++) {
                    int col = nWs + ni * 8 + ((lane & 3) << 1) + c;
                    float e = (col < NCTX) ? __expf((sc[mi][ni][hf * 2 + c] - m) * scale) : 0.f;
                    sc[mi][ni][hf * 2 + c] = e;
                    s += e;
                }
            s += __shfl_xor_sync(0xffffffffu, s, 1);
            s += __shfl_xor_sync(0xffffffffu, s, 2);
            if ((lane & 3) == 0) ssu[half * 128 + row] = s;
        }
    __syncthreads();
#pragma unroll
    for (int mi = 0; mi < 2; mi++)
#pragma unroll
        for (int hf = 0; hf < 2; hf++) {
            int row = mW + mi * 16 + (lane >> 2) + hf * 8;
            float inv = 1.f / (ssu[row] + ssu[128 + row]);
#pragma unroll
            for (int ni = 0; ni < 5; ni++) {
                int col = nWs + ni * 8 + ((lane & 3) << 1);
                float v0 = (col < NCTX) ? sc[mi][ni][hf * 2] * inv : 0.f;
                float v1 = (col + 1 < NCTX) ? sc[mi][ni][hf * 2 + 1] * inv : 0.f;
                psm[row * PSTU + (nWs >> 1) + ni * 4 + (lane & 3)] = pk2(v0, v1);
            }
        }
    __syncthreads();

    if (stream == 0) {
        const __half* ph = (const __half*)psm;
        for (int u = tid; u < 128 * 8; u += 256) {
            int r = u >> 3, i = u & 7;
            g_mraw[((size_t)i * NHEAD + h) * SQ + q0 + r] =
                __half2float(ph[r * (2 * PSTU) + sidx[i]]);
        }
    }

    // PV with LDSM on unswizzled stride-44 arrays
    int nW = (warp & 1) * 80;
    uint32_t sbP = (uint32_t)__cvta_generic_to_shared(psm);
    uint32_t sbV = (uint32_t)__cvta_generic_to_shared(vsm);
    int apr[2];
#pragma unroll
    for (int mi = 0; mi < 2; mi++) apr[mi] = mW + (mi << 4) + ((lm & 1) << 3) + lrow;
    int aco = (lm >> 1) << 2;
    int bvr[5];
#pragma unroll
    for (int np = 0; np < 5; np++) bvr[np] = nW + (np << 4) + ((lm >> 1) << 3) + lrow;
    int bco = (lm & 1) << 2;

    float oa[2][10][4];
#pragma unroll
    for (int a = 0; a < 2; a++)
#pragma unroll
        for (int b = 0; b < 10; b++)
#pragma unroll
            for (int c = 0; c < 4; c++) oa[a][b][c] = 0.f;
#pragma unroll
    for (int kst = 0; kst < 5; kst++) {
        int ka0 = kst * 8;
        uint32_t af[2][4], bf[10][2];
#pragma unroll
        for (int mi = 0; mi < 2; mi++)
            ldsm4(af[mi], sbP + ((uint32_t)(apr[mi] * PSTU + ka0 + aco) << 2));
#pragma unroll
        for (int np = 0; np < 5; np++) {
            uint32_t r4[4];
            ldsm4(r4, sbV + ((uint32_t)(bvr[np] * PSTU + ka0 + bco) << 2));
            bf[np * 2][0] = r4[0]; bf[np * 2][1] = r4[1];
            bf[np * 2 + 1][0] = r4[2]; bf[np * 2 + 1][1] = r4[3];
        }
#pragma unroll
        for (int mi = 0; mi < 2; mi++)
#pragma unroll
            for (int ni = 0; ni < 10; ni++) mma16(oa[mi][ni], af[mi], bf[ni]);
    }
#pragma unroll
    for (int mi = 0; mi < 2; mi++)
#pragma unroll
        for (int hf = 0; hf < 2; hf++) {
            int g = q0 + mW + mi * 16 + (lane >> 2) + hf * 8;
            __half* orow = g_pre + ((size_t)stream * SQ + g) * CHN + h * HD;
#pragma unroll
            for (int ni = 0; ni < 10; ni++) {
                int col = nW + (ni << 3) + ((lane & 3) << 1);
                *(uint32_t*)(orow + col) = pk2(oa[mi][ni][hf * 2], oa[mi][ni][hf * 2 + 1]);
            }
        }
}

// ---------------- per-instance gate max ----------------
__global__ void mmax_k() {
    __shared__ float red[256];
    int i = blockIdx.x;
    float mx = 0.f;
    const float* p = g_mraw + (size_t)i * NHEAD * SQ;
    for (int idx = threadIdx.x; idx < NHEAD * SQ; idx += 256) mx = fmaxf(mx, p[idx]);
    red[threadIdx.x] = mx;
    __syncthreads();
    for (int s = 128; s > 0; s >>= 1) {
        if (threadIdx.x < s) red[threadIdx.x] = fmaxf(red[threadIdx.x], red[threadIdx.x + s]);
        __syncthreads();
    }
    if (threadIdx.x == 0) g_mmax[i] = red[0];
}

// ============ fully fused local attention (LDSM) ============
__global__ void __launch_bounds__(256) fused_l2_k() {
    extern __shared__ __align__(16) uint32_t smu[];
    uint32_t* plm = smu;
    uint32_t* vsm = smu + 64 * PLU;
    float* smx = (float*)(smu + 64 * PLU + 160 * VLU);
    float* ssu = smx + 256;

    int z = blockIdx.y;
    int inst = z >> 3, h = z & 7;
    int q0 = blockIdx.x << 6;
    int tid = threadIdx.x, lane = tid & 31, warp = tid >> 5;

    const __half* Qb  = g_q2 + (size_t)SQ * CHN + (size_t)q0 * CHN + h * HD;
    const __half* Klb = g_kl + (size_t)inst * LLOC * CHN + h * HD;
    const __half* Vt  = g_vlT + (size_t)inst * CHN * LLOCP + (size_t)h * HD * LLOCP;

    uint32_t* strm = vsm;
    auto issueQK = [&](int st, int kt) {
        int k0 = kt << 5;
        uint32_t* base = strm + st * 5632;
        {
            int r = tid >> 2, cu = (tid & 3) << 2;
            cp16(base + SWOFF(r, cu), Qb + (size_t)r * CHN + k0 + (cu << 1), true);
        }
        for (int u = tid; u < 1152; u += 256) {
            int r = u >> 2, cu = (u & 3) << 2;
            int kr = (r < LLOC) ? r : (LLOC - 1);
            cp16(base + 1024 + SWOFF(r, cu), Klb + (size_t)kr * CHN + k0 + (cu << 1), true);
        }
        CP_COMMIT;
    };
    issueQK(0, 0);

    int mW2 = (warp >> 2) << 5;
    int nW4 = (warp & 3) * 72;
    int lrow = lane & 7, lm = lane >> 3;
    int aqr[2], aqx[2];
#pragma unroll
    for (int mi = 0; mi < 2; mi++) {
        aqr[mi] = mW2 + (mi << 4) + ((lm & 1) << 3) + lrow;
        aqx[mi] = (aqr[mi] >> 1) & 3;
    }
    int achk = lm >> 1;
    int bkr[4], bkx[4];
#pragma unroll
    for (int np = 0; np < 4; np++) {
        bkr[np] = nW4 + (np << 4) + ((lm >> 1) << 3) + lrow;
        bkx[np] = (bkr[np] >> 1) & 3;
    }
    int bchk = lm & 1;
    int b2r = nW4 + 64 + lrow;
    int b2x = (b2r >> 1) & 3;
    int b2c = (lane >> 3) & 1;
    uint32_t sbS = (uint32_t)__cvta_generic_to_shared(strm);

    float sc[2][9][4];
#pragma unroll
    for (int a = 0; a < 2; a++)
#pragma unroll
        for (int b = 0; b < 9; b++)
#pragma unroll
            for (int c = 0; c < 4; c++) sc[a][b][c] = 0.f;

    for (int kt = 0; kt < 5; kt++) {
        if (kt < 4) { issueQK((kt + 1) & 1, kt + 1); CP_WAIT1; }
        else        { CP_WAIT0; }
        __syncthreads();
        uint32_t stQ = sbS + (kt & 1) * 22528;            // 5632 u32
        uint32_t stK = stQ + 4096;                        // +1024 u32
#pragma unroll
        for (int kk = 0; kk < 2; kk++) {
            uint32_t af[2][4], bf[9][2];
#pragma unroll
            for (int mi = 0; mi < 2; mi++) {
                uint32_t au = (uint32_t)(aqr[mi] << 4) + ((((kk << 1) + achk) ^ aqx[mi]) << 2);
                ldsm4(af[mi], stQ + (au << 2));
            }
#pragma unroll
            for (int np = 0; np < 4; np++) {
                uint32_t bu = (uint32_t)(bkr[np] << 4) + ((((kk << 1) + bchk) ^ bkx[np]) << 2);
                uint32_t r4[4];
                ldsm4(r4, stK + (bu << 2));
                bf[np * 2][0] = r4[0]; bf[np * 2][1] = r4[1];
                bf[np * 2 + 1][0] = r4[2]; bf[np * 2 + 1][1] = r4[3];
            }
            {
                uint32_t bu = (uint32_t)(b2r << 4) + ((((kk << 1) + b2c) ^ b2x) << 2);
                uint32_t r2[2];
                ldsm2(r2, stK + (bu << 2));
                bf[8][0] = r2[0]; bf[8][1] = r2[1];
            }
#pragma unroll
            for (int mi = 0; mi < 2; mi++)
#pragma unroll
                for (int ni = 0; ni < 9; ni++) mma16(sc[mi][ni], af[mi], bf[ni]);
        }
        __syncthreads();
    }

    for (int u = tid; u < 160 * 34; u += 256) {
        int d = u / 34, c = u % 34;
        cp16(vsm + d * VLU + c * 4, Vt + (size_t)d * LLOCP + c * 8, true);
    }
    CP_COMMIT;

    const float scale = 0.07905694150420949f;
    float gden = 0.5f / g_mmax[inst];
#pragma unroll
    for (int mi = 0; mi < 2; mi++)
#pragma unroll
        for (int hf = 0; hf < 2; hf++) {
            int row = mW2 + mi * 16 + (lane >> 2) + hf * 8;
            float mx = -1e30f;
#pragma unroll
            for (int ni = 0; ni < 9; ni++)
#pragma unroll
                for (int c = 0; c < 2; c++) {
                    int col = nW4 + ni * 8 + ((lane & 3) << 1) + c;
                    if (col < LLOC) mx = fmaxf(mx, sc[mi][ni][hf * 2 + c]);
                }
            mx = fmaxf(mx, __shfl_xor_sync(0xffffffffu, mx, 1));
            mx = fmaxf(mx, __shfl_xor_sync(0xffffffffu, mx, 2));
            if ((lane & 3) == 0) smx[row * 4 + (warp & 3)] = mx;
        }
    __syncthreads();
#pragma unroll
    for (int mi = 0; mi < 2; mi++)
#pragma unroll
        for (int hf = 0; hf < 2; hf++) {
            int row = mW2 + mi * 16 + (lane >> 2) + hf * 8;
            float m = fmaxf(fmaxf(smx[row * 4], smx[row * 4 + 1]),
                            fmaxf(smx[row * 4 + 2], smx[row * 4 + 3]));
            float s = 0.f;
#pragma unroll
            for (int ni = 0; ni < 9; ni++)
#pragma unroll
                for (int c = 0; c < 2; c++) {
                    int col = nW4 + ni * 8 + ((lane & 3) << 1) + c;
                    float e = (col < LLOC) ? __expf((sc[mi][ni][hf * 2 + c] - m) * scale) : 0.f;
                    sc[mi][ni][hf * 2 + c] = e;
                    s += e;
                }
            s += __shfl_xor_sync(0xffffffffu, s, 1);
            s += __shfl_xor_sync(0xffffffffu, s, 2);
            if ((lane & 3) == 0) ssu[row * 4 + (warp & 3)] = s;
        }
    __syncthreads();
#pragma unroll
    for (int mi = 0; mi < 2; mi++)
#pragma unroll
        for (int hf = 0; hf < 2; hf++) {
            int row = mW2 + mi * 16 + (lane >> 2) + hf * 8;
            float s = ssu[row * 4] + ssu[row * 4 + 1] + ssu[row * 4 + 2] + ssu[row * 4 + 3];
            float f = g_mraw[(size_t)z * SQ + q0 + row] * gden / s;
#pragma unroll
            for (int ni = 0; ni < 9; ni++) {
                int ucol = (nW4 >> 1) + ni * 4 + (lane & 3);
                if (ucol < 136)
                    plm[row * PLU + ucol] = pk2(sc[mi][ni][hf * 2] * f, sc[mi][ni][hf * 2 + 1] * f);
            }
        }
    CP_WAIT0;
    __syncthreads();

    // PV with LDSM on unswizzled stride-140 arrays
    int nW = (warp & 3) * 40;
    uint32_t sbP = (uint32_t)__cvta_generic_to_shared(plm);
    uint32_t sbV = (uint32_t)__cvta_generic_to_shared(vsm);
    int apr[2];
#pragma unroll
    for (int mi = 0; mi < 2; mi++) apr[mi] = mW2 + (mi << 4) + ((lm & 1) << 3) + lrow;
    int aco = (lm >> 1) << 2;
    int bvr[2];
#pragma unroll
    for (int np = 0; np < 2; np++) bvr[np] = nW + (np << 4) + ((lm >> 1) << 3) + lrow;
    int bco = (lm & 1) << 2;
    int v2r = nW + 32 + lrow;
    int v2c = ((lane >> 3) & 1) << 2;

    float oa[2][5][4];
#pragma unroll
    for (int a = 0; a < 2; a++)
#pragma unroll
        for (int b = 0; b < 5; b++)
#pragma unroll
            for (int c = 0; c < 4; c++) oa[a][b][c] = 0.f;

#pragma unroll 1
    for (int ch = 0; ch < 17; ch++) {
        int ka0 = ch * 8;
        uint32_t af[2][4], bf[5][2];
#pragma unroll
        for (int mi = 0; mi < 2; mi++)
            ldsm4(af[mi], sbP + ((uint32_t)(apr[mi] * PLU + ka0 + aco) << 2));
#pragma unroll
        for (int np = 0; np < 2; np++) {
            uint32_t r4[4];
            ldsm4(r4, sbV + ((uint32_t)(bvr[np] * VLU + ka0 + bco) << 2));
            bf[np * 2][0] = r4[0]; bf[np * 2][1] = r4[1];
            bf[np * 2 + 1][0] = r4[2]; bf[np * 2 + 1][1] = r4[3];
        }
        {
            uint32_t r2[2];
            ldsm2(r2, sbV + ((uint32_t)(v2r * VLU + ka0 + v2c) << 2));
            bf[4][0] = r2[0]; bf[4][1] = r2[1];
        }
#pragma unroll
        for (int mi = 0; mi < 2; mi++)
#pragma unroll
            for (int ni = 0; ni < 5; ni++) mma16(oa[mi][ni], af[mi], bf[ni]);
    }

#pragma unroll
    for (int mi = 0; mi < 2; mi++)
#pragma unroll
        for (int hf = 0; hf < 2; hf++) {
            int g = q0 + mW2 + mi * 16 + (lane >> 2) + hf * 8;
            __half* prow = g_pre + ((size_t)(inst + 1) * SQ + g) * CHN + h * HD;
#pragma unroll
            for (int ni = 0; ni < 5; ni++) {
                int col = nW + (ni << 3) + ((lane & 3) << 1);
                __half2 old = *(__half2*)(prow + col);
                float o0 = 0.5f * __half2float(old.x) + oa[mi][ni][hf * 2];
                float o1 = 0.5f * __half2float(old.y) + oa[mi][ni][hf * 2 + 1];
                *(uint32_t*)(prow + col) = pk2(o0, o1);
            }
        }
}

// ---------------- fuser premix ----------------
__global__ void premix_k(const float* __restrict__ bbox) {
    int s = blockIdx.x;
    int y = s >> 6, x = s & 63;
    float wgt[8];
    wgt[0] = 1.f;
    float sw = 1.f;
    const int off[4] = {3, 4, 11, 12};
#pragma unroll
    for (int i = 0; i < 7; i++) {
        float wmin = floorf(1024.f * bbox[i * 4 + 0]);
        float hmin = floorf(1024.f * bbox[i * 4 + 1]);
        float wmax = floorf(1024.f * bbox[i * 4 + 2]);
        float hmax = floorf(1024.f * bbox[i * 4 + 3]);
        float R = 0.f, Cv = 0.f;
#pragma unroll
        for (int j = 0; j < 4; j++) {
            float yy = (float)(16 * y + off[j]);
            float xx = (float)(16 * x + off[j]);
            if (yy >= hmin && yy < hmax) R += 0.25f;
            if (xx >= wmin && xx < wmax) Cv += 0.25f;
        }
        float g = 10.f * R * Cv;
        wgt[i + 1] = g;
        sw += g;
    }
    if (threadIdx.x == 0) g_sumw[s] = sw;
    for (int c = threadIdx.x; c < CHN; c += 256) {
        float acc = 0.f;
#pragma unroll
        for (int j = 0; j < 8; j++)
            acc += wgt[j] * __half2float(g_pre[((size_t)(1 + j) * SQ + s) * CHN + c]);
        g_mix[(size_t)s * CHN + c] = __float2half_rn(acc);
    }
}

// ---------------- final ----------------
__global__ void final_k(const float* __restrict__ bout, float* __restrict__ out) {
    int s = blockIdx.x;
    float sw = g_sumw[s];
    float den = 1.f / (sw + 1e-6f);
    for (int c = threadIdx.x; c < CHN; c += 256) {
        float b = bout[c];
        out[(size_t)s * CHN + c] = g_out2[(size_t)s * CHN + c] + b;
        out[(size_t)(SQ + s) * CHN + c] = (g_out2[(size_t)(SQ + s) * CHN + c] + b * sw) * den;
    }
}

// ---------------- launch ----------------
extern "C" void kernel_launch(void* const* d_in, const int* in_sizes, int n_in,
                              void* d_out, int out_size) {
    const float* hs   = (const float*)d_in[0];
    const float* ctx  = (const float*)d_in[1];
    const float* lf   = (const float*)d_in[2];
    const float* bbox = (const float*)d_in[3];
    const float* Wq   = (const float*)d_in[4];
    const float* Wk   = (const float*)d_in[5];
    const float* Wv   = (const float*)d_in[6];
    const float* Wkg  = (const float*)d_in[7];
    const float* Wvg  = (const float*)d_in[8];
    const float* Wkl  = (const float*)d_in[9];
    const float* Wvl  = (const float*)d_in[10];
    const float* Wout = (const float*)d_in[11];
    const float* bout = (const float*)d_in[12];
    const int*   lidx = (const int*)d_in[13];
    float* out = (float*)d_out;

    __half *hsH, *ctxH, *lfH, *WqT, *WkT, *WvT, *WkgT, *WvgT, *WklT, *WvlT, *WoutT;
    __half *vp, *vTp, *vlp, *vlTp;
    cudaGetSymbolAddress((void**)&hsH, g_hsH);
    cudaGetSymbolAddress((void**)&ctxH, g_ctxH);
    cudaGetSymbolAddress((void**)&lfH, g_lfH);
    cudaGetSymbolAddress((void**)&WqT, g_WqT);
    cudaGetSymbolAddress((void**)&WkT, g_WkT);
    cudaGetSymbolAddress((void**)&WvT, g_WvT);
    cudaGetSymbolAddress((void**)&WkgT, g_WkgT);
    cudaGetSymbolAddress((void**)&WvgT, g_WvgT);
    cudaGetSymbolAddress((void**)&WklT, g_WklT);
    cudaGetSymbolAddress((void**)&WvlT, g_WvlT);
    cudaGetSymbolAddress((void**)&WoutT, g_WoutT);
    cudaGetSymbolAddress((void**)&vp, g_v);
    cudaGetSymbolAddress((void**)&vTp, g_vT);
    cudaGetSymbolAddress((void**)&vlp, g_vl);
    cudaGetSymbolAddress((void**)&vlTp, g_vlT);

    const int smemA = (2 * 2048 * 2 + 128 * PSTU + 160 * PSTU + 512) * 4;
    const int smemL = (64 * PLU + 160 * VLU + 512) * 4;
    cudaFuncSetAttribute(fused_g_k, cudaFuncAttributeMaxDynamicSharedMemorySize, smemA);
    cudaFuncSetAttribute(fused_l2_k, cudaFuncAttributeMaxDynamicSharedMemorySize, smemL);
    cudaFuncSetAttribute(gemm_h, cudaFuncAttributeMaxDynamicSharedMemorySize, SMEM3);

    cudaStream_t sA = g_si.sA, sB = g_si.sB, sC = g_si.sC;
    dim3 tb(32, 8);

    setup_k<<<1, 32>>>();
    cudaEventRecord(g_si.evRoot, 0);
    cudaStreamWaitEvent(sA, g_si.evRoot, 0);
    cudaStreamWaitEvent(sB, g_si.evRoot, 0);
    cudaStreamWaitEvent(sC, g_si.evRoot, 0);

    long long nHs = 2LL * SQ * CHN, nCtx = (long long)NST * NCTX * CC, nLf = (long long)NSTR * LLOC * CC;

    // main track
    round_h<<<(int)((nHs / 8 + 255) / 256), 256>>>(hs, hsH, nHs);
    transpose_k<float><<<dim3(40, 40, 1), tb>>>(Wq, WqT, CHN, CHN, CHN, CHN, 0, 0);
    gemm_h<<<dim3(10, 64, 1), 256, SMEM3>>>(0, CHN, CHN, CHN, CHN, CHN, 1);

    // track A
    round_h<<<(int)((nCtx / 8 + 255) / 256), 256, 0, sA>>>(ctx, ctxH, nCtx);
    transpose_k<float><<<dim3(40, 24, 1), tb, 0, sA>>>(Wk, WkT, CC, CHN, CHN, CC, 0, 0);
    transpose_k<float><<<dim3(40, 24, 1), tb, 0, sA>>>(Wv, WvT, CC, CHN, CHN, CC, 0, 0);
    transpose_k<float><<<dim3(40, 24, 1), tb, 0, sA>>>(Wkg, WkgT, CC, CHN, CHN, CC, 0, 0);
    transpose_k<float><<<dim3(40, 24, 1), tb, 0, sA>>>(Wvg, WvgT, CC, CHN, CHN, CC, 0, 0);
    gemm_h<<<dim3(10, 6, 4), 256, SMEM3, sA>>>(1, CHN, CC, CC, CC, CHN, 1);
    kv_select_k<<<(NSTR * NCTX * CHN / 2 + 255) / 256, 256, 0, sA>>>(lidx);
    transpose_k<__half><<<dim3(40, 3, NST), tb, 0, sA>>>(vp, vTp, NCTX, CHN, CHN, NCTXP,
                                                         (long long)NCTX * CHN, (long long)CHN * NCTXP);
    cudaEventRecord(g_si.ev1, sA);

    // track B
    round_h<<<(int)((nLf / 8 + 255) / 256), 256, 0, sB>>>(lf, lfH, nLf);
    transpose_k<float><<<dim3(40, 24, 1), tb, 0, sB>>>(Wkl, WklT, CC, CHN, CHN, CC, 0, 0);
    transpose_k<float><<<dim3(40, 24, 1), tb, 0, sB>>>(Wvl, WvlT, CC, CHN, CHN, CC, 0, 0);
    gemm_h<<<dim3(10, 17, 2), 256, SMEM3, sB>>>(5, CHN, CC, CC, CC, CHN, 1);
    transpose_k<__half><<<dim3(40, 9, NSTR), tb, 0, sB>>>(vlp, vlTp, LLOC, CHN, CHN, LLOCP,
                                                          (long long)LLOC * CHN, (long long)CHN * LLOCP);
    cudaEventRecord(g_si.ev2, sB);

    // track C
    transpose_k<float><<<dim3(40, 40, 1), tb, 0, sC>>>(Wout, WoutT, CHN, CHN, CHN, CHN, 0, 0);
    cudaEventRecord(g_si.ev3, sC);

    // global attention
    cudaStreamWaitEvent(0, g_si.ev1, 0);
    fused_g_k<<<dim3(32, 72), 256, smemA>>>(lidx);
    mmax_k<<<8, 256>>>();
    cudaEventRecord(g_si.evG, 0);

    // uncond out-projection concurrent with local attention
    cudaStreamWaitEvent(sA, g_si.evG, 0);
    cudaStreamWaitEvent(sA, g_si.ev3, 0);
    gemm_h<<<dim3(10, 32, 1), 256, SMEM3, sA>>>(7, CHN, CHN, CHN, CHN, CHN, 0);
    cudaEventRecord(g_si.evO7, sA);

    // local attention
    cudaStreamWaitEvent(0, g_si.ev2, 0);
    fused_l2_k<<<dim3(64, 64), 256, smemL>>>();

    // premix + cond out-projection
    premix_k<<<SQ, 256>>>(bbox);
    cudaStreamWaitEvent(0, g_si.ev3, 0);
    gemm_h<<<dim3(10, 32, 1), 256, SMEM3>>>(8, CHN, CHN, CHN, CHN, CHN, 0);
    cudaStreamWaitEvent(0, g_si.evO7, 0);
    final_k<<<SQ, 256>>>(bout, out);
}

// round 14
// speedup vs baseline: 2.7328x; 1.0101x over previous
#include <cuda_runtime.h>
#include <cuda_fp16.h>
#include <math.h>
#include <stdint.h>

#define SQ 4096
#define CHN 1280
#define CC 768
#define NHEAD 8
#define HD 160
#define NCTX 77
#define NCTXP 80
#define NST 9
#define NSTR 8
#define LLOC 257
#define LLOCP 272
#define PSTU 44
#define PLU 140
#define VLU 140
#define SMEM3 (3 * 2048 * 2 * 4)

// ---------------- scratch ----------------
__device__ __align__(256) __half g_hsH[2 * SQ * CHN];
__device__ __align__(256) __half g_ctxH[NST * NCTX * CC];
__device__ __align__(256) __half g_lfH[NSTR * LLOC * CC];
__device__ __align__(256) __half g_q2[2 * SQ * CHN];
__device__ __align__(256) __half g_k[NST * NCTX * CHN];
__device__ __align__(256) __half g_v[NST * NCTX * CHN];
__device__ __align__(256) __half g_kg[NSTR * NCTX * CHN];
__device__ __align__(256) __half g_vg[NSTR * NCTX * CHN];
__device__ __align__(256) __half g_kl[NSTR * LLOC * CHN];
__device__ __align__(256) __half g_vl[NSTR * LLOC * CHN];
__device__ __align__(256) __half g_WqT[CHN * CHN];
__device__ __align__(256) __half g_WkT[CHN * CC];
__device__ __align__(256) __half g_WvT[CHN * CC];
__device__ __align__(256) __half g_WkgT[CHN * CC];
__device__ __align__(256) __half g_WvgT[CHN * CC];
__device__ __align__(256) __half g_WklT[CHN * CC];
__device__ __align__(256) __half g_WvlT[CHN * CC];
__device__ __align__(256) __half g_WoutT[CHN * CHN];
__device__ __align__(256) __half g_vT[NST * CHN * NCTXP];
__device__ __align__(256) __half g_vlT[NSTR * CHN * LLOCP];
__device__ __align__(256) __half g_pre[NST * SQ * CHN];
__device__ __align__(256) __half g_mix[SQ * CHN];
__device__ float g_mraw[NSTR * NHEAD * SQ];
__device__ float g_mmax[NSTR];
__device__ float g_sumw[SQ];

__device__ const __half* d_Ap[16];
__device__ const __half* d_Bp[16];
__device__ void*         d_Cp[16];
__device__ int           d_Mt[16];

// ---------------- streams/events ----------------
struct StreamInit {
    cudaStream_t sA, sB, sC;
    cudaEvent_t evRoot, ev1, ev2, ev3, evG, evO7;
    StreamInit() {
        cudaStreamCreateWithFlags(&sA, cudaStreamNonBlocking);
        cudaStreamCreateWithFlags(&sB, cudaStreamNonBlocking);
        cudaStreamCreateWithFlags(&sC, cudaStreamNonBlocking);
        cudaEventCreateWithFlags(&evRoot, cudaEventDisableTiming);
        cudaEventCreateWithFlags(&ev1, cudaEventDisableTiming);
        cudaEventCreateWithFlags(&ev2, cudaEventDisableTiming);
        cudaEventCreateWithFlags(&ev3, cudaEventDisableTiming);
        cudaEventCreateWithFlags(&evG, cudaEventDisableTiming);
        cudaEventCreateWithFlags(&evO7, cudaEventDisableTiming);
    }
};
static StreamInit g_si;

// ---------------- helpers ----------------
__device__ __forceinline__ uint32_t pk2(float a, float b) {
    __half2 h = __halves2half2(__float2half_rn(a), __float2half_rn(b));
    return *(uint32_t*)&h;
}
__device__ __forceinline__ void cp16(void* sdst, const void* gsrc, bool p) {
    uint32_t sa = (uint32_t)__cvta_generic_to_shared(sdst);
    int sz = p ? 16 : 0;
    asm volatile("cp.async.cg.shared.global [%0], [%1], 16, %2;" :: "r"(sa), "l"(gsrc), "r"(sz));
}
#define CP_COMMIT asm volatile("cp.async.commit_group;")
#define CP_WAIT0 asm volatile("cp.async.wait_group 0;")
#define CP_WAIT1 asm volatile("cp.async.wait_group 1;")
__device__ __forceinline__ void mma16(float* c, const uint32_t* a, const uint32_t* b) {
    asm volatile(
        "mma.sync.aligned.m16n8k16.row.col.f32.f16.f16.f32 "
        "{%0,%1,%2,%3}, {%4,%5,%6,%7}, {%8,%9}, {%0,%1,%2,%3};"
        : "+f"(c[0]), "+f"(c[1]), "+f"(c[2]), "+f"(c[3])
        : "r"(a[0]), "r"(a[1]), "r"(a[2]), "r"(a[3]), "r"(b[0]), "r"(b[1]));
}
__device__ __forceinline__ void ldsm4(uint32_t* r, uint32_t addr) {
    asm volatile("ldmatrix.sync.aligned.m8n8.x4.shared.b16 {%0,%1,%2,%3}, [%4];"
                 : "=r"(r[0]), "=r"(r[1]), "=r"(r[2]), "=r"(r[3]) : "r"(addr));
}
__device__ __forceinline__ void ldsm2(uint32_t* r, uint32_t addr) {
    asm volatile("ldmatrix.sync.aligned.m8n8.x2.shared.b16 {%0,%1}, [%2];"
                 : "=r"(r[0]), "=r"(r[1]) : "r"(addr));
}
#define SWOFF(r, c) (((r) << 4) + ((((((c) >> 2) ^ (((r) >> 1) & 3))) << 2) | ((c) & 3)))

// ---------------- setup ----------------
__global__ void setup_k(float* out) {
    if (threadIdx.x == 0) {
        d_Ap[0] = g_hsH;               d_Bp[0] = g_WqT;   d_Cp[0] = g_q2;    d_Mt[0] = 2 * SQ;
        d_Ap[1] = g_ctxH;              d_Bp[1] = g_WkT;   d_Cp[1] = g_k;     d_Mt[1] = NST * NCTX;
        d_Ap[2] = g_ctxH;              d_Bp[2] = g_WvT;   d_Cp[2] = g_v;     d_Mt[2] = NST * NCTX;
        d_Ap[3] = g_ctxH + NCTX * CC;  d_Bp[3] = g_WkgT;  d_Cp[3] = g_kg;    d_Mt[3] = NSTR * NCTX;
        d_Ap[4] = g_ctxH + NCTX * CC;  d_Bp[4] = g_WvgT;  d_Cp[4] = g_vg;    d_Mt[4] = NSTR * NCTX;
        d_Ap[5] = g_lfH;               d_Bp[5] = g_WklT;  d_Cp[5] = g_kl;    d_Mt[5] = NSTR * LLOC;
        d_Ap[6] = g_lfH;               d_Bp[6] = g_WvlT;  d_Cp[6] = g_vl;    d_Mt[6] = NSTR * LLOC;
        d_Ap[7] = g_pre;               d_Bp[7] = g_WoutT; d_Cp[7] = out;     d_Mt[7] = SQ;
        d_Ap[8] = g_mix;               d_Bp[8] = g_WoutT; d_Cp[8] = out + (size_t)SQ * CHN;
        d_Mt[8] = SQ;
    }
}

// ---------------- round inputs to fp16 ----------------
__global__ void round_h(const float* __restrict__ src, __half* __restrict__ dst, long long n) {
    long long i = ((long long)blockIdx.x * blockDim.x + threadIdx.x) * 8;
    if (i + 7 < n) {
        float4 a = *(const float4*)(src + i);
        float4 b = *(const float4*)(src + i + 4);
        uint4 u;
        u.x = pk2(a.x, a.y); u.y = pk2(a.z, a.w);
        u.z = pk2(b.x, b.y); u.w = pk2(b.z, b.w);
        *(uint4*)(dst + i) = u;
    } else {
        for (long long j = i; j < n; j++) dst[j] = __float2half_rn(src[j]);
    }
}

// ---------------- transpose ----------------
template <typename TS>
__global__ void transpose_k(const TS* __restrict__ src, __half* __restrict__ dst,
                            int R, int C, int ldS, int ldD, long long sBS, long long dBS) {
    __shared__ float t[32][33];
    src += blockIdx.z * sBS;
    dst += blockIdx.z * dBS;
    int c0 = blockIdx.x << 5, r0 = blockIdx.y << 5;
    int tx = threadIdx.x, ty = threadIdx.y;
#pragma unroll
    for (int j = 0; j < 4; j++) {
        int rr = r0 + ty + j * 8, cc = c0 + tx;
        t[ty + j * 8][tx] = (rr < R && cc < C) ? (float)src[(size_t)rr * ldS + cc] : 0.f;
    }
    __syncthreads();
#pragma unroll
    for (int j = 0; j < 4; j++) {
        int cc = c0 + ty + j * 8, rr = r0 + tx;
        if (cc < C && rr < ldD)
            dst[(size_t)cc * ldD + rr] = __float2half_rn(t[tx][ty + j * 8]);
    }
}

// ---------------- batched NT fp16 GEMM (R8 core + fused output epilogue) ------
// mode bits: 1 = half output; 4 = add bias (float out); 8 = fuser normalize
__global__ void __launch_bounds__(256, 2) gemm_h(int slot, int N, int K,
                                                 int lda, int ldb, int ldc, int mode,
                                                 const float* __restrict__ bias) {
    extern __shared__ __align__(16) uint32_t smg[];
    uint32_t* As = smg;
    uint32_t* Bs = smg + 3 * 2048;
    const __half* Ab = d_Ap[slot + blockIdx.z];
    const __half* Bb = d_Bp[slot + blockIdx.z];
    void* Cm         = d_Cp[slot + blockIdx.z];
    const int M      = d_Mt[slot + blockIdx.z];
    int tid = threadIdx.x, lane = tid & 31, warp = tid >> 5;
    int mBase = blockIdx.y << 7, nBase = blockIdx.x << 7;
    int mW = (warp >> 2) << 6, nW = (warp & 3) << 5;
    float acc[4][4][4];
#pragma unroll
    for (int a = 0; a < 4; a++)
#pragma unroll
        for (int b = 0; b < 4; b++)
#pragma unroll
            for (int cI = 0; cI < 4; cI++) acc[a][b][cI] = 0.f;

    int KT = K >> 5;
    auto issue = [&](int st, int kt) {
        int k0 = kt << 5;
#pragma unroll
        for (int i = 0; i < 2; i++) {
            int idx = tid + (i << 8);
            int r = idx >> 2, cu = (idx & 3) << 2;
            int gr = mBase + r; bool pa = gr < M; if (!pa) gr = M - 1;
            cp16(&As[st * 2048 + SWOFF(r, cu)], Ab + (size_t)gr * lda + k0 + (cu << 1), pa);
            int gn = nBase + r; bool pb = gn < N; if (!pb) gn = N - 1;
            cp16(&Bs[st * 2048 + SWOFF(r, cu)], Bb + (size_t)gn * ldb + k0 + (cu << 1), pb);
        }
        CP_COMMIT;
    };
    issue(0, 0);
    issue(1, 1);

    int lrow = lane & 7;
    int lm = lane >> 3;
    int arow[4], axor[4];
#pragma unroll
    for (int mi = 0; mi < 4; mi++) {
        arow[mi] = mW + (mi << 4) + ((lm & 1) << 3) + lrow;
        axor[mi] = (arow[mi] >> 1) & 3;
    }
    int achk = lm >> 1;
    int brow[2], bxor[2];
#pragma unroll
    for (int np = 0; np < 2; np++) {
        brow[np] = nW + (np << 4) + ((lm >> 1) << 3) + lrow;
        bxor[np] = (brow[np] >> 1) & 3;
    }
    int bchk = lm & 1;
    uint32_t sbA = (uint32_t)__cvta_generic_to_shared(As);
    uint32_t sbB = (uint32_t)__cvta_generic_to_shared(Bs);

    for (int kt = 0; kt < KT; kt++) {
        if (kt + 1 < KT) { CP_WAIT1; } else { CP_WAIT0; }
        __syncthreads();
        if (kt + 2 < KT) issue((kt + 2) % 3, kt + 2);
        uint32_t stA = sbA + (kt % 3) * 8192;
        uint32_t stB = sbB + (kt % 3) * 8192;
#pragma unroll
        for (int kk = 0; kk < 2; kk++) {
            uint32_t af[4][4], bf[4][2];
#pragma unroll
            for (int mi = 0; mi < 4; mi++) {
                uint32_t au = (uint32_t)(arow[mi] << 4) + ((((kk << 1) + achk) ^ axor[mi]) << 2);
                ldsm4(af[mi], stA + (au << 2));
            }
#pragma unroll
            for (int np = 0; np < 2; np++) {
                uint32_t bu = (uint32_t)(brow[np] << 4) + ((((kk << 1) + bchk) ^ bxor[np]) << 2);
                uint32_t r4[4];
                ldsm4(r4, stB + (bu << 2));
                bf[np * 2][0] = r4[0]; bf[np * 2][1] = r4[1];
                bf[np * 2 + 1][0] = r4[2]; bf[np * 2 + 1][1] = r4[3];
            }
#pragma unroll
            for (int mi = 0; mi < 4; mi++)
#pragma unroll
                for (int ni = 0; ni < 4; ni++) mma16(acc[mi][ni], af[mi], bf[ni]);
        }
    }
#pragma unroll
    for (int mi = 0; mi < 4; mi++) {
#pragma unroll
        for (int half = 0; half < 2; half++) {
            int gm = mBase + mW + (mi << 4) + (lane >> 2) + half * 8;
            if (gm >= M) continue;
            float sw = 0.f, den = 0.f;
            if (mode & 8) { sw = g_sumw[gm]; den = 1.f / (sw + 1e-6f); }
#pragma unroll
            for (int ni = 0; ni < 4; ni++) {
                int gn = nBase + nW + (ni << 3) + ((lane & 3) << 1);
                if (gn + 1 >= N) continue;
                float v0 = acc[mi][ni][half * 2], v1 = acc[mi][ni][half * 2 + 1];
                if (mode & 1) {
                    __half* crow = (__half*)Cm + (size_t)gm * ldc;
                    *(uint32_t*)(crow + gn) = pk2(v0, v1);
                } else {
                    float* crow = (float*)Cm + (size_t)gm * ldc;
                    if (mode & 4) {
                        float b0 = bias[gn], b1 = bias[gn + 1];
                        if (mode & 8) {
                            v0 = (v0 + b0 * sw) * den;
                            v1 = (v1 + b1 * sw) * den;
                        } else {
                            v0 += b0;
                            v1 += b1;
                        }
                    }
                    crow[gn] = v0;
                    crow[gn + 1] = v1;
                }
            }
        }
    }
}

// ---------------- ELITE K/V select ----------------
__global__ void kv_select_k(const int* __restrict__ lidx) {
    int idx = blockIdx.x * 256 + threadIdx.x;
    const int tot = NSTR * NCTX * CHN / 2;
    if (idx >= tot) return;
    int st = idx / (NCTX * CHN / 2);
    if (lidx[st] >= 0) {
        ((uint32_t*)g_k)[NCTX * CHN / 2 + idx] = ((const uint32_t*)g_kg)[idx];
        ((uint32_t*)g_v)[NCTX * CHN / 2 + idx] = ((const uint32_t*)g_vg)[idx];
    }
}

// ============ fused global attention (fp16, 2 CTAs/SM, LDSM) ============
__global__ void __launch_bounds__(256, 2) fused_g_k(const int* __restrict__ lidx) {
    extern __shared__ __align__(16) uint32_t smu[];
    uint32_t* qb  = smu;
    uint32_t* kb  = smu + 4096;
    uint32_t* psm = smu + 8192;
    uint32_t* vsm = psm + 128 * PSTU;
    float* smx = (float*)(vsm + 160 * PSTU);
    float* ssu = smx + 256;
    __shared__ int sidx[8];

    int bh = blockIdx.y;
    int stream = bh >> 3, h = bh & 7;
    int q0 = blockIdx.x << 7;
    int tid = threadIdx.x, lane = tid & 31, warp = tid >> 5;
    if (tid < 8) sidx[tid] = lidx[tid];

    const __half* Qb = g_q2 + (stream ? (size_t)SQ * CHN : 0) + (size_t)q0 * CHN + h * HD;
    const __half* Kb = g_k + (size_t)stream * NCTX * CHN + h * HD;
    const __half* Vt = g_vT + (size_t)stream * CHN * NCTXP + (size_t)h * HD * NCTXP;

    for (int u = tid; u < 160 * 10; u += 256) {
        int d = u / 10, c = u % 10;
        cp16(vsm + d * PSTU + c * 4, Vt + (size_t)d * NCTXP + c * 8, true);
    }
    CP_COMMIT;

    auto issueQK = [&](int st, int kt) {
        int k0 = kt << 5;
#pragma unroll
        for (int i = 0; i < 2; i++) {
            int idx = tid + (i << 8);
            int r = idx >> 2, cu = (idx & 3) << 2;
            cp16(&qb[st * 2048 + SWOFF(r, cu)], Qb + (size_t)r * CHN + k0 + (cu << 1), true);
            int kr = (r < NCTX) ? r : (NCTX - 1);
            cp16(&kb[st * 2048 + SWOFF(r, cu)], Kb + (size_t)kr * CHN + k0 + (cu << 1), true);
        }
        CP_COMMIT;
    };
    issueQK(0, 0);

    int mW = (warp >> 1) << 5;
    int nWs = (warp & 1) * 40;
    int lrow = lane & 7, lm = lane >> 3;
    int aqr[2], aqx[2];
#pragma unroll
    for (int mi = 0; mi < 2; mi++) {
        aqr[mi] = mW + (mi << 4) + ((lm & 1) << 3) + lrow;
        aqx[mi] = (aqr[mi] >> 1) & 3;
    }
    int achk = lm >> 1;
    int bkr[2], bkx[2];
#pragma unroll
    for (int np = 0; np < 2; np++) {
        bkr[np] = nWs + (np << 4) + ((lm >> 1) << 3) + lrow;
        bkx[np] = (bkr[np] >> 1) & 3;
    }
    int bchk = lm & 1;
    int b2r = nWs + 32 + lrow;
    int b2x = (b2r >> 1) & 3;
    int b2c = (lane >> 3) & 1;
    uint32_t sbQ = (uint32_t)__cvta_generic_to_shared(qb);
    uint32_t sbK = (uint32_t)__cvta_generic_to_shared(kb);

    float sc[2][5][4];
#pragma unroll
    for (int a = 0; a < 2; a++)
#pragma unroll
        for (int b = 0; b < 5; b++)
#pragma unroll
            for (int c = 0; c < 4; c++) sc[a][b][c] = 0.f;

    for (int kt = 0; kt < 5; kt++) {
        if (kt < 4) { issueQK((kt + 1) & 1, kt + 1); CP_WAIT1; }
        else        { CP_WAIT0; }
        __syncthreads();
        uint32_t stQ = sbQ + (kt & 1) * 8192;
        uint32_t stK = sbK + (kt & 1) * 8192;
#pragma unroll
        for (int kk = 0; kk < 2; kk++) {
            uint32_t af[2][4], bf[5][2];
#pragma unroll
            for (int mi = 0; mi < 2; mi++) {
                uint32_t au = (uint32_t)(aqr[mi] << 4) + ((((kk << 1) + achk) ^ aqx[mi]) << 2);
                ldsm4(af[mi], stQ + (au << 2));
            }
#pragma unroll
            for (int np = 0; np < 2; np++) {
                uint32_t bu = (uint32_t)(bkr[np] << 4) + ((((kk << 1) + bchk) ^ bkx[np]) << 2);
                uint32_t r4[4];
                ldsm4(r4, stK + (bu << 2));
                bf[np * 2][0] = r4[0]; bf[np * 2][1] = r4[1];
                bf[np * 2 + 1][0] = r4[2]; bf[np * 2 + 1][1] = r4[3];
            }
            {
                uint32_t bu = (uint32_t)(b2r << 4) + ((((kk << 1) + b2c) ^ b2x) << 2);
                uint32_t r2[2];
                ldsm2(r2, stK + (bu << 2));
                bf[4][0] = r2[0]; bf[4][1] = r2[1];
            }
#pragma unroll
            for (int mi = 0; mi < 2; mi++)
#pragma unroll
                for (int ni = 0; ni < 5; ni++) mma16(sc[mi][ni], af[mi], bf[ni]);
        }
        __syncthreads();
    }

    const float scale = 0.07905694150420949f;
    int half = warp & 1;
#pragma unroll
    for (int mi = 0; mi < 2; mi++)
#pragma unroll
        for (int hf = 0; hf < 2; hf++) {
            int row = mW + mi * 16 + (lane >> 2) + hf * 8;
            float mx = -1e30f;
#pragma unroll
            for (int ni = 0; ni < 5; ni++)
#pragma unroll
                for (int c = 0; c < 2; c++) {
                    int col = nWs + ni * 8 + ((lane & 3) << 1) + c;
                    if (col < NCTX) mx = fmaxf(mx, sc[mi][ni][hf * 2 + c]);
                }
            mx = fmaxf(mx, __shfl_xor_sync(0xffffffffu, mx, 1));
            mx = fmaxf(mx, __shfl_xor_sync(0xffffffffu, mx, 2));
            if ((lane & 3) == 0) smx[half * 128 + row] = mx;
        }
    __syncthreads();
#pragma unroll
    for (int mi = 0; mi < 2; mi++)
#pragma unroll
        for (int hf = 0; hf < 2; hf++) {
            int row = mW + mi * 16 + (lane >> 2) + hf * 8;
            float m = fmaxf(smx[row], smx[128 + row]);
            float s = 0.f;
#pragma unroll
            for (int ni = 0; ni < 5; ni++)
#pragma unroll
                for (int c = 0; c < 2; c++) {
                    int col = nWs + ni * 8 + ((lane & 3) << 1) + c;
                    float e = (col < NCTX) ? __expf((sc[mi][ni][hf * 2 + c] - m) * scale) : 0.f;
                    sc[mi][ni][hf * 2 + c] = e;
                    s += e;
                }
            s += __shfl_xor_sync(0xffffffffu, s, 1);
            s += __shfl_xor_sync(0xffffffffu, s, 2);
            if ((lane & 3) == 0) ssu[half * 128 + row] = s;
        }
    __syncthreads();
#pragma unroll
    for (int mi = 0; mi < 2; mi++)
#pragma unroll
        for (int hf = 0; hf < 2; hf++) {
            int row = mW + mi * 16 + (lane >> 2) + hf * 8;
            float inv = 1.f / (ssu[row] + ssu[128 + row]);
#pragma unroll
            for (int ni = 0; ni < 5; ni++) {
                int col = nWs + ni * 8 + ((lane & 3) << 1);
                float v0 = (col < NCTX) ? sc[mi][ni][hf * 2] * inv : 0.f;
                float v1 = (col + 1 < NCTX) ? sc[mi][ni][hf * 2 + 1] * inv : 0.f;
                psm[row * PSTU + (nWs >> 1) + ni * 4 + (lane & 3)] = pk2(v0, v1);
            }
        }
    __syncthreads();

    if (stream == 0) {
        const __half* ph = (const __half*)psm;
        for (int u = tid; u < 128 * 8; u += 256) {
            int r = u >> 3, i = u & 7;
            g_mraw[((size_t)i * NHEAD + h) * SQ + q0 + r] =
                __half2float(ph[r * (2 * PSTU) + sidx[i]]);
        }
    }

    int nW = (warp & 1) * 80;
    uint32_t sbP = (uint32_t)__cvta_generic_to_shared(psm);
    uint32_t sbV = (uint32_t)__cvta_generic_to_shared(vsm);
    int apr[2];
#pragma unroll
    for (int mi = 0; mi < 2; mi++) apr[mi] = mW + (mi << 4) + ((lm & 1) << 3) + lrow;
    int aco = (lm >> 1) << 2;
    int bvr[5];
#pragma unroll
    for (int np = 0; np < 5; np++) bvr[np] = nW + (np << 4) + ((lm >> 1) << 3) + lrow;
    int bco = (lm & 1) << 2;

    float oa[2][10][4];
#pragma unroll
    for (int a = 0; a < 2; a++)
#pragma unroll
        for (int b = 0; b < 10; b++)
#pragma unroll
            for (int c = 0; c < 4; c++) oa[a][b][c] = 0.f;
#pragma unroll
    for (int kst = 0; kst < 5; kst++) {
        int ka0 = kst * 8;
        uint32_t af[2][4], bf[10][2];
#pragma unroll
        for (int mi = 0; mi < 2; mi++)
            ldsm4(af[mi], sbP + ((uint32_t)(apr[mi] * PSTU + ka0 + aco) << 2));
#pragma unroll
        for (int np = 0; np < 5; np++) {
            uint32_t r4[4];
            ldsm4(r4, sbV + ((uint32_t)(bvr[np] * PSTU + ka0 + bco) << 2));
            bf[np * 2][0] = r4[0]; bf[np * 2][1] = r4[1];
            bf[np * 2 + 1][0] = r4[2]; bf[np * 2 + 1][1] = r4[3];
        }
#pragma unroll
        for (int mi = 0; mi < 2; mi++)
#pragma unroll
            for (int ni = 0; ni < 10; ni++) mma16(oa[mi][ni], af[mi], bf[ni]);
    }
#pragma unroll
    for (int mi = 0; mi < 2; mi++)
#pragma unroll
        for (int hf = 0; hf < 2; hf++) {
            int g = q0 + mW + mi * 16 + (lane >> 2) + hf * 8;
            __half* orow = g_pre + ((size_t)stream * SQ + g) * CHN + h * HD;
#pragma unroll
            for (int ni = 0; ni < 10; ni++) {
                int col = nW + (ni << 3) + ((lane & 3) << 1);
                *(uint32_t*)(orow + col) = pk2(oa[mi][ni][hf * 2], oa[mi][ni][hf * 2 + 1]);
            }
        }
}

// ---------------- per-instance gate max ----------------
__global__ void mmax_k() {
    __shared__ float red[256];
    int i = blockIdx.x;
    float mx = 0.f;
    const float* p = g_mraw + (size_t)i * NHEAD * SQ;
    for (int idx = threadIdx.x; idx < NHEAD * SQ; idx += 256) mx = fmaxf(mx, p[idx]);
    red[threadIdx.x] = mx;
    __syncthreads();
    for (int s = 128; s > 0; s >>= 1) {
        if (threadIdx.x < s) red[threadIdx.x] = fmaxf(red[threadIdx.x], red[threadIdx.x + s]);
        __syncthreads();
    }
    if (threadIdx.x == 0) g_mmax[i] = red[0];
}

// ============ fully fused local attention (LDSM) ============
__global__ void __launch_bounds__(256) fused_l2_k() {
    extern __shared__ __align__(16) uint32_t smu[];
    uint32_t* plm = smu;
    uint32_t* vsm = smu + 64 * PLU;
    float* smx = (float*)(smu + 64 * PLU + 160 * VLU);
    float* ssu = smx + 256;

    int z = blockIdx.y;
    int inst = z >> 3, h = z & 7;
    int q0 = blockIdx.x << 6;
    int tid = threadIdx.x, lane = tid & 31, warp = tid >> 5;

    const __half* Qb  = g_q2 + (size_t)SQ * CHN + (size_t)q0 * CHN + h * HD;
    const __half* Klb = g_kl + (size_t)inst * LLOC * CHN + h * HD;
    const __half* Vt  = g_vlT + (size_t)inst * CHN * LLOCP + (size_t)h * HD * LLOCP;

    uint32_t* strm = vsm;
    auto issueQK = [&](int st, int kt) {
        int k0 = kt << 5;
        uint32_t* base = strm + st * 5632;
        {
            int r = tid >> 2, cu = (tid & 3) << 2;
            cp16(base + SWOFF(r, cu), Qb + (size_t)r * CHN + k0 + (cu << 1), true);
        }
        for (int u = tid; u < 1152; u += 256) {
            int r = u >> 2, cu = (u & 3) << 2;
            int kr = (r < LLOC) ? r : (LLOC - 1);
            cp16(base + 1024 + SWOFF(r, cu), Klb + (size_t)kr * CHN + k0 + (cu << 1), true);
        }
        CP_COMMIT;
    };
    issueQK(0, 0);

    int mW2 = (warp >> 2) << 5;
    int nW4 = (warp & 3) * 72;
    int lrow = lane & 7, lm = lane >> 3;
    int aqr[2], aqx[2];
#pragma unroll
    for (int mi = 0; mi < 2; mi++) {
        aqr[mi] = mW2 + (mi << 4) + ((lm & 1) << 3) + lrow;
        aqx[mi] = (aqr[mi] >> 1) & 3;
    }
    int achk = lm >> 1;
    int bkr[4], bkx[4];
#pragma unroll
    for (int np = 0; np < 4; np++) {
        bkr[np] = nW4 + (np << 4) + ((lm >> 1) << 3) + lrow;
        bkx[np] = (bkr[np] >> 1) & 3;
    }
    int bchk = lm & 1;
    int b2r = nW4 + 64 + lrow;
    int b2x = (b2r >> 1) & 3;
    int b2c = (lane >> 3) & 1;
    uint32_t sbS = (uint32_t)__cvta_generic_to_shared(strm);

    float sc[2][9][4];
#pragma unroll
    for (int a = 0; a < 2; a++)
#pragma unroll
        for (int b = 0; b < 9; b++)
#pragma unroll
            for (int c = 0; c < 4; c++) sc[a][b][c] = 0.f;

    for (int kt = 0; kt < 5; kt++) {
        if (kt < 4) { issueQK((kt + 1) & 1, kt + 1); CP_WAIT1; }
        else        { CP_WAIT0; }
        __syncthreads();
        uint32_t stQ = sbS + (kt & 1) * 22528;
        uint32_t stK = stQ + 4096;
#pragma unroll
        for (int kk = 0; kk < 2; kk++) {
            uint32_t af[2][4], bf[9][2];
#pragma unroll
            for (int mi = 0; mi < 2; mi++) {
                uint32_t au = (uint32_t)(aqr[mi] << 4) + ((((kk << 1) + achk) ^ aqx[mi]) << 2);
                ldsm4(af[mi], stQ + (au << 2));
            }
#pragma unroll
            for (int np = 0; np < 4; np++) {
                uint32_t bu = (uint32_t)(bkr[np] << 4) + ((((kk << 1) + bchk) ^ bkx[np]) << 2);
                uint32_t r4[4];
                ldsm4(r4, stK + (bu << 2));
                bf[np * 2][0] = r4[0]; bf[np * 2][1] = r4[1];
                bf[np * 2 + 1][0] = r4[2]; bf[np * 2 + 1][1] = r4[3];
            }
            {
                uint32_t bu = (uint32_t)(b2r << 4) + ((((kk << 1) + b2c) ^ b2x) << 2);
                uint32_t r2[2];
                ldsm2(r2, stK + (bu << 2));
                bf[8][0] = r2[0]; bf[8][1] = r2[1];
            }
#pragma unroll
            for (int mi = 0; mi < 2; mi++)
#pragma unroll
                for (int ni = 0; ni < 9; ni++) mma16(sc[mi][ni], af[mi], bf[ni]);
        }
        __syncthreads();
    }

    for (int u = tid; u < 160 * 34; u += 256) {
        int d = u / 34, c = u % 34;
        cp16(vsm + d * VLU + c * 4, Vt + (size_t)d * LLOCP + c * 8, true);
    }
    CP_COMMIT;

    const float scale = 0.07905694150420949f;
    float gden = 0.5f / g_mmax[inst];
#pragma unroll
    for (int mi = 0; mi < 2; mi++)
#pragma unroll
        for (int hf = 0; hf < 2; hf++) {
            int row = mW2 + mi * 16 + (lane >> 2) + hf * 8;
            float mx = -1e30f;
#pragma unroll
            for (int ni = 0; ni < 9; ni++)
#pragma unroll
                for (int c = 0; c < 2; c++) {
                    int col = nW4 + ni * 8 + ((lane & 3) << 1) + c;
                    if (col < LLOC) mx = fmaxf(mx, sc[mi][ni][hf * 2 + c]);
                }
            mx = fmaxf(mx, __shfl_xor_sync(0xffffffffu, mx, 1));
            mx = fmaxf(mx, __shfl_xor_sync(0xffffffffu, mx, 2));
            if ((lane & 3) == 0) smx[row * 4 + (warp & 3)] = mx;
        }
    __syncthreads();
#pragma unroll
    for (int mi = 0; mi < 2; mi++)
#pragma unroll
        for (int hf = 0; hf < 2; hf++) {
            int row = mW2 + mi * 16 + (lane >> 2) + hf * 8;
            float m = fmaxf(fmaxf(smx[row * 4], smx[row * 4 + 1]),
                            fmaxf(smx[row * 4 + 2], smx[row * 4 + 3]));
            float s = 0.f;
#pragma unroll
            for (int ni = 0; ni < 9; ni++)
#pragma unroll
                for (int c = 0; c < 2; c++) {
                    int col = nW4 + ni * 8 + ((lane & 3) << 1) + c;
                    float e = (col < LLOC) ? __expf((sc[mi][ni][hf * 2 + c] - m) * scale) : 0.f;
                    sc[mi][ni][hf * 2 + c] = e;
                    s += e;
                }
            s += __shfl_xor_sync(0xffffffffu, s, 1);
            s += __shfl_xor_sync(0xffffffffu, s, 2);
            if ((lane & 3) == 0) ssu[row * 4 + (warp & 3)] = s;
        }
    __syncthreads();
#pragma unroll
    for (int mi = 0; mi < 2; mi++)
#pragma unroll
        for (int hf = 0; hf < 2; hf++) {
            int row = mW2 + mi * 16 + (lane >> 2) + hf * 8;
            float s = ssu[row * 4] + ssu[row * 4 + 1] + ssu[row * 4 + 2] + ssu[row * 4 + 3];
            float f = g_mraw[(size_t)z * SQ + q0 + row] * gden / s;
#pragma unroll
            for (int ni = 0; ni < 9; ni++) {
                int ucol = (nW4 >> 1) + ni * 4 + (lane & 3);
                if (ucol < 136)
                    plm[row * PLU + ucol] = pk2(sc[mi][ni][hf * 2] * f, sc[mi][ni][hf * 2 + 1] * f);
            }
        }
    CP_WAIT0;
    __syncthreads();

    int nW = (warp & 3) * 40;
    uint32_t sbP = (uint32_t)__cvta_generic_to_shared(plm);
    uint32_t sbV = (uint32_t)__cvta_generic_to_shared(vsm);
    int apr[2];
#pragma unroll
    for (int mi = 0; mi < 2; mi++) apr[mi] = mW2 + (mi << 4) + ((lm & 1) << 3) + lrow;
    int aco = (lm >> 1) << 2;
    int bvr[2];
#pragma unroll
    for (int np = 0; np < 2; np++) bvr[np] = nW + (np << 4) + ((lm >> 1) << 3) + lrow;
    int bco = (lm & 1) << 2;
    int v2r = nW + 32 + lrow;
    int v2c = ((lane >> 3) & 1) << 2;

    float oa[2][5][4];
#pragma unroll
    for (int a = 0; a < 2; a++)
#pragma unroll
        for (int b = 0; b < 5; b++)
#pragma unroll
            for (int c = 0; c < 4; c++) oa[a][b][c] = 0.f;

#pragma unroll 1
    for (int ch = 0; ch < 17; ch++) {
        int ka0 = ch * 8;
        uint32_t af[2][4], bf[5][2];
#pragma unroll
        for (int mi = 0; mi < 2; mi++)
            ldsm4(af[mi], sbP + ((uint32_t)(apr[mi] * PLU + ka0 + aco) << 2));
#pragma unroll
        for (int np = 0; np < 2; np++) {
            uint32_t r4[4];
            ldsm4(r4, sbV + ((uint32_t)(bvr[np] * VLU + ka0 + bco) << 2));
            bf[np * 2][0] = r4[0]; bf[np * 2][1] = r4[1];
            bf[np * 2 + 1][0] = r4[2]; bf[np * 2 + 1][1] = r4[3];
        }
        {
            uint32_t r2[2];
            ldsm2(r2, sbV + ((uint32_t)(v2r * VLU + ka0 + v2c) << 2));
            bf[4][0] = r2[0]; bf[4][1] = r2[1];
        }
#pragma unroll
        for (int mi = 0; mi < 2; mi++)
#pragma unroll
            for (int ni = 0; ni < 5; ni++) mma16(oa[mi][ni], af[mi], bf[ni]);
    }

#pragma unroll
    for (int mi = 0; mi < 2; mi++)
#pragma unroll
        for (int hf = 0; hf < 2; hf++) {
            int g = q0 + mW2 + mi * 16 + (lane >> 2) + hf * 8;
            __half* prow = g_pre + ((size_t)(inst + 1) * SQ + g) * CHN + h * HD;
#pragma unroll
            for (int ni = 0; ni < 5; ni++) {
                int col = nW + (ni << 3) + ((lane & 3) << 1);
                __half2 old = *(__half2*)(prow + col);
                float o0 = 0.5f * __half2float(old.x) + oa[mi][ni][hf * 2];
                float o1 = 0.5f * __half2float(old.y) + oa[mi][ni][hf * 2 + 1];
                *(uint32_t*)(prow + col) = pk2(o0, o1);
            }
        }
}

// ---------------- fuser premix ----------------
__global__ void premix_k(const float* __restrict__ bbox) {
    int s = blockIdx.x;
    int y = s >> 6, x = s & 63;
    float wgt[8];
    wgt[0] = 1.f;
    float sw = 1.f;
    const int off[4] = {3, 4, 11, 12};
#pragma unroll
    for (int i = 0; i < 7; i++) {
        float wmin = floorf(1024.f * bbox[i * 4 + 0]);
        float hmin = floorf(1024.f * bbox[i * 4 + 1]);
        float wmax = floorf(1024.f * bbox[i * 4 + 2]);
        float hmax = floorf(1024.f * bbox[i * 4 + 3]);
        float R = 0.f, Cv = 0.f;
#pragma unroll
        for (int j = 0; j < 4; j++) {
            float yy = (float)(16 * y + off[j]);
            float xx = (float)(16 * x + off[j]);
            if (yy >= hmin && yy < hmax) R += 0.25f;
            if (xx >= wmin && xx < wmax) Cv += 0.25f;
        }
        float g = 10.f * R * Cv;
        wgt[i + 1] = g;
        sw += g;
    }
    if (threadIdx.x == 0) g_sumw[s] = sw;
    for (int c = threadIdx.x; c < CHN; c += 256) {
        float acc = 0.f;
#pragma unroll
        for (int j = 0; j < 8; j++)
            acc += wgt[j] * __half2float(g_pre[((size_t)(1 + j) * SQ + s) * CHN + c]);
        g_mix[(size_t)s * CHN + c] = __float2half_rn(acc);
    }
}

// ---------------- launch ----------------
extern "C" void kernel_launch(void* const* d_in, const int* in_sizes, int n_in,
                              void* d_out, int out_size) {
    const float* hs   = (const float*)d_in[0];
    const float* ctx  = (const float*)d_in[1];
    const float* lf   = (const float*)d_in[2];
    const float* bbox = (const float*)d_in[3];
    const float* Wq   = (const float*)d_in[4];
    const float* Wk   = (const float*)d_in[5];
    const float* Wv   = (const float*)d_in[6];
    const float* Wkg  = (const float*)d_in[7];
    const float* Wvg  = (const float*)d_in[8];
    const float* Wkl  = (const float*)d_in[9];
    const float* Wvl  = (const float*)d_in[10];
    const float* Wout = (const float*)d_in[11];
    const float* bout = (const float*)d_in[12];
    const int*   lidx = (const int*)d_in[13];
    float* out = (float*)d_out;

    __half *hsH, *ctxH, *lfH, *WqT, *WkT, *WvT, *WkgT, *WvgT, *WklT, *WvlT, *WoutT;
    __half *vp, *vTp, *vlp, *vlTp;
    cudaGetSymbolAddress((void**)&hsH, g_hsH);
    cudaGetSymbolAddress((void**)&ctxH, g_ctxH);
    cudaGetSymbolAddress((void**)&lfH, g_lfH);
    cudaGetSymbolAddress((void**)&WqT, g_WqT);
    cudaGetSymbolAddress((void**)&WkT, g_WkT);
    cudaGetSymbolAddress((void**)&WvT, g_WvT);
    cudaGetSymbolAddress((void**)&WkgT, g_WkgT);
    cudaGetSymbolAddress((void**)&WvgT, g_WvgT);
    cudaGetSymbolAddress((void**)&WklT, g_WklT);
    cudaGetSymbolAddress((void**)&WvlT, g_WvlT);
    cudaGetSymbolAddress((void**)&WoutT, g_WoutT);
    cudaGetSymbolAddress((void**)&vp, g_v);
    cudaGetSymbolAddress((void**)&vTp, g_vT);
    cudaGetSymbolAddress((void**)&vlp, g_vl);
    cudaGetSymbolAddress((void**)&vlTp, g_vlT);

    const int smemA = (2 * 2048 * 2 + 128 * PSTU + 160 * PSTU + 512) * 4;
    const int smemL = (64 * PLU + 160 * VLU + 512) * 4;
    cudaFuncSetAttribute(fused_g_k, cudaFuncAttributeMaxDynamicSharedMemorySize, smemA);
    cudaFuncSetAttribute(fused_l2_k, cudaFuncAttributeMaxDynamicSharedMemorySize, smemL);
    cudaFuncSetAttribute(gemm_h, cudaFuncAttributeMaxDynamicSharedMemorySize, SMEM3);

    cudaStream_t sA = g_si.sA, sB = g_si.sB, sC = g_si.sC;
    dim3 tb(32, 8);

    setup_k<<<1, 32>>>(out);
    cudaEventRecord(g_si.evRoot, 0);
    cudaStreamWaitEvent(sA, g_si.evRoot, 0);
    cudaStreamWaitEvent(sB, g_si.evRoot, 0);
    cudaStreamWaitEvent(sC, g_si.evRoot, 0);

    long long nHs = 2LL * SQ * CHN, nCtx = (long long)NST * NCTX * CC, nLf = (long long)NSTR * LLOC * CC;

    // main track: hs -> WqT -> Q projection
    round_h<<<(int)((nHs / 8 + 255) / 256), 256>>>(hs, hsH, nHs);
    transpose_k<float><<<dim3(40, 40, 1), tb>>>(Wq, WqT, CHN, CHN, CHN, CHN, 0, 0);
    gemm_h<<<dim3(10, 64, 1), 256, SMEM3>>>(0, CHN, CHN, CHN, CHN, CHN, 1, nullptr);

    // track A: ctx -> K/V/Kg/Vg -> select -> vT
    round_h<<<(int)((nCtx / 8 + 255) / 256), 256, 0, sA>>>(ctx, ctxH, nCtx);
    transpose_k<float><<<dim3(40, 24, 1), tb, 0, sA>>>(Wk, WkT, CC, CHN, CHN, CC, 0, 0);
    transpose_k<float><<<dim3(40, 24, 1), tb, 0, sA>>>(Wv, WvT, CC, CHN, CHN, CC, 0, 0);
    transpose_k<float><<<dim3(40, 24, 1), tb, 0, sA>>>(Wkg, WkgT, CC, CHN, CHN, CC, 0, 0);
    transpose_k<float><<<dim3(40, 24, 1), tb, 0, sA>>>(Wvg, WvgT, CC, CHN, CHN, CC, 0, 0);
    gemm_h<<<dim3(10, 6, 4), 256, SMEM3, sA>>>(1, CHN, CC, CC, CC, CHN, 1, nullptr);
    kv_select_k<<<(NSTR * NCTX * CHN / 2 + 255) / 256, 256, 0, sA>>>(lidx);
    transpose_k<__half><<<dim3(40, 3, NST), tb, 0, sA>>>(vp, vTp, NCTX, CHN, CHN, NCTXP,
                                                         (long long)NCTX * CHN, (long long)CHN * NCTXP);
    cudaEventRecord(g_si.ev1, sA);

    // track B: lf -> Kl/Vl -> vlT
    round_h<<<(int)((nLf / 8 + 255) / 256), 256, 0, sB>>>(lf, lfH, nLf);
    transpose_k<float><<<dim3(40, 24, 1), tb, 0, sB>>>(Wkl, WklT, CC, CHN, CHN, CC, 0, 0);
    transpose_k<float><<<dim3(40, 24, 1), tb, 0, sB>>>(Wvl, WvlT, CC, CHN, CHN, CC, 0, 0);
    gemm_h<<<dim3(10, 17, 2), 256, SMEM3, sB>>>(5, CHN, CC, CC, CC, CHN, 1, nullptr);
    transpose_k<__half><<<dim3(40, 9, NSTR), tb, 0, sB>>>(vlp, vlTp, LLOC, CHN, CHN, LLOCP,
                                                          (long long)LLOC * CHN, (long long)CHN * LLOCP);
    cudaEventRecord(g_si.ev2, sB);

    // track C: Wout transpose
    transpose_k<float><<<dim3(40, 40, 1), tb, 0, sC>>>(Wout, WoutT, CHN, CHN, CHN, CHN, 0, 0);
    cudaEventRecord(g_si.ev3, sC);

    // global attention
    cudaStreamWaitEvent(0, g_si.ev1, 0);
    fused_g_k<<<dim3(32, 72), 256, smemA>>>(lidx);
    mmax_k<<<8, 256>>>();
    cudaEventRecord(g_si.evG, 0);

    // uncond out-projection (bias fused; writes d_out rows [0,SQ)) concurrent
    // with local attention below
    cudaStreamWaitEvent(sA, g_si.evG, 0);
    cudaStreamWaitEvent(sA, g_si.ev3, 0);
    gemm_h<<<dim3(10, 32, 1), 256, SMEM3, sA>>>(7, CHN, CHN, CHN, CHN, CHN, 4, bout);
    cudaEventRecord(g_si.evO7, sA);

    // local attention
    cudaStreamWaitEvent(0, g_si.ev2, 0);
    fused_l2_k<<<dim3(64, 64), 256, smemL>>>();

    // premix (computes g_sumw) + cond out-projection (bias+fuser fused;
    // writes d_out rows [SQ, 2*SQ))
    premix_k<<<SQ, 256>>>(bbox);
    cudaStreamWaitEvent(0, g_si.ev3, 0);
    gemm_h<<<dim3(10, 32, 1), 256, SMEM3>>>(8, CHN, CHN, CHN, CHN, CHN, 12, bout);

    // join stream A back into the capture-origin stream
    cudaStreamWaitEvent(0, g_si.evO7, 0);
}

// round 15
// speedup vs baseline: 3.0124x; 1.1023x over previous
#include <cuda_runtime.h>
#include <cuda_fp16.h>
#include <math.h>
#include <stdint.h>

#define SQ 4096
#define CHN 1280
#define CC 768
#define NHEAD 8
#define HD 160
#define NCTX 77
#define NCTXP 80
#define NST 9
#define NSTR 8
#define LLOC 257
#define LLOCP 272
#define PSTU 44
#define PLU 140
#define VLU 140
#define SMEM3 (3 * 2048 * 2 * 4)

// ---------------- scratch ----------------
__device__ __align__(256) __half g_hsH[2 * SQ * CHN];
__device__ __align__(256) __half g_ctxH[NST * NCTX * CC];
__device__ __align__(256) __half g_lfH[NSTR * LLOC * CC];
__device__ __align__(256) __half g_q2[2 * SQ * CHN];
__device__ __align__(256) __half g_k[NST * NCTX * CHN];
__device__ __align__(256) __half g_v[NST * NCTX * CHN];
__device__ __align__(256) __half g_kg[NSTR * NCTX * CHN];
__device__ __align__(256) __half g_vg[NSTR * NCTX * CHN];
__device__ __align__(256) __half g_kl[NSTR * LLOC * CHN];
__device__ __align__(256) __half g_vl[NSTR * LLOC * CHN];
__device__ __align__(256) __half g_WqT[CHN * CHN];
__device__ __align__(256) __half g_WkT[CHN * CC];
__device__ __align__(256) __half g_WvT[CHN * CC];
__device__ __align__(256) __half g_WkgT[CHN * CC];
__device__ __align__(256) __half g_WvgT[CHN * CC];
__device__ __align__(256) __half g_WklT[CHN * CC];
__device__ __align__(256) __half g_WvlT[CHN * CC];
__device__ __align__(256) __half g_WoutT[CHN * CHN];
__device__ __align__(256) __half g_vT[NST * CHN * NCTXP];
__device__ __align__(256) __half g_vlT[NSTR * CHN * LLOCP];
__device__ __align__(256) __half g_pre[NST * SQ * CHN];
__device__ __align__(256) __half g_mix[SQ * CHN];
__device__ float g_mraw[NSTR * NHEAD * SQ];
__device__ float g_mmax[NSTR];
__device__ float g_sumw[SQ];

__device__ const __half* d_Ap[16];
__device__ const __half* d_Bp[16];
__device__ void*         d_Cp[16];
__device__ int           d_Mt[16];

// ---------------- streams/events ----------------
struct StreamInit {
    cudaStream_t sA, sB, sC;
    cudaEvent_t evRoot, ev1, ev2, ev3, evG, evO7;
    StreamInit() {
        cudaStreamCreateWithFlags(&sA, cudaStreamNonBlocking);
        cudaStreamCreateWithFlags(&sB, cudaStreamNonBlocking);
        cudaStreamCreateWithFlags(&sC, cudaStreamNonBlocking);
        cudaEventCreateWithFlags(&evRoot, cudaEventDisableTiming);
        cudaEventCreateWithFlags(&ev1, cudaEventDisableTiming);
        cudaEventCreateWithFlags(&ev2, cudaEventDisableTiming);
        cudaEventCreateWithFlags(&ev3, cudaEventDisableTiming);
        cudaEventCreateWithFlags(&evG, cudaEventDisableTiming);
        cudaEventCreateWithFlags(&evO7, cudaEventDisableTiming);
    }
};
static StreamInit g_si;

// ---------------- helpers ----------------
__device__ __forceinline__ uint32_t pk2(float a, float b) {
    __half2 h = __halves2half2(__float2half_rn(a), __float2half_rn(b));
    return *(uint32_t*)&h;
}
__device__ __forceinline__ void cp16(void* sdst, const void* gsrc, bool p) {
    uint32_t sa = (uint32_t)__cvta_generic_to_shared(sdst);
    int sz = p ? 16 : 0;
    asm volatile("cp.async.cg.shared.global [%0], [%1], 16, %2;" :: "r"(sa), "l"(gsrc), "r"(sz));
}
#define CP_COMMIT asm volatile("cp.async.commit_group;")
#define CP_WAIT0 asm volatile("cp.async.wait_group 0;")
#define CP_WAIT1 asm volatile("cp.async.wait_group 1;")
__device__ __forceinline__ void mma16(float* c, const uint32_t* a, const uint32_t* b) {
    asm volatile(
        "mma.sync.aligned.m16n8k16.row.col.f32.f16.f16.f32 "
        "{%0,%1,%2,%3}, {%4,%5,%6,%7}, {%8,%9}, {%0,%1,%2,%3};"
        : "+f"(c[0]), "+f"(c[1]), "+f"(c[2]), "+f"(c[3])
        : "r"(a[0]), "r"(a[1]), "r"(a[2]), "r"(a[3]), "r"(b[0]), "r"(b[1]));
}
__device__ __forceinline__ void ldsm4(uint32_t* r, uint32_t addr) {
    asm volatile("ldmatrix.sync.aligned.m8n8.x4.shared.b16 {%0,%1,%2,%3}, [%4];"
                 : "=r"(r[0]), "=r"(r[1]), "=r"(r[2]), "=r"(r[3]) : "r"(addr));
}
__device__ __forceinline__ void ldsm2(uint32_t* r, uint32_t addr) {
    asm volatile("ldmatrix.sync.aligned.m8n8.x2.shared.b16 {%0,%1}, [%2];"
                 : "=r"(r[0]), "=r"(r[1]) : "r"(addr));
}
#define SWOFF(r, c) (((r) << 4) + ((((((c) >> 2) ^ (((r) >> 1) & 3))) << 2) | ((c) & 3)))

// ---------------- setup ----------------
__global__ void setup_k(float* out) {
    if (threadIdx.x == 0) {
        d_Ap[0] = g_hsH;               d_Bp[0] = g_WqT;   d_Cp[0] = g_q2;    d_Mt[0] = 2 * SQ;
        d_Ap[1] = g_ctxH;              d_Bp[1] = g_WkT;   d_Cp[1] = g_k;     d_Mt[1] = NST * NCTX;
        d_Ap[2] = g_ctxH;              d_Bp[2] = g_WvT;   d_Cp[2] = g_v;     d_Mt[2] = NST * NCTX;
        d_Ap[3] = g_ctxH + NCTX * CC;  d_Bp[3] = g_WkgT;  d_Cp[3] = g_kg;    d_Mt[3] = NSTR * NCTX;
        d_Ap[4] = g_ctxH + NCTX * CC;  d_Bp[4] = g_WvgT;  d_Cp[4] = g_vg;    d_Mt[4] = NSTR * NCTX;
        d_Ap[5] = g_lfH;               d_Bp[5] = g_WklT;  d_Cp[5] = g_kl;    d_Mt[5] = NSTR * LLOC;
        d_Ap[6] = g_lfH;               d_Bp[6] = g_WvlT;  d_Cp[6] = g_vl;    d_Mt[6] = NSTR * LLOC;
        d_Ap[7] = g_pre;               d_Bp[7] = g_WoutT; d_Cp[7] = out;     d_Mt[7] = SQ;
        d_Ap[8] = g_mix;               d_Bp[8] = g_WoutT; d_Cp[8] = out + (size_t)SQ * CHN;
        d_Mt[8] = SQ;
    }
}

// ---------------- round inputs to fp16 ----------------
__global__ void round_h(const float* __restrict__ src, __half* __restrict__ dst, long long n) {
    long long i = ((long long)blockIdx.x * blockDim.x + threadIdx.x) * 8;
    if (i + 7 < n) {
        float4 a = *(const float4*)(src + i);
        float4 b = *(const float4*)(src + i + 4);
        uint4 u;
        u.x = pk2(a.x, a.y); u.y = pk2(a.z, a.w);
        u.z = pk2(b.x, b.y); u.w = pk2(b.z, b.w);
        *(uint4*)(dst + i) = u;
    } else {
        for (long long j = i; j < n; j++) dst[j] = __float2half_rn(src[j]);
    }
}

// ---------------- transpose ----------------
template <typename TS>
__global__ void transpose_k(const TS* __restrict__ src, __half* __restrict__ dst,
                            int R, int C, int ldS, int ldD, long long sBS, long long dBS) {
    __shared__ float t[32][33];
    src += blockIdx.z * sBS;
    dst += blockIdx.z * dBS;
    int c0 = blockIdx.x << 5, r0 = blockIdx.y << 5;
    int tx = threadIdx.x, ty = threadIdx.y;
#pragma unroll
    for (int j = 0; j < 4; j++) {
        int rr = r0 + ty + j * 8, cc = c0 + tx;
        t[ty + j * 8][tx] = (rr < R && cc < C) ? (float)src[(size_t)rr * ldS + cc] : 0.f;
    }
    __syncthreads();
#pragma unroll
    for (int j = 0; j < 4; j++) {
        int cc = c0 + ty + j * 8, rr = r0 + tx;
        if (cc < C && rr < ldD)
            dst[(size_t)cc * ldD + rr] = __float2half_rn(t[tx][ty + j * 8]);
    }
}

// ---------------- batched NT fp16 GEMM (R8 core + fused output epilogue) ------
// mode bits: 1 = half output; 4 = add bias (float out); 8 = fuser normalize
__global__ void __launch_bounds__(256, 2) gemm_h(int slot, int N, int K,
                                                 int lda, int ldb, int ldc, int mode,
                                                 const float* __restrict__ bias) {
    extern __shared__ __align__(16) uint32_t smg[];
    uint32_t* As = smg;
    uint32_t* Bs = smg + 3 * 2048;
    const __half* Ab = d_Ap[slot + blockIdx.z];
    const __half* Bb = d_Bp[slot + blockIdx.z];
    void* Cm         = d_Cp[slot + blockIdx.z];
    const int M      = d_Mt[slot + blockIdx.z];
    int tid = threadIdx.x, lane = tid & 31, warp = tid >> 5;
    int mBase = blockIdx.y << 7, nBase = blockIdx.x << 7;
    int mW = (warp >> 2) << 6, nW = (warp & 3) << 5;
    float acc[4][4][4];
#pragma unroll
    for (int a = 0; a < 4; a++)
#pragma unroll
        for (int b = 0; b < 4; b++)
#pragma unroll
            for (int cI = 0; cI < 4; cI++) acc[a][b][cI] = 0.f;

    int KT = K >> 5;
    auto issue = [&](int st, int kt) {
        int k0 = kt << 5;
#pragma unroll
        for (int i = 0; i < 2; i++) {
            int idx = tid + (i << 8);
            int r = idx >> 2, cu = (idx & 3) << 2;
            int gr = mBase + r; bool pa = gr < M; if (!pa) gr = M - 1;
            cp16(&As[st * 2048 + SWOFF(r, cu)], Ab + (size_t)gr * lda + k0 + (cu << 1), pa);
            int gn = nBase + r; bool pb = gn < N; if (!pb) gn = N - 1;
            cp16(&Bs[st * 2048 + SWOFF(r, cu)], Bb + (size_t)gn * ldb + k0 + (cu << 1), pb);
        }
        CP_COMMIT;
    };
    issue(0, 0);
    issue(1, 1);

    int lrow = lane & 7;
    int lm = lane >> 3;
    int arow[4], axor[4];
#pragma unroll
    for (int mi = 0; mi < 4; mi++) {
        arow[mi] = mW + (mi << 4) + ((lm & 1) << 3) + lrow;
        axor[mi] = (arow[mi] >> 1) & 3;
    }
    int achk = lm >> 1;
    int brow[2], bxor[2];
#pragma unroll
    for (int np = 0; np < 2; np++) {
        brow[np] = nW + (np << 4) + ((lm >> 1) << 3) + lrow;
        bxor[np] = (brow[np] >> 1) & 3;
    }
    int bchk = lm & 1;
    uint32_t sbA = (uint32_t)__cvta_generic_to_shared(As);
    uint32_t sbB = (uint32_t)__cvta_generic_to_shared(Bs);

    for (int kt = 0; kt < KT; kt++) {
        if (kt + 1 < KT) { CP_WAIT1; } else { CP_WAIT0; }
        __syncthreads();
        if (kt + 2 < KT) issue((kt + 2) % 3, kt + 2);
        uint32_t stA = sbA + (kt % 3) * 8192;
        uint32_t stB = sbB + (kt % 3) * 8192;
#pragma unroll
        for (int kk = 0; kk < 2; kk++) {
            uint32_t af[4][4], bf[4][2];
#pragma unroll
            for (int mi = 0; mi < 4; mi++) {
                uint32_t au = (uint32_t)(arow[mi] << 4) + ((((kk << 1) + achk) ^ axor[mi]) << 2);
                ldsm4(af[mi], stA + (au << 2));
            }
#pragma unroll
            for (int np = 0; np < 2; np++) {
                uint32_t bu = (uint32_t)(brow[np] << 4) + ((((kk << 1) + bchk) ^ bxor[np]) << 2);
                uint32_t r4[4];
                ldsm4(r4, stB + (bu << 2));
                bf[np * 2][0] = r4[0]; bf[np * 2][1] = r4[1];
                bf[np * 2 + 1][0] = r4[2]; bf[np * 2 + 1][1] = r4[3];
            }
#pragma unroll
            for (int mi = 0; mi < 4; mi++)
#pragma unroll
                for (int ni = 0; ni < 4; ni++) mma16(acc[mi][ni], af[mi], bf[ni]);
        }
    }
#pragma unroll
    for (int mi = 0; mi < 4; mi++) {
#pragma unroll
        for (int half = 0; half < 2; half++) {
            int gm = mBase + mW + (mi << 4) + (lane >> 2) + half * 8;
            if (gm >= M) continue;
            float sw = 0.f, den = 0.f;
            if (mode & 8) { sw = g_sumw[gm]; den = 1.f / (sw + 1e-6f); }
#pragma unroll
            for (int ni = 0; ni < 4; ni++) {
                int gn = nBase + nW + (ni << 3) + ((lane & 3) << 1);
                if (gn + 1 >= N) continue;
                float v0 = acc[mi][ni][half * 2], v1 = acc[mi][ni][half * 2 + 1];
                if (mode & 1) {
                    __half* crow = (__half*)Cm + (size_t)gm * ldc;
                    *(uint32_t*)(crow + gn) = pk2(v0, v1);
                } else {
                    float* crow = (float*)Cm + (size_t)gm * ldc;
                    if (mode & 4) {
                        float b0 = bias[gn], b1 = bias[gn + 1];
                        if (mode & 8) {
                            v0 = (v0 + b0 * sw) * den;
                            v1 = (v1 + b1 * sw) * den;
                        } else {
                            v0 += b0;
                            v1 += b1;
                        }
                    }
                    crow[gn] = v0;
                    crow[gn + 1] = v1;
                }
            }
        }
    }
}

// ---------------- ELITE K/V select ----------------
__global__ void kv_select_k(const int* __restrict__ lidx) {
    int idx = blockIdx.x * 256 + threadIdx.x;
    const int tot = NSTR * NCTX * CHN / 2;
    if (idx >= tot) return;
    int st = idx / (NCTX * CHN / 2);
    if (lidx[st] >= 0) {
        ((uint32_t*)g_k)[NCTX * CHN / 2 + idx] = ((const uint32_t*)g_kg)[idx];
        ((uint32_t*)g_v)[NCTX * CHN / 2 + idx] = ((const uint32_t*)g_vg)[idx];
    }
}

// ============ fused global attention (fp16, 2 CTAs/SM, LDSM) ============
__global__ void __launch_bounds__(256, 2) fused_g_k(const int* __restrict__ lidx) {
    extern __shared__ __align__(16) uint32_t smu[];
    uint32_t* qb  = smu;
    uint32_t* kb  = smu + 4096;
    uint32_t* psm = smu + 8192;
    uint32_t* vsm = psm + 128 * PSTU;
    float* smx = (float*)(vsm + 160 * PSTU);
    float* ssu = smx + 256;
    __shared__ int sidx[8];

    int bh = blockIdx.y;
    int stream = bh >> 3, h = bh & 7;
    int q0 = blockIdx.x << 7;
    int tid = threadIdx.x, lane = tid & 31, warp = tid >> 5;
    if (tid < 8) sidx[tid] = lidx[tid];

    const __half* Qb = g_q2 + (stream ? (size_t)SQ * CHN : 0) + (size_t)q0 * CHN + h * HD;
    const __half* Kb = g_k + (size_t)stream * NCTX * CHN + h * HD;
    const __half* Vt = g_vT + (size_t)stream * CHN * NCTXP + (size_t)h * HD * NCTXP;

    for (int u = tid; u < 160 * 10; u += 256) {
        int d = u / 10, c = u % 10;
        cp16(vsm + d * PSTU + c * 4, Vt + (size_t)d * NCTXP + c * 8, true);
    }
    CP_COMMIT;

    auto issueQK = [&](int st, int kt) {
        int k0 = kt << 5;
#pragma unroll
        for (int i = 0; i < 2; i++) {
            int idx = tid + (i << 8);
            int r = idx >> 2, cu = (idx & 3) << 2;
            cp16(&qb[st * 2048 + SWOFF(r, cu)], Qb + (size_t)r * CHN + k0 + (cu << 1), true);
            int kr = (r < NCTX) ? r : (NCTX - 1);
            cp16(&kb[st * 2048 + SWOFF(r, cu)], Kb + (size_t)kr * CHN + k0 + (cu << 1), true);
        }
        CP_COMMIT;
    };
    issueQK(0, 0);

    int mW = (warp >> 1) << 5;
    int nWs = (warp & 1) * 40;
    int lrow = lane & 7, lm = lane >> 3;
    int aqr[2], aqx[2];
#pragma unroll
    for (int mi = 0; mi < 2; mi++) {
        aqr[mi] = mW + (mi << 4) + ((lm & 1) << 3) + lrow;
        aqx[mi] = (aqr[mi] >> 1) & 3;
    }
    int achk = lm >> 1;
    int bkr[2], bkx[2];
#pragma unroll
    for (int np = 0; np < 2; np++) {
        bkr[np] = nWs + (np << 4) + ((lm >> 1) << 3) + lrow;
        bkx[np] = (bkr[np] >> 1) & 3;
    }
    int bchk = lm & 1;
    int b2r = nWs + 32 + lrow;
    int b2x = (b2r >> 1) & 3;
    int b2c = (lane >> 3) & 1;
    uint32_t sbQ = (uint32_t)__cvta_generic_to_shared(qb);
    uint32_t sbK = (uint32_t)__cvta_generic_to_shared(kb);

    float sc[2][5][4];
#pragma unroll
    for (int a = 0; a < 2; a++)
#pragma unroll
        for (int b = 0; b < 5; b++)
#pragma unroll
            for (int c = 0; c < 4; c++) sc[a][b][c] = 0.f;

    for (int kt = 0; kt < 5; kt++) {
        if (kt < 4) { issueQK((kt + 1) & 1, kt + 1); CP_WAIT1; }
        else        { CP_WAIT0; }
        __syncthreads();
        uint32_t stQ = sbQ + (kt & 1) * 8192;
        uint32_t stK = sbK + (kt & 1) * 8192;
#pragma unroll
        for (int kk = 0; kk < 2; kk++) {
            uint32_t af[2][4], bf[5][2];
#pragma unroll
            for (int mi = 0; mi < 2; mi++) {
                uint32_t au = (uint32_t)(aqr[mi] << 4) + ((((kk << 1) + achk) ^ aqx[mi]) << 2);
                ldsm4(af[mi], stQ + (au << 2));
            }
#pragma unroll
            for (int np = 0; np < 2; np++) {
                uint32_t bu = (uint32_t)(bkr[np] << 4) + ((((kk << 1) + bchk) ^ bkx[np]) << 2);
                uint32_t r4[4];
                ldsm4(r4, stK + (bu << 2));
                bf[np * 2][0] = r4[0]; bf[np * 2][1] = r4[1];
                bf[np * 2 + 1][0] = r4[2]; bf[np * 2 + 1][1] = r4[3];
            }
            {
                uint32_t bu = (uint32_t)(b2r << 4) + ((((kk << 1) + b2c) ^ b2x) << 2);
                uint32_t r2[2];
                ldsm2(r2, stK + (bu << 2));
                bf[4][0] = r2[0]; bf[4][1] = r2[1];
            }
#pragma unroll
            for (int mi = 0; mi < 2; mi++)
#pragma unroll
                for (int ni = 0; ni < 5; ni++) mma16(sc[mi][ni], af[mi], bf[ni]);
        }
        __syncthreads();
    }

    const float scale = 0.07905694150420949f;
    int half = warp & 1;
#pragma unroll
    for (int mi = 0; mi < 2; mi++)
#pragma unroll
        for (int hf = 0; hf < 2; hf++) {
            int row = mW + mi * 16 + (lane >> 2) + hf * 8;
            float mx = -1e30f;
#pragma unroll
            for (int ni = 0; ni < 5; ni++)
#pragma unroll
                for (int c = 0; c < 2; c++) {
                    int col = nWs + ni * 8 + ((lane & 3) << 1) + c;
                    if (col < NCTX) mx = fmaxf(mx, sc[mi][ni][hf * 2 + c]);
                }
            mx = fmaxf(mx, __shfl_xor_sync(0xffffffffu, mx, 1));
            mx = fmaxf(mx, __shfl_xor_sync(0xffffffffu, mx, 2));
            if ((lane & 3) == 0) smx[half * 128 + row] = mx;
        }
    __syncthreads();
#pragma unroll
    for (int mi = 0; mi < 2; mi++)
#pragma unroll
        for (int hf = 0; hf < 2; hf++) {
            int row = mW + mi * 16 + (lane >> 2) + hf * 8;
            float m = fmaxf(smx[row], smx[128 + row]);
            float s = 0.f;
#pragma unroll
            for (int ni = 0; ni < 5; ni++)
#pragma unroll
                for (int c = 0; c < 2; c++) {
                    int col = nWs + ni * 8 + ((lane & 3) << 1) + c;
                    float e = (col < NCTX) ? __expf((sc[mi][ni][hf * 2 + c] - m) * scale) : 0.f;
                    sc[mi][ni][hf * 2 + c] = e;
                    s += e;
                }
            s += __shfl_xor_sync(0xffffffffu, s, 1);
            s += __shfl_xor_sync(0xffffffffu, s, 2);
            if ((lane & 3) == 0) ssu[half * 128 + row] = s;
        }
    __syncthreads();
#pragma unroll
    for (int mi = 0; mi < 2; mi++)
#pragma unroll
        for (int hf = 0; hf < 2; hf++) {
            int row = mW + mi * 16 + (lane >> 2) + hf * 8;
            float inv = 1.f / (ssu[row] + ssu[128 + row]);
#pragma unroll
            for (int ni = 0; ni < 5; ni++) {
                int col = nWs + ni * 8 + ((lane & 3) << 1);
                float v0 = (col < NCTX) ? sc[mi][ni][hf * 2] * inv : 0.f;
                float v1 = (col + 1 < NCTX) ? sc[mi][ni][hf * 2 + 1] * inv : 0.f;
                psm[row * PSTU + (nWs >> 1) + ni * 4 + (lane & 3)] = pk2(v0, v1);
            }
        }
    __syncthreads();

    if (stream == 0) {
        const __half* ph = (const __half*)psm;
        for (int u = tid; u < 128 * 8; u += 256) {
            int r = u >> 3, i = u & 7;
            g_mraw[((size_t)i * NHEAD + h) * SQ + q0 + r] =
                __half2float(ph[r * (2 * PSTU) + sidx[i]]);
        }
    }

    int nW = (warp & 1) * 80;
    uint32_t sbP = (uint32_t)__cvta_generic_to_shared(psm);
    uint32_t sbV = (uint32_t)__cvta_generic_to_shared(vsm);
    int apr[2];
#pragma unroll
    for (int mi = 0; mi < 2; mi++) apr[mi] = mW + (mi << 4) + ((lm & 1) << 3) + lrow;
    int aco = (lm >> 1) << 2;
    int bvr[5];
#pragma unroll
    for (int np = 0; np < 5; np++) bvr[np] = nW + (np << 4) + ((lm >> 1) << 3) + lrow;
    int bco = (lm & 1) << 2;

    float oa[2][10][4];
#pragma unroll
    for (int a = 0; a < 2; a++)
#pragma unroll
        for (int b = 0; b < 10; b++)
#pragma unroll
            for (int c = 0; c < 4; c++) oa[a][b][c] = 0.f;
#pragma unroll
    for (int kst = 0; kst < 5; kst++) {
        int ka0 = kst * 8;
        uint32_t af[2][4], bf[10][2];
#pragma unroll
        for (int mi = 0; mi < 2; mi++)
            ldsm4(af[mi], sbP + ((uint32_t)(apr[mi] * PSTU + ka0 + aco) << 2));
#pragma unroll
        for (int np = 0; np < 5; np++) {
            uint32_t r4[4];
            ldsm4(r4, sbV + ((uint32_t)(bvr[np] * PSTU + ka0 + bco) << 2));
            bf[np * 2][0] = r4[0]; bf[np * 2][1] = r4[1];
            bf[np * 2 + 1][0] = r4[2]; bf[np * 2 + 1][1] = r4[3];
        }
#pragma unroll
        for (int mi = 0; mi < 2; mi++)
#pragma unroll
            for (int ni = 0; ni < 10; ni++) mma16(oa[mi][ni], af[mi], bf[ni]);
    }
#pragma unroll
    for (int mi = 0; mi < 2; mi++)
#pragma unroll
        for (int hf = 0; hf < 2; hf++) {
            int g = q0 + mW + mi * 16 + (lane >> 2) + hf * 8;
            __half* orow = g_pre + ((size_t)stream * SQ + g) * CHN + h * HD;
#pragma unroll
            for (int ni = 0; ni < 10; ni++) {
                int col = nW + (ni << 3) + ((lane & 3) << 1);
                *(uint32_t*)(orow + col) = pk2(oa[mi][ni][hf * 2], oa[mi][ni][hf * 2 + 1]);
            }
        }
}

// ---------------- per-instance gate max ----------------
__global__ void mmax_k() {
    __shared__ float red[256];
    int i = blockIdx.x;
    float mx = 0.f;
    const float* p = g_mraw + (size_t)i * NHEAD * SQ;
    for (int idx = threadIdx.x; idx < NHEAD * SQ; idx += 256) mx = fmaxf(mx, p[idx]);
    red[threadIdx.x] = mx;
    __syncthreads();
    for (int s = 128; s > 0; s >>= 1) {
        if (threadIdx.x < s) red[threadIdx.x] = fmaxf(red[threadIdx.x], red[threadIdx.x + s]);
        __syncthreads();
    }
    if (threadIdx.x == 0) g_mmax[i] = red[0];
}

// ============ fully fused local attention: 128-row q-tiles ============
// grid (32 qtiles of 128 rows, 64 ih), 256 threads
__global__ void __launch_bounds__(256) fused_l2_k() {
    extern __shared__ __align__(16) uint32_t smu[];
    uint32_t* plm = smu;                             // 128 * PLU
    uint32_t* vsm = smu + 128 * PLU;                 // 160 * VLU (aliases QK staging)
    float* smx = (float*)(smu + 128 * PLU + 160 * VLU);  // 128 * 2
    float* ssu = smx + 256;                          // 128 * 2

    int z = blockIdx.y;
    int inst = z >> 3, h = z & 7;
    int q0 = blockIdx.x << 7;
    int tid = threadIdx.x, lane = tid & 31, warp = tid >> 5;

    const __half* Qb  = g_q2 + (size_t)SQ * CHN + (size_t)q0 * CHN + h * HD;
    const __half* Klb = g_kl + (size_t)inst * LLOC * CHN + h * HD;
    const __half* Vt  = g_vlT + (size_t)inst * CHN * LLOCP + (size_t)h * HD * LLOCP;

    // staging aliased over vsm: per stage Q 128x32h (2048 u32) + K 288x32h (4608 u32)
    uint32_t* strm = vsm;
    auto issueQK = [&](int st, int kt) {
        int k0 = kt << 5;
        uint32_t* base = strm + st * 6656;
#pragma unroll
        for (int i = 0; i < 2; i++) {
            int idx = tid + (i << 8);
            int r = idx >> 2, cu = (idx & 3) << 2;
            cp16(base + SWOFF(r, cu), Qb + (size_t)r * CHN + k0 + (cu << 1), true);
        }
        for (int u = tid; u < 1152; u += 256) {
            int r = u >> 2, cu = (u & 3) << 2;
            int kr = (r < LLOC) ? r : (LLOC - 1);
            cp16(base + 2048 + SWOFF(r, cu), Klb + (size_t)kr * CHN + k0 + (cu << 1), true);
        }
        CP_COMMIT;
    };
    issueQK(0, 0);

    int mW2 = (warp >> 1) << 5;       // 0,32,64,96
    int nW4 = (warp & 1) * 144;       // 0,144
    int lrow = lane & 7, lm = lane >> 3;
    int aqr[2], aqx[2];
#pragma unroll
    for (int mi = 0; mi < 2; mi++) {
        aqr[mi] = mW2 + (mi << 4) + ((lm & 1) << 3) + lrow;
        aqx[mi] = (aqr[mi] >> 1) & 3;
    }
    int achk = lm >> 1;
    int bkr[9], bkx[9];
#pragma unroll
    for (int np = 0; np < 9; np++) {
        bkr[np] = nW4 + (np << 4) + ((lm >> 1) << 3) + lrow;
        bkx[np] = (bkr[np] >> 1) & 3;
    }
    int bchk = lm & 1;
    uint32_t sbS = (uint32_t)__cvta_generic_to_shared(strm);

    float sc[2][18][4];
#pragma unroll
    for (int a = 0; a < 2; a++)
#pragma unroll
        for (int b = 0; b < 18; b++)
#pragma unroll
            for (int c = 0; c < 4; c++) sc[a][b][c] = 0.f;

    for (int kt = 0; kt < 5; kt++) {
        if (kt < 4) { issueQK((kt + 1) & 1, kt + 1); CP_WAIT1; }
        else        { CP_WAIT0; }
        __syncthreads();
        uint32_t stQ = sbS + (kt & 1) * 26624;        // 6656 u32 * 4
        uint32_t stK = stQ + 8192;                    // +2048 u32
#pragma unroll
        for (int kk = 0; kk < 2; kk++) {
            uint32_t af[2][4], bf[18][2];
#pragma unroll
            for (int mi = 0; mi < 2; mi++) {
                uint32_t au = (uint32_t)(aqr[mi] << 4) + ((((kk << 1) + achk) ^ aqx[mi]) << 2);
                ldsm4(af[mi], stQ + (au << 2));
            }
#pragma unroll
            for (int np = 0; np < 9; np++) {
                uint32_t bu = (uint32_t)(bkr[np] << 4) + ((((kk << 1) + bchk) ^ bkx[np]) << 2);
                uint32_t r4[4];
                ldsm4(r4, stK + (bu << 2));
                bf[np * 2][0] = r4[0]; bf[np * 2][1] = r4[1];
                bf[np * 2 + 1][0] = r4[2]; bf[np * 2 + 1][1] = r4[3];
            }
#pragma unroll
            for (int mi = 0; mi < 2; mi++)
#pragma unroll
                for (int ni = 0; ni < 18; ni++) mma16(sc[mi][ni], af[mi], bf[ni]);
        }
        __syncthreads();
    }

    // V^T load into vsm (overwrites staging; all staged reads done)
    for (int u = tid; u < 160 * 34; u += 256) {
        int d = u / 34, c = u % 34;
        cp16(vsm + d * VLU + c * 4, Vt + (size_t)d * LLOCP + c * 8, true);
    }
    CP_COMMIT;

    // register softmax (cross-warp partials over 2 warps)
    const float scale = 0.07905694150420949f;
    float gden = 0.5f / g_mmax[inst];
#pragma unroll
    for (int mi = 0; mi < 2; mi++)
#pragma unroll
        for (int hf = 0; hf < 2; hf++) {
            int row = mW2 + mi * 16 + (lane >> 2) + hf * 8;
            float mx = -1e30f;
#pragma unroll
            for (int ni = 0; ni < 18; ni++)
#pragma unroll
                for (int c = 0; c < 2; c++) {
                    int col = nW4 + ni * 8 + ((lane & 3) << 1) + c;
                    if (col < LLOC) mx = fmaxf(mx, sc[mi][ni][hf * 2 + c]);
                }
            mx = fmaxf(mx, __shfl_xor_sync(0xffffffffu, mx, 1));
            mx = fmaxf(mx, __shfl_xor_sync(0xffffffffu, mx, 2));
            if ((lane & 3) == 0) smx[row * 2 + (warp & 1)] = mx;
        }
    __syncthreads();
#pragma unroll
    for (int mi = 0; mi < 2; mi++)
#pragma unroll
        for (int hf = 0; hf < 2; hf++) {
            int row = mW2 + mi * 16 + (lane >> 2) + hf * 8;
            float m = fmaxf(smx[row * 2], smx[row * 2 + 1]);
            float s = 0.f;
#pragma unroll
            for (int ni = 0; ni < 18; ni++)
#pragma unroll
                for (int c = 0; c < 2; c++) {
                    int col = nW4 + ni * 8 + ((lane & 3) << 1) + c;
                    float e = (col < LLOC) ? __expf((sc[mi][ni][hf * 2 + c] - m) * scale) : 0.f;
                    sc[mi][ni][hf * 2 + c] = e;
                    s += e;
                }
            s += __shfl_xor_sync(0xffffffffu, s, 1);
            s += __shfl_xor_sync(0xffffffffu, s, 2);
            if ((lane & 3) == 0) ssu[row * 2 + (warp & 1)] = s;
        }
    __syncthreads();
#pragma unroll
    for (int mi = 0; mi < 2; mi++)
#pragma unroll
        for (int hf = 0; hf < 2; hf++) {
            int row = mW2 + mi * 16 + (lane >> 2) + hf * 8;
            float s = ssu[row * 2] + ssu[row * 2 + 1];
            float f = g_mraw[(size_t)z * SQ + q0 + row] * gden / s;
#pragma unroll
            for (int ni = 0; ni < 18; ni++) {
                int ucol = (nW4 >> 1) + ni * 4 + (lane & 3);
                if (ucol < 136)
                    plm[row * PLU + ucol] = pk2(sc[mi][ni][hf * 2] * f, sc[mi][ni][hf * 2 + 1] * f);
            }
        }
    CP_WAIT0;
    __syncthreads();   // plm writes + V arrival visible to all

    // PV: O[128][160] = P[128][272] @ Vl[272][160], V resident, sync-free
    int nW = (warp & 1) * 80;
    uint32_t sbP = (uint32_t)__cvta_generic_to_shared(plm);
    uint32_t sbV = (uint32_t)__cvta_generic_to_shared(vsm);
    int apr[2];
#pragma unroll
    for (int mi = 0; mi < 2; mi++) apr[mi] = mW2 + (mi << 4) + ((lm & 1) << 3) + lrow;
    int aco = (lm >> 1) << 2;
    int bvr[5];
#pragma unroll
    for (int np = 0; np < 5; np++) bvr[np] = nW + (np << 4) + ((lm >> 1) << 3) + lrow;
    int bco = (lm & 1) << 2;

    float oa[2][10][4];
#pragma unroll
    for (int a = 0; a < 2; a++)
#pragma unroll
        for (int b = 0; b < 10; b++)
#pragma unroll
            for (int c = 0; c < 4; c++) oa[a][b][c] = 0.f;

#pragma unroll 1
    for (int ch = 0; ch < 17; ch++) {
        int ka0 = ch * 8;
        uint32_t af[2][4], bf[10][2];
#pragma unroll
        for (int mi = 0; mi < 2; mi++)
            ldsm4(af[mi], sbP + ((uint32_t)(apr[mi] * PLU + ka0 + aco) << 2));
#pragma unroll
        for (int np = 0; np < 5; np++) {
            uint32_t r4[4];
            ldsm4(r4, sbV + ((uint32_t)(bvr[np] * VLU + ka0 + bco) << 2));
            bf[np * 2][0] = r4[0]; bf[np * 2][1] = r4[1];
            bf[np * 2 + 1][0] = r4[2]; bf[np * 2 + 1][1] = r4[3];
        }
#pragma unroll
        for (int mi = 0; mi < 2; mi++)
#pragma unroll
            for (int ni = 0; ni < 10; ni++) mma16(oa[mi][ni], af[mi], bf[ni]);
    }

    // epilogue: blend 0.5*pre + O
#pragma unroll
    for (int mi = 0; mi < 2; mi++)
#pragma unroll
        for (int hf = 0; hf < 2; hf++) {
            int g = q0 + mW2 + mi * 16 + (lane >> 2) + hf * 8;
            __half* prow = g_pre + ((size_t)(inst + 1) * SQ + g) * CHN + h * HD;
#pragma unroll
            for (int ni = 0; ni < 10; ni++) {
                int col = nW + (ni << 3) + ((lane & 3) << 1);
                __half2 old = *(__half2*)(prow + col);
                float o0 = 0.5f * __half2float(old.x) + oa[mi][ni][hf * 2];
                float o1 = 0.5f * __half2float(old.y) + oa[mi][ni][hf * 2 + 1];
                *(uint32_t*)(prow + col) = pk2(o0, o1);
            }
        }
}

// ---------------- fuser premix ----------------
__global__ void premix_k(const float* __restrict__ bbox) {
    int s = blockIdx.x;
    int y = s >> 6, x = s & 63;
    float wgt[8];
    wgt[0] = 1.f;
    float sw = 1.f;
    const int off[4] = {3, 4, 11, 12};
#pragma unroll
    for (int i = 0; i < 7; i++) {
        float wmin = floorf(1024.f * bbox[i * 4 + 0]);
        float hmin = floorf(1024.f * bbox[i * 4 + 1]);
        float wmax = floorf(1024.f * bbox[i * 4 + 2]);
        float hmax = floorf(1024.f * bbox[i * 4 + 3]);
        float R = 0.f, Cv = 0.f;
#pragma unroll
        for (int j = 0; j < 4; j++) {
            float yy = (float)(16 * y + off[j]);
            float xx = (float)(16 * x + off[j]);
            if (yy >= hmin && yy < hmax) R += 0.25f;
            if (xx >= wmin && xx < wmax) Cv += 0.25f;
        }
        float g = 10.f * R * Cv;
        wgt[i + 1] = g;
        sw += g;
    }
    if (threadIdx.x == 0) g_sumw[s] = sw;
    for (int c = threadIdx.x; c < CHN; c += 256) {
        float acc = 0.f;
#pragma unroll
        for (int j = 0; j < 8; j++)
            acc += wgt[j] * __half2float(g_pre[((size_t)(1 + j) * SQ + s) * CHN + c]);
        g_mix[(size_t)s * CHN + c] = __float2half_rn(acc);
    }
}

// ---------------- launch ----------------
extern "C" void kernel_launch(void* const* d_in, const int* in_sizes, int n_in,
                              void* d_out, int out_size) {
    const float* hs   = (const float*)d_in[0];
    const float* ctx  = (const float*)d_in[1];
    const float* lf   = (const float*)d_in[2];
    const float* bbox = (const float*)d_in[3];
    const float* Wq   = (const float*)d_in[4];
    const float* Wk   = (const float*)d_in[5];
    const float* Wv   = (const float*)d_in[6];
    const float* Wkg  = (const float*)d_in[7];
    const float* Wvg  = (const float*)d_in[8];
    const float* Wkl  = (const float*)d_in[9];
    const float* Wvl  = (const float*)d_in[10];
    const float* Wout = (const float*)d_in[11];
    const float* bout = (const float*)d_in[12];
    const int*   lidx = (const int*)d_in[13];
    float* out = (float*)d_out;

    __half *hsH, *ctxH, *lfH, *WqT, *WkT, *WvT, *WkgT, *WvgT, *WklT, *WvlT, *WoutT;
    __half *vp, *vTp, *vlp, *vlTp;
    cudaGetSymbolAddress((void**)&hsH, g_hsH);
    cudaGetSymbolAddress((void**)&ctxH, g_ctxH);
    cudaGetSymbolAddress((void**)&lfH, g_lfH);
    cudaGetSymbolAddress((void**)&WqT, g_WqT);
    cudaGetSymbolAddress((void**)&WkT, g_WkT);
    cudaGetSymbolAddress((void**)&WvT, g_WvT);
    cudaGetSymbolAddress((void**)&WkgT, g_WkgT);
    cudaGetSymbolAddress((void**)&WvgT, g_WvgT);
    cudaGetSymbolAddress((void**)&WklT, g_WklT);
    cudaGetSymbolAddress((void**)&WvlT, g_WvlT);
    cudaGetSymbolAddress((void**)&WoutT, g_WoutT);
    cudaGetSymbolAddress((void**)&vp, g_v);
    cudaGetSymbolAddress((void**)&vTp, g_vT);
    cudaGetSymbolAddress((void**)&vlp, g_vl);
    cudaGetSymbolAddress((void**)&vlTp, g_vlT);

    const int smemA = (2 * 2048 * 2 + 128 * PSTU + 160 * PSTU + 512) * 4;
    const int smemL = (128 * PLU + 160 * VLU + 512) * 4;   // 163,840 B
    cudaFuncSetAttribute(fused_g_k, cudaFuncAttributeMaxDynamicSharedMemorySize, smemA);
    cudaFuncSetAttribute(fused_l2_k, cudaFuncAttributeMaxDynamicSharedMemorySize, smemL);
    cudaFuncSetAttribute(gemm_h, cudaFuncAttributeMaxDynamicSharedMemorySize, SMEM3);

    cudaStream_t sA = g_si.sA, sB = g_si.sB, sC = g_si.sC;
    dim3 tb(32, 8);

    setup_k<<<1, 32>>>(out);
    cudaEventRecord(g_si.evRoot, 0);
    cudaStreamWaitEvent(sA, g_si.evRoot, 0);
    cudaStreamWaitEvent(sB, g_si.evRoot, 0);
    cudaStreamWaitEvent(sC, g_si.evRoot, 0);

    long long nHs = 2LL * SQ * CHN, nCtx = (long long)NST * NCTX * CC, nLf = (long long)NSTR * LLOC * CC;

    // main track: hs -> WqT -> Q projection
    round_h<<<(int)((nHs / 8 + 255) / 256), 256>>>(hs, hsH, nHs);
    transpose_k<float><<<dim3(40, 40, 1), tb>>>(Wq, WqT, CHN, CHN, CHN, CHN, 0, 0);
    gemm_h<<<dim3(10, 64, 1), 256, SMEM3>>>(0, CHN, CHN, CHN, CHN, CHN, 1, nullptr);

    // track A: ctx -> K/V/Kg/Vg -> select -> vT
    round_h<<<(int)((nCtx / 8 + 255) / 256), 256, 0, sA>>>(ctx, ctxH, nCtx);
    transpose_k<float><<<dim3(40, 24, 1), tb, 0, sA>>>(Wk, WkT, CC, CHN, CHN, CC, 0, 0);
    transpose_k<float><<<dim3(40, 24, 1), tb, 0, sA>>>(Wv, WvT, CC, CHN, CHN, CC, 0, 0);
    transpose_k<float><<<dim3(40, 24, 1), tb, 0, sA>>>(Wkg, WkgT, CC, CHN, CHN, CC, 0, 0);
    transpose_k<float><<<dim3(40, 24, 1), tb, 0, sA>>>(Wvg, WvgT, CC, CHN, CHN, CC, 0, 0);
    gemm_h<<<dim3(10, 6, 4), 256, SMEM3, sA>>>(1, CHN, CC, CC, CC, CHN, 1, nullptr);
    kv_select_k<<<(NSTR * NCTX * CHN / 2 + 255) / 256, 256, 0, sA>>>(lidx);
    transpose_k<__half><<<dim3(40, 3, NST), tb, 0, sA>>>(vp, vTp, NCTX, CHN, CHN, NCTXP,
                                                         (long long)NCTX * CHN, (long long)CHN * NCTXP);
    cudaEventRecord(g_si.ev1, sA);

    // track B: lf -> Kl/Vl -> vlT
    round_h<<<(int)((nLf / 8 + 255) / 256), 256, 0, sB>>>(lf, lfH, nLf);
    transpose_k<float><<<dim3(40, 24, 1), tb, 0, sB>>>(Wkl, WklT, CC, CHN, CHN, CC, 0, 0);
    transpose_k<float><<<dim3(40, 24, 1), tb, 0, sB>>>(Wvl, WvlT, CC, CHN, CHN, CC, 0, 0);
    gemm_h<<<dim3(10, 17, 2), 256, SMEM3, sB>>>(5, CHN, CC, CC, CC, CHN, 1, nullptr);
    transpose_k<__half><<<dim3(40, 9, NSTR), tb, 0, sB>>>(vlp, vlTp, LLOC, CHN, CHN, LLOCP,
                                                          (long long)LLOC * CHN, (long long)CHN * LLOCP);
    cudaEventRecord(g_si.ev2, sB);

    // track C: Wout transpose
    transpose_k<float><<<dim3(40, 40, 1), tb, 0, sC>>>(Wout, WoutT, CHN, CHN, CHN, CHN, 0, 0);
    cudaEventRecord(g_si.ev3, sC);

    // global attention
    cudaStreamWaitEvent(0, g_si.ev1, 0);
    fused_g_k<<<dim3(32, 72), 256, smemA>>>(lidx);
    mmax_k<<<8, 256>>>();
    cudaEventRecord(g_si.evG, 0);

    // uncond out-projection (bias fused) concurrent with local attention
    cudaStreamWaitEvent(sA, g_si.evG, 0);
    cudaStreamWaitEvent(sA, g_si.ev3, 0);
    gemm_h<<<dim3(10, 32, 1), 256, SMEM3, sA>>>(7, CHN, CHN, CHN, CHN, CHN, 4, bout);
    cudaEventRecord(g_si.evO7, sA);

    // local attention (128-row q-tiles)
    cudaStreamWaitEvent(0, g_si.ev2, 0);
    fused_l2_k<<<dim3(32, 64), 256, smemL>>>();

    // premix + cond out-projection (bias+fuser fused)
    premix_k<<<SQ, 256>>>(bbox);
    cudaStreamWaitEvent(0, g_si.ev3, 0);
    gemm_h<<<dim3(10, 32, 1), 256, SMEM3>>>(8, CHN, CHN, CHN, CHN, CHN, 12, bout);

    // join stream A back into the capture-origin stream
    cudaStreamWaitEvent(0, g_si.evO7, 0);
}